// round 1
// baseline (speedup 1.0000x reference)
#include <cuda_runtime.h>
#include <math.h>

#define HEADS 8
#define DH    64
#define INNER 512
#define DIM   256
#define MSAH  128
#define MSAW  256
#define NTOK  (MSAH*MSAW)

// -------- scratch (static device globals; no runtime allocation) --------
__device__ float g_Q1 [(size_t)NTOK*INNER];
__device__ float g_KV1[(size_t)NTOK*2*INNER];
__device__ float g_Q2 [(size_t)NTOK*INNER];
__device__ float g_KV2[(size_t)NTOK*2*INNER];
__device__ float g_O1 [(size_t)NTOK*INNER];
__device__ float g_O2 [(size_t)NTOK*INNER];
__device__ float g_P2 [(size_t)HEADS*MSAW*MSAW];

// ======================= generic 128x128x8 SGEMM =======================
// C[M,N] = A[M,K] @ B[K,N]  (+ C if accumulate) (+ bias[N] if bias)
__global__ __launch_bounds__(256)
void sgemm_k(const float* __restrict__ A, const float* __restrict__ B,
             float* __restrict__ C, int M, int N, int K,
             int accumulate, const float* __restrict__ bias)
{
    __shared__ float As[8][128];
    __shared__ float Bs[8][128];
    const int tid = threadIdx.x;
    const int tx = tid & 15, ty = tid >> 4;
    const int bx = blockIdx.x, by = blockIdx.y;

    const float* Ab = A + (size_t)by * 128 * K;
    const float* Bb = B + (size_t)bx * 128;

    float acc[8][8];
#pragma unroll
    for (int i = 0; i < 8; i++)
#pragma unroll
        for (int j = 0; j < 8; j++) acc[i][j] = 0.f;

    const int arow = tid >> 1, acol = (tid & 1) * 4;   // A tile 128x8
    const int brow = tid >> 5, bcol = (tid & 31) * 4;  // B tile 8x128

    for (int k0 = 0; k0 < K; k0 += 8) {
        float4 a4 = *(const float4*)(Ab + (size_t)arow * K + k0 + acol);
        As[acol + 0][arow] = a4.x;
        As[acol + 1][arow] = a4.y;
        As[acol + 2][arow] = a4.z;
        As[acol + 3][arow] = a4.w;
        *(float4*)&Bs[brow][bcol] = *(const float4*)(Bb + (size_t)(k0 + brow) * N + bcol);
        __syncthreads();
#pragma unroll
        for (int k = 0; k < 8; k++) {
            float ra[8], rb[8];
            *(float4*)&ra[0] = *(const float4*)&As[k][ty * 8];
            *(float4*)&ra[4] = *(const float4*)&As[k][ty * 8 + 4];
            *(float4*)&rb[0] = *(const float4*)&Bs[k][tx * 8];
            *(float4*)&rb[4] = *(const float4*)&Bs[k][tx * 8 + 4];
#pragma unroll
            for (int i = 0; i < 8; i++)
#pragma unroll
                for (int j = 0; j < 8; j++)
                    acc[i][j] = fmaf(ra[i], rb[j], acc[i][j]);
        }
        __syncthreads();
    }

#pragma unroll
    for (int i = 0; i < 8; i++) {
        const int row = by * 128 + ty * 8 + i;
        float* Crow = C + (size_t)row * N + bx * 128 + tx * 8;
#pragma unroll
        for (int j = 0; j < 8; j++) {
            float v = acc[i][j];
            if (bias)       v += bias[bx * 128 + tx * 8 + j];
            if (accumulate) v += Crow[j];
            Crow[j] = v;
        }
    }
}

// ================= column attention: one block per (w, head) =================
// seq over h (128 tokens). q/k/v rows at n = h*MSAW + w.
#define COL_SMEM ((128*65 + 128*64 + 128*64 + 128*129) * 4)
__global__ __launch_bounds__(128)
void col_attn(const float* __restrict__ Q, const float* __restrict__ KV,
              float* __restrict__ O)
{
    extern __shared__ float sm[];
    float* qs = sm;                  // 128 x 65 (padded)
    float* ks = sm + 128 * 65;       // 128 x 64
    float* vs = ks + 128 * 64;       // 128 x 64
    float* ps = vs + 128 * 64;       // 128 x 129 (padded)

    const int wi = blockIdx.x, head = blockIdx.y;
    const int tid = threadIdx.x;

    for (int t = tid; t < 128 * 16; t += 128) {
        const int row = t >> 4, c4 = (t & 15) << 2;
        const float4 q4 = *(const float4*)(Q + ((size_t)(row * MSAW + wi)) * INNER + head * DH + c4);
        qs[row * 65 + c4 + 0] = q4.x;
        qs[row * 65 + c4 + 1] = q4.y;
        qs[row * 65 + c4 + 2] = q4.z;
        qs[row * 65 + c4 + 3] = q4.w;
        const float* kvp = KV + ((size_t)(row * MSAW + wi)) * (2 * INNER) + head * DH + c4;
        *(float4*)&ks[row * 64 + c4] = *(const float4*)kvp;
        *(float4*)&vs[row * 64 + c4] = *(const float4*)(kvp + INNER);
    }
    __syncthreads();

    const int i = tid;
    float qreg[64];
#pragma unroll
    for (int d = 0; d < 64; d++) qreg[d] = qs[i * 65 + d];

    const float scale = 0.125f;  // 64^-0.5
    float m = -1e30f;
    for (int j = 0; j < 128; j++) {
        float a0 = 0.f, a1 = 0.f, a2 = 0.f, a3 = 0.f;
#pragma unroll
        for (int d4 = 0; d4 < 16; d4++) {
            const float4 kk = *(const float4*)&ks[j * 64 + d4 * 4];
            a0 = fmaf(qreg[d4 * 4 + 0], kk.x, a0);
            a1 = fmaf(qreg[d4 * 4 + 1], kk.y, a1);
            a2 = fmaf(qreg[d4 * 4 + 2], kk.z, a2);
            a3 = fmaf(qreg[d4 * 4 + 3], kk.w, a3);
        }
        const float dot = ((a0 + a1) + (a2 + a3)) * scale;
        ps[i * 129 + j] = dot;
        m = fmaxf(m, dot);
    }
    float s = 0.f;
    for (int j = 0; j < 128; j++) {
        const float e = __expf(ps[i * 129 + j] - m);
        ps[i * 129 + j] = e;
        s += e;
    }
    const float inv = 1.f / s;

    float acc[64];
#pragma unroll
    for (int d = 0; d < 64; d++) acc[d] = 0.f;
    for (int j = 0; j < 128; j++) {
        const float pj = ps[i * 129 + j] * inv;
#pragma unroll
        for (int d4 = 0; d4 < 16; d4++) {
            const float4 vv = *(const float4*)&vs[j * 64 + d4 * 4];
            acc[d4 * 4 + 0] = fmaf(pj, vv.x, acc[d4 * 4 + 0]);
            acc[d4 * 4 + 1] = fmaf(pj, vv.y, acc[d4 * 4 + 1]);
            acc[d4 * 4 + 2] = fmaf(pj, vv.z, acc[d4 * 4 + 2]);
            acc[d4 * 4 + 3] = fmaf(pj, vv.w, acc[d4 * 4 + 3]);
        }
    }
    float* op = O + ((size_t)(i * MSAW + wi)) * INNER + head * DH;
#pragma unroll
    for (int d4 = 0; d4 < 16; d4++)
        *(float4*)(op + d4 * 4) = make_float4(acc[d4 * 4 + 0], acc[d4 * 4 + 1],
                                              acc[d4 * 4 + 2], acc[d4 * 4 + 3]);
}

// ========== tied-row attention: dots[H,i,j] = ts * sum_{r,d} q k ==========
// grid (jtile=4, itile=4, head=8); 64x64 output tile, contracting r(128)*d(64)
__global__ __launch_bounds__(256)
void row_dots(const float* __restrict__ Q, const float* __restrict__ KV,
              float* __restrict__ S)
{
    __shared__ float As[64 * 64];  // [d][i]
    __shared__ float Bs[64 * 64];  // [d][j]
    const int j0 = blockIdx.x * 64, i0 = blockIdx.y * 64, head = blockIdx.z;
    const int tid = threadIdx.x, tx = tid & 15, ty = tid >> 4;

    float acc[4][4];
#pragma unroll
    for (int a = 0; a < 4; a++)
#pragma unroll
        for (int b = 0; b < 4; b++) acc[a][b] = 0.f;

    for (int r = 0; r < MSAH; r++) {
        for (int t = tid; t < 64 * 16; t += 256) {
            const int rr = t >> 4, c4 = (t & 15) << 2;
            const float4 q4 = *(const float4*)(Q + ((size_t)(r * MSAW + i0 + rr)) * INNER + head * DH + c4);
            As[(c4 + 0) * 64 + rr] = q4.x;
            As[(c4 + 1) * 64 + rr] = q4.y;
            As[(c4 + 2) * 64 + rr] = q4.z;
            As[(c4 + 3) * 64 + rr] = q4.w;
            const float4 k4 = *(const float4*)(KV + ((size_t)(r * MSAW + j0 + rr)) * (2 * INNER) + head * DH + c4);
            Bs[(c4 + 0) * 64 + rr] = k4.x;
            Bs[(c4 + 1) * 64 + rr] = k4.y;
            Bs[(c4 + 2) * 64 + rr] = k4.z;
            Bs[(c4 + 3) * 64 + rr] = k4.w;
        }
        __syncthreads();
#pragma unroll 8
        for (int d = 0; d < 64; d++) {
            float ra[4], rb[4];
            *(float4*)ra = *(const float4*)&As[d * 64 + ty * 4];
            *(float4*)rb = *(const float4*)&Bs[d * 64 + tx * 4];
#pragma unroll
            for (int a = 0; a < 4; a++)
#pragma unroll
                for (int b = 0; b < 4; b++)
                    acc[a][b] = fmaf(ra[a], rb[b], acc[a][b]);
        }
        __syncthreads();
    }
    const float ts = 0.011048543456039806f;  // (1/8) * 128^-0.5
#pragma unroll
    for (int a = 0; a < 4; a++)
#pragma unroll
        for (int b = 0; b < 4; b++)
            S[(size_t)head * (MSAW * MSAW) + (size_t)(i0 + ty * 4 + a) * MSAW + (j0 + tx * 4 + b)]
                = acc[a][b] * ts;
}

// softmax over last dim (256) of P[2048][256], in place
__global__ __launch_bounds__(256)
void softmax_rows(float* __restrict__ P)
{
    const int row = blockIdx.x, tid = threadIdx.x;
    __shared__ float red[34];
    const float v = P[(size_t)row * MSAW + tid];
    float m = v;
#pragma unroll
    for (int o = 16; o; o >>= 1) m = fmaxf(m, __shfl_xor_sync(0xffffffffu, m, o));
    if ((tid & 31) == 0) red[tid >> 5] = m;
    __syncthreads();
    if (tid == 0) {
        float mm = red[0];
#pragma unroll
        for (int w = 1; w < 8; w++) mm = fmaxf(mm, red[w]);
        red[32] = mm;
    }
    __syncthreads();
    const float e = __expf(v - red[32]);
    float s = e;
#pragma unroll
    for (int o = 16; o; o >>= 1) s += __shfl_xor_sync(0xffffffffu, s, o);
    if ((tid & 31) == 0) red[8 + (tid >> 5)] = s;
    __syncthreads();
    if (tid == 0) {
        float ss = 0.f;
#pragma unroll
        for (int w = 0; w < 8; w++) ss += red[8 + w];
        red[33] = 1.f / ss;
    }
    __syncthreads();
    P[(size_t)row * MSAW + tid] = e * red[33];
}

// o[r,i,H,d] = sum_j P[H,i,j] * v[r,j,H,d]   grid (itile=4, head=8, r=128)
__global__ __launch_bounds__(256)
void row_av(const float* __restrict__ P, const float* __restrict__ KV,
            float* __restrict__ O)
{
    __shared__ float Ps[64 * 64];  // [j][i]
    __shared__ float Vs[64 * 64];  // [j][d]
    const int i0 = blockIdx.x * 64, head = blockIdx.y, r = blockIdx.z;
    const int tid = threadIdx.x, tx = tid & 15, ty = tid >> 4;

    float acc[4][4];
#pragma unroll
    for (int a = 0; a < 4; a++)
#pragma unroll
        for (int b = 0; b < 4; b++) acc[a][b] = 0.f;

    for (int j0 = 0; j0 < MSAW; j0 += 64) {
        for (int t = tid; t < 64 * 16; t += 256) {
            const int a = t >> 4, c4 = (t & 15) << 2;
            const float4 p4 = *(const float4*)(P + (size_t)head * (MSAW * MSAW)
                                               + (size_t)(i0 + a) * MSAW + j0 + c4);
            Ps[(c4 + 0) * 64 + a] = p4.x;
            Ps[(c4 + 1) * 64 + a] = p4.y;
            Ps[(c4 + 2) * 64 + a] = p4.z;
            Ps[(c4 + 3) * 64 + a] = p4.w;
            *(float4*)&Vs[a * 64 + c4] =
                *(const float4*)(KV + ((size_t)(r * MSAW + j0 + a)) * (2 * INNER) + INNER + head * DH + c4);
        }
        __syncthreads();
#pragma unroll 8
        for (int j = 0; j < 64; j++) {
            float ra[4], rb[4];
            *(float4*)ra = *(const float4*)&Ps[j * 64 + ty * 4];
            *(float4*)rb = *(const float4*)&Vs[j * 64 + tx * 4];
#pragma unroll
            for (int a = 0; a < 4; a++)
#pragma unroll
                for (int b = 0; b < 4; b++)
                    acc[a][b] = fmaf(ra[a], rb[b], acc[a][b]);
        }
        __syncthreads();
    }
#pragma unroll
    for (int a = 0; a < 4; a++) {
        float* op = O + ((size_t)(r * MSAW + i0 + ty * 4 + a)) * INNER + head * DH + tx * 4;
        *(float4*)op = make_float4(acc[a][0], acc[a][1], acc[a][2], acc[a][3]);
    }
}

// =============================== launch ===============================
extern "C" void kernel_launch(void* const* d_in, const int* in_sizes, int n_in,
                              void* d_out, int out_size)
{
    const float* x      = (const float*)d_in[0];
    const float* wq_w   = (const float*)d_in[1];
    const float* wkv_w  = (const float*)d_in[2];
    const float* wout_w = (const float*)d_in[3];
    const float* wout_b = (const float*)d_in[4];
    const float* hq_w   = (const float*)d_in[5];
    const float* hkv_w  = (const float*)d_in[6];
    const float* hout_w = (const float*)d_in[7];
    const float* hout_b = (const float*)d_in[8];
    float* out = (float*)d_out;

    void* p;
    float *Q1, *KV1, *Q2, *KV2, *O1, *O2, *P2;
    cudaGetSymbolAddress(&p, g_Q1);  Q1  = (float*)p;
    cudaGetSymbolAddress(&p, g_KV1); KV1 = (float*)p;
    cudaGetSymbolAddress(&p, g_Q2);  Q2  = (float*)p;
    cudaGetSymbolAddress(&p, g_KV2); KV2 = (float*)p;
    cudaGetSymbolAddress(&p, g_O1);  O1  = (float*)p;
    cudaGetSymbolAddress(&p, g_O2);  O2  = (float*)p;
    cudaGetSymbolAddress(&p, g_P2);  P2  = (float*)p;

    cudaFuncSetAttribute(col_attn, cudaFuncAttributeMaxDynamicSharedMemorySize, COL_SMEM);

    // projections
    sgemm_k<<<dim3(INNER / 128, NTOK / 128), 256>>>(x, wq_w,  Q1,  NTOK, INNER,     DIM, 0, nullptr);
    sgemm_k<<<dim3(2 * INNER / 128, NTOK / 128), 256>>>(x, wkv_w, KV1, NTOK, 2 * INNER, DIM, 0, nullptr);
    sgemm_k<<<dim3(INNER / 128, NTOK / 128), 256>>>(x, hq_w,  Q2,  NTOK, INNER,     DIM, 0, nullptr);
    sgemm_k<<<dim3(2 * INNER / 128, NTOK / 128), 256>>>(x, hkv_w, KV2, NTOK, 2 * INNER, DIM, 0, nullptr);

    // column attention (per w, per head)
    col_attn<<<dim3(MSAW, HEADS), 128, COL_SMEM>>>(Q1, KV1, O1);

    // tied row attention
    row_dots<<<dim3(4, 4, HEADS), 256>>>(Q2, KV2, P2);
    softmax_rows<<<HEADS * MSAW, 256>>>(P2);
    row_av<<<dim3(4, HEADS, MSAH), 256>>>(P2, KV2, O2);

    // output projections: out = O1@wout + wout_b, then += O2@hout + hout_b
    sgemm_k<<<dim3(DIM / 128, NTOK / 128), 256>>>(O1, wout_w, out, NTOK, DIM, INNER, 0, wout_b);
    sgemm_k<<<dim3(DIM / 128, NTOK / 128), 256>>>(O2, hout_w, out, NTOK, DIM, INNER, 1, hout_b);
}

// round 3
// speedup vs baseline: 2.2938x; 2.2938x over previous
#include <cuda_runtime.h>
#include <cuda_bf16.h>
#include <math.h>
#include <cstdint>

#define HEADS 8
#define DH    64
#define INNER 512
#define DIM   256
#define MSAH  128
#define MSAW  256
#define NTOK  (MSAH*MSAW)

// -------- scratch (static device globals; no runtime allocation) --------
__device__ float g_Q1 [(size_t)NTOK*INNER];
__device__ float g_KV1[(size_t)NTOK*2*INNER];
__device__ float g_Q2 [(size_t)NTOK*INNER];
__device__ float g_KV2[(size_t)NTOK*2*INNER];
__device__ float g_O1 [(size_t)NTOK*INNER];
__device__ float g_O2 [(size_t)NTOK*INNER];
__device__ float g_P2 [(size_t)HEADS*MSAW*MSAW];          // softmaxed probs
__device__ float g_Pp [(size_t)32*MSAW*MSAW];             // dots split-K partials

// ===================== warp-MMA helpers (base-target PTX) =====================
__device__ __forceinline__ uint32_t smem_u32(const void* p) {
    uint32_t a;
    asm("{ .reg .u64 t; cvta.to.shared.u64 t, %1; cvt.u32.u64 %0, t; }" : "=r"(a) : "l"(p));
    return a;
}
__device__ __forceinline__ void ldsm4(uint32_t& r0, uint32_t& r1, uint32_t& r2, uint32_t& r3, uint32_t a) {
    asm volatile("ldmatrix.sync.aligned.m8n8.x4.shared.b16 {%0,%1,%2,%3}, [%4];"
                 : "=r"(r0), "=r"(r1), "=r"(r2), "=r"(r3) : "r"(a));
}
__device__ __forceinline__ void ldsm2(uint32_t& r0, uint32_t& r1, uint32_t a) {
    asm volatile("ldmatrix.sync.aligned.m8n8.x2.shared.b16 {%0,%1}, [%2];"
                 : "=r"(r0), "=r"(r1) : "r"(a));
}
__device__ __forceinline__ void ldsm2t(uint32_t& r0, uint32_t& r1, uint32_t a) {
    asm volatile("ldmatrix.sync.aligned.m8n8.x2.trans.shared.b16 {%0,%1}, [%2];"
                 : "=r"(r0), "=r"(r1) : "r"(a));
}
__device__ __forceinline__ void mma16816(float* c, uint32_t a0, uint32_t a1, uint32_t a2, uint32_t a3,
                                         uint32_t b0, uint32_t b1) {
    asm volatile("mma.sync.aligned.m16n8k16.row.col.f32.bf16.bf16.f32 "
                 "{%0,%1,%2,%3}, {%4,%5,%6,%7}, {%8,%9}, {%0,%1,%2,%3};"
                 : "+f"(c[0]), "+f"(c[1]), "+f"(c[2]), "+f"(c[3])
                 : "r"(a0), "r"(a1), "r"(a2), "r"(a3), "r"(b0), "r"(b1));
}
__device__ __forceinline__ uint32_t pack_hi(float x, float y) {
    __nv_bfloat162 h = __floats2bfloat162_rn(x, y);
    return *(uint32_t*)&h;
}
__device__ __forceinline__ void split2(float v, __nv_bfloat16& h, __nv_bfloat16& l) {
    h = __float2bfloat16(v);
    l = __float2bfloat16(v - __bfloat162float(h));
}

// ================= generic bf16x3 mma GEMM core =================
// C[TM,TN] += A@B. A global: element (m,k) at Ab + m*sAr + (k>>6)*sAk + (k&63).
// B global: BT=1: element (k,n) at Bb + k*sBr + n  (n contiguous)
//           BT=0: element (n,k) at Bb + n*sBr + (k>>6)*sBk + (k&63)
// Warp tile 64x32. TM=WM*64, TN=WN*32. THREADS=WM*WN*32.
template<int WM, int WN, int BT>
__device__ __forceinline__ void gemm_core(
    const float* __restrict__ Ab, size_t sAr, size_t sAk,
    const float* __restrict__ Bb, size_t sBr, size_t sBk,
    float* __restrict__ Cb, int ldc, int K,
    const float* __restrict__ bias, int accum)
{
    constexpr int TM = WM * 64, TN = WN * 32;
    constexpr int THREADS = WM * WN * 32;
    constexpr int AP = 24;                       // A smem pitch (halves) = 48B, 16B-aligned, conflict-free
    constexpr int BP = BT ? (TN + 8) : 24;       // B smem pitch (halves)
    constexpr int AHALF = TM * AP;               // halves per A buffer (hi or lo)
    constexpr int BHALF = BT ? 16 * BP : TN * 24;
    constexpr int STAGE = 2 * AHALF + 2 * BHALF; // halves per stage
    constexpr int NA4 = TM * 4 / THREADS;        // float4 A loads / thread
    constexpr int NB4 = (BT ? 16 * (TN / 4) : TN * 4) / THREADS;
    constexpr int TN4 = TN / 4;

    extern __shared__ __nv_bfloat16 smn[];

    const int tid = threadIdx.x, warp = tid >> 5, lane = tid & 31;
    const int wm = warp / WN, wn = warp % WN;

    float c[4][4][4];
#pragma unroll
    for (int mt = 0; mt < 4; mt++)
#pragma unroll
        for (int nt = 0; nt < 4; nt++)
#pragma unroll
            for (int e = 0; e < 4; e++) c[mt][nt][e] = 0.f;

    float4 ra[NA4], rb[NB4];

    auto loadA = [&](int cc) {
        const int k0 = cc * 16;
        const size_t cb = (size_t)(k0 >> 6) * sAk + (k0 & 63);
#pragma unroll
        for (int i = 0; i < NA4; i++) {
            const int idx = i * THREADS + tid;
            const int row = idx >> 2, q = idx & 3;
            ra[i] = *(const float4*)(Ab + (size_t)row * sAr + cb + q * 4);
        }
    };
    auto loadB = [&](int cc) {
        const int k0 = cc * 16;
#pragma unroll
        for (int i = 0; i < NB4; i++) {
            const int idx = i * THREADS + tid;
            if (BT) {
                const int kr = idx / TN4, q = idx % TN4;
                rb[i] = *(const float4*)(Bb + (size_t)(k0 + kr) * sBr + q * 4);
            } else {
                const int nr = idx >> 2, q = idx & 3;
                rb[i] = *(const float4*)(Bb + (size_t)nr * sBr
                                         + (size_t)(k0 >> 6) * sBk + (k0 & 63) + q * 4);
            }
        }
    };
    auto storeA = [&](int s) {
        __nv_bfloat16* Ah = smn + (size_t)s * STAGE;
        __nv_bfloat16* Al = Ah + AHALF;
#pragma unroll
        for (int i = 0; i < NA4; i++) {
            const int idx = i * THREADS + tid;
            const int row = idx >> 2, q = idx & 3;
            const float4 v = ra[i];
            __nv_bfloat16 hx, lx, hy, ly, hz, lz, hw, lw;
            split2(v.x, hx, lx); split2(v.y, hy, ly);
            split2(v.z, hz, lz); split2(v.w, hw, lw);
            const int off = row * AP + q * 4;
            *(uint32_t*)(Ah + off)     = pack_hi(__bfloat162float(hx), __bfloat162float(hy));
            *(uint32_t*)(Ah + off + 2) = pack_hi(__bfloat162float(hz), __bfloat162float(hw));
            *(uint32_t*)(Al + off)     = pack_hi(__bfloat162float(lx), __bfloat162float(ly));
            *(uint32_t*)(Al + off + 2) = pack_hi(__bfloat162float(lz), __bfloat162float(lw));
        }
    };
    auto storeB = [&](int s) {
        __nv_bfloat16* Bh = smn + (size_t)s * STAGE + 2 * AHALF;
        __nv_bfloat16* Bl = Bh + BHALF;
#pragma unroll
        for (int i = 0; i < NB4; i++) {
            const int idx = i * THREADS + tid;
            int off;
            if (BT) { const int kr = idx / TN4, q = idx % TN4; off = kr * BP + q * 4; }
            else    { const int nr = idx >> 2, q = idx & 3;    off = nr * 24 + q * 4; }
            const float4 v = rb[i];
            __nv_bfloat16 hx, lx, hy, ly, hz, lz, hw, lw;
            split2(v.x, hx, lx); split2(v.y, hy, ly);
            split2(v.z, hz, lz); split2(v.w, hw, lw);
            *(uint32_t*)(Bh + off)     = pack_hi(__bfloat162float(hx), __bfloat162float(hy));
            *(uint32_t*)(Bh + off + 2) = pack_hi(__bfloat162float(hz), __bfloat162float(hw));
            *(uint32_t*)(Bl + off)     = pack_hi(__bfloat162float(lx), __bfloat162float(ly));
            *(uint32_t*)(Bl + off + 2) = pack_hi(__bfloat162float(lz), __bfloat162float(lw));
        }
    };
    auto compute = [&](int s) {
        __nv_bfloat16* Ah = smn + (size_t)s * STAGE;
        __nv_bfloat16* Al = Ah + AHALF;
        __nv_bfloat16* Bh = smn + (size_t)s * STAGE + 2 * AHALF;
        __nv_bfloat16* Bl = Bh + BHALF;
        uint32_t ah[4][4], al[4][4], bh[4][2], bl[4][2];
#pragma unroll
        for (int mt = 0; mt < 4; mt++) {
            const int row = wm * 64 + mt * 16 + (lane & 15);
            const int ko = ((lane >> 4) & 1) * 8;
            ldsm4(ah[mt][0], ah[mt][1], ah[mt][2], ah[mt][3], smem_u32(Ah + row * AP + ko));
            ldsm4(al[mt][0], al[mt][1], al[mt][2], al[mt][3], smem_u32(Al + row * AP + ko));
        }
#pragma unroll
        for (int nt = 0; nt < 4; nt++) {
            if (BT) {
                const int k = (lane & 7) + ((lane >> 3) & 1) * 8;
                const int ncol = wn * 32 + nt * 8;
                ldsm2t(bh[nt][0], bh[nt][1], smem_u32(Bh + k * BP + ncol));
                ldsm2t(bl[nt][0], bl[nt][1], smem_u32(Bl + k * BP + ncol));
            } else {
                const int nrow = wn * 32 + nt * 8 + (lane & 7);
                const int ko = ((lane >> 3) & 1) * 8;
                ldsm2(bh[nt][0], bh[nt][1], smem_u32(Bh + nrow * 24 + ko));
                ldsm2(bl[nt][0], bl[nt][1], smem_u32(Bl + nrow * 24 + ko));
            }
        }
#pragma unroll
        for (int mt = 0; mt < 4; mt++)
#pragma unroll
            for (int nt = 0; nt < 4; nt++) {
                mma16816(c[mt][nt], ah[mt][0], ah[mt][1], ah[mt][2], ah[mt][3], bh[nt][0], bh[nt][1]);
                mma16816(c[mt][nt], ah[mt][0], ah[mt][1], ah[mt][2], ah[mt][3], bl[nt][0], bl[nt][1]);
                mma16816(c[mt][nt], al[mt][0], al[mt][1], al[mt][2], al[mt][3], bh[nt][0], bh[nt][1]);
            }
    };

    const int NC = K >> 4;
    loadA(0); loadB(0);
    storeA(0); storeB(0);
    __syncthreads();
    for (int cc = 0; cc < NC; cc++) {
        const int s = cc & 1;
        if (cc + 1 < NC) { loadA(cc + 1); loadB(cc + 1); }
        compute(s);
        if (cc + 1 < NC) { storeA(s ^ 1); storeB(s ^ 1); }
        __syncthreads();
    }

    // epilogue
    const int g = lane >> 2, tg = lane & 3;
#pragma unroll
    for (int mt = 0; mt < 4; mt++) {
#pragma unroll
        for (int nt = 0; nt < 4; nt++) {
            const int row0 = wm * 64 + mt * 16 + g;
            const int col = wn * 32 + nt * 8 + tg * 2;
            float2 v0 = make_float2(c[mt][nt][0], c[mt][nt][1]);
            float2 v1 = make_float2(c[mt][nt][2], c[mt][nt][3]);
            if (bias) {
                const float b0 = bias[col], b1 = bias[col + 1];
                v0.x += b0; v0.y += b1; v1.x += b0; v1.y += b1;
            }
            float* p0 = Cb + (size_t)row0 * ldc + col;
            float* p1 = Cb + (size_t)(row0 + 8) * ldc + col;
            if (accum) {
                const float2 o0 = *(float2*)p0, o1 = *(float2*)p1;
                v0.x += o0.x; v0.y += o0.y; v1.x += o1.x; v1.y += o1.y;
            }
            *(float2*)p0 = v0;
            *(float2*)p1 = v1;
        }
    }
}

// ---- wrappers ----
__global__ __launch_bounds__(256)
void gemm_proj(const float* __restrict__ A, const float* __restrict__ B,
               float* __restrict__ C, int N, int K, int accum, const float* __restrict__ bias)
{
    const int m0 = blockIdx.y * 128, n0 = blockIdx.x * 128;
    gemm_core<2, 4, 1>(A + (size_t)m0 * K, K, 64,
                       B + n0, N, 0,
                       C + (size_t)m0 * N + n0, N, K,
                       bias ? bias + n0 : nullptr, accum);
}

__global__ __launch_bounds__(256)
void gemm_dots(const float* __restrict__ Q, const float* __restrict__ KV, float* __restrict__ Pp)
{
    const int j0 = blockIdx.x * 128, i0 = blockIdx.y * 128;
    const int h = blockIdx.z >> 2, s = blockIdx.z & 3;
    const size_t r0 = (size_t)s * 32;
    gemm_core<2, 4, 0>(Q + (size_t)h * 64 + (size_t)i0 * INNER + r0 * MSAW * INNER,
                       INNER, (size_t)MSAW * INNER,
                       KV + (size_t)h * 64 + (size_t)j0 * 2 * INNER + r0 * MSAW * 2 * INNER,
                       2 * INNER, (size_t)MSAW * 2 * INNER,
                       Pp + (size_t)blockIdx.z * (MSAW * MSAW) + (size_t)i0 * MSAW + j0,
                       MSAW, 32 * 64, nullptr, 0);
}

__global__ __launch_bounds__(128)
void gemm_av(const float* __restrict__ P, const float* __restrict__ KV, float* __restrict__ O)
{
    const int i0 = blockIdx.x * 128;
    const int h = blockIdx.y, r = blockIdx.z;
    gemm_core<2, 2, 1>(P + (size_t)h * (MSAW * MSAW) + (size_t)i0 * MSAW, MSAW, 64,
                       KV + INNER + (size_t)h * 64 + (size_t)r * MSAW * 2 * INNER, 2 * INNER, 0,
                       O + ((size_t)r * MSAW + i0) * INNER + h * 64, INNER, MSAW,
                       nullptr, 0);
}

// smem sizes (bytes)
#define SM_PROJ ((2 * (2 * 128 * 24 + 2 * 16 * 136)) * 2)
#define SM_DOTS ((2 * (2 * 128 * 24 + 2 * 128 * 24)) * 2)
#define SM_AV   ((2 * (2 * 128 * 24 + 2 * 16 * 72)) * 2)

// ================= column attention (FFMA, unchanged) =================
#define COL_SMEM ((128*65 + 128*64 + 128*64 + 128*129) * 4)
__global__ __launch_bounds__(128)
void col_attn(const float* __restrict__ Q, const float* __restrict__ KV,
              float* __restrict__ O)
{
    extern __shared__ float smf[];
    float* qs = smf;
    float* ks = smf + 128 * 65;
    float* vs = ks + 128 * 64;
    float* ps = vs + 128 * 64;

    const int wi = blockIdx.x, head = blockIdx.y;
    const int tid = threadIdx.x;

    for (int t = tid; t < 128 * 16; t += 128) {
        const int row = t >> 4, c4 = (t & 15) << 2;
        const float4 q4 = *(const float4*)(Q + ((size_t)(row * MSAW + wi)) * INNER + head * DH + c4);
        qs[row * 65 + c4 + 0] = q4.x;
        qs[row * 65 + c4 + 1] = q4.y;
        qs[row * 65 + c4 + 2] = q4.z;
        qs[row * 65 + c4 + 3] = q4.w;
        const float* kvp = KV + ((size_t)(row * MSAW + wi)) * (2 * INNER) + head * DH + c4;
        *(float4*)&ks[row * 64 + c4] = *(const float4*)kvp;
        *(float4*)&vs[row * 64 + c4] = *(const float4*)(kvp + INNER);
    }
    __syncthreads();

    const int i = tid;
    float qreg[64];
#pragma unroll
    for (int d = 0; d < 64; d++) qreg[d] = qs[i * 65 + d];

    const float scale = 0.125f;
    float m = -1e30f;
    for (int j = 0; j < 128; j++) {
        float a0 = 0.f, a1 = 0.f, a2 = 0.f, a3 = 0.f;
#pragma unroll
        for (int d4 = 0; d4 < 16; d4++) {
            const float4 kk = *(const float4*)&ks[j * 64 + d4 * 4];
            a0 = fmaf(qreg[d4 * 4 + 0], kk.x, a0);
            a1 = fmaf(qreg[d4 * 4 + 1], kk.y, a1);
            a2 = fmaf(qreg[d4 * 4 + 2], kk.z, a2);
            a3 = fmaf(qreg[d4 * 4 + 3], kk.w, a3);
        }
        const float dot = ((a0 + a1) + (a2 + a3)) * scale;
        ps[i * 129 + j] = dot;
        m = fmaxf(m, dot);
    }
    float s = 0.f;
    for (int j = 0; j < 128; j++) {
        const float e = __expf(ps[i * 129 + j] - m);
        ps[i * 129 + j] = e;
        s += e;
    }
    const float inv = 1.f / s;

    float acc[64];
#pragma unroll
    for (int d = 0; d < 64; d++) acc[d] = 0.f;
    for (int j = 0; j < 128; j++) {
        const float pj = ps[i * 129 + j] * inv;
#pragma unroll
        for (int d4 = 0; d4 < 16; d4++) {
            const float4 vv = *(const float4*)&vs[j * 64 + d4 * 4];
            acc[d4 * 4 + 0] = fmaf(pj, vv.x, acc[d4 * 4 + 0]);
            acc[d4 * 4 + 1] = fmaf(pj, vv.y, acc[d4 * 4 + 1]);
            acc[d4 * 4 + 2] = fmaf(pj, vv.z, acc[d4 * 4 + 2]);
            acc[d4 * 4 + 3] = fmaf(pj, vv.w, acc[d4 * 4 + 3]);
        }
    }
    float* op = O + ((size_t)(i * MSAW + wi)) * INNER + head * DH;
#pragma unroll
    for (int d4 = 0; d4 < 16; d4++)
        *(float4*)(op + d4 * 4) = make_float4(acc[d4 * 4 + 0], acc[d4 * 4 + 1],
                                              acc[d4 * 4 + 2], acc[d4 * 4 + 3]);
}

// ============= reduce 4 dots partials + scale + softmax over j =============
__global__ __launch_bounds__(256)
void softmax_reduce(const float* __restrict__ Pp, float* __restrict__ P)
{
    const int h = blockIdx.x >> 8, i = blockIdx.x & 255;
    const int tid = threadIdx.x;
    __shared__ float red[34];
    float v = 0.f;
#pragma unroll
    for (int s = 0; s < 4; s++)
        v += Pp[((size_t)(h * 4 + s) * MSAW + i) * MSAW + tid];
    v *= 0.011048543456039806f;  // (1/8) * 128^-0.5

    float m = v;
#pragma unroll
    for (int o = 16; o; o >>= 1) m = fmaxf(m, __shfl_xor_sync(0xffffffffu, m, o));
    if ((tid & 31) == 0) red[tid >> 5] = m;
    __syncthreads();
    if (tid == 0) {
        float mm = red[0];
#pragma unroll
        for (int w = 1; w < 8; w++) mm = fmaxf(mm, red[w]);
        red[32] = mm;
    }
    __syncthreads();
    const float e = __expf(v - red[32]);
    float s = e;
#pragma unroll
    for (int o = 16; o; o >>= 1) s += __shfl_xor_sync(0xffffffffu, s, o);
    if ((tid & 31) == 0) red[8 + (tid >> 5)] = s;
    __syncthreads();
    if (tid == 0) {
        float ss = 0.f;
#pragma unroll
        for (int w = 0; w < 8; w++) ss += red[8 + w];
        red[33] = 1.f / ss;
    }
    __syncthreads();
    P[((size_t)h * MSAW + i) * MSAW + tid] = e * red[33];
}

// =============================== launch ===============================
extern "C" void kernel_launch(void* const* d_in, const int* in_sizes, int n_in,
                              void* d_out, int out_size)
{
    const float* x      = (const float*)d_in[0];
    const float* wq_w   = (const float*)d_in[1];
    const float* wkv_w  = (const float*)d_in[2];
    const float* wout_w = (const float*)d_in[3];
    const float* wout_b = (const float*)d_in[4];
    const float* hq_w   = (const float*)d_in[5];
    const float* hkv_w  = (const float*)d_in[6];
    const float* hout_w = (const float*)d_in[7];
    const float* hout_b = (const float*)d_in[8];
    float* out = (float*)d_out;

    void* p;
    float *Q1, *KV1, *Q2, *KV2, *O1, *O2, *P2, *Pp;
    cudaGetSymbolAddress(&p, g_Q1);  Q1  = (float*)p;
    cudaGetSymbolAddress(&p, g_KV1); KV1 = (float*)p;
    cudaGetSymbolAddress(&p, g_Q2);  Q2  = (float*)p;
    cudaGetSymbolAddress(&p, g_KV2); KV2 = (float*)p;
    cudaGetSymbolAddress(&p, g_O1);  O1  = (float*)p;
    cudaGetSymbolAddress(&p, g_O2);  O2  = (float*)p;
    cudaGetSymbolAddress(&p, g_P2);  P2  = (float*)p;
    cudaGetSymbolAddress(&p, g_Pp);  Pp  = (float*)p;

    cudaFuncSetAttribute(col_attn,  cudaFuncAttributeMaxDynamicSharedMemorySize, COL_SMEM);
    cudaFuncSetAttribute(gemm_proj, cudaFuncAttributeMaxDynamicSharedMemorySize, SM_PROJ);
    cudaFuncSetAttribute(gemm_dots, cudaFuncAttributeMaxDynamicSharedMemorySize, SM_DOTS);
    cudaFuncSetAttribute(gemm_av,   cudaFuncAttributeMaxDynamicSharedMemorySize, SM_AV);

    // projections (tensor path)
    gemm_proj<<<dim3(INNER / 128, NTOK / 128), 256, SM_PROJ>>>(x, wq_w,  Q1,  INNER,     DIM, 0, nullptr);
    gemm_proj<<<dim3(2 * INNER / 128, NTOK / 128), 256, SM_PROJ>>>(x, wkv_w, KV1, 2 * INNER, DIM, 0, nullptr);
    gemm_proj<<<dim3(INNER / 128, NTOK / 128), 256, SM_PROJ>>>(x, hq_w,  Q2,  INNER,     DIM, 0, nullptr);
    gemm_proj<<<dim3(2 * INNER / 128, NTOK / 128), 256, SM_PROJ>>>(x, hkv_w, KV2, 2 * INNER, DIM, 0, nullptr);

    // column attention
    col_attn<<<dim3(MSAW, HEADS), 128, COL_SMEM>>>(Q1, KV1, O1);

    // tied row attention
    gemm_dots<<<dim3(2, 2, 32), 256, SM_DOTS>>>(Q2, KV2, Pp);
    softmax_reduce<<<HEADS * MSAW, 256>>>(Pp, P2);
    gemm_av<<<dim3(2, HEADS, MSAH), 128, SM_AV>>>(P2, KV2, O2);

    // output projections
    gemm_proj<<<dim3(DIM / 128, NTOK / 128), 256, SM_PROJ>>>(O1, wout_w, out, DIM, INNER, 0, wout_b);
    gemm_proj<<<dim3(DIM / 128, NTOK / 128), 256, SM_PROJ>>>(O2, hout_w, out, DIM, INNER, 1, hout_b);
}

// round 4
// speedup vs baseline: 3.1646x; 1.3796x over previous
#include <cuda_runtime.h>
#include <cuda_bf16.h>
#include <math.h>
#include <cstdint>

#define HEADS 8
#define DH    64
#define INNER 512
#define DIM   256
#define MSAH  128
#define MSAW  256
#define NTOK  (MSAH*MSAW)

typedef __nv_bfloat16 bf16;

// -------- scratch (static device globals; no runtime allocation) --------
__device__ bf16 g_xh [(size_t)NTOK*DIM],      g_xl [(size_t)NTOK*DIM];
__device__ bf16 g_wqh [(size_t)DIM*INNER],    g_wql [(size_t)DIM*INNER];
__device__ bf16 g_wkvh[(size_t)DIM*2*INNER],  g_wkvl[(size_t)DIM*2*INNER];
__device__ bf16 g_hqh [(size_t)DIM*INNER],    g_hql [(size_t)DIM*INNER];
__device__ bf16 g_hkvh[(size_t)DIM*2*INNER],  g_hkvl[(size_t)DIM*2*INNER];
__device__ bf16 g_wouth[(size_t)INNER*DIM],   g_woutl[(size_t)INNER*DIM];
__device__ bf16 g_houth[(size_t)INNER*DIM],   g_houtl[(size_t)INNER*DIM];
__device__ bf16 g_q1h [(size_t)NTOK*INNER],   g_q1l [(size_t)NTOK*INNER];
__device__ bf16 g_kv1h[(size_t)NTOK*2*INNER], g_kv1l[(size_t)NTOK*2*INNER];
__device__ bf16 g_q2h [(size_t)NTOK*INNER],   g_q2l [(size_t)NTOK*INNER];
__device__ bf16 g_kv2h[(size_t)NTOK*2*INNER], g_kv2l[(size_t)NTOK*2*INNER];
__device__ bf16 g_o1h [(size_t)NTOK*INNER],   g_o1l [(size_t)NTOK*INNER];
__device__ bf16 g_o2h [(size_t)NTOK*INNER],   g_o2l [(size_t)NTOK*INNER];
__device__ bf16 g_p2h [(size_t)HEADS*MSAW*MSAW], g_p2l [(size_t)HEADS*MSAW*MSAW];
__device__ float g_Pp [(size_t)32*MSAW*MSAW];

// ===================== helpers =====================
__device__ __forceinline__ uint32_t smem_u32(const void* p) {
    uint32_t a;
    asm("{ .reg .u64 t; cvta.to.shared.u64 t, %1; cvt.u32.u64 %0, t; }" : "=r"(a) : "l"(p));
    return a;
}
__device__ __forceinline__ void ldsm4(uint32_t& r0, uint32_t& r1, uint32_t& r2, uint32_t& r3, uint32_t a) {
    asm volatile("ldmatrix.sync.aligned.m8n8.x4.shared.b16 {%0,%1,%2,%3}, [%4];"
                 : "=r"(r0), "=r"(r1), "=r"(r2), "=r"(r3) : "r"(a));
}
__device__ __forceinline__ void ldsm2(uint32_t& r0, uint32_t& r1, uint32_t a) {
    asm volatile("ldmatrix.sync.aligned.m8n8.x2.shared.b16 {%0,%1}, [%2];"
                 : "=r"(r0), "=r"(r1) : "r"(a));
}
__device__ __forceinline__ void ldsm2t(uint32_t& r0, uint32_t& r1, uint32_t a) {
    asm volatile("ldmatrix.sync.aligned.m8n8.x2.trans.shared.b16 {%0,%1}, [%2];"
                 : "=r"(r0), "=r"(r1) : "r"(a));
}
__device__ __forceinline__ void mma16816(float* c, const uint32_t* a, const uint32_t* b) {
    asm volatile("mma.sync.aligned.m16n8k16.row.col.f32.bf16.bf16.f32 "
                 "{%0,%1,%2,%3}, {%4,%5,%6,%7}, {%8,%9}, {%0,%1,%2,%3};"
                 : "+f"(c[0]), "+f"(c[1]), "+f"(c[2]), "+f"(c[3])
                 : "r"(a[0]), "r"(a[1]), "r"(a[2]), "r"(a[3]), "r"(b[0]), "r"(b[1]));
}
__device__ __forceinline__ void split_pair(float a, float b, uint32_t& hi, uint32_t& lo) {
    bf16 ha = __float2bfloat16(a), hb = __float2bfloat16(b);
    bf16 la = __float2bfloat16(a - __bfloat162float(ha));
    bf16 lb = __float2bfloat16(b - __bfloat162float(hb));
    __nv_bfloat162 h2 = __halves2bfloat162(ha, hb);
    __nv_bfloat162 l2 = __halves2bfloat162(la, lb);
    hi = *(uint32_t*)&h2;
    lo = *(uint32_t*)&l2;
}

// ================= split fp32 -> bf16 hi/lo planes =================
__global__ __launch_bounds__(256)
void split_f32(const float* __restrict__ in, bf16* __restrict__ H, bf16* __restrict__ L, int n4)
{
    const int i = blockIdx.x * 256 + threadIdx.x;
    if (i >= n4) return;
    const float4 v = ((const float4*)in)[i];
    uint32_t h0, l0, h1, l1;
    split_pair(v.x, v.y, h0, l0);
    split_pair(v.z, v.w, h1, l1);
    *(uint2*)(H + (size_t)i * 4) = make_uint2(h0, h1);
    *(uint2*)(L + (size_t)i * 4) = make_uint2(l0, l1);
}

// ================= generic pre-split bf16x3 mma GEMM =================
// A planes: element (m,k) at m*sAr + (k>>6)*sAk + (k&63)   (halves)
// B planes: BT=1: (k,n) at k*sBr + n ; BT=0: (n,k) at n*sBr + (k>>6)*sBk + (k&63)
// OSPLIT=0: fp32 out (bias/accum).  OSPLIT=1: write hi/lo bf16 planes.
template<int WM, int WN, int BT, int OSPLIT>
__device__ __forceinline__ void gemm_core2(
    const bf16* __restrict__ Ah_, const bf16* __restrict__ Al_, size_t sAr, size_t sAk,
    const bf16* __restrict__ Bh_, const bf16* __restrict__ Bl_, size_t sBr, size_t sBk,
    float* __restrict__ Cf, bf16* __restrict__ Chp, bf16* __restrict__ Clp,
    int ldc, int K, const float* __restrict__ bias, int accum)
{
    constexpr int TM = WM * 64, TN = WN * 32;
    constexpr int THREADS = WM * WN * 32;
    constexpr int AP = 24;
    constexpr int BP = BT ? (TN + 8) : 24;
    constexpr int AH = TM * AP;
    constexpr int BH = BT ? 16 * BP : TN * 24;
    constexpr int STAGE = 2 * AH + 2 * BH;
    constexpr int NA = TM * 2 / THREADS;                 // uint4 loads per plane
    constexpr int NB = BT ? (2 * TN / THREADS) : (TN * 2 / THREADS);

    extern __shared__ bf16 smn[];
    const int tid = threadIdx.x, warp = tid >> 5, lane = tid & 31;
    const int wm = warp / WN, wn = warp % WN;

    float c[4][4][4];
#pragma unroll
    for (int mt = 0; mt < 4; mt++)
#pragma unroll
        for (int nt = 0; nt < 4; nt++)
#pragma unroll
            for (int e = 0; e < 4; e++) c[mt][nt][e] = 0.f;

    uint4 rah[NA], ral[NA], rbh[NB], rbl[NB];

    auto loadA = [&](int cc) {
        const int k0 = cc * 16;
        const size_t cb = (size_t)(k0 >> 6) * sAk + (k0 & 63);
#pragma unroll
        for (int i = 0; i < NA; i++) {
            const int idx = i * THREADS + tid;
            const int row = idx >> 1, g = (idx & 1) * 8;
            const size_t off = (size_t)row * sAr + cb + g;
            rah[i] = *(const uint4*)(Ah_ + off);
            ral[i] = *(const uint4*)(Al_ + off);
        }
    };
    auto loadB = [&](int cc) {
        const int k0 = cc * 16;
#pragma unroll
        for (int i = 0; i < NB; i++) {
            const int idx = i * THREADS + tid;
            size_t off;
            if (BT) {
                const int kr = idx / (TN / 8), q = idx % (TN / 8);
                off = (size_t)(k0 + kr) * sBr + q * 8;
            } else {
                const int nr = idx >> 1, g = (idx & 1) * 8;
                off = (size_t)nr * sBr + (size_t)(k0 >> 6) * sBk + (k0 & 63) + g;
            }
            rbh[i] = *(const uint4*)(Bh_ + off);
            rbl[i] = *(const uint4*)(Bl_ + off);
        }
    };
    auto storeA = [&](int s) {
        bf16* Ah = smn + (size_t)s * STAGE;
        bf16* Al = Ah + AH;
#pragma unroll
        for (int i = 0; i < NA; i++) {
            const int idx = i * THREADS + tid;
            const int row = idx >> 1, g = (idx & 1) * 8;
            *(uint4*)(Ah + row * AP + g) = rah[i];
            *(uint4*)(Al + row * AP + g) = ral[i];
        }
    };
    auto storeB = [&](int s) {
        bf16* Bh = smn + (size_t)s * STAGE + 2 * AH;
        bf16* Bl = Bh + BH;
#pragma unroll
        for (int i = 0; i < NB; i++) {
            const int idx = i * THREADS + tid;
            int off;
            if (BT) { const int kr = idx / (TN / 8), q = idx % (TN / 8); off = kr * BP + q * 8; }
            else    { const int nr = idx >> 1, g = (idx & 1) * 8;        off = nr * 24 + g; }
            *(uint4*)(Bh + off) = rbh[i];
            *(uint4*)(Bl + off) = rbl[i];
        }
    };
    auto compute = [&](int s) {
        bf16* Ah = smn + (size_t)s * STAGE;
        bf16* Al = Ah + AH;
        bf16* Bh = smn + (size_t)s * STAGE + 2 * AH;
        bf16* Bl = Bh + BH;
        uint32_t ah[4][4], al[4][4], bh[4][2], bl[4][2];
#pragma unroll
        for (int mt = 0; mt < 4; mt++) {
            const int row = wm * 64 + mt * 16 + (lane & 15);
            const int ko = ((lane >> 4) & 1) * 8;
            ldsm4(ah[mt][0], ah[mt][1], ah[mt][2], ah[mt][3], smem_u32(Ah + row * AP + ko));
            ldsm4(al[mt][0], al[mt][1], al[mt][2], al[mt][3], smem_u32(Al + row * AP + ko));
        }
#pragma unroll
        for (int nt = 0; nt < 4; nt++) {
            if (BT) {
                const int k = (lane & 7) + ((lane >> 3) & 1) * 8;
                const int ncol = wn * 32 + nt * 8;
                ldsm2t(bh[nt][0], bh[nt][1], smem_u32(Bh + k * BP + ncol));
                ldsm2t(bl[nt][0], bl[nt][1], smem_u32(Bl + k * BP + ncol));
            } else {
                const int nrow = wn * 32 + nt * 8 + (lane & 7);
                const int ko = ((lane >> 3) & 1) * 8;
                ldsm2(bh[nt][0], bh[nt][1], smem_u32(Bh + nrow * 24 + ko));
                ldsm2(bl[nt][0], bl[nt][1], smem_u32(Bl + nrow * 24 + ko));
            }
        }
#pragma unroll
        for (int mt = 0; mt < 4; mt++)
#pragma unroll
            for (int nt = 0; nt < 4; nt++) {
                mma16816(c[mt][nt], ah[mt], bh[nt]);
                mma16816(c[mt][nt], ah[mt], bl[nt]);
                mma16816(c[mt][nt], al[mt], bh[nt]);
            }
    };

    const int NC = K >> 4;
    loadA(0); loadB(0);
    storeA(0); storeB(0);
    __syncthreads();
    for (int cc = 0; cc < NC; cc++) {
        const int s = cc & 1;
        if (cc + 1 < NC) { loadA(cc + 1); loadB(cc + 1); }
        compute(s);
        if (cc + 1 < NC) { storeA(s ^ 1); storeB(s ^ 1); }
        __syncthreads();
    }

    const int g = lane >> 2, tg = lane & 3;
#pragma unroll
    for (int mt = 0; mt < 4; mt++) {
#pragma unroll
        for (int nt = 0; nt < 4; nt++) {
            const int row0 = wm * 64 + mt * 16 + g;
            const int col = wn * 32 + nt * 8 + tg * 2;
            float2 v0 = make_float2(c[mt][nt][0], c[mt][nt][1]);
            float2 v1 = make_float2(c[mt][nt][2], c[mt][nt][3]);
            if (OSPLIT) {
                uint32_t h0, l0, h1, l1;
                split_pair(v0.x, v0.y, h0, l0);
                split_pair(v1.x, v1.y, h1, l1);
                *(uint32_t*)(Chp + (size_t)row0 * ldc + col) = h0;
                *(uint32_t*)(Clp + (size_t)row0 * ldc + col) = l0;
                *(uint32_t*)(Chp + (size_t)(row0 + 8) * ldc + col) = h1;
                *(uint32_t*)(Clp + (size_t)(row0 + 8) * ldc + col) = l1;
            } else {
                if (bias) {
                    const float b0 = bias[col], b1 = bias[col + 1];
                    v0.x += b0; v0.y += b1; v1.x += b0; v1.y += b1;
                }
                float* p0 = Cf + (size_t)row0 * ldc + col;
                float* p1 = Cf + (size_t)(row0 + 8) * ldc + col;
                if (accum) {
                    const float2 o0 = *(float2*)p0, o1 = *(float2*)p1;
                    v0.x += o0.x; v0.y += o0.y; v1.x += o1.x; v1.y += o1.y;
                }
                *(float2*)p0 = v0;
                *(float2*)p1 = v1;
            }
        }
    }
}

// ---- wrappers ----
__global__ __launch_bounds__(256)
void gemm_proj_split(const bf16* __restrict__ Ah, const bf16* __restrict__ Al,
                     const bf16* __restrict__ Bh, const bf16* __restrict__ Bl,
                     bf16* __restrict__ Ch, bf16* __restrict__ Cl, int N, int K)
{
    const int m0 = blockIdx.y * 128, n0 = blockIdx.x * 128;
    gemm_core2<2, 4, 1, 1>(Ah + (size_t)m0 * K, Al + (size_t)m0 * K, K, 64,
                           Bh + n0, Bl + n0, N, 0,
                           nullptr, Ch + (size_t)m0 * N + n0, Cl + (size_t)m0 * N + n0,
                           N, K, nullptr, 0);
}

__global__ __launch_bounds__(256)
void gemm_out_f32(const bf16* __restrict__ Ah, const bf16* __restrict__ Al,
                  const bf16* __restrict__ Bh, const bf16* __restrict__ Bl,
                  float* __restrict__ C, int N, int K, int accum, const float* __restrict__ bias)
{
    const int m0 = blockIdx.y * 128, n0 = blockIdx.x * 128;
    gemm_core2<2, 4, 1, 0>(Ah + (size_t)m0 * K, Al + (size_t)m0 * K, K, 64,
                           Bh + n0, Bl + n0, N, 0,
                           C + (size_t)m0 * N + n0, nullptr, nullptr,
                           N, K, bias ? bias + n0 : nullptr, accum);
}

__global__ __launch_bounds__(256)
void gemm_dots2(const bf16* __restrict__ Qh, const bf16* __restrict__ Ql,
                const bf16* __restrict__ Kh, const bf16* __restrict__ Kl,
                float* __restrict__ Pp)
{
    const int j0 = blockIdx.x * 128, i0 = blockIdx.y * 128;
    const int h = blockIdx.z >> 2, s = blockIdx.z & 3;
    const size_t r0 = (size_t)s * 32;
    const size_t aoff = (size_t)h * 64 + (size_t)i0 * INNER + r0 * MSAW * INNER;
    const size_t boff = (size_t)h * 64 + (size_t)j0 * 2 * INNER + r0 * MSAW * 2 * INNER;
    gemm_core2<2, 4, 0, 0>(Qh + aoff, Ql + aoff, INNER, (size_t)MSAW * INNER,
                           Kh + boff, Kl + boff, 2 * INNER, (size_t)MSAW * 2 * INNER,
                           Pp + (size_t)blockIdx.z * (MSAW * MSAW) + (size_t)i0 * MSAW + j0,
                           nullptr, nullptr, MSAW, 32 * 64, nullptr, 0);
}

__global__ __launch_bounds__(128)
void gemm_av2(const bf16* __restrict__ Ph, const bf16* __restrict__ Pl,
              const bf16* __restrict__ Vh, const bf16* __restrict__ Vl,
              bf16* __restrict__ Oh, bf16* __restrict__ Ol)
{
    const int i0 = blockIdx.x * 128;
    const int h = blockIdx.y, r = blockIdx.z;
    const size_t aoff = (size_t)h * (MSAW * MSAW) + (size_t)i0 * MSAW;
    const size_t boff = (size_t)INNER + (size_t)h * 64 + (size_t)r * MSAW * 2 * INNER;
    const size_t coff = ((size_t)r * MSAW + i0) * INNER + h * 64;
    gemm_core2<2, 2, 1, 1>(Ph + aoff, Pl + aoff, MSAW, 64,
                           Vh + boff, Vl + boff, 2 * INNER, 0,
                           nullptr, Oh + coff, Ol + coff, INNER, MSAW, nullptr, 0);
}

#define SM_PROJ ((2 * (2 * 128 * 24 + 2 * 16 * 136)) * 2)
#define SM_DOTS ((2 * (2 * 128 * 24 + 2 * 128 * 24)) * 2)
#define SM_AV   ((2 * (2 * 128 * 24 + 2 * 16 * 72)) * 2)

// ================= tensor column attention =================
// one block per (w, head), 256 threads (8 warps); warp handles 16 query rows.
#define COL_SMEM2 (6 * 128 * 72 * 2)
__global__ __launch_bounds__(256)
void col_attn2(const bf16* __restrict__ qh, const bf16* __restrict__ ql,
               const bf16* __restrict__ kvh, const bf16* __restrict__ kvl,
               bf16* __restrict__ oh, bf16* __restrict__ ol)
{
    extern __shared__ bf16 smc[];
    const int PL = 128 * 72;
    bf16 *sqh = smc,          *sql = smc + PL;
    bf16 *skh = smc + 2 * PL, *skl = smc + 3 * PL;
    bf16 *svh = smc + 4 * PL, *svl = smc + 5 * PL;

    const int wi = blockIdx.x, head = blockIdx.y;
    const int tid = threadIdx.x, warp = tid >> 5, lane = tid & 31;

#pragma unroll
    for (int i = 0; i < 4; i++) {
        const int idx = i * 256 + tid;
        const int row = idx >> 3, g = (idx & 7) * 8;
        const size_t gq = ((size_t)(row * MSAW + wi)) * INNER + head * 64 + g;
        const size_t gk = ((size_t)(row * MSAW + wi)) * 2 * INNER + head * 64 + g;
        *(uint4*)(sqh + row * 72 + g) = *(const uint4*)(qh + gq);
        *(uint4*)(sql + row * 72 + g) = *(const uint4*)(ql + gq);
        *(uint4*)(skh + row * 72 + g) = *(const uint4*)(kvh + gk);
        *(uint4*)(skl + row * 72 + g) = *(const uint4*)(kvl + gk);
        *(uint4*)(svh + row * 72 + g) = *(const uint4*)(kvh + gk + INNER);
        *(uint4*)(svl + row * 72 + g) = *(const uint4*)(kvl + gk + INNER);
    }
    __syncthreads();

    const int m0 = warp * 16;
    float s[16][4];
#pragma unroll
    for (int nt = 0; nt < 16; nt++)
#pragma unroll
        for (int e = 0; e < 4; e++) s[nt][e] = 0.f;

    // S = Q @ K^T (3-product split)
#pragma unroll
    for (int kc = 0; kc < 4; kc++) {
        uint32_t ah[4], al[4];
        const int arow = m0 + (lane & 15);
        const int acol = kc * 16 + ((lane >> 4) & 1) * 8;
        ldsm4(ah[0], ah[1], ah[2], ah[3], smem_u32(sqh + arow * 72 + acol));
        ldsm4(al[0], al[1], al[2], al[3], smem_u32(sql + arow * 72 + acol));
#pragma unroll
        for (int nt = 0; nt < 16; nt++) {
            uint32_t bh[2], bl[2];
            const int brow = nt * 8 + (lane & 7);
            const int bcol = kc * 16 + ((lane >> 3) & 1) * 8;
            ldsm2(bh[0], bh[1], smem_u32(skh + brow * 72 + bcol));
            ldsm2(bl[0], bl[1], smem_u32(skl + brow * 72 + bcol));
            mma16816(s[nt], ah, bh);
            mma16816(s[nt], ah, bl);
            mma16816(s[nt], al, bh);
        }
    }

    // softmax over j (row r0 = m0 + g via regs 0/1, row r0+8 via regs 2/3)
    const float sc = 0.125f;
    float mx0 = -1e30f, mx1 = -1e30f;
#pragma unroll
    for (int nt = 0; nt < 16; nt++) {
        mx0 = fmaxf(mx0, fmaxf(s[nt][0], s[nt][1]));
        mx1 = fmaxf(mx1, fmaxf(s[nt][2], s[nt][3]));
    }
    mx0 = fmaxf(mx0, __shfl_xor_sync(0xffffffffu, mx0, 1));
    mx0 = fmaxf(mx0, __shfl_xor_sync(0xffffffffu, mx0, 2));
    mx1 = fmaxf(mx1, __shfl_xor_sync(0xffffffffu, mx1, 1));
    mx1 = fmaxf(mx1, __shfl_xor_sync(0xffffffffu, mx1, 2));
    float sum0 = 0.f, sum1 = 0.f;
#pragma unroll
    for (int nt = 0; nt < 16; nt++) {
        s[nt][0] = __expf(sc * (s[nt][0] - mx0)); sum0 += s[nt][0];
        s[nt][1] = __expf(sc * (s[nt][1] - mx0)); sum0 += s[nt][1];
        s[nt][2] = __expf(sc * (s[nt][2] - mx1)); sum1 += s[nt][2];
        s[nt][3] = __expf(sc * (s[nt][3] - mx1)); sum1 += s[nt][3];
    }
    sum0 += __shfl_xor_sync(0xffffffffu, sum0, 1);
    sum0 += __shfl_xor_sync(0xffffffffu, sum0, 2);
    sum1 += __shfl_xor_sync(0xffffffffu, sum1, 1);
    sum1 += __shfl_xor_sync(0xffffffffu, sum1, 2);
    const float inv0 = 1.f / sum0, inv1 = 1.f / sum1;
#pragma unroll
    for (int nt = 0; nt < 16; nt++) {
        s[nt][0] *= inv0; s[nt][1] *= inv0;
        s[nt][2] *= inv1; s[nt][3] *= inv1;
    }

    // O = P @ V (P repacked from accumulator frags; 3-product split)
    float o[8][4];
#pragma unroll
    for (int dt = 0; dt < 8; dt++)
#pragma unroll
        for (int e = 0; e < 4; e++) o[dt][e] = 0.f;

#pragma unroll
    for (int jc = 0; jc < 8; jc++) {
        uint32_t pah[4], pal[4];
        split_pair(s[2 * jc][0],     s[2 * jc][1],     pah[0], pal[0]);
        split_pair(s[2 * jc][2],     s[2 * jc][3],     pah[1], pal[1]);
        split_pair(s[2 * jc + 1][0], s[2 * jc + 1][1], pah[2], pal[2]);
        split_pair(s[2 * jc + 1][2], s[2 * jc + 1][3], pah[3], pal[3]);
        const int jrow = jc * 16 + (lane & 7) + ((lane >> 3) & 1) * 8;
#pragma unroll
        for (int dt = 0; dt < 8; dt++) {
            uint32_t bh[2], bl[2];
            ldsm2t(bh[0], bh[1], smem_u32(svh + jrow * 72 + dt * 8));
            ldsm2t(bl[0], bl[1], smem_u32(svl + jrow * 72 + dt * 8));
            mma16816(o[dt], pah, bh);
            mma16816(o[dt], pah, bl);
            mma16816(o[dt], pal, bh);
        }
    }

    // write O1 hi/lo planes
    const int g = lane >> 2, tg = lane & 3;
    const int r0 = m0 + g, r1 = r0 + 8;
#pragma unroll
    for (int dt = 0; dt < 8; dt++) {
        const int d = head * 64 + dt * 8 + tg * 2;
        const size_t b0 = ((size_t)(r0 * MSAW + wi)) * INNER + d;
        const size_t b1 = ((size_t)(r1 * MSAW + wi)) * INNER + d;
        uint32_t h0, l0, h1, l1;
        split_pair(o[dt][0], o[dt][1], h0, l0);
        split_pair(o[dt][2], o[dt][3], h1, l1);
        *(uint32_t*)(oh + b0) = h0;
        *(uint32_t*)(ol + b0) = l0;
        *(uint32_t*)(oh + b1) = h1;
        *(uint32_t*)(ol + b1) = l1;
    }
}

// ============= reduce 4 dots partials + scale + softmax -> hi/lo planes =============
__global__ __launch_bounds__(256)
void softmax_reduce2(const float* __restrict__ Pp, bf16* __restrict__ Ph, bf16* __restrict__ Pl)
{
    const int h = blockIdx.x >> 8, i = blockIdx.x & 255;
    const int tid = threadIdx.x;
    __shared__ float red[34];
    float v = 0.f;
#pragma unroll
    for (int s = 0; s < 4; s++)
        v += Pp[((size_t)(h * 4 + s) * MSAW + i) * MSAW + tid];
    v *= 0.011048543456039806f;  // (1/8) * 128^-0.5

    float m = v;
#pragma unroll
    for (int o = 16; o; o >>= 1) m = fmaxf(m, __shfl_xor_sync(0xffffffffu, m, o));
    if ((tid & 31) == 0) red[tid >> 5] = m;
    __syncthreads();
    if (tid == 0) {
        float mm = red[0];
#pragma unroll
        for (int w = 1; w < 8; w++) mm = fmaxf(mm, red[w]);
        red[32] = mm;
    }
    __syncthreads();
    const float e = __expf(v - red[32]);
    float s = e;
#pragma unroll
    for (int o = 16; o; o >>= 1) s += __shfl_xor_sync(0xffffffffu, s, o);
    if ((tid & 31) == 0) red[8 + (tid >> 5)] = s;
    __syncthreads();
    if (tid == 0) {
        float ss = 0.f;
#pragma unroll
        for (int w = 0; w < 8; w++) ss += red[8 + w];
        red[33] = 1.f / ss;
    }
    __syncthreads();
    const float p = e * red[33];
    const bf16 hp = __float2bfloat16(p);
    const bf16 lp = __float2bfloat16(p - __bfloat162float(hp));
    const size_t off = ((size_t)h * MSAW + i) * MSAW + tid;
    Ph[off] = hp;
    Pl[off] = lp;
}

// =============================== launch ===============================
extern "C" void kernel_launch(void* const* d_in, const int* in_sizes, int n_in,
                              void* d_out, int out_size)
{
    const float* x      = (const float*)d_in[0];
    const float* wq_w   = (const float*)d_in[1];
    const float* wkv_w  = (const float*)d_in[2];
    const float* wout_w = (const float*)d_in[3];
    const float* wout_b = (const float*)d_in[4];
    const float* hq_w   = (const float*)d_in[5];
    const float* hkv_w  = (const float*)d_in[6];
    const float* hout_w = (const float*)d_in[7];
    const float* hout_b = (const float*)d_in[8];
    float* out = (float*)d_out;

    void* p;
    bf16 *xh, *xl, *wqh, *wql, *wkvh, *wkvl, *hqh, *hql, *hkvh, *hkvl;
    bf16 *wouth, *woutl, *houth, *houtl;
    bf16 *q1h, *q1l, *kv1h, *kv1l, *q2h, *q2l, *kv2h, *kv2l;
    bf16 *o1h, *o1l, *o2h, *o2l, *p2h, *p2l;
    float* Pp;
    cudaGetSymbolAddress(&p, g_xh);    xh = (bf16*)p;
    cudaGetSymbolAddress(&p, g_xl);    xl = (bf16*)p;
    cudaGetSymbolAddress(&p, g_wqh);   wqh = (bf16*)p;
    cudaGetSymbolAddress(&p, g_wql);   wql = (bf16*)p;
    cudaGetSymbolAddress(&p, g_wkvh);  wkvh = (bf16*)p;
    cudaGetSymbolAddress(&p, g_wkvl);  wkvl = (bf16*)p;
    cudaGetSymbolAddress(&p, g_hqh);   hqh = (bf16*)p;
    cudaGetSymbolAddress(&p, g_hql);   hql = (bf16*)p;
    cudaGetSymbolAddress(&p, g_hkvh);  hkvh = (bf16*)p;
    cudaGetSymbolAddress(&p, g_hkvl);  hkvl = (bf16*)p;
    cudaGetSymbolAddress(&p, g_wouth); wouth = (bf16*)p;
    cudaGetSymbolAddress(&p, g_woutl); woutl = (bf16*)p;
    cudaGetSymbolAddress(&p, g_houth); houth = (bf16*)p;
    cudaGetSymbolAddress(&p, g_houtl); houtl = (bf16*)p;
    cudaGetSymbolAddress(&p, g_q1h);   q1h = (bf16*)p;
    cudaGetSymbolAddress(&p, g_q1l);   q1l = (bf16*)p;
    cudaGetSymbolAddress(&p, g_kv1h);  kv1h = (bf16*)p;
    cudaGetSymbolAddress(&p, g_kv1l);  kv1l = (bf16*)p;
    cudaGetSymbolAddress(&p, g_q2h);   q2h = (bf16*)p;
    cudaGetSymbolAddress(&p, g_q2l);   q2l = (bf16*)p;
    cudaGetSymbolAddress(&p, g_kv2h);  kv2h = (bf16*)p;
    cudaGetSymbolAddress(&p, g_kv2l);  kv2l = (bf16*)p;
    cudaGetSymbolAddress(&p, g_o1h);   o1h = (bf16*)p;
    cudaGetSymbolAddress(&p, g_o1l);   o1l = (bf16*)p;
    cudaGetSymbolAddress(&p, g_o2h);   o2h = (bf16*)p;
    cudaGetSymbolAddress(&p, g_o2l);   o2l = (bf16*)p;
    cudaGetSymbolAddress(&p, g_p2h);   p2h = (bf16*)p;
    cudaGetSymbolAddress(&p, g_p2l);   p2l = (bf16*)p;
    cudaGetSymbolAddress(&p, g_Pp);    Pp = (float*)p;

    cudaFuncSetAttribute(gemm_proj_split, cudaFuncAttributeMaxDynamicSharedMemorySize, SM_PROJ);
    cudaFuncSetAttribute(gemm_out_f32,    cudaFuncAttributeMaxDynamicSharedMemorySize, SM_PROJ);
    cudaFuncSetAttribute(gemm_dots2,      cudaFuncAttributeMaxDynamicSharedMemorySize, SM_DOTS);
    cudaFuncSetAttribute(gemm_av2,        cudaFuncAttributeMaxDynamicSharedMemorySize, SM_AV);
    cudaFuncSetAttribute(col_attn2,       cudaFuncAttributeMaxDynamicSharedMemorySize, COL_SMEM2);

    // split inputs/weights to bf16 hi/lo planes
    split_f32<<<(NTOK * DIM / 4) / 256, 256>>>(x, xh, xl, NTOK * DIM / 4);
    split_f32<<<(DIM * INNER / 4) / 256, 256>>>(wq_w, wqh, wql, DIM * INNER / 4);
    split_f32<<<(DIM * 2 * INNER / 4) / 256, 256>>>(wkv_w, wkvh, wkvl, DIM * 2 * INNER / 4);
    split_f32<<<(DIM * INNER / 4) / 256, 256>>>(hq_w, hqh, hql, DIM * INNER / 4);
    split_f32<<<(DIM * 2 * INNER / 4) / 256, 256>>>(hkv_w, hkvh, hkvl, DIM * 2 * INNER / 4);
    split_f32<<<(INNER * DIM / 4) / 256, 256>>>(wout_w, wouth, woutl, INNER * DIM / 4);
    split_f32<<<(INNER * DIM / 4) / 256, 256>>>(hout_w, houth, houtl, INNER * DIM / 4);

    // projections -> split planes
    gemm_proj_split<<<dim3(INNER / 128, NTOK / 128), 256, SM_PROJ>>>(xh, xl, wqh, wql, q1h, q1l, INNER, DIM);
    gemm_proj_split<<<dim3(2 * INNER / 128, NTOK / 128), 256, SM_PROJ>>>(xh, xl, wkvh, wkvl, kv1h, kv1l, 2 * INNER, DIM);
    gemm_proj_split<<<dim3(INNER / 128, NTOK / 128), 256, SM_PROJ>>>(xh, xl, hqh, hql, q2h, q2l, INNER, DIM);
    gemm_proj_split<<<dim3(2 * INNER / 128, NTOK / 128), 256, SM_PROJ>>>(xh, xl, hkvh, hkvl, kv2h, kv2l, 2 * INNER, DIM);

    // column attention (tensor)
    col_attn2<<<dim3(MSAW, HEADS), 256, COL_SMEM2>>>(q1h, q1l, kv1h, kv1l, o1h, o1l);

    // tied row attention
    gemm_dots2<<<dim3(2, 2, 32), 256, SM_DOTS>>>(q2h, q2l, kv2h, kv2l, Pp);
    softmax_reduce2<<<HEADS * MSAW, 256>>>(Pp, p2h, p2l);
    gemm_av2<<<dim3(2, HEADS, MSAH), 128, SM_AV>>>(p2h, p2l, kv2h, kv2l, o2h, o2l);

    // output projections
    gemm_out_f32<<<dim3(DIM / 128, NTOK / 128), 256, SM_PROJ>>>(o1h, o1l, wouth, woutl, out, DIM, INNER, 0, wout_b);
    gemm_out_f32<<<dim3(DIM / 128, NTOK / 128), 256, SM_PROJ>>>(o2h, o2l, houth, houtl, out, DIM, INNER, 1, hout_b);
}

// round 5
// speedup vs baseline: 3.1947x; 1.0095x over previous
#include <cuda_runtime.h>
#include <cuda_bf16.h>
#include <math.h>
#include <cstdint>

#define HEADS 8
#define DH    64
#define INNER 512
#define DIM   256
#define MSAH  128
#define MSAW  256
#define NTOK  (MSAH*MSAW)

typedef __nv_bfloat16 bf16;

// -------- scratch (static device globals; no runtime allocation) --------
__device__ bf16 g_xh [(size_t)NTOK*DIM],      g_xl [(size_t)NTOK*DIM];
__device__ bf16 g_wqh [(size_t)DIM*INNER],    g_wql [(size_t)DIM*INNER];
__device__ bf16 g_wkvh[(size_t)DIM*2*INNER],  g_wkvl[(size_t)DIM*2*INNER];
__device__ bf16 g_hqh [(size_t)DIM*INNER],    g_hql [(size_t)DIM*INNER];
__device__ bf16 g_hkvh[(size_t)DIM*2*INNER],  g_hkvl[(size_t)DIM*2*INNER];
__device__ bf16 g_wouth[(size_t)INNER*DIM],   g_woutl[(size_t)INNER*DIM];
__device__ bf16 g_houth[(size_t)INNER*DIM],   g_houtl[(size_t)INNER*DIM];
__device__ bf16 g_q1h [(size_t)NTOK*INNER],   g_q1l [(size_t)NTOK*INNER];
__device__ bf16 g_kv1h[(size_t)NTOK*2*INNER], g_kv1l[(size_t)NTOK*2*INNER];
__device__ bf16 g_q2h [(size_t)NTOK*INNER],   g_q2l [(size_t)NTOK*INNER];
__device__ bf16 g_kv2h[(size_t)NTOK*2*INNER], g_kv2l[(size_t)NTOK*2*INNER];
__device__ bf16 g_o1h [(size_t)NTOK*INNER],   g_o1l [(size_t)NTOK*INNER];
__device__ bf16 g_o2h [(size_t)NTOK*INNER],   g_o2l [(size_t)NTOK*INNER];
__device__ bf16 g_p2h [(size_t)HEADS*MSAW*MSAW], g_p2l [(size_t)HEADS*MSAW*MSAW];
__device__ float g_Pp [(size_t)32*MSAW*MSAW];

// ===================== helpers =====================
__device__ __forceinline__ uint32_t smem_u32(const void* p) {
    uint32_t a;
    asm("{ .reg .u64 t; cvta.to.shared.u64 t, %1; cvt.u32.u64 %0, t; }" : "=r"(a) : "l"(p));
    return a;
}
__device__ __forceinline__ void ldsm4(uint32_t& r0, uint32_t& r1, uint32_t& r2, uint32_t& r3, uint32_t a) {
    asm volatile("ldmatrix.sync.aligned.m8n8.x4.shared.b16 {%0,%1,%2,%3}, [%4];"
                 : "=r"(r0), "=r"(r1), "=r"(r2), "=r"(r3) : "r"(a));
}
__device__ __forceinline__ void ldsm2(uint32_t& r0, uint32_t& r1, uint32_t a) {
    asm volatile("ldmatrix.sync.aligned.m8n8.x2.shared.b16 {%0,%1}, [%2];"
                 : "=r"(r0), "=r"(r1) : "r"(a));
}
__device__ __forceinline__ void ldsm2t(uint32_t& r0, uint32_t& r1, uint32_t a) {
    asm volatile("ldmatrix.sync.aligned.m8n8.x2.trans.shared.b16 {%0,%1}, [%2];"
                 : "=r"(r0), "=r"(r1) : "r"(a));
}
__device__ __forceinline__ void mma16816(float* c, const uint32_t* a, const uint32_t* b) {
    asm volatile("mma.sync.aligned.m16n8k16.row.col.f32.bf16.bf16.f32 "
                 "{%0,%1,%2,%3}, {%4,%5,%6,%7}, {%8,%9}, {%0,%1,%2,%3};"
                 : "+f"(c[0]), "+f"(c[1]), "+f"(c[2]), "+f"(c[3])
                 : "r"(a[0]), "r"(a[1]), "r"(a[2]), "r"(a[3]), "r"(b[0]), "r"(b[1]));
}
__device__ __forceinline__ void cpa16(uint32_t dst, const void* src) {
    asm volatile("cp.async.cg.shared.global [%0], [%1], 16;" :: "r"(dst), "l"(src));
}
#define CP_COMMIT() asm volatile("cp.async.commit_group;" ::: "memory")
#define CP_WAIT1()  asm volatile("cp.async.wait_group 1;" ::: "memory")
__device__ __forceinline__ void split_pair(float a, float b, uint32_t& hi, uint32_t& lo) {
    bf16 ha = __float2bfloat16(a), hb = __float2bfloat16(b);
    bf16 la = __float2bfloat16(a - __bfloat162float(ha));
    bf16 lb = __float2bfloat16(b - __bfloat162float(hb));
    __nv_bfloat162 h2 = __halves2bfloat162(ha, hb);
    __nv_bfloat162 l2 = __halves2bfloat162(la, lb);
    hi = *(uint32_t*)&h2;
    lo = *(uint32_t*)&l2;
}

// ================= split fp32 -> bf16 hi/lo planes =================
__global__ __launch_bounds__(256)
void split_f32(const float* __restrict__ in, bf16* __restrict__ H, bf16* __restrict__ L, int n4)
{
    const int i = blockIdx.x * 256 + threadIdx.x;
    if (i >= n4) return;
    const float4 v = ((const float4*)in)[i];
    uint32_t h0, l0, h1, l1;
    split_pair(v.x, v.y, h0, l0);
    split_pair(v.z, v.w, h1, l1);
    *(uint2*)(H + (size_t)i * 4) = make_uint2(h0, h1);
    *(uint2*)(L + (size_t)i * 4) = make_uint2(l0, l1);
}

// ================= pre-split bf16x3 mma GEMM, cp.async 3-stage =================
// A planes: element (m,k) at m*sAr + (k>>6)*sAk + (k&63)   (halves)
// B planes: BT=1: (k,n) at k*sBr + n ; BT=0: (n,k) at n*sBr + (k>>6)*sBk + (k&63)
// OSPLIT=0: fp32 out (bias/accum).  OSPLIT=1: write hi/lo bf16 planes.
template<int WM, int WN, int BT, int OSPLIT>
__device__ __forceinline__ void gemm_core3(
    const bf16* __restrict__ Ah_, const bf16* __restrict__ Al_, size_t sAr, size_t sAk,
    const bf16* __restrict__ Bh_, const bf16* __restrict__ Bl_, size_t sBr, size_t sBk,
    float* __restrict__ Cf, bf16* __restrict__ Chp, bf16* __restrict__ Clp,
    int ldc, int K, const float* __restrict__ bias, int accum)
{
    constexpr int TM = WM * 64, TN = WN * 32;
    constexpr int THREADS = WM * WN * 32;
    constexpr int AP = 24;
    constexpr int BP = BT ? (TN + 8) : 24;
    constexpr int AH = TM * AP;
    constexpr int BH = BT ? 16 * BP : TN * 24;
    constexpr int STAGE = 2 * AH + 2 * BH;
    constexpr int NA = TM * 2 / THREADS;
    constexpr int NB = BT ? (2 * TN / THREADS) : (TN * 2 / THREADS);
    constexpr int NSTG = 3;

    extern __shared__ bf16 smn[];
    const int tid = threadIdx.x, warp = tid >> 5, lane = tid & 31;
    const int wm = warp / WN, wn = warp % WN;

    float c[4][4][4];
#pragma unroll
    for (int mt = 0; mt < 4; mt++)
#pragma unroll
        for (int nt = 0; nt < 4; nt++)
#pragma unroll
            for (int e = 0; e < 4; e++) c[mt][nt][e] = 0.f;

    auto issue = [&](int cc) {
        const int s = cc % NSTG;
        bf16* Ah = smn + (size_t)s * STAGE;
        bf16* Al = Ah + AH;
        bf16* Bh = Ah + 2 * AH;
        bf16* Bl = Bh + BH;
        const int k0 = cc * 16;
        const size_t cb = (size_t)(k0 >> 6) * sAk + (k0 & 63);
#pragma unroll
        for (int i = 0; i < NA; i++) {
            const int idx = i * THREADS + tid;
            const int row = idx >> 1, g = (idx & 1) * 8;
            const size_t go = (size_t)row * sAr + cb + g;
            const int off = row * AP + g;
            cpa16(smem_u32(Ah + off), Ah_ + go);
            cpa16(smem_u32(Al + off), Al_ + go);
        }
#pragma unroll
        for (int i = 0; i < NB; i++) {
            const int idx = i * THREADS + tid;
            size_t go; int off;
            if (BT) {
                const int kr = idx / (TN / 8), q = idx % (TN / 8);
                go = (size_t)(k0 + kr) * sBr + q * 8;
                off = kr * BP + q * 8;
            } else {
                const int nr = idx >> 1, g = (idx & 1) * 8;
                go = (size_t)nr * sBr + (size_t)(k0 >> 6) * sBk + (k0 & 63) + g;
                off = nr * 24 + g;
            }
            cpa16(smem_u32(Bh + off), Bh_ + go);
            cpa16(smem_u32(Bl + off), Bl_ + go);
        }
    };

    auto compute = [&](int s) {
        bf16* Ah = smn + (size_t)s * STAGE;
        bf16* Al = Ah + AH;
        bf16* Bh = Ah + 2 * AH;
        bf16* Bl = Bh + BH;
        uint32_t ah[4][4], al[4][4], bh[4][2], bl[4][2];
#pragma unroll
        for (int mt = 0; mt < 4; mt++) {
            const int row = wm * 64 + mt * 16 + (lane & 15);
            const int ko = ((lane >> 4) & 1) * 8;
            ldsm4(ah[mt][0], ah[mt][1], ah[mt][2], ah[mt][3], smem_u32(Ah + row * AP + ko));
            ldsm4(al[mt][0], al[mt][1], al[mt][2], al[mt][3], smem_u32(Al + row * AP + ko));
        }
#pragma unroll
        for (int nt = 0; nt < 4; nt++) {
            if (BT) {
                const int k = (lane & 7) + ((lane >> 3) & 1) * 8;
                const int ncol = wn * 32 + nt * 8;
                ldsm2t(bh[nt][0], bh[nt][1], smem_u32(Bh + k * BP + ncol));
                ldsm2t(bl[nt][0], bl[nt][1], smem_u32(Bl + k * BP + ncol));
            } else {
                const int nrow = wn * 32 + nt * 8 + (lane & 7);
                const int ko = ((lane >> 3) & 1) * 8;
                ldsm2(bh[nt][0], bh[nt][1], smem_u32(Bh + nrow * 24 + ko));
                ldsm2(bl[nt][0], bl[nt][1], smem_u32(Bl + nrow * 24 + ko));
            }
        }
#pragma unroll
        for (int mt = 0; mt < 4; mt++)
#pragma unroll
            for (int nt = 0; nt < 4; nt++) {
                mma16816(c[mt][nt], ah[mt], bh[nt]);
                mma16816(c[mt][nt], ah[mt], bl[nt]);
                mma16816(c[mt][nt], al[mt], bh[nt]);
            }
    };

    const int NC = K >> 4;
    issue(0); CP_COMMIT();
    issue(1); CP_COMMIT();
    for (int cc = 0; cc < NC; cc++) {
        CP_WAIT1();
        __syncthreads();
        if (cc + 2 < NC) issue(cc + 2);
        CP_COMMIT();                       // one group per iteration (possibly empty)
        compute(cc % NSTG);
    }

    const int g = lane >> 2, tg = lane & 3;
#pragma unroll
    for (int mt = 0; mt < 4; mt++) {
#pragma unroll
        for (int nt = 0; nt < 4; nt++) {
            const int row0 = wm * 64 + mt * 16 + g;
            const int col = wn * 32 + nt * 8 + tg * 2;
            float2 v0 = make_float2(c[mt][nt][0], c[mt][nt][1]);
            float2 v1 = make_float2(c[mt][nt][2], c[mt][nt][3]);
            if (OSPLIT) {
                uint32_t h0, l0, h1, l1;
                split_pair(v0.x, v0.y, h0, l0);
                split_pair(v1.x, v1.y, h1, l1);
                *(uint32_t*)(Chp + (size_t)row0 * ldc + col) = h0;
                *(uint32_t*)(Clp + (size_t)row0 * ldc + col) = l0;
                *(uint32_t*)(Chp + (size_t)(row0 + 8) * ldc + col) = h1;
                *(uint32_t*)(Clp + (size_t)(row0 + 8) * ldc + col) = l1;
            } else {
                if (bias) {
                    const float b0 = bias[col], b1 = bias[col + 1];
                    v0.x += b0; v0.y += b1; v1.x += b0; v1.y += b1;
                }
                float* p0 = Cf + (size_t)row0 * ldc + col;
                float* p1 = Cf + (size_t)(row0 + 8) * ldc + col;
                if (accum) {
                    const float2 o0 = *(float2*)p0, o1 = *(float2*)p1;
                    v0.x += o0.x; v0.y += o0.y; v1.x += o1.x; v1.y += o1.y;
                }
                *(float2*)p0 = v0;
                *(float2*)p1 = v1;
            }
        }
    }
}

// ---- wrappers ----
__global__ __launch_bounds__(256)
void gemm_proj_split(const bf16* __restrict__ Ah, const bf16* __restrict__ Al,
                     const bf16* __restrict__ Bh, const bf16* __restrict__ Bl,
                     bf16* __restrict__ Ch, bf16* __restrict__ Cl, int N, int K)
{
    const int m0 = blockIdx.y * 128, n0 = blockIdx.x * 128;
    gemm_core3<2, 4, 1, 1>(Ah + (size_t)m0 * K, Al + (size_t)m0 * K, K, 64,
                           Bh + n0, Bl + n0, N, 0,
                           nullptr, Ch + (size_t)m0 * N + n0, Cl + (size_t)m0 * N + n0,
                           N, K, nullptr, 0);
}

__global__ __launch_bounds__(256)
void gemm_out_f32(const bf16* __restrict__ Ah, const bf16* __restrict__ Al,
                  const bf16* __restrict__ Bh, const bf16* __restrict__ Bl,
                  float* __restrict__ C, int N, int K, int accum, const float* __restrict__ bias)
{
    const int m0 = blockIdx.y * 128, n0 = blockIdx.x * 128;
    gemm_core3<2, 4, 1, 0>(Ah + (size_t)m0 * K, Al + (size_t)m0 * K, K, 64,
                           Bh + n0, Bl + n0, N, 0,
                           C + (size_t)m0 * N + n0, nullptr, nullptr,
                           N, K, bias ? bias + n0 : nullptr, accum);
}

__global__ __launch_bounds__(256)
void gemm_dots2(const bf16* __restrict__ Qh, const bf16* __restrict__ Ql,
                const bf16* __restrict__ Kh, const bf16* __restrict__ Kl,
                float* __restrict__ Pp)
{
    const int j0 = blockIdx.x * 128, i0 = blockIdx.y * 128;
    const int h = blockIdx.z >> 2, s = blockIdx.z & 3;
    const size_t r0 = (size_t)s * 32;
    const size_t aoff = (size_t)h * 64 + (size_t)i0 * INNER + r0 * MSAW * INNER;
    const size_t boff = (size_t)h * 64 + (size_t)j0 * 2 * INNER + r0 * MSAW * 2 * INNER;
    gemm_core3<2, 4, 0, 0>(Qh + aoff, Ql + aoff, INNER, (size_t)MSAW * INNER,
                           Kh + boff, Kl + boff, 2 * INNER, (size_t)MSAW * 2 * INNER,
                           Pp + (size_t)blockIdx.z * (MSAW * MSAW) + (size_t)i0 * MSAW + j0,
                           nullptr, nullptr, MSAW, 32 * 64, nullptr, 0);
}

__global__ __launch_bounds__(128)
void gemm_av2(const bf16* __restrict__ Ph, const bf16* __restrict__ Pl,
              const bf16* __restrict__ Vh, const bf16* __restrict__ Vl,
              bf16* __restrict__ Oh, bf16* __restrict__ Ol)
{
    const int i0 = blockIdx.x * 128;
    const int h = blockIdx.y, r = blockIdx.z;
    const size_t aoff = (size_t)h * (MSAW * MSAW) + (size_t)i0 * MSAW;
    const size_t boff = (size_t)INNER + (size_t)h * 64 + (size_t)r * MSAW * 2 * INNER;
    const size_t coff = ((size_t)r * MSAW + i0) * INNER + h * 64;
    gemm_core3<2, 2, 1, 1>(Ph + aoff, Pl + aoff, MSAW, 64,
                           Vh + boff, Vl + boff, 2 * INNER, 0,
                           nullptr, Oh + coff, Ol + coff, INNER, MSAW, nullptr, 0);
}

// smem bytes: 3 stages
#define SM_PROJ (3 * (2 * 128 * 24 + 2 * 16 * 136) * 2)
#define SM_DOTS (3 * (2 * 128 * 24 + 2 * 128 * 24) * 2)
#define SM_AV   (3 * (2 * 128 * 24 + 2 * 16 * 72) * 2)

// ================= tensor column attention =================
#define COL_SMEM2 (6 * 128 * 72 * 2)
__global__ __launch_bounds__(256)
void col_attn2(const bf16* __restrict__ qh, const bf16* __restrict__ ql,
               const bf16* __restrict__ kvh, const bf16* __restrict__ kvl,
               bf16* __restrict__ oh, bf16* __restrict__ ol)
{
    extern __shared__ bf16 smc[];
    const int PL = 128 * 72;
    bf16 *sqh = smc,          *sql = smc + PL;
    bf16 *skh = smc + 2 * PL, *skl = smc + 3 * PL;
    bf16 *svh = smc + 4 * PL, *svl = smc + 5 * PL;

    const int wi = blockIdx.x, head = blockIdx.y;
    const int tid = threadIdx.x, warp = tid >> 5, lane = tid & 31;

#pragma unroll
    for (int i = 0; i < 4; i++) {
        const int idx = i * 256 + tid;
        const int row = idx >> 3, g = (idx & 7) * 8;
        const size_t gq = ((size_t)(row * MSAW + wi)) * INNER + head * 64 + g;
        const size_t gk = ((size_t)(row * MSAW + wi)) * 2 * INNER + head * 64 + g;
        cpa16(smem_u32(sqh + row * 72 + g), qh + gq);
        cpa16(smem_u32(sql + row * 72 + g), ql + gq);
        cpa16(smem_u32(skh + row * 72 + g), kvh + gk);
        cpa16(smem_u32(skl + row * 72 + g), kvl + gk);
        cpa16(smem_u32(svh + row * 72 + g), kvh + gk + INNER);
        cpa16(smem_u32(svl + row * 72 + g), kvl + gk + INNER);
    }
    CP_COMMIT();
    asm volatile("cp.async.wait_group 0;" ::: "memory");
    __syncthreads();

    const int m0 = warp * 16;
    float s[16][4];
#pragma unroll
    for (int nt = 0; nt < 16; nt++)
#pragma unroll
        for (int e = 0; e < 4; e++) s[nt][e] = 0.f;

#pragma unroll
    for (int kc = 0; kc < 4; kc++) {
        uint32_t ah[4], al[4];
        const int arow = m0 + (lane & 15);
        const int acol = kc * 16 + ((lane >> 4) & 1) * 8;
        ldsm4(ah[0], ah[1], ah[2], ah[3], smem_u32(sqh + arow * 72 + acol));
        ldsm4(al[0], al[1], al[2], al[3], smem_u32(sql + arow * 72 + acol));
#pragma unroll
        for (int nt = 0; nt < 16; nt++) {
            uint32_t bh[2], bl[2];
            const int brow = nt * 8 + (lane & 7);
            const int bcol = kc * 16 + ((lane >> 3) & 1) * 8;
            ldsm2(bh[0], bh[1], smem_u32(skh + brow * 72 + bcol));
            ldsm2(bl[0], bl[1], smem_u32(skl + brow * 72 + bcol));
            mma16816(s[nt], ah, bh);
            mma16816(s[nt], ah, bl);
            mma16816(s[nt], al, bh);
        }
    }

    const float sc = 0.125f;
    float mx0 = -1e30f, mx1 = -1e30f;
#pragma unroll
    for (int nt = 0; nt < 16; nt++) {
        mx0 = fmaxf(mx0, fmaxf(s[nt][0], s[nt][1]));
        mx1 = fmaxf(mx1, fmaxf(s[nt][2], s[nt][3]));
    }
    mx0 = fmaxf(mx0, __shfl_xor_sync(0xffffffffu, mx0, 1));
    mx0 = fmaxf(mx0, __shfl_xor_sync(0xffffffffu, mx0, 2));
    mx1 = fmaxf(mx1, __shfl_xor_sync(0xffffffffu, mx1, 1));
    mx1 = fmaxf(mx1, __shfl_xor_sync(0xffffffffu, mx1, 2));
    float sum0 = 0.f, sum1 = 0.f;
#pragma unroll
    for (int nt = 0; nt < 16; nt++) {
        s[nt][0] = __expf(sc * (s[nt][0] - mx0)); sum0 += s[nt][0];
        s[nt][1] = __expf(sc * (s[nt][1] - mx0)); sum0 += s[nt][1];
        s[nt][2] = __expf(sc * (s[nt][2] - mx1)); sum1 += s[nt][2];
        s[nt][3] = __expf(sc * (s[nt][3] - mx1)); sum1 += s[nt][3];
    }
    sum0 += __shfl_xor_sync(0xffffffffu, sum0, 1);
    sum0 += __shfl_xor_sync(0xffffffffu, sum0, 2);
    sum1 += __shfl_xor_sync(0xffffffffu, sum1, 1);
    sum1 += __shfl_xor_sync(0xffffffffu, sum1, 2);
    const float inv0 = 1.f / sum0, inv1 = 1.f / sum1;
#pragma unroll
    for (int nt = 0; nt < 16; nt++) {
        s[nt][0] *= inv0; s[nt][1] *= inv0;
        s[nt][2] *= inv1; s[nt][3] *= inv1;
    }

    float o[8][4];
#pragma unroll
    for (int dt = 0; dt < 8; dt++)
#pragma unroll
        for (int e = 0; e < 4; e++) o[dt][e] = 0.f;

#pragma unroll
    for (int jc = 0; jc < 8; jc++) {
        uint32_t pah[4], pal[4];
        split_pair(s[2 * jc][0],     s[2 * jc][1],     pah[0], pal[0]);
        split_pair(s[2 * jc][2],     s[2 * jc][3],     pah[1], pal[1]);
        split_pair(s[2 * jc + 1][0], s[2 * jc + 1][1], pah[2], pal[2]);
        split_pair(s[2 * jc + 1][2], s[2 * jc + 1][3], pah[3], pal[3]);
        const int jrow = jc * 16 + (lane & 7) + ((lane >> 3) & 1) * 8;
#pragma unroll
        for (int dt = 0; dt < 8; dt++) {
            uint32_t bh[2], bl[2];
            ldsm2t(bh[0], bh[1], smem_u32(svh + jrow * 72 + dt * 8));
            ldsm2t(bl[0], bl[1], smem_u32(svl + jrow * 72 + dt * 8));
            mma16816(o[dt], pah, bh);
            mma16816(o[dt], pah, bl);
            mma16816(o[dt], pal, bh);
        }
    }

    const int g = lane >> 2, tg = lane & 3;
    const int r0 = m0 + g, r1 = r0 + 8;
#pragma unroll
    for (int dt = 0; dt < 8; dt++) {
        const int d = head * 64 + dt * 8 + tg * 2;
        const size_t b0 = ((size_t)(r0 * MSAW + wi)) * INNER + d;
        const size_t b1 = ((size_t)(r1 * MSAW + wi)) * INNER + d;
        uint32_t h0, l0, h1, l1;
        split_pair(o[dt][0], o[dt][1], h0, l0);
        split_pair(o[dt][2], o[dt][3], h1, l1);
        *(uint32_t*)(oh + b0) = h0;
        *(uint32_t*)(ol + b0) = l0;
        *(uint32_t*)(oh + b1) = h1;
        *(uint32_t*)(ol + b1) = l1;
    }
}

// ============= reduce 4 dots partials + scale + softmax -> hi/lo planes =============
__global__ __launch_bounds__(256)
void softmax_reduce2(const float* __restrict__ Pp, bf16* __restrict__ Ph, bf16* __restrict__ Pl)
{
    const int h = blockIdx.x >> 8, i = blockIdx.x & 255;
    const int tid = threadIdx.x;
    __shared__ float red[34];
    float v = 0.f;
#pragma unroll
    for (int s = 0; s < 4; s++)
        v += Pp[((size_t)(h * 4 + s) * MSAW + i) * MSAW + tid];
    v *= 0.011048543456039806f;  // (1/8) * 128^-0.5

    float m = v;
#pragma unroll
    for (int o = 16; o; o >>= 1) m = fmaxf(m, __shfl_xor_sync(0xffffffffu, m, o));
    if ((tid & 31) == 0) red[tid >> 5] = m;
    __syncthreads();
    if (tid == 0) {
        float mm = red[0];
#pragma unroll
        for (int w = 1; w < 8; w++) mm = fmaxf(mm, red[w]);
        red[32] = mm;
    }
    __syncthreads();
    const float e = __expf(v - red[32]);
    float s = e;
#pragma unroll
    for (int o = 16; o; o >>= 1) s += __shfl_xor_sync(0xffffffffu, s, o);
    if ((tid & 31) == 0) red[8 + (tid >> 5)] = s;
    __syncthreads();
    if (tid == 0) {
        float ss = 0.f;
#pragma unroll
        for (int w = 0; w < 8; w++) ss += red[8 + w];
        red[33] = 1.f / ss;
    }
    __syncthreads();
    const float p = e * red[33];
    const bf16 hp = __float2bfloat16(p);
    const bf16 lp = __float2bfloat16(p - __bfloat162float(hp));
    const size_t off = ((size_t)h * MSAW + i) * MSAW + tid;
    Ph[off] = hp;
    Pl[off] = lp;
}

// =============================== launch ===============================
extern "C" void kernel_launch(void* const* d_in, const int* in_sizes, int n_in,
                              void* d_out, int out_size)
{
    const float* x      = (const float*)d_in[0];
    const float* wq_w   = (const float*)d_in[1];
    const float* wkv_w  = (const float*)d_in[2];
    const float* wout_w = (const float*)d_in[3];
    const float* wout_b = (const float*)d_in[4];
    const float* hq_w   = (const float*)d_in[5];
    const float* hkv_w  = (const float*)d_in[6];
    const float* hout_w = (const float*)d_in[7];
    const float* hout_b = (const float*)d_in[8];
    float* out = (float*)d_out;

    void* p;
    bf16 *xh, *xl, *wqh, *wql, *wkvh, *wkvl, *hqh, *hql, *hkvh, *hkvl;
    bf16 *wouth, *woutl, *houth, *houtl;
    bf16 *q1h, *q1l, *kv1h, *kv1l, *q2h, *q2l, *kv2h, *kv2l;
    bf16 *o1h, *o1l, *o2h, *o2l, *p2h, *p2l;
    float* Pp;
    cudaGetSymbolAddress(&p, g_xh);    xh = (bf16*)p;
    cudaGetSymbolAddress(&p, g_xl);    xl = (bf16*)p;
    cudaGetSymbolAddress(&p, g_wqh);   wqh = (bf16*)p;
    cudaGetSymbolAddress(&p, g_wql);   wql = (bf16*)p;
    cudaGetSymbolAddress(&p, g_wkvh);  wkvh = (bf16*)p;
    cudaGetSymbolAddress(&p, g_wkvl);  wkvl = (bf16*)p;
    cudaGetSymbolAddress(&p, g_hqh);   hqh = (bf16*)p;
    cudaGetSymbolAddress(&p, g_hql);   hql = (bf16*)p;
    cudaGetSymbolAddress(&p, g_hkvh);  hkvh = (bf16*)p;
    cudaGetSymbolAddress(&p, g_hkvl);  hkvl = (bf16*)p;
    cudaGetSymbolAddress(&p, g_wouth); wouth = (bf16*)p;
    cudaGetSymbolAddress(&p, g_woutl); woutl = (bf16*)p;
    cudaGetSymbolAddress(&p, g_houth); houth = (bf16*)p;
    cudaGetSymbolAddress(&p, g_houtl); houtl = (bf16*)p;
    cudaGetSymbolAddress(&p, g_q1h);   q1h = (bf16*)p;
    cudaGetSymbolAddress(&p, g_q1l);   q1l = (bf16*)p;
    cudaGetSymbolAddress(&p, g_kv1h);  kv1h = (bf16*)p;
    cudaGetSymbolAddress(&p, g_kv1l);  kv1l = (bf16*)p;
    cudaGetSymbolAddress(&p, g_q2h);   q2h = (bf16*)p;
    cudaGetSymbolAddress(&p, g_q2l);   q2l = (bf16*)p;
    cudaGetSymbolAddress(&p, g_kv2h);  kv2h = (bf16*)p;
    cudaGetSymbolAddress(&p, g_kv2l);  kv2l = (bf16*)p;
    cudaGetSymbolAddress(&p, g_o1h);   o1h = (bf16*)p;
    cudaGetSymbolAddress(&p, g_o1l);   o1l = (bf16*)p;
    cudaGetSymbolAddress(&p, g_o2h);   o2h = (bf16*)p;
    cudaGetSymbolAddress(&p, g_o2l);   o2l = (bf16*)p;
    cudaGetSymbolAddress(&p, g_p2h);   p2h = (bf16*)p;
    cudaGetSymbolAddress(&p, g_p2l);   p2l = (bf16*)p;
    cudaGetSymbolAddress(&p, g_Pp);    Pp = (float*)p;

    cudaFuncSetAttribute(gemm_proj_split, cudaFuncAttributeMaxDynamicSharedMemorySize, SM_PROJ);
    cudaFuncSetAttribute(gemm_out_f32,    cudaFuncAttributeMaxDynamicSharedMemorySize, SM_PROJ);
    cudaFuncSetAttribute(gemm_dots2,      cudaFuncAttributeMaxDynamicSharedMemorySize, SM_DOTS);
    cudaFuncSetAttribute(gemm_av2,        cudaFuncAttributeMaxDynamicSharedMemorySize, SM_AV);
    cudaFuncSetAttribute(col_attn2,       cudaFuncAttributeMaxDynamicSharedMemorySize, COL_SMEM2);

    split_f32<<<(NTOK * DIM / 4) / 256, 256>>>(x, xh, xl, NTOK * DIM / 4);
    split_f32<<<(DIM * INNER / 4) / 256, 256>>>(wq_w, wqh, wql, DIM * INNER / 4);
    split_f32<<<(DIM * 2 * INNER / 4) / 256, 256>>>(wkv_w, wkvh, wkvl, DIM * 2 * INNER / 4);
    split_f32<<<(DIM * INNER / 4) / 256, 256>>>(hq_w, hqh, hql, DIM * INNER / 4);
    split_f32<<<(DIM * 2 * INNER / 4) / 256, 256>>>(hkv_w, hkvh, hkvl, DIM * 2 * INNER / 4);
    split_f32<<<(INNER * DIM / 4) / 256, 256>>>(wout_w, wouth, woutl, INNER * DIM / 4);
    split_f32<<<(INNER * DIM / 4) / 256, 256>>>(hout_w, houth, houtl, INNER * DIM / 4);

    gemm_proj_split<<<dim3(INNER / 128, NTOK / 128), 256, SM_PROJ>>>(xh, xl, wqh, wql, q1h, q1l, INNER, DIM);
    gemm_proj_split<<<dim3(2 * INNER / 128, NTOK / 128), 256, SM_PROJ>>>(xh, xl, wkvh, wkvl, kv1h, kv1l, 2 * INNER, DIM);
    gemm_proj_split<<<dim3(INNER / 128, NTOK / 128), 256, SM_PROJ>>>(xh, xl, hqh, hql, q2h, q2l, INNER, DIM);
    gemm_proj_split<<<dim3(2 * INNER / 128, NTOK / 128), 256, SM_PROJ>>>(xh, xl, hkvh, hkvl, kv2h, kv2l, 2 * INNER, DIM);

    col_attn2<<<dim3(MSAW, HEADS), 256, COL_SMEM2>>>(q1h, q1l, kv1h, kv1l, o1h, o1l);

    gemm_dots2<<<dim3(2, 2, 32), 256, SM_DOTS>>>(q2h, q2l, kv2h, kv2l, Pp);
    softmax_reduce2<<<HEADS * MSAW, 256>>>(Pp, p2h, p2l);
    gemm_av2<<<dim3(2, HEADS, MSAH), 128, SM_AV>>>(p2h, p2l, kv2h, kv2l, o2h, o2l);

    gemm_out_f32<<<dim3(DIM / 128, NTOK / 128), 256, SM_PROJ>>>(o1h, o1l, wouth, woutl, out, DIM, INNER, 0, wout_b);
    gemm_out_f32<<<dim3(DIM / 128, NTOK / 128), 256, SM_PROJ>>>(o2h, o2l, houth, houtl, out, DIM, INNER, 1, hout_b);
}

// round 6
// speedup vs baseline: 3.4067x; 1.0664x over previous
#include <cuda_runtime.h>
#include <cuda_bf16.h>
#include <math.h>
#include <cstdint>

#define HEADS 8
#define DH    64
#define INNER 512
#define DIM   256
#define MSAH  128
#define MSAW  256
#define NTOK  (MSAH*MSAW)

typedef __nv_bfloat16 bf16;

// -------- scratch (static device globals; no runtime allocation) --------
__device__ bf16 g_xh [(size_t)NTOK*DIM],      g_xl [(size_t)NTOK*DIM];
__device__ bf16 g_wqh [(size_t)DIM*INNER],    g_wql [(size_t)DIM*INNER];
__device__ bf16 g_wkvh[(size_t)DIM*2*INNER],  g_wkvl[(size_t)DIM*2*INNER];
__device__ bf16 g_hqh [(size_t)DIM*INNER],    g_hql [(size_t)DIM*INNER];
__device__ bf16 g_hkvh[(size_t)DIM*2*INNER],  g_hkvl[(size_t)DIM*2*INNER];
__device__ bf16 g_wouth[(size_t)INNER*DIM],   g_woutl[(size_t)INNER*DIM];
__device__ bf16 g_houth[(size_t)INNER*DIM],   g_houtl[(size_t)INNER*DIM];
__device__ bf16 g_q1h [(size_t)NTOK*INNER],   g_q1l [(size_t)NTOK*INNER];
__device__ bf16 g_kv1h[(size_t)NTOK*2*INNER], g_kv1l[(size_t)NTOK*2*INNER];
__device__ bf16 g_q2h [(size_t)NTOK*INNER],   g_q2l [(size_t)NTOK*INNER];
__device__ bf16 g_kv2h[(size_t)NTOK*2*INNER], g_kv2l[(size_t)NTOK*2*INNER];
__device__ bf16 g_o1h [(size_t)NTOK*INNER],   g_o1l [(size_t)NTOK*INNER];
__device__ bf16 g_o2h [(size_t)NTOK*INNER],   g_o2l [(size_t)NTOK*INNER];
__device__ bf16 g_p2h [(size_t)HEADS*MSAW*MSAW], g_p2l [(size_t)HEADS*MSAW*MSAW];
__device__ float g_Pp [(size_t)32*MSAW*MSAW];

// ===================== helpers =====================
__device__ __forceinline__ uint32_t smem_u32(const void* p) {
    uint32_t a;
    asm("{ .reg .u64 t; cvta.to.shared.u64 t, %1; cvt.u32.u64 %0, t; }" : "=r"(a) : "l"(p));
    return a;
}
__device__ __forceinline__ void ldsm4(uint32_t& r0, uint32_t& r1, uint32_t& r2, uint32_t& r3, uint32_t a) {
    asm volatile("ldmatrix.sync.aligned.m8n8.x4.shared.b16 {%0,%1,%2,%3}, [%4];"
                 : "=r"(r0), "=r"(r1), "=r"(r2), "=r"(r3) : "r"(a));
}
__device__ __forceinline__ void ldsm2(uint32_t& r0, uint32_t& r1, uint32_t a) {
    asm volatile("ldmatrix.sync.aligned.m8n8.x2.shared.b16 {%0,%1}, [%2];"
                 : "=r"(r0), "=r"(r1) : "r"(a));
}
__device__ __forceinline__ void ldsm2t(uint32_t& r0, uint32_t& r1, uint32_t a) {
    asm volatile("ldmatrix.sync.aligned.m8n8.x2.trans.shared.b16 {%0,%1}, [%2];"
                 : "=r"(r0), "=r"(r1) : "r"(a));
}
__device__ __forceinline__ void mma16816(float* c, const uint32_t* a, const uint32_t* b) {
    asm volatile("mma.sync.aligned.m16n8k16.row.col.f32.bf16.bf16.f32 "
                 "{%0,%1,%2,%3}, {%4,%5,%6,%7}, {%8,%9}, {%0,%1,%2,%3};"
                 : "+f"(c[0]), "+f"(c[1]), "+f"(c[2]), "+f"(c[3])
                 : "r"(a[0]), "r"(a[1]), "r"(a[2]), "r"(a[3]), "r"(b[0]), "r"(b[1]));
}
__device__ __forceinline__ void cpa16(uint32_t dst, const void* src) {
    asm volatile("cp.async.cg.shared.global [%0], [%1], 16;" :: "r"(dst), "l"(src));
}
#define CP_COMMIT() asm volatile("cp.async.commit_group;" ::: "memory")
#define CP_WAIT2()  asm volatile("cp.async.wait_group 2;" ::: "memory")
#define CP_WAIT0()  asm volatile("cp.async.wait_group 0;" ::: "memory")
__device__ __forceinline__ void split_pair(float a, float b, uint32_t& hi, uint32_t& lo) {
    bf16 ha = __float2bfloat16(a), hb = __float2bfloat16(b);
    bf16 la = __float2bfloat16(a - __bfloat162float(ha));
    bf16 lb = __float2bfloat16(b - __bfloat162float(hb));
    __nv_bfloat162 h2 = __halves2bfloat162(ha, hb);
    __nv_bfloat162 l2 = __halves2bfloat162(la, lb);
    hi = *(uint32_t*)&h2;
    lo = *(uint32_t*)&l2;
}

// ================= split fp32 -> bf16 hi/lo planes =================
__device__ __forceinline__ void split_one(const float* in, bf16* H, bf16* L, int i) {
    const float4 v = ((const float4*)in)[i];
    uint32_t h0, l0, h1, l1;
    split_pair(v.x, v.y, h0, l0);
    split_pair(v.z, v.w, h1, l1);
    *(uint2*)(H + (size_t)i * 4) = make_uint2(h0, h1);
    *(uint2*)(L + (size_t)i * 4) = make_uint2(l0, l1);
}
__global__ __launch_bounds__(256)
void split_f32(const float* __restrict__ in, bf16* __restrict__ H, bf16* __restrict__ L, int n4)
{
    const int i = blockIdx.x * 256 + threadIdx.x;
    if (i < n4) split_one(in, H, L, i);
}
// all six weights in one launch; segment bounds in f4 units
__global__ __launch_bounds__(256)
void split_w6(const float* wq, const float* wkv, const float* hq, const float* hkv,
              const float* wo, const float* ho,
              bf16* wqh, bf16* wql, bf16* wkvh, bf16* wkvl,
              bf16* hqh, bf16* hql, bf16* hkvh, bf16* hkvl,
              bf16* woh, bf16* wol, bf16* hoh, bf16* hol)
{
    const int i = blockIdx.x * 256 + threadIdx.x;
    if (i < 32768)        split_one(wq,  wqh,  wql,  i);
    else if (i < 98304)   split_one(wkv, wkvh, wkvl, i - 32768);
    else if (i < 131072)  split_one(hq,  hqh,  hql,  i - 98304);
    else if (i < 196608)  split_one(hkv, hkvh, hkvl, i - 131072);
    else if (i < 229376)  split_one(wo,  woh,  wol,  i - 196608);
    else                  split_one(ho,  hoh,  hol,  i - 229376);
}

// ================= pre-split bf16x3 mma GEMM, cp.async 4-stage =================
// A planes: element (m,k) at m*sAr + (k>>6)*sAk + (k&63)   (halves)
// B planes: BT=1: (k,n) at k*sBr + n ; BT=0: (n,k) at n*sBr + (k>>6)*sBk + (k&63)
// DUAL=1: second A/B pointer set used for k >= K1 (same strides).
// OSPLIT=0: fp32 out (bias, bias2).  OSPLIT=1: write hi/lo bf16 planes.
template<int WM, int WN, int BT, int OSPLIT, int DUAL>
__device__ __forceinline__ void gemm_core4(
    const bf16* __restrict__ Ah_, const bf16* __restrict__ Al_, size_t sAr, size_t sAk,
    const bf16* __restrict__ Bh_, const bf16* __restrict__ Bl_, size_t sBr, size_t sBk,
    const bf16* __restrict__ Ah2_, const bf16* __restrict__ Al2_,
    const bf16* __restrict__ Bh2_, const bf16* __restrict__ Bl2_, int K1,
    float* __restrict__ Cf, bf16* __restrict__ Chp, bf16* __restrict__ Clp,
    int ldc, int K, const float* __restrict__ bias, const float* __restrict__ bias2)
{
    constexpr int TM = WM * 64, TN = WN * 32;
    constexpr int THREADS = WM * WN * 32;
    constexpr int AP = 24;
    constexpr int BP = BT ? (TN + 8) : 24;
    constexpr int AH = TM * AP;
    constexpr int BH = BT ? 16 * BP : TN * 24;
    constexpr int STAGE = 2 * AH + 2 * BH;
    constexpr int NA = TM * 2 / THREADS;
    constexpr int NB = BT ? (2 * TN / THREADS) : (TN * 2 / THREADS);
    constexpr int NSTG = 4;

    extern __shared__ bf16 smn[];
    const int tid = threadIdx.x, warp = tid >> 5, lane = tid & 31;
    const int wm = warp / WN, wn = warp % WN;

    float c[4][4][4];
#pragma unroll
    for (int mt = 0; mt < 4; mt++)
#pragma unroll
        for (int nt = 0; nt < 4; nt++)
#pragma unroll
            for (int e = 0; e < 4; e++) c[mt][nt][e] = 0.f;

    auto issue = [&](int cc) {
        const int s = cc % NSTG;
        bf16* Ah = smn + (size_t)s * STAGE;
        bf16* Al = Ah + AH;
        bf16* Bh = Ah + 2 * AH;
        bf16* Bl = Bh + BH;
        int k0 = cc * 16;
        const bf16 *Ap = Ah_, *Alp = Al_, *Bp = Bh_, *Blp = Bl_;
        if (DUAL && k0 >= K1) { Ap = Ah2_; Alp = Al2_; Bp = Bh2_; Blp = Bl2_; k0 -= K1; }
        const size_t cb = (size_t)(k0 >> 6) * sAk + (k0 & 63);
#pragma unroll
        for (int i = 0; i < NA; i++) {
            const int idx = i * THREADS + tid;
            const int row = idx >> 1, g = (idx & 1) * 8;
            const size_t go = (size_t)row * sAr + cb + g;
            const int off = row * AP + g;
            cpa16(smem_u32(Ah + off), Ap + go);
            cpa16(smem_u32(Al + off), Alp + go);
        }
#pragma unroll
        for (int i = 0; i < NB; i++) {
            const int idx = i * THREADS + tid;
            size_t go; int off;
            if (BT) {
                const int kr = idx / (TN / 8), q = idx % (TN / 8);
                go = (size_t)(k0 + kr) * sBr + q * 8;
                off = kr * BP + q * 8;
            } else {
                const int nr = idx >> 1, g = (idx & 1) * 8;
                go = (size_t)nr * sBr + (size_t)(k0 >> 6) * sBk + (k0 & 63) + g;
                off = nr * 24 + g;
            }
            cpa16(smem_u32(Bh + off), Bp + go);
            cpa16(smem_u32(Bl + off), Blp + go);
        }
    };

    auto compute = [&](int s) {
        bf16* Ah = smn + (size_t)s * STAGE;
        bf16* Al = Ah + AH;
        bf16* Bh = Ah + 2 * AH;
        bf16* Bl = Bh + BH;
        uint32_t ah[4][4], al[4][4], bh[4][2], bl[4][2];
#pragma unroll
        for (int mt = 0; mt < 4; mt++) {
            const int row = wm * 64 + mt * 16 + (lane & 15);
            const int ko = ((lane >> 4) & 1) * 8;
            ldsm4(ah[mt][0], ah[mt][1], ah[mt][2], ah[mt][3], smem_u32(Ah + row * AP + ko));
            ldsm4(al[mt][0], al[mt][1], al[mt][2], al[mt][3], smem_u32(Al + row * AP + ko));
        }
#pragma unroll
        for (int nt = 0; nt < 4; nt++) {
            if (BT) {
                const int k = (lane & 7) + ((lane >> 3) & 1) * 8;
                const int ncol = wn * 32 + nt * 8;
                ldsm2t(bh[nt][0], bh[nt][1], smem_u32(Bh + k * BP + ncol));
                ldsm2t(bl[nt][0], bl[nt][1], smem_u32(Bl + k * BP + ncol));
            } else {
                const int nrow = wn * 32 + nt * 8 + (lane & 7);
                const int ko = ((lane >> 3) & 1) * 8;
                ldsm2(bh[nt][0], bh[nt][1], smem_u32(Bh + nrow * 24 + ko));
                ldsm2(bl[nt][0], bl[nt][1], smem_u32(Bl + nrow * 24 + ko));
            }
        }
        // product-major: maximize independent accumulator chains
#pragma unroll
        for (int mt = 0; mt < 4; mt++)
#pragma unroll
            for (int nt = 0; nt < 4; nt++)
                mma16816(c[mt][nt], ah[mt], bh[nt]);
#pragma unroll
        for (int mt = 0; mt < 4; mt++)
#pragma unroll
            for (int nt = 0; nt < 4; nt++)
                mma16816(c[mt][nt], ah[mt], bl[nt]);
#pragma unroll
        for (int mt = 0; mt < 4; mt++)
#pragma unroll
            for (int nt = 0; nt < 4; nt++)
                mma16816(c[mt][nt], al[mt], bh[nt]);
    };

    const int NC = K >> 4;
    issue(0); CP_COMMIT();
    issue(1); CP_COMMIT();
    issue(2); CP_COMMIT();
    for (int cc = 0; cc < NC; cc++) {
        CP_WAIT2();
        __syncthreads();
        if (cc + 3 < NC) issue(cc + 3);
        CP_COMMIT();
        compute(cc % NSTG);
    }

    const int g = lane >> 2, tg = lane & 3;
#pragma unroll
    for (int mt = 0; mt < 4; mt++) {
#pragma unroll
        for (int nt = 0; nt < 4; nt++) {
            const int row0 = wm * 64 + mt * 16 + g;
            const int col = wn * 32 + nt * 8 + tg * 2;
            float2 v0 = make_float2(c[mt][nt][0], c[mt][nt][1]);
            float2 v1 = make_float2(c[mt][nt][2], c[mt][nt][3]);
            if (OSPLIT) {
                uint32_t h0, l0, h1, l1;
                split_pair(v0.x, v0.y, h0, l0);
                split_pair(v1.x, v1.y, h1, l1);
                *(uint32_t*)(Chp + (size_t)row0 * ldc + col) = h0;
                *(uint32_t*)(Clp + (size_t)row0 * ldc + col) = l0;
                *(uint32_t*)(Chp + (size_t)(row0 + 8) * ldc + col) = h1;
                *(uint32_t*)(Clp + (size_t)(row0 + 8) * ldc + col) = l1;
            } else {
                float b0 = 0.f, b1 = 0.f;
                if (bias)  { b0 += bias[col];  b1 += bias[col + 1]; }
                if (bias2) { b0 += bias2[col]; b1 += bias2[col + 1]; }
                v0.x += b0; v0.y += b1; v1.x += b0; v1.y += b1;
                *(float2*)(Cf + (size_t)row0 * ldc + col) = v0;
                *(float2*)(Cf + (size_t)(row0 + 8) * ldc + col) = v1;
            }
        }
    }
}

// ---- wrappers ----
// all 4 projections: grid (12, 256, 2); z = family (0: w-attn, 1: h-attn)
__global__ __launch_bounds__(256, 2)
void gemm_proj_all(const bf16* __restrict__ xh, const bf16* __restrict__ xl,
                   const bf16* __restrict__ wqh, const bf16* __restrict__ wql,
                   const bf16* __restrict__ wkvh, const bf16* __restrict__ wkvl,
                   const bf16* __restrict__ hqh, const bf16* __restrict__ hql,
                   const bf16* __restrict__ hkvh, const bf16* __restrict__ hkvl,
                   bf16* __restrict__ q1h, bf16* __restrict__ q1l,
                   bf16* __restrict__ kv1h, bf16* __restrict__ kv1l,
                   bf16* __restrict__ q2h, bf16* __restrict__ q2l,
                   bf16* __restrict__ kv2h, bf16* __restrict__ kv2l)
{
    const int m0 = blockIdx.y * 128;
    const int n0 = blockIdx.x * 128;
    const int fam = blockIdx.z;
    const bf16 *Bh, *Bl;
    bf16 *Ch, *Cl;
    int ldc;
    if (n0 < INNER) {
        Bh = (fam ? hqh : wqh) + n0;
        Bl = (fam ? hql : wql) + n0;
        Ch = (fam ? q2h : q1h) + (size_t)m0 * INNER + n0;
        Cl = (fam ? q2l : q1l) + (size_t)m0 * INNER + n0;
        ldc = INNER;
    } else {
        const int nn = n0 - INNER;
        Bh = (fam ? hkvh : wkvh) + nn;
        Bl = (fam ? hkvl : wkvl) + nn;
        Ch = (fam ? kv2h : kv1h) + (size_t)m0 * 2 * INNER + nn;
        Cl = (fam ? kv2l : kv1l) + (size_t)m0 * 2 * INNER + nn;
        ldc = 2 * INNER;
    }
    const int Nw = (n0 < INNER) ? INNER : 2 * INNER;
    gemm_core4<2, 4, 1, 1, 0>(xh + (size_t)m0 * DIM, xl + (size_t)m0 * DIM, DIM, 64,
                              Bh, Bl, Nw, 0,
                              nullptr, nullptr, nullptr, nullptr, 0,
                              nullptr, Ch, Cl, ldc, DIM, nullptr, nullptr);
}

// fused output: out = O1@wout + O2@hout + wout_b + hout_b   (dual K segments)
__global__ __launch_bounds__(256, 2)
void gemm_out_fused(const bf16* __restrict__ o1h, const bf16* __restrict__ o1l,
                    const bf16* __restrict__ o2h, const bf16* __restrict__ o2l,
                    const bf16* __restrict__ wouth, const bf16* __restrict__ woutl,
                    const bf16* __restrict__ houth, const bf16* __restrict__ houtl,
                    float* __restrict__ C, const float* __restrict__ wout_b,
                    const float* __restrict__ hout_b)
{
    const int m0 = blockIdx.y * 128, n0 = blockIdx.x * 128;
    gemm_core4<2, 4, 1, 0, 1>(o1h + (size_t)m0 * INNER, o1l + (size_t)m0 * INNER, INNER, 64,
                              wouth + n0, woutl + n0, DIM, 0,
                              o2h + (size_t)m0 * INNER, o2l + (size_t)m0 * INNER,
                              houth + n0, houtl + n0, INNER,
                              C + (size_t)m0 * DIM + n0, nullptr, nullptr,
                              DIM, 2 * INNER, wout_b + n0, hout_b + n0);
}

__global__ __launch_bounds__(256, 2)
void gemm_dots2(const bf16* __restrict__ Qh, const bf16* __restrict__ Ql,
                const bf16* __restrict__ Kh, const bf16* __restrict__ Kl,
                float* __restrict__ Pp)
{
    const int j0 = blockIdx.x * 128, i0 = blockIdx.y * 128;
    const int h = blockIdx.z >> 2, s = blockIdx.z & 3;
    const size_t r0 = (size_t)s * 32;
    const size_t aoff = (size_t)h * 64 + (size_t)i0 * INNER + r0 * MSAW * INNER;
    const size_t boff = (size_t)h * 64 + (size_t)j0 * 2 * INNER + r0 * MSAW * 2 * INNER;
    gemm_core4<2, 4, 0, 0, 0>(Qh + aoff, Ql + aoff, INNER, (size_t)MSAW * INNER,
                              Kh + boff, Kl + boff, 2 * INNER, (size_t)MSAW * 2 * INNER,
                              nullptr, nullptr, nullptr, nullptr, 0,
                              Pp + (size_t)blockIdx.z * (MSAW * MSAW) + (size_t)i0 * MSAW + j0,
                              nullptr, nullptr, MSAW, 32 * 64, nullptr, nullptr);
}

__global__ __launch_bounds__(128, 3)
void gemm_av2(const bf16* __restrict__ Ph, const bf16* __restrict__ Pl,
              const bf16* __restrict__ Vh, const bf16* __restrict__ Vl,
              bf16* __restrict__ Oh, bf16* __restrict__ Ol)
{
    const int i0 = blockIdx.x * 128;
    const int h = blockIdx.y, r = blockIdx.z;
    const size_t aoff = (size_t)h * (MSAW * MSAW) + (size_t)i0 * MSAW;
    const size_t boff = (size_t)INNER + (size_t)h * 64 + (size_t)r * MSAW * 2 * INNER;
    const size_t coff = ((size_t)r * MSAW + i0) * INNER + h * 64;
    gemm_core4<2, 2, 1, 1, 0>(Ph + aoff, Pl + aoff, MSAW, 64,
                              Vh + boff, Vl + boff, 2 * INNER, 0,
                              nullptr, nullptr, nullptr, nullptr, 0,
                              nullptr, Oh + coff, Ol + coff, INNER, MSAW, nullptr, nullptr);
}

// smem bytes: 4 stages
#define SM_PROJ (4 * (2 * 128 * 24 + 2 * 16 * 136) * 2)
#define SM_DOTS (4 * (2 * 128 * 24 + 2 * 128 * 24) * 2)
#define SM_AV   (4 * (2 * 128 * 24 + 2 * 16 * 72) * 2)

// ================= tensor column attention =================
#define COL_SMEM2 (6 * 128 * 72 * 2)
__global__ __launch_bounds__(256, 2)
void col_attn2(const bf16* __restrict__ qh, const bf16* __restrict__ ql,
               const bf16* __restrict__ kvh, const bf16* __restrict__ kvl,
               bf16* __restrict__ oh, bf16* __restrict__ ol)
{
    extern __shared__ bf16 smc[];
    const int PL = 128 * 72;
    bf16 *sqh = smc,          *sql = smc + PL;
    bf16 *skh = smc + 2 * PL, *skl = smc + 3 * PL;
    bf16 *svh = smc + 4 * PL, *svl = smc + 5 * PL;

    const int wi = blockIdx.x, head = blockIdx.y;
    const int tid = threadIdx.x, warp = tid >> 5, lane = tid & 31;

#pragma unroll
    for (int i = 0; i < 4; i++) {
        const int idx = i * 256 + tid;
        const int row = idx >> 3, g = (idx & 7) * 8;
        const size_t gq = ((size_t)(row * MSAW + wi)) * INNER + head * 64 + g;
        const size_t gk = ((size_t)(row * MSAW + wi)) * 2 * INNER + head * 64 + g;
        cpa16(smem_u32(sqh + row * 72 + g), qh + gq);
        cpa16(smem_u32(sql + row * 72 + g), ql + gq);
        cpa16(smem_u32(skh + row * 72 + g), kvh + gk);
        cpa16(smem_u32(skl + row * 72 + g), kvl + gk);
        cpa16(smem_u32(svh + row * 72 + g), kvh + gk + INNER);
        cpa16(smem_u32(svl + row * 72 + g), kvl + gk + INNER);
    }
    CP_COMMIT();
    CP_WAIT0();
    __syncthreads();

    const int m0 = warp * 16;
    float s[16][4];
#pragma unroll
    for (int nt = 0; nt < 16; nt++)
#pragma unroll
        for (int e = 0; e < 4; e++) s[nt][e] = 0.f;

#pragma unroll
    for (int kc = 0; kc < 4; kc++) {
        uint32_t ah[4], al[4];
        const int arow = m0 + (lane & 15);
        const int acol = kc * 16 + ((lane >> 4) & 1) * 8;
        ldsm4(ah[0], ah[1], ah[2], ah[3], smem_u32(sqh + arow * 72 + acol));
        ldsm4(al[0], al[1], al[2], al[3], smem_u32(sql + arow * 72 + acol));
#pragma unroll
        for (int ng = 0; ng < 4; ng++) {
            uint32_t bh[4][2], bl[4][2];
#pragma unroll
            for (int t = 0; t < 4; t++) {
                const int nt = ng * 4 + t;
                const int brow = nt * 8 + (lane & 7);
                const int bcol = kc * 16 + ((lane >> 3) & 1) * 8;
                ldsm2(bh[t][0], bh[t][1], smem_u32(skh + brow * 72 + bcol));
                ldsm2(bl[t][0], bl[t][1], smem_u32(skl + brow * 72 + bcol));
            }
#pragma unroll
            for (int t = 0; t < 4; t++) mma16816(s[ng * 4 + t], ah, bh[t]);
#pragma unroll
            for (int t = 0; t < 4; t++) mma16816(s[ng * 4 + t], ah, bl[t]);
#pragma unroll
            for (int t = 0; t < 4; t++) mma16816(s[ng * 4 + t], al, bh[t]);
        }
    }

    const float sc = 0.125f;
    float mx0 = -1e30f, mx1 = -1e30f;
#pragma unroll
    for (int nt = 0; nt < 16; nt++) {
        mx0 = fmaxf(mx0, fmaxf(s[nt][0], s[nt][1]));
        mx1 = fmaxf(mx1, fmaxf(s[nt][2], s[nt][3]));
    }
    mx0 = fmaxf(mx0, __shfl_xor_sync(0xffffffffu, mx0, 1));
    mx0 = fmaxf(mx0, __shfl_xor_sync(0xffffffffu, mx0, 2));
    mx1 = fmaxf(mx1, __shfl_xor_sync(0xffffffffu, mx1, 1));
    mx1 = fmaxf(mx1, __shfl_xor_sync(0xffffffffu, mx1, 2));
    float sum0 = 0.f, sum1 = 0.f;
#pragma unroll
    for (int nt = 0; nt < 16; nt++) {
        s[nt][0] = __expf(sc * (s[nt][0] - mx0)); sum0 += s[nt][0];
        s[nt][1] = __expf(sc * (s[nt][1] - mx0)); sum0 += s[nt][1];
        s[nt][2] = __expf(sc * (s[nt][2] - mx1)); sum1 += s[nt][2];
        s[nt][3] = __expf(sc * (s[nt][3] - mx1)); sum1 += s[nt][3];
    }
    sum0 += __shfl_xor_sync(0xffffffffu, sum0, 1);
    sum0 += __shfl_xor_sync(0xffffffffu, sum0, 2);
    sum1 += __shfl_xor_sync(0xffffffffu, sum1, 1);
    sum1 += __shfl_xor_sync(0xffffffffu, sum1, 2);
    const float inv0 = 1.f / sum0, inv1 = 1.f / sum1;
#pragma unroll
    for (int nt = 0; nt < 16; nt++) {
        s[nt][0] *= inv0; s[nt][1] *= inv0;
        s[nt][2] *= inv1; s[nt][3] *= inv1;
    }

    float o[8][4];
#pragma unroll
    for (int dt = 0; dt < 8; dt++)
#pragma unroll
        for (int e = 0; e < 4; e++) o[dt][e] = 0.f;

#pragma unroll
    for (int jc = 0; jc < 8; jc++) {
        uint32_t pah[4], pal[4];
        split_pair(s[2 * jc][0],     s[2 * jc][1],     pah[0], pal[0]);
        split_pair(s[2 * jc][2],     s[2 * jc][3],     pah[1], pal[1]);
        split_pair(s[2 * jc + 1][0], s[2 * jc + 1][1], pah[2], pal[2]);
        split_pair(s[2 * jc + 1][2], s[2 * jc + 1][3], pah[3], pal[3]);
        const int jrow = jc * 16 + (lane & 7) + ((lane >> 3) & 1) * 8;
#pragma unroll
        for (int dg = 0; dg < 2; dg++) {
            uint32_t bh[4][2], bl[4][2];
#pragma unroll
            for (int t = 0; t < 4; t++) {
                const int dt = dg * 4 + t;
                ldsm2t(bh[t][0], bh[t][1], smem_u32(svh + jrow * 72 + dt * 8));
                ldsm2t(bl[t][0], bl[t][1], smem_u32(svl + jrow * 72 + dt * 8));
            }
#pragma unroll
            for (int t = 0; t < 4; t++) mma16816(o[dg * 4 + t], pah, bh[t]);
#pragma unroll
            for (int t = 0; t < 4; t++) mma16816(o[dg * 4 + t], pah, bl[t]);
#pragma unroll
            for (int t = 0; t < 4; t++) mma16816(o[dg * 4 + t], pal, bh[t]);
        }
    }

    const int g = lane >> 2, tg = lane & 3;
    const int r0 = m0 + g, r1 = r0 + 8;
#pragma unroll
    for (int dt = 0; dt < 8; dt++) {
        const int d = head * 64 + dt * 8 + tg * 2;
        const size_t b0 = ((size_t)(r0 * MSAW + wi)) * INNER + d;
        const size_t b1 = ((size_t)(r1 * MSAW + wi)) * INNER + d;
        uint32_t h0, l0, h1, l1;
        split_pair(o[dt][0], o[dt][1], h0, l0);
        split_pair(o[dt][2], o[dt][3], h1, l1);
        *(uint32_t*)(oh + b0) = h0;
        *(uint32_t*)(ol + b0) = l0;
        *(uint32_t*)(oh + b1) = h1;
        *(uint32_t*)(ol + b1) = l1;
    }
}

// ============= reduce 4 dots partials + scale + softmax -> hi/lo planes =============
__global__ __launch_bounds__(256)
void softmax_reduce2(const float* __restrict__ Pp, bf16* __restrict__ Ph, bf16* __restrict__ Pl)
{
    const int h = blockIdx.x >> 8, i = blockIdx.x & 255;
    const int tid = threadIdx.x;
    __shared__ float red[34];
    float v = 0.f;
#pragma unroll
    for (int s = 0; s < 4; s++)
        v += Pp[((size_t)(h * 4 + s) * MSAW + i) * MSAW + tid];
    v *= 0.011048543456039806f;  // (1/8) * 128^-0.5

    float m = v;
#pragma unroll
    for (int o = 16; o; o >>= 1) m = fmaxf(m, __shfl_xor_sync(0xffffffffu, m, o));
    if ((tid & 31) == 0) red[tid >> 5] = m;
    __syncthreads();
    if (tid == 0) {
        float mm = red[0];
#pragma unroll
        for (int w = 1; w < 8; w++) mm = fmaxf(mm, red[w]);
        red[32] = mm;
    }
    __syncthreads();
    const float e = __expf(v - red[32]);
    float s = e;
#pragma unroll
    for (int o = 16; o; o >>= 1) s += __shfl_xor_sync(0xffffffffu, s, o);
    if ((tid & 31) == 0) red[8 + (tid >> 5)] = s;
    __syncthreads();
    if (tid == 0) {
        float ss = 0.f;
#pragma unroll
        for (int w = 0; w < 8; w++) ss += red[8 + w];
        red[33] = 1.f / ss;
    }
    __syncthreads();
    const float p = e * red[33];
    const bf16 hp = __float2bfloat16(p);
    const bf16 lp = __float2bfloat16(p - __bfloat162float(hp));
    const size_t off = ((size_t)h * MSAW + i) * MSAW + tid;
    Ph[off] = hp;
    Pl[off] = lp;
}

// =============================== launch ===============================
extern "C" void kernel_launch(void* const* d_in, const int* in_sizes, int n_in,
                              void* d_out, int out_size)
{
    const float* x      = (const float*)d_in[0];
    const float* wq_w   = (const float*)d_in[1];
    const float* wkv_w  = (const float*)d_in[2];
    const float* wout_w = (const float*)d_in[3];
    const float* wout_b = (const float*)d_in[4];
    const float* hq_w   = (const float*)d_in[5];
    const float* hkv_w  = (const float*)d_in[6];
    const float* hout_w = (const float*)d_in[7];
    const float* hout_b = (const float*)d_in[8];
    float* out = (float*)d_out;

    void* p;
    bf16 *xh, *xl, *wqh, *wql, *wkvh, *wkvl, *hqh, *hql, *hkvh, *hkvl;
    bf16 *wouth, *woutl, *houth, *houtl;
    bf16 *q1h, *q1l, *kv1h, *kv1l, *q2h, *q2l, *kv2h, *kv2l;
    bf16 *o1h, *o1l, *o2h, *o2l, *p2h, *p2l;
    float* Pp;
    cudaGetSymbolAddress(&p, g_xh);    xh = (bf16*)p;
    cudaGetSymbolAddress(&p, g_xl);    xl = (bf16*)p;
    cudaGetSymbolAddress(&p, g_wqh);   wqh = (bf16*)p;
    cudaGetSymbolAddress(&p, g_wql);   wql = (bf16*)p;
    cudaGetSymbolAddress(&p, g_wkvh);  wkvh = (bf16*)p;
    cudaGetSymbolAddress(&p, g_wkvl);  wkvl = (bf16*)p;
    cudaGetSymbolAddress(&p, g_hqh);   hqh = (bf16*)p;
    cudaGetSymbolAddress(&p, g_hql);   hql = (bf16*)p;
    cudaGetSymbolAddress(&p, g_hkvh);  hkvh = (bf16*)p;
    cudaGetSymbolAddress(&p, g_hkvl);  hkvl = (bf16*)p;
    cudaGetSymbolAddress(&p, g_wouth); wouth = (bf16*)p;
    cudaGetSymbolAddress(&p, g_woutl); woutl = (bf16*)p;
    cudaGetSymbolAddress(&p, g_houth); houth = (bf16*)p;
    cudaGetSymbolAddress(&p, g_houtl); houtl = (bf16*)p;
    cudaGetSymbolAddress(&p, g_q1h);   q1h = (bf16*)p;
    cudaGetSymbolAddress(&p, g_q1l);   q1l = (bf16*)p;
    cudaGetSymbolAddress(&p, g_kv1h);  kv1h = (bf16*)p;
    cudaGetSymbolAddress(&p, g_kv1l);  kv1l = (bf16*)p;
    cudaGetSymbolAddress(&p, g_q2h);   q2h = (bf16*)p;
    cudaGetSymbolAddress(&p, g_q2l);   q2l = (bf16*)p;
    cudaGetSymbolAddress(&p, g_kv2h);  kv2h = (bf16*)p;
    cudaGetSymbolAddress(&p, g_kv2l);  kv2l = (bf16*)p;
    cudaGetSymbolAddress(&p, g_o1h);   o1h = (bf16*)p;
    cudaGetSymbolAddress(&p, g_o1l);   o1l = (bf16*)p;
    cudaGetSymbolAddress(&p, g_o2h);   o2h = (bf16*)p;
    cudaGetSymbolAddress(&p, g_o2l);   o2l = (bf16*)p;
    cudaGetSymbolAddress(&p, g_p2h);   p2h = (bf16*)p;
    cudaGetSymbolAddress(&p, g_p2l);   p2l = (bf16*)p;
    cudaGetSymbolAddress(&p, g_Pp);    Pp = (float*)p;

    cudaFuncSetAttribute(gemm_proj_all,  cudaFuncAttributeMaxDynamicSharedMemorySize, SM_PROJ);
    cudaFuncSetAttribute(gemm_out_fused, cudaFuncAttributeMaxDynamicSharedMemorySize, SM_PROJ);
    cudaFuncSetAttribute(gemm_dots2,     cudaFuncAttributeMaxDynamicSharedMemorySize, SM_DOTS);
    cudaFuncSetAttribute(gemm_av2,       cudaFuncAttributeMaxDynamicSharedMemorySize, SM_AV);
    cudaFuncSetAttribute(col_attn2,      cudaFuncAttributeMaxDynamicSharedMemorySize, COL_SMEM2);

    split_f32<<<(NTOK * DIM / 4) / 256, 256>>>(x, xh, xl, NTOK * DIM / 4);
    split_w6<<<1024, 256>>>(wq_w, wkv_w, hq_w, hkv_w, wout_w, hout_w,
                            wqh, wql, wkvh, wkvl, hqh, hql, hkvh, hkvl,
                            wouth, woutl, houth, houtl);

    gemm_proj_all<<<dim3(12, NTOK / 128, 2), 256, SM_PROJ>>>(
        xh, xl, wqh, wql, wkvh, wkvl, hqh, hql, hkvh, hkvl,
        q1h, q1l, kv1h, kv1l, q2h, q2l, kv2h, kv2l);

    col_attn2<<<dim3(MSAW, HEADS), 256, COL_SMEM2>>>(q1h, q1l, kv1h, kv1l, o1h, o1l);

    gemm_dots2<<<dim3(2, 2, 32), 256, SM_DOTS>>>(q2h, q2l, kv2h, kv2l, Pp);
    softmax_reduce2<<<HEADS * MSAW, 256>>>(Pp, p2h, p2l);
    gemm_av2<<<dim3(2, HEADS, MSAH), 128, SM_AV>>>(p2h, p2l, kv2h, kv2l, o2h, o2l);

    gemm_out_fused<<<dim3(2, NTOK / 128), 256, SM_PROJ>>>(
        o1h, o1l, o2h, o2l, wouth, woutl, houth, houtl, out, wout_b, hout_b);
}

// round 7
// speedup vs baseline: 3.4926x; 1.0252x over previous
#include <cuda_runtime.h>
#include <cuda_bf16.h>
#include <math.h>
#include <cstdint>

#define HEADS 8
#define DH    64
#define INNER 512
#define DIM   256
#define MSAH  128
#define MSAW  256
#define NTOK  (MSAH*MSAW)

typedef __nv_bfloat16 bf16;

// -------- scratch (static device globals; no runtime allocation) --------
__device__ bf16 g_xh [(size_t)NTOK*DIM],      g_xl [(size_t)NTOK*DIM];
__device__ bf16 g_wqh [(size_t)DIM*INNER],    g_wql [(size_t)DIM*INNER];
__device__ bf16 g_wkvh[(size_t)DIM*2*INNER],  g_wkvl[(size_t)DIM*2*INNER];
__device__ bf16 g_hqh [(size_t)DIM*INNER],    g_hql [(size_t)DIM*INNER];
__device__ bf16 g_hkvh[(size_t)DIM*2*INNER],  g_hkvl[(size_t)DIM*2*INNER];
__device__ bf16 g_wouth[(size_t)INNER*DIM],   g_woutl[(size_t)INNER*DIM];
__device__ bf16 g_houth[(size_t)INNER*DIM],   g_houtl[(size_t)INNER*DIM];
__device__ bf16 g_q1h [(size_t)NTOK*INNER],   g_q1l [(size_t)NTOK*INNER];
__device__ bf16 g_kv1h[(size_t)NTOK*2*INNER], g_kv1l[(size_t)NTOK*2*INNER];
__device__ bf16 g_q2h [(size_t)NTOK*INNER],   g_q2l [(size_t)NTOK*INNER];
__device__ bf16 g_kv2h[(size_t)NTOK*2*INNER], g_kv2l[(size_t)NTOK*2*INNER];
__device__ bf16 g_o1h [(size_t)NTOK*INNER],   g_o1l [(size_t)NTOK*INNER];
__device__ bf16 g_o2h [(size_t)NTOK*INNER],   g_o2l [(size_t)NTOK*INNER];
__device__ bf16 g_p2h [(size_t)HEADS*MSAW*MSAW], g_p2l [(size_t)HEADS*MSAW*MSAW];
__device__ float g_Pp [(size_t)32*MSAW*MSAW];

// ===================== helpers =====================
__device__ __forceinline__ uint32_t smem_u32(const void* p) {
    uint32_t a;
    asm("{ .reg .u64 t; cvta.to.shared.u64 t, %1; cvt.u32.u64 %0, t; }" : "=r"(a) : "l"(p));
    return a;
}
__device__ __forceinline__ void ldsm4(uint32_t& r0, uint32_t& r1, uint32_t& r2, uint32_t& r3, uint32_t a) {
    asm volatile("ldmatrix.sync.aligned.m8n8.x4.shared.b16 {%0,%1,%2,%3}, [%4];"
                 : "=r"(r0), "=r"(r1), "=r"(r2), "=r"(r3) : "r"(a));
}
__device__ __forceinline__ void ldsm4t(uint32_t& r0, uint32_t& r1, uint32_t& r2, uint32_t& r3, uint32_t a) {
    asm volatile("ldmatrix.sync.aligned.m8n8.x4.trans.shared.b16 {%0,%1,%2,%3}, [%4];"
                 : "=r"(r0), "=r"(r1), "=r"(r2), "=r"(r3) : "r"(a));
}
__device__ __forceinline__ void mma16816(float* c, const uint32_t* a, const uint32_t* b) {
    asm volatile("mma.sync.aligned.m16n8k16.row.col.f32.bf16.bf16.f32 "
                 "{%0,%1,%2,%3}, {%4,%5,%6,%7}, {%8,%9}, {%0,%1,%2,%3};"
                 : "+f"(c[0]), "+f"(c[1]), "+f"(c[2]), "+f"(c[3])
                 : "r"(a[0]), "r"(a[1]), "r"(a[2]), "r"(a[3]), "r"(b[0]), "r"(b[1]));
}
__device__ __forceinline__ void cpa16(uint32_t dst, const void* src) {
    asm volatile("cp.async.cg.shared.global [%0], [%1], 16;" :: "r"(dst), "l"(src));
}
#define CP_COMMIT() asm volatile("cp.async.commit_group;" ::: "memory")
#define CP_WAIT2()  asm volatile("cp.async.wait_group 2;" ::: "memory")
#define CP_WAIT0()  asm volatile("cp.async.wait_group 0;" ::: "memory")
__device__ __forceinline__ void split_pair(float a, float b, uint32_t& hi, uint32_t& lo) {
    bf16 ha = __float2bfloat16(a), hb = __float2bfloat16(b);
    bf16 la = __float2bfloat16(a - __bfloat162float(ha));
    bf16 lb = __float2bfloat16(b - __bfloat162float(hb));
    __nv_bfloat162 h2 = __halves2bfloat162(ha, hb);
    __nv_bfloat162 l2 = __halves2bfloat162(la, lb);
    hi = *(uint32_t*)&h2;
    lo = *(uint32_t*)&l2;
}

// ================= split fp32 -> bf16 hi/lo planes (one launch) =================
__device__ __forceinline__ void split_one(const float* in, bf16* H, bf16* L, int i) {
    const float4 v = ((const float4*)in)[i];
    uint32_t h0, l0, h1, l1;
    split_pair(v.x, v.y, h0, l0);
    split_pair(v.z, v.w, h1, l1);
    *(uint2*)(H + (size_t)i * 4) = make_uint2(h0, h1);
    *(uint2*)(L + (size_t)i * 4) = make_uint2(l0, l1);
}
__global__ __launch_bounds__(256)
void split_all(const float* x, const float* wq, const float* wkv, const float* hq,
               const float* hkv, const float* wo, const float* ho,
               bf16* xh, bf16* xl,
               bf16* wqh, bf16* wql, bf16* wkvh, bf16* wkvl,
               bf16* hqh, bf16* hql, bf16* hkvh, bf16* hkvl,
               bf16* woh, bf16* wol, bf16* hoh, bf16* hol)
{
    const int b = blockIdx.x;
    if (b < 8192) {
        split_one(x, xh, xl, b * 256 + threadIdx.x);
        return;
    }
    const int i = (b - 8192) * 256 + threadIdx.x;
    if (i < 32768)        split_one(wq,  wqh,  wql,  i);
    else if (i < 98304)   split_one(wkv, wkvh, wkvl, i - 32768);
    else if (i < 131072)  split_one(hq,  hqh,  hql,  i - 98304);
    else if (i < 196608)  split_one(hkv, hkvh, hkvl, i - 131072);
    else if (i < 229376)  split_one(wo,  woh,  wol,  i - 196608);
    else                  split_one(ho,  hoh,  hol,  i - 229376);
}

// ================= pre-split bf16x3 mma GEMM, cp.async 4-stage =================
template<int WM, int WN, int BT, int OSPLIT, int DUAL>
__device__ __forceinline__ void gemm_core4(
    const bf16* __restrict__ Ah_, const bf16* __restrict__ Al_, size_t sAr, size_t sAk,
    const bf16* __restrict__ Bh_, const bf16* __restrict__ Bl_, size_t sBr, size_t sBk,
    const bf16* __restrict__ Ah2_, const bf16* __restrict__ Al2_,
    const bf16* __restrict__ Bh2_, const bf16* __restrict__ Bl2_, int K1,
    float* __restrict__ Cf, bf16* __restrict__ Chp, bf16* __restrict__ Clp,
    int ldc, int K, const float* __restrict__ bias, const float* __restrict__ bias2)
{
    constexpr int TM = WM * 64, TN = WN * 32;
    constexpr int THREADS = WM * WN * 32;
    constexpr int AP = 24;
    constexpr int BP = BT ? (TN + 8) : 24;
    constexpr int AH = TM * AP;
    constexpr int BH = BT ? 16 * BP : TN * 24;
    constexpr int STAGE = 2 * AH + 2 * BH;
    constexpr int NA = TM * 2 / THREADS;
    constexpr int NB = BT ? (2 * TN / THREADS) : (TN * 2 / THREADS);
    constexpr int NSTG = 4;

    extern __shared__ bf16 smn[];
    const int tid = threadIdx.x, warp = tid >> 5, lane = tid & 31;
    const int wm = warp / WN, wn = warp % WN;

    float c[4][4][4];
#pragma unroll
    for (int mt = 0; mt < 4; mt++)
#pragma unroll
        for (int nt = 0; nt < 4; nt++)
#pragma unroll
            for (int e = 0; e < 4; e++) c[mt][nt][e] = 0.f;

    auto issue = [&](int cc) {
        const int s = cc % NSTG;
        bf16* Ah = smn + (size_t)s * STAGE;
        bf16* Al = Ah + AH;
        bf16* Bh = Ah + 2 * AH;
        bf16* Bl = Bh + BH;
        int k0 = cc * 16;
        const bf16 *Ap = Ah_, *Alp = Al_, *Bp = Bh_, *Blp = Bl_;
        if (DUAL && k0 >= K1) { Ap = Ah2_; Alp = Al2_; Bp = Bh2_; Blp = Bl2_; k0 -= K1; }
        const size_t cb = (size_t)(k0 >> 6) * sAk + (k0 & 63);
#pragma unroll
        for (int i = 0; i < NA; i++) {
            const int idx = i * THREADS + tid;
            const int row = idx >> 1, g = (idx & 1) * 8;
            const size_t go = (size_t)row * sAr + cb + g;
            const int off = row * AP + g;
            cpa16(smem_u32(Ah + off), Ap + go);
            cpa16(smem_u32(Al + off), Alp + go);
        }
#pragma unroll
        for (int i = 0; i < NB; i++) {
            const int idx = i * THREADS + tid;
            size_t go; int off;
            if (BT) {
                const int kr = idx / (TN / 8), q = idx % (TN / 8);
                go = (size_t)(k0 + kr) * sBr + q * 8;
                off = kr * BP + q * 8;
            } else {
                const int nr = idx >> 1, g = (idx & 1) * 8;
                go = (size_t)nr * sBr + (size_t)(k0 >> 6) * sBk + (k0 & 63) + g;
                off = nr * 24 + g;
            }
            cpa16(smem_u32(Bh + off), Bp + go);
            cpa16(smem_u32(Bl + off), Blp + go);
        }
    };

    auto compute = [&](int s) {
        bf16* Ah = smn + (size_t)s * STAGE;
        bf16* Al = Ah + AH;
        bf16* Bh = Ah + 2 * AH;
        bf16* Bl = Bh + BH;
        uint32_t ah[4][4], al[4][4], bh[4][2], bl[4][2];
#pragma unroll
        for (int mt = 0; mt < 4; mt++) {
            const int row = wm * 64 + mt * 16 + (lane & 15);
            const int ko = ((lane >> 4) & 1) * 8;
            ldsm4(ah[mt][0], ah[mt][1], ah[mt][2], ah[mt][3], smem_u32(Ah + row * AP + ko));
            ldsm4(al[mt][0], al[mt][1], al[mt][2], al[mt][3], smem_u32(Al + row * AP + ko));
        }
        // B frags via x4: one ldmatrix covers 2 n-tiles (both k-halves)
#pragma unroll
        for (int np = 0; np < 2; np++) {
            if (BT) {
                const int k = (lane & 7) + ((lane >> 3) & 1) * 8;
                const int col = wn * 32 + np * 16 + ((lane >> 4) & 1) * 8;
                ldsm4t(bh[2*np][0], bh[2*np][1], bh[2*np+1][0], bh[2*np+1][1],
                       smem_u32(Bh + k * BP + col));
                ldsm4t(bl[2*np][0], bl[2*np][1], bl[2*np+1][0], bl[2*np+1][1],
                       smem_u32(Bl + k * BP + col));
            } else {
                const int nrow = wn * 32 + np * 16 + (lane & 7) + ((lane >> 4) & 1) * 8;
                const int ko = ((lane >> 3) & 1) * 8;
                ldsm4(bh[2*np][0], bh[2*np][1], bh[2*np+1][0], bh[2*np+1][1],
                      smem_u32(Bh + nrow * 24 + ko));
                ldsm4(bl[2*np][0], bl[2*np][1], bl[2*np+1][0], bl[2*np+1][1],
                      smem_u32(Bl + nrow * 24 + ko));
            }
        }
        // product-major
#pragma unroll
        for (int mt = 0; mt < 4; mt++)
#pragma unroll
            for (int nt = 0; nt < 4; nt++)
                mma16816(c[mt][nt], ah[mt], bh[nt]);
#pragma unroll
        for (int mt = 0; mt < 4; mt++)
#pragma unroll
            for (int nt = 0; nt < 4; nt++)
                mma16816(c[mt][nt], ah[mt], bl[nt]);
#pragma unroll
        for (int mt = 0; mt < 4; mt++)
#pragma unroll
            for (int nt = 0; nt < 4; nt++)
                mma16816(c[mt][nt], al[mt], bh[nt]);
    };

    const int NC = K >> 4;
    issue(0); CP_COMMIT();
    issue(1); CP_COMMIT();
    issue(2); CP_COMMIT();
    for (int cc = 0; cc < NC; cc++) {
        CP_WAIT2();
        __syncthreads();
        if (cc + 3 < NC) issue(cc + 3);
        CP_COMMIT();
        compute(cc % NSTG);
    }

    const int g = lane >> 2, tg = lane & 3;
#pragma unroll
    for (int mt = 0; mt < 4; mt++) {
#pragma unroll
        for (int nt = 0; nt < 4; nt++) {
            const int row0 = wm * 64 + mt * 16 + g;
            const int col = wn * 32 + nt * 8 + tg * 2;
            float2 v0 = make_float2(c[mt][nt][0], c[mt][nt][1]);
            float2 v1 = make_float2(c[mt][nt][2], c[mt][nt][3]);
            if (OSPLIT) {
                uint32_t h0, l0, h1, l1;
                split_pair(v0.x, v0.y, h0, l0);
                split_pair(v1.x, v1.y, h1, l1);
                *(uint32_t*)(Chp + (size_t)row0 * ldc + col) = h0;
                *(uint32_t*)(Clp + (size_t)row0 * ldc + col) = l0;
                *(uint32_t*)(Chp + (size_t)(row0 + 8) * ldc + col) = h1;
                *(uint32_t*)(Clp + (size_t)(row0 + 8) * ldc + col) = l1;
            } else {
                float b0 = 0.f, b1 = 0.f;
                if (bias)  { b0 += bias[col];  b1 += bias[col + 1]; }
                if (bias2) { b0 += bias2[col]; b1 += bias2[col + 1]; }
                v0.x += b0; v0.y += b1; v1.x += b0; v1.y += b1;
                *(float2*)(Cf + (size_t)row0 * ldc + col) = v0;
                *(float2*)(Cf + (size_t)(row0 + 8) * ldc + col) = v1;
            }
        }
    }
}

// ---- wrappers ----
__global__ __launch_bounds__(256, 2)
void gemm_proj_all(const bf16* __restrict__ xh, const bf16* __restrict__ xl,
                   const bf16* __restrict__ wqh, const bf16* __restrict__ wql,
                   const bf16* __restrict__ wkvh, const bf16* __restrict__ wkvl,
                   const bf16* __restrict__ hqh, const bf16* __restrict__ hql,
                   const bf16* __restrict__ hkvh, const bf16* __restrict__ hkvl,
                   bf16* __restrict__ q1h, bf16* __restrict__ q1l,
                   bf16* __restrict__ kv1h, bf16* __restrict__ kv1l,
                   bf16* __restrict__ q2h, bf16* __restrict__ q2l,
                   bf16* __restrict__ kv2h, bf16* __restrict__ kv2l)
{
    const int m0 = blockIdx.y * 128;
    const int n0 = blockIdx.x * 128;
    const int fam = blockIdx.z;
    const bf16 *Bh, *Bl;
    bf16 *Ch, *Cl;
    int ldc;
    if (n0 < INNER) {
        Bh = (fam ? hqh : wqh) + n0;
        Bl = (fam ? hql : wql) + n0;
        Ch = (fam ? q2h : q1h) + (size_t)m0 * INNER + n0;
        Cl = (fam ? q2l : q1l) + (size_t)m0 * INNER + n0;
        ldc = INNER;
    } else {
        const int nn = n0 - INNER;
        Bh = (fam ? hkvh : wkvh) + nn;
        Bl = (fam ? hkvl : wkvl) + nn;
        Ch = (fam ? kv2h : kv1h) + (size_t)m0 * 2 * INNER + nn;
        Cl = (fam ? kv2l : kv1l) + (size_t)m0 * 2 * INNER + nn;
        ldc = 2 * INNER;
    }
    const int Nw = (n0 < INNER) ? INNER : 2 * INNER;
    gemm_core4<2, 4, 1, 1, 0>(xh + (size_t)m0 * DIM, xl + (size_t)m0 * DIM, DIM, 64,
                              Bh, Bl, Nw, 0,
                              nullptr, nullptr, nullptr, nullptr, 0,
                              nullptr, Ch, Cl, ldc, DIM, nullptr, nullptr);
}

__global__ __launch_bounds__(256, 2)
void gemm_out_fused(const bf16* __restrict__ o1h, const bf16* __restrict__ o1l,
                    const bf16* __restrict__ o2h, const bf16* __restrict__ o2l,
                    const bf16* __restrict__ wouth, const bf16* __restrict__ woutl,
                    const bf16* __restrict__ houth, const bf16* __restrict__ houtl,
                    float* __restrict__ C, const float* __restrict__ wout_b,
                    const float* __restrict__ hout_b)
{
    const int m0 = blockIdx.y * 128, n0 = blockIdx.x * 128;
    gemm_core4<2, 4, 1, 0, 1>(o1h + (size_t)m0 * INNER, o1l + (size_t)m0 * INNER, INNER, 64,
                              wouth + n0, woutl + n0, DIM, 0,
                              o2h + (size_t)m0 * INNER, o2l + (size_t)m0 * INNER,
                              houth + n0, houtl + n0, INNER,
                              C + (size_t)m0 * DIM + n0, nullptr, nullptr,
                              DIM, 2 * INNER, wout_b + n0, hout_b + n0);
}

__global__ __launch_bounds__(128, 3)
void gemm_av2(const bf16* __restrict__ Ph, const bf16* __restrict__ Pl,
              const bf16* __restrict__ Vh, const bf16* __restrict__ Vl,
              bf16* __restrict__ Oh, bf16* __restrict__ Ol)
{
    const int i0 = blockIdx.x * 128;
    const int h = blockIdx.y, r = blockIdx.z;
    const size_t aoff = (size_t)h * (MSAW * MSAW) + (size_t)i0 * MSAW;
    const size_t boff = (size_t)INNER + (size_t)h * 64 + (size_t)r * MSAW * 2 * INNER;
    const size_t coff = ((size_t)r * MSAW + i0) * INNER + h * 64;
    gemm_core4<2, 2, 1, 1, 0>(Ph + aoff, Pl + aoff, MSAW, 64,
                              Vh + boff, Vl + boff, 2 * INNER, 0,
                              nullptr, nullptr, nullptr, nullptr, 0,
                              nullptr, Oh + coff, Ol + coff, INNER, MSAW, nullptr, nullptr);
}

// smem bytes: 4 stages
#define SM_PROJ (4 * (2 * 128 * 24 + 2 * 16 * 136) * 2)
#define SM_AV   (4 * (2 * 128 * 24 + 2 * 16 * 72) * 2)
#define COL_SMEM2 (6 * 128 * 72 * 2)

// ================= column attention body =================
__device__ __forceinline__
void col_attn_body(int wi, int head,
                   const bf16* __restrict__ qh, const bf16* __restrict__ ql,
                   const bf16* __restrict__ kvh, const bf16* __restrict__ kvl,
                   bf16* __restrict__ oh, bf16* __restrict__ ol)
{
    extern __shared__ bf16 smc[];
    const int PL = 128 * 72;
    bf16 *sqh = smc,          *sql = smc + PL;
    bf16 *skh = smc + 2 * PL, *skl = smc + 3 * PL;
    bf16 *svh = smc + 4 * PL, *svl = smc + 5 * PL;

    const int tid = threadIdx.x, warp = tid >> 5, lane = tid & 31;

#pragma unroll
    for (int i = 0; i < 4; i++) {
        const int idx = i * 256 + tid;
        const int row = idx >> 3, g = (idx & 7) * 8;
        const size_t gq = ((size_t)(row * MSAW + wi)) * INNER + head * 64 + g;
        const size_t gk = ((size_t)(row * MSAW + wi)) * 2 * INNER + head * 64 + g;
        cpa16(smem_u32(sqh + row * 72 + g), qh + gq);
        cpa16(smem_u32(sql + row * 72 + g), ql + gq);
        cpa16(smem_u32(skh + row * 72 + g), kvh + gk);
        cpa16(smem_u32(skl + row * 72 + g), kvl + gk);
        cpa16(smem_u32(svh + row * 72 + g), kvh + gk + INNER);
        cpa16(smem_u32(svl + row * 72 + g), kvl + gk + INNER);
    }
    CP_COMMIT();
    CP_WAIT0();
    __syncthreads();

    const int m0 = warp * 16;
    float s[16][4];
#pragma unroll
    for (int nt = 0; nt < 16; nt++)
#pragma unroll
        for (int e = 0; e < 4; e++) s[nt][e] = 0.f;

#pragma unroll
    for (int kc = 0; kc < 4; kc++) {
        uint32_t ah[4], al[4];
        const int arow = m0 + (lane & 15);
        const int acol = kc * 16 + ((lane >> 4) & 1) * 8;
        ldsm4(ah[0], ah[1], ah[2], ah[3], smem_u32(sqh + arow * 72 + acol));
        ldsm4(al[0], al[1], al[2], al[3], smem_u32(sql + arow * 72 + acol));
#pragma unroll
        for (int ng = 0; ng < 4; ng++) {
            uint32_t bh[4][2], bl[4][2];
#pragma unroll
            for (int npp = 0; npp < 2; npp++) {
                const int nt0 = ng * 4 + npp * 2;
                const int brow = nt0 * 8 + (lane & 7) + ((lane >> 4) & 1) * 8;
                const int bcol = kc * 16 + ((lane >> 3) & 1) * 8;
                ldsm4(bh[npp*2][0], bh[npp*2][1], bh[npp*2+1][0], bh[npp*2+1][1],
                      smem_u32(skh + brow * 72 + bcol));
                ldsm4(bl[npp*2][0], bl[npp*2][1], bl[npp*2+1][0], bl[npp*2+1][1],
                      smem_u32(skl + brow * 72 + bcol));
            }
#pragma unroll
            for (int t = 0; t < 4; t++) mma16816(s[ng * 4 + t], ah, bh[t]);
#pragma unroll
            for (int t = 0; t < 4; t++) mma16816(s[ng * 4 + t], ah, bl[t]);
#pragma unroll
            for (int t = 0; t < 4; t++) mma16816(s[ng * 4 + t], al, bh[t]);
        }
    }

    const float sc = 0.125f;
    float mx0 = -1e30f, mx1 = -1e30f;
#pragma unroll
    for (int nt = 0; nt < 16; nt++) {
        mx0 = fmaxf(mx0, fmaxf(s[nt][0], s[nt][1]));
        mx1 = fmaxf(mx1, fmaxf(s[nt][2], s[nt][3]));
    }
    mx0 = fmaxf(mx0, __shfl_xor_sync(0xffffffffu, mx0, 1));
    mx0 = fmaxf(mx0, __shfl_xor_sync(0xffffffffu, mx0, 2));
    mx1 = fmaxf(mx1, __shfl_xor_sync(0xffffffffu, mx1, 1));
    mx1 = fmaxf(mx1, __shfl_xor_sync(0xffffffffu, mx1, 2));
    float sum0 = 0.f, sum1 = 0.f;
#pragma unroll
    for (int nt = 0; nt < 16; nt++) {
        s[nt][0] = __expf(sc * (s[nt][0] - mx0)); sum0 += s[nt][0];
        s[nt][1] = __expf(sc * (s[nt][1] - mx0)); sum0 += s[nt][1];
        s[nt][2] = __expf(sc * (s[nt][2] - mx1)); sum1 += s[nt][2];
        s[nt][3] = __expf(sc * (s[nt][3] - mx1)); sum1 += s[nt][3];
    }
    sum0 += __shfl_xor_sync(0xffffffffu, sum0, 1);
    sum0 += __shfl_xor_sync(0xffffffffu, sum0, 2);
    sum1 += __shfl_xor_sync(0xffffffffu, sum1, 1);
    sum1 += __shfl_xor_sync(0xffffffffu, sum1, 2);
    const float inv0 = 1.f / sum0, inv1 = 1.f / sum1;
#pragma unroll
    for (int nt = 0; nt < 16; nt++) {
        s[nt][0] *= inv0; s[nt][1] *= inv0;
        s[nt][2] *= inv1; s[nt][3] *= inv1;
    }

    float o[8][4];
#pragma unroll
    for (int dt = 0; dt < 8; dt++)
#pragma unroll
        for (int e = 0; e < 4; e++) o[dt][e] = 0.f;

#pragma unroll
    for (int jc = 0; jc < 8; jc++) {
        uint32_t pah[4], pal[4];
        split_pair(s[2 * jc][0],     s[2 * jc][1],     pah[0], pal[0]);
        split_pair(s[2 * jc][2],     s[2 * jc][3],     pah[1], pal[1]);
        split_pair(s[2 * jc + 1][0], s[2 * jc + 1][1], pah[2], pal[2]);
        split_pair(s[2 * jc + 1][2], s[2 * jc + 1][3], pah[3], pal[3]);
        const int jrow = jc * 16 + (lane & 7) + ((lane >> 3) & 1) * 8;
#pragma unroll
        for (int dg = 0; dg < 2; dg++) {
            uint32_t bh[4][2], bl[4][2];
#pragma unroll
            for (int dpp = 0; dpp < 2; dpp++) {
                const int dt0 = dg * 4 + dpp * 2;
                const int dcol = dt0 * 8 + ((lane >> 4) & 1) * 8;
                ldsm4t(bh[dpp*2][0], bh[dpp*2][1], bh[dpp*2+1][0], bh[dpp*2+1][1],
                       smem_u32(svh + jrow * 72 + dcol));
                ldsm4t(bl[dpp*2][0], bl[dpp*2][1], bl[dpp*2+1][0], bl[dpp*2+1][1],
                       smem_u32(svl + jrow * 72 + dcol));
            }
#pragma unroll
            for (int t = 0; t < 4; t++) mma16816(o[dg * 4 + t], pah, bh[t]);
#pragma unroll
            for (int t = 0; t < 4; t++) mma16816(o[dg * 4 + t], pah, bl[t]);
#pragma unroll
            for (int t = 0; t < 4; t++) mma16816(o[dg * 4 + t], pal, bh[t]);
        }
    }

    const int g = lane >> 2, tg = lane & 3;
    const int r0 = m0 + g, r1 = r0 + 8;
#pragma unroll
    for (int dt = 0; dt < 8; dt++) {
        const int d = head * 64 + dt * 8 + tg * 2;
        const size_t b0 = ((size_t)(r0 * MSAW + wi)) * INNER + d;
        const size_t b1 = ((size_t)(r1 * MSAW + wi)) * INNER + d;
        uint32_t h0, l0, h1, l1;
        split_pair(o[dt][0], o[dt][1], h0, l0);
        split_pair(o[dt][2], o[dt][3], h1, l1);
        *(uint32_t*)(oh + b0) = h0;
        *(uint32_t*)(ol + b0) = l0;
        *(uint32_t*)(oh + b1) = h1;
        *(uint32_t*)(ol + b1) = l1;
    }
}

// ============= fused attention: dots tiles (blocks 0..127) + col attn (128..2175) =============
__global__ __launch_bounds__(256, 2)
void attn_fused(const bf16* __restrict__ q1h, const bf16* __restrict__ q1l,
                const bf16* __restrict__ kv1h, const bf16* __restrict__ kv1l,
                const bf16* __restrict__ q2h, const bf16* __restrict__ q2l,
                const bf16* __restrict__ kv2h, const bf16* __restrict__ kv2l,
                bf16* __restrict__ o1h, bf16* __restrict__ o1l,
                float* __restrict__ Pp)
{
    const int b = blockIdx.x;
    if (b < 128) {
        const int j0 = (b & 1) * 128, i0 = ((b >> 1) & 1) * 128;
        const int z = b >> 2;
        const int h = z >> 2, s = z & 3;
        const size_t r0 = (size_t)s * 32;
        const size_t aoff = (size_t)h * 64 + (size_t)i0 * INNER + r0 * MSAW * INNER;
        const size_t boff = (size_t)h * 64 + (size_t)j0 * 2 * INNER + r0 * MSAW * 2 * INNER;
        gemm_core4<2, 4, 0, 0, 0>(q2h + aoff, q2l + aoff, INNER, (size_t)MSAW * INNER,
                                  kv2h + boff, kv2l + boff, 2 * INNER, (size_t)MSAW * 2 * INNER,
                                  nullptr, nullptr, nullptr, nullptr, 0,
                                  Pp + (size_t)z * (MSAW * MSAW) + (size_t)i0 * MSAW + j0,
                                  nullptr, nullptr, MSAW, 32 * 64, nullptr, nullptr);
    } else {
        const int cb = b - 128;
        col_attn_body(cb & 255, cb >> 8, q1h, q1l, kv1h, kv1l, o1h, o1l);
    }
}

// ============= reduce 4 dots partials + scale + softmax -> hi/lo planes =============
__global__ __launch_bounds__(256)
void softmax_reduce2(const float* __restrict__ Pp, bf16* __restrict__ Ph, bf16* __restrict__ Pl)
{
    const int h = blockIdx.x >> 8, i = blockIdx.x & 255;
    const int tid = threadIdx.x;
    __shared__ float red[34];
    float v = 0.f;
#pragma unroll
    for (int s = 0; s < 4; s++)
        v += Pp[((size_t)(h * 4 + s) * MSAW + i) * MSAW + tid];
    v *= 0.011048543456039806f;  // (1/8) * 128^-0.5

    float m = v;
#pragma unroll
    for (int o = 16; o; o >>= 1) m = fmaxf(m, __shfl_xor_sync(0xffffffffu, m, o));
    if ((tid & 31) == 0) red[tid >> 5] = m;
    __syncthreads();
    if (tid == 0) {
        float mm = red[0];
#pragma unroll
        for (int w = 1; w < 8; w++) mm = fmaxf(mm, red[w]);
        red[32] = mm;
    }
    __syncthreads();
    const float e = __expf(v - red[32]);
    float s = e;
#pragma unroll
    for (int o = 16; o; o >>= 1) s += __shfl_xor_sync(0xffffffffu, s, o);
    if ((tid & 31) == 0) red[8 + (tid >> 5)] = s;
    __syncthreads();
    if (tid == 0) {
        float ss = 0.f;
#pragma unroll
        for (int w = 0; w < 8; w++) ss += red[8 + w];
        red[33] = 1.f / ss;
    }
    __syncthreads();
    const float p = e * red[33];
    const bf16 hp = __float2bfloat16(p);
    const bf16 lp = __float2bfloat16(p - __bfloat162float(hp));
    const size_t off = ((size_t)h * MSAW + i) * MSAW + tid;
    Ph[off] = hp;
    Pl[off] = lp;
}

// =============================== launch ===============================
extern "C" void kernel_launch(void* const* d_in, const int* in_sizes, int n_in,
                              void* d_out, int out_size)
{
    const float* x      = (const float*)d_in[0];
    const float* wq_w   = (const float*)d_in[1];
    const float* wkv_w  = (const float*)d_in[2];
    const float* wout_w = (const float*)d_in[3];
    const float* wout_b = (const float*)d_in[4];
    const float* hq_w   = (const float*)d_in[5];
    const float* hkv_w  = (const float*)d_in[6];
    const float* hout_w = (const float*)d_in[7];
    const float* hout_b = (const float*)d_in[8];
    float* out = (float*)d_out;

    void* p;
    bf16 *xh, *xl, *wqh, *wql, *wkvh, *wkvl, *hqh, *hql, *hkvh, *hkvl;
    bf16 *wouth, *woutl, *houth, *houtl;
    bf16 *q1h, *q1l, *kv1h, *kv1l, *q2h, *q2l, *kv2h, *kv2l;
    bf16 *o1h, *o1l, *o2h, *o2l, *p2h, *p2l;
    float* Pp;
    cudaGetSymbolAddress(&p, g_xh);    xh = (bf16*)p;
    cudaGetSymbolAddress(&p, g_xl);    xl = (bf16*)p;
    cudaGetSymbolAddress(&p, g_wqh);   wqh = (bf16*)p;
    cudaGetSymbolAddress(&p, g_wql);   wql = (bf16*)p;
    cudaGetSymbolAddress(&p, g_wkvh);  wkvh = (bf16*)p;
    cudaGetSymbolAddress(&p, g_wkvl);  wkvl = (bf16*)p;
    cudaGetSymbolAddress(&p, g_hqh);   hqh = (bf16*)p;
    cudaGetSymbolAddress(&p, g_hql);   hql = (bf16*)p;
    cudaGetSymbolAddress(&p, g_hkvh);  hkvh = (bf16*)p;
    cudaGetSymbolAddress(&p, g_hkvl);  hkvl = (bf16*)p;
    cudaGetSymbolAddress(&p, g_wouth); wouth = (bf16*)p;
    cudaGetSymbolAddress(&p, g_woutl); woutl = (bf16*)p;
    cudaGetSymbolAddress(&p, g_houth); houth = (bf16*)p;
    cudaGetSymbolAddress(&p, g_houtl); houtl = (bf16*)p;
    cudaGetSymbolAddress(&p, g_q1h);   q1h = (bf16*)p;
    cudaGetSymbolAddress(&p, g_q1l);   q1l = (bf16*)p;
    cudaGetSymbolAddress(&p, g_kv1h);  kv1h = (bf16*)p;
    cudaGetSymbolAddress(&p, g_kv1l);  kv1l = (bf16*)p;
    cudaGetSymbolAddress(&p, g_q2h);   q2h = (bf16*)p;
    cudaGetSymbolAddress(&p, g_q2l);   q2l = (bf16*)p;
    cudaGetSymbolAddress(&p, g_kv2h);  kv2h = (bf16*)p;
    cudaGetSymbolAddress(&p, g_kv2l);  kv2l = (bf16*)p;
    cudaGetSymbolAddress(&p, g_o1h);   o1h = (bf16*)p;
    cudaGetSymbolAddress(&p, g_o1l);   o1l = (bf16*)p;
    cudaGetSymbolAddress(&p, g_o2h);   o2h = (bf16*)p;
    cudaGetSymbolAddress(&p, g_o2l);   o2l = (bf16*)p;
    cudaGetSymbolAddress(&p, g_p2h);   p2h = (bf16*)p;
    cudaGetSymbolAddress(&p, g_p2l);   p2l = (bf16*)p;
    cudaGetSymbolAddress(&p, g_Pp);    Pp = (float*)p;

    cudaFuncSetAttribute(gemm_proj_all,  cudaFuncAttributeMaxDynamicSharedMemorySize, SM_PROJ);
    cudaFuncSetAttribute(gemm_out_fused, cudaFuncAttributeMaxDynamicSharedMemorySize, SM_PROJ);
    cudaFuncSetAttribute(gemm_av2,       cudaFuncAttributeMaxDynamicSharedMemorySize, SM_AV);
    cudaFuncSetAttribute(attn_fused,     cudaFuncAttributeMaxDynamicSharedMemorySize, COL_SMEM2);

    split_all<<<8192 + 1024, 256>>>(x, wq_w, wkv_w, hq_w, hkv_w, wout_w, hout_w,
                                    xh, xl, wqh, wql, wkvh, wkvl, hqh, hql, hkvh, hkvl,
                                    wouth, woutl, houth, houtl);

    gemm_proj_all<<<dim3(12, NTOK / 128, 2), 256, SM_PROJ>>>(
        xh, xl, wqh, wql, wkvh, wkvl, hqh, hql, hkvh, hkvl,
        q1h, q1l, kv1h, kv1l, q2h, q2l, kv2h, kv2l);

    attn_fused<<<128 + MSAW * HEADS, 256, COL_SMEM2>>>(
        q1h, q1l, kv1h, kv1l, q2h, q2l, kv2h, kv2l, o1h, o1l, Pp);

    softmax_reduce2<<<HEADS * MSAW, 256>>>(Pp, p2h, p2l);
    gemm_av2<<<dim3(2, HEADS, MSAH), 128, SM_AV>>>(p2h, p2l, kv2h, kv2l, o2h, o2l);

    gemm_out_fused<<<dim3(2, NTOK / 128), 256, SM_PROJ>>>(
        o1h, o1l, o2h, o2l, wouth, woutl, houth, houtl, out, wout_b, hout_b);
}

// round 9
// speedup vs baseline: 3.6820x; 1.0542x over previous
#include <cuda_runtime.h>
#include <cuda_bf16.h>
#include <math.h>
#include <cstdint>

#define HEADS 8
#define DH    64
#define INNER 512
#define DIM   256
#define MSAH  128
#define MSAW  256
#define NTOK  (MSAH*MSAW)

typedef __nv_bfloat16 bf16;

// -------- scratch (static device globals; no runtime allocation) --------
__device__ bf16 g_xh [(size_t)NTOK*DIM],      g_xl [(size_t)NTOK*DIM];
__device__ bf16 g_wqh [(size_t)DIM*INNER],    g_wql [(size_t)DIM*INNER];
__device__ bf16 g_wkvh[(size_t)DIM*2*INNER],  g_wkvl[(size_t)DIM*2*INNER];
__device__ bf16 g_hqh [(size_t)DIM*INNER],    g_hql [(size_t)DIM*INNER];
__device__ bf16 g_hkvh[(size_t)DIM*2*INNER],  g_hkvl[(size_t)DIM*2*INNER];
__device__ bf16 g_wouth[(size_t)INNER*DIM],   g_woutl[(size_t)INNER*DIM];
__device__ bf16 g_houth[(size_t)INNER*DIM],   g_houtl[(size_t)INNER*DIM];
__device__ bf16 g_q1h [(size_t)NTOK*INNER],   g_q1l [(size_t)NTOK*INNER];
__device__ bf16 g_kv1h[(size_t)NTOK*2*INNER], g_kv1l[(size_t)NTOK*2*INNER];
__device__ bf16 g_q2h [(size_t)NTOK*INNER],   g_q2l [(size_t)NTOK*INNER];
__device__ bf16 g_kv2h[(size_t)NTOK*2*INNER], g_kv2l[(size_t)NTOK*2*INNER];
__device__ bf16 g_o1h [(size_t)NTOK*INNER],   g_o1l [(size_t)NTOK*INNER];
__device__ bf16 g_o2h [(size_t)NTOK*INNER],   g_o2l [(size_t)NTOK*INNER];
__device__ bf16 g_p2h [(size_t)HEADS*MSAW*MSAW], g_p2l [(size_t)HEADS*MSAW*MSAW];
__device__ float g_Pp [(size_t)32*MSAW*MSAW];

// ===================== helpers =====================
__device__ __forceinline__ uint32_t smem_u32(const void* p) {
    uint32_t a;
    asm("{ .reg .u64 t; cvta.to.shared.u64 t, %1; cvt.u32.u64 %0, t; }" : "=r"(a) : "l"(p));
    return a;
}
__device__ __forceinline__ void ldsm4(uint32_t& r0, uint32_t& r1, uint32_t& r2, uint32_t& r3, uint32_t a) {
    asm volatile("ldmatrix.sync.aligned.m8n8.x4.shared.b16 {%0,%1,%2,%3}, [%4];"
                 : "=r"(r0), "=r"(r1), "=r"(r2), "=r"(r3) : "r"(a));
}
__device__ __forceinline__ void ldsm4t(uint32_t& r0, uint32_t& r1, uint32_t& r2, uint32_t& r3, uint32_t a) {
    asm volatile("ldmatrix.sync.aligned.m8n8.x4.trans.shared.b16 {%0,%1,%2,%3}, [%4];"
                 : "=r"(r0), "=r"(r1), "=r"(r2), "=r"(r3) : "r"(a));
}
__device__ __forceinline__ void mma16816(float* c, const uint32_t* a, const uint32_t* b) {
    asm volatile("mma.sync.aligned.m16n8k16.row.col.f32.bf16.bf16.f32 "
                 "{%0,%1,%2,%3}, {%4,%5,%6,%7}, {%8,%9}, {%0,%1,%2,%3};"
                 : "+f"(c[0]), "+f"(c[1]), "+f"(c[2]), "+f"(c[3])
                 : "r"(a[0]), "r"(a[1]), "r"(a[2]), "r"(a[3]), "r"(b[0]), "r"(b[1]));
}
__device__ __forceinline__ void cpa16(uint32_t dst, const void* src) {
    asm volatile("cp.async.cg.shared.global [%0], [%1], 16;" :: "r"(dst), "l"(src));
}
#define CP_COMMIT() asm volatile("cp.async.commit_group;" ::: "memory")
#define CP_WAIT1()  asm volatile("cp.async.wait_group 1;" ::: "memory")
#define CP_WAIT2()  asm volatile("cp.async.wait_group 2;" ::: "memory")
#define CP_WAIT0()  asm volatile("cp.async.wait_group 0;" ::: "memory")
__device__ __forceinline__ void split_pair(float a, float b, uint32_t& hi, uint32_t& lo) {
    bf16 ha = __float2bfloat16(a), hb = __float2bfloat16(b);
    bf16 la = __float2bfloat16(a - __bfloat162float(ha));
    bf16 lb = __float2bfloat16(b - __bfloat162float(hb));
    __nv_bfloat162 h2 = __halves2bfloat162(ha, hb);
    __nv_bfloat162 l2 = __halves2bfloat162(la, lb);
    hi = *(uint32_t*)&h2;
    lo = *(uint32_t*)&l2;
}

// ================= split fp32 -> bf16 hi/lo planes (one launch) =================
__device__ __forceinline__ void split_one(const float* in, bf16* H, bf16* L, int i) {
    const float4 v = ((const float4*)in)[i];
    uint32_t h0, l0, h1, l1;
    split_pair(v.x, v.y, h0, l0);
    split_pair(v.z, v.w, h1, l1);
    *(uint2*)(H + (size_t)i * 4) = make_uint2(h0, h1);
    *(uint2*)(L + (size_t)i * 4) = make_uint2(l0, l1);
}
__global__ __launch_bounds__(256)
void split_all(const float* x, const float* wq, const float* wkv, const float* hq,
               const float* hkv, const float* wo, const float* ho,
               bf16* xh, bf16* xl,
               bf16* wqh, bf16* wql, bf16* wkvh, bf16* wkvl,
               bf16* hqh, bf16* hql, bf16* hkvh, bf16* hkvl,
               bf16* woh, bf16* wol, bf16* hoh, bf16* hol)
{
    const int b = blockIdx.x;
    if (b < 8192) {
        split_one(x, xh, xl, b * 256 + threadIdx.x);
        return;
    }
    const int i = (b - 8192) * 256 + threadIdx.x;
    if (i < 32768)        split_one(wq,  wqh,  wql,  i);
    else if (i < 98304)   split_one(wkv, wkvh, wkvl, i - 32768);
    else if (i < 131072)  split_one(hq,  hqh,  hql,  i - 98304);
    else if (i < 196608)  split_one(hkv, hkvh, hkvl, i - 131072);
    else if (i < 229376)  split_one(wo,  woh,  wol,  i - 196608);
    else                  split_one(ho,  hoh,  hol,  i - 229376);
}

// ================= pre-split bf16x3 mma GEMM, cp.async pipeline =================
// CH: K-chunk (16 or 32). NSTG: stages. Accumulation order identical to CH=16 path.
template<int WM, int WN, int BT, int OSPLIT, int DUAL, int CH, int NSTG>
__device__ __forceinline__ void gemm_core5(
    const bf16* __restrict__ Ah_, const bf16* __restrict__ Al_, size_t sAr, size_t sAk,
    const bf16* __restrict__ Bh_, const bf16* __restrict__ Bl_, size_t sBr, size_t sBk,
    const bf16* __restrict__ Ah2_, const bf16* __restrict__ Al2_,
    const bf16* __restrict__ Bh2_, const bf16* __restrict__ Bl2_, int K1,
    float* __restrict__ Cf, bf16* __restrict__ Chp, bf16* __restrict__ Clp,
    int ldc, int K, const float* __restrict__ bias, const float* __restrict__ bias2)
{
    constexpr int TM = WM * 64, TN = WN * 32;
    constexpr int THREADS = WM * WN * 32;
    constexpr int AP = CH + 8;                       // A (and BT=0 B) pitch in halves
    constexpr int BP = BT ? (TN + 8) : (CH + 8);
    constexpr int AH = TM * AP;
    constexpr int BH = BT ? CH * BP : TN * AP;
    constexpr int STAGE = 2 * AH + 2 * BH;
    constexpr int C8 = CH / 8;                       // 16B groups per row
    constexpr int NA = TM * C8 / THREADS;
    constexpr int NB = BT ? (CH * TN / 8) / THREADS : (TN * C8) / THREADS;

    extern __shared__ bf16 smn[];
    const int tid = threadIdx.x, warp = tid >> 5, lane = tid & 31;
    const int wm = warp / WN, wn = warp % WN;

    float c[4][4][4];
#pragma unroll
    for (int mt = 0; mt < 4; mt++)
#pragma unroll
        for (int nt = 0; nt < 4; nt++)
#pragma unroll
            for (int e = 0; e < 4; e++) c[mt][nt][e] = 0.f;

    auto issue = [&](int cc) {
        const int s = cc % NSTG;
        bf16* Ah = smn + (size_t)s * STAGE;
        bf16* Al = Ah + AH;
        bf16* Bh = Ah + 2 * AH;
        bf16* Bl = Bh + BH;
        int k0 = cc * CH;
        const bf16 *Ap = Ah_, *Alp = Al_, *Bp = Bh_, *Blp = Bl_;
        if (DUAL && k0 >= K1) { Ap = Ah2_; Alp = Al2_; Bp = Bh2_; Blp = Bl2_; k0 -= K1; }
        const size_t cb = (size_t)(k0 >> 6) * sAk + (k0 & 63);
#pragma unroll
        for (int i = 0; i < NA; i++) {
            const int idx = i * THREADS + tid;
            const int row = idx / C8, g = (idx % C8) * 8;
            const size_t go = (size_t)row * sAr + cb + g;
            const int off = row * AP + g;
            cpa16(smem_u32(Ah + off), Ap + go);
            cpa16(smem_u32(Al + off), Alp + go);
        }
#pragma unroll
        for (int i = 0; i < NB; i++) {
            const int idx = i * THREADS + tid;
            size_t go; int off;
            if (BT) {
                const int kr = idx / (TN / 8), q = idx % (TN / 8);
                go = (size_t)(k0 + kr) * sBr + q * 8;
                off = kr * BP + q * 8;
            } else {
                const int nr = idx / C8, g = (idx % C8) * 8;
                go = (size_t)nr * sBr + (size_t)(k0 >> 6) * sBk + (k0 & 63) + g;
                off = nr * AP + g;
            }
            cpa16(smem_u32(Bh + off), Bp + go);
            cpa16(smem_u32(Bl + off), Blp + go);
        }
    };

    auto compute = [&](int s) {
        bf16* Ah = smn + (size_t)s * STAGE;
        bf16* Al = Ah + AH;
        bf16* Bh = Ah + 2 * AH;
        bf16* Bl = Bh + BH;
#pragma unroll
        for (int h = 0; h < CH / 16; h++) {
            uint32_t ah[4][4], al[4][4], bh[4][2], bl[4][2];
#pragma unroll
            for (int mt = 0; mt < 4; mt++) {
                const int row = wm * 64 + mt * 16 + (lane & 15);
                const int ko = h * 16 + ((lane >> 4) & 1) * 8;
                ldsm4(ah[mt][0], ah[mt][1], ah[mt][2], ah[mt][3], smem_u32(Ah + row * AP + ko));
                ldsm4(al[mt][0], al[mt][1], al[mt][2], al[mt][3], smem_u32(Al + row * AP + ko));
            }
#pragma unroll
            for (int np = 0; np < 2; np++) {
                if (BT) {
                    const int k = h * 16 + (lane & 7) + ((lane >> 3) & 1) * 8;
                    const int col = wn * 32 + np * 16 + ((lane >> 4) & 1) * 8;
                    ldsm4t(bh[2*np][0], bh[2*np][1], bh[2*np+1][0], bh[2*np+1][1],
                           smem_u32(Bh + k * BP + col));
                    ldsm4t(bl[2*np][0], bl[2*np][1], bl[2*np+1][0], bl[2*np+1][1],
                           smem_u32(Bl + k * BP + col));
                } else {
                    const int nrow = wn * 32 + np * 16 + (lane & 7) + ((lane >> 4) & 1) * 8;
                    const int ko = h * 16 + ((lane >> 3) & 1) * 8;
                    ldsm4(bh[2*np][0], bh[2*np][1], bh[2*np+1][0], bh[2*np+1][1],
                          smem_u32(Bh + nrow * AP + ko));
                    ldsm4(bl[2*np][0], bl[2*np][1], bl[2*np+1][0], bl[2*np+1][1],
                          smem_u32(Bl + nrow * AP + ko));
                }
            }
            // product-major
#pragma unroll
            for (int mt = 0; mt < 4; mt++)
#pragma unroll
                for (int nt = 0; nt < 4; nt++)
                    mma16816(c[mt][nt], ah[mt], bh[nt]);
#pragma unroll
            for (int mt = 0; mt < 4; mt++)
#pragma unroll
                for (int nt = 0; nt < 4; nt++)
                    mma16816(c[mt][nt], ah[mt], bl[nt]);
#pragma unroll
            for (int mt = 0; mt < 4; mt++)
#pragma unroll
                for (int nt = 0; nt < 4; nt++)
                    mma16816(c[mt][nt], al[mt], bh[nt]);
        }
    };

    const int NC = K / CH;
#pragma unroll
    for (int p = 0; p < NSTG - 1; p++) { issue(p); CP_COMMIT(); }
    for (int cc = 0; cc < NC; cc++) {
        if constexpr (NSTG == 3) CP_WAIT1(); else CP_WAIT2();
        __syncthreads();
        if (cc + NSTG - 1 < NC) issue(cc + NSTG - 1);
        CP_COMMIT();
        compute(cc % NSTG);
    }

    const int g = lane >> 2, tg = lane & 3;
#pragma unroll
    for (int mt = 0; mt < 4; mt++) {
#pragma unroll
        for (int nt = 0; nt < 4; nt++) {
            const int row0 = wm * 64 + mt * 16 + g;
            const int col = wn * 32 + nt * 8 + tg * 2;
            float2 v0 = make_float2(c[mt][nt][0], c[mt][nt][1]);
            float2 v1 = make_float2(c[mt][nt][2], c[mt][nt][3]);
            if (OSPLIT) {
                uint32_t h0, l0, h1, l1;
                split_pair(v0.x, v0.y, h0, l0);
                split_pair(v1.x, v1.y, h1, l1);
                *(uint32_t*)(Chp + (size_t)row0 * ldc + col) = h0;
                *(uint32_t*)(Clp + (size_t)row0 * ldc + col) = l0;
                *(uint32_t*)(Chp + (size_t)(row0 + 8) * ldc + col) = h1;
                *(uint32_t*)(Clp + (size_t)(row0 + 8) * ldc + col) = l1;
            } else {
                float b0 = 0.f, b1 = 0.f;
                if (bias)  { b0 += bias[col];  b1 += bias[col + 1]; }
                if (bias2) { b0 += bias2[col]; b1 += bias2[col + 1]; }
                v0.x += b0; v0.y += b1; v1.x += b0; v1.y += b1;
                *(float2*)(Cf + (size_t)row0 * ldc + col) = v0;
                *(float2*)(Cf + (size_t)(row0 + 8) * ldc + col) = v1;
            }
        }
    }
}

// ---- wrappers ----
__global__ __launch_bounds__(256, 2)
void gemm_proj_all(const bf16* __restrict__ xh, const bf16* __restrict__ xl,
                   const bf16* __restrict__ wqh, const bf16* __restrict__ wql,
                   const bf16* __restrict__ wkvh, const bf16* __restrict__ wkvl,
                   const bf16* __restrict__ hqh, const bf16* __restrict__ hql,
                   const bf16* __restrict__ hkvh, const bf16* __restrict__ hkvl,
                   bf16* __restrict__ q1h, bf16* __restrict__ q1l,
                   bf16* __restrict__ kv1h, bf16* __restrict__ kv1l,
                   bf16* __restrict__ q2h, bf16* __restrict__ q2l,
                   bf16* __restrict__ kv2h, bf16* __restrict__ kv2l)
{
    const int m0 = blockIdx.y * 128;
    const int n0 = blockIdx.x * 128;
    const int fam = blockIdx.z;
    const bf16 *Bh, *Bl;
    bf16 *Ch, *Cl;
    int ldc;
    if (n0 < INNER) {
        Bh = (fam ? hqh : wqh) + n0;
        Bl = (fam ? hql : wql) + n0;
        Ch = (fam ? q2h : q1h) + (size_t)m0 * INNER + n0;
        Cl = (fam ? q2l : q1l) + (size_t)m0 * INNER + n0;
        ldc = INNER;
    } else {
        const int nn = n0 - INNER;
        Bh = (fam ? hkvh : wkvh) + nn;
        Bl = (fam ? hkvl : wkvl) + nn;
        Ch = (fam ? kv2h : kv1h) + (size_t)m0 * 2 * INNER + nn;
        Cl = (fam ? kv2l : kv1l) + (size_t)m0 * 2 * INNER + nn;
        ldc = 2 * INNER;
    }
    const int Nw = (n0 < INNER) ? INNER : 2 * INNER;
    gemm_core5<2, 4, 1, 1, 0, 32, 3>(xh + (size_t)m0 * DIM, xl + (size_t)m0 * DIM, DIM, 64,
                                     Bh, Bl, Nw, 0,
                                     nullptr, nullptr, nullptr, nullptr, 0,
                                     nullptr, Ch, Cl, ldc, DIM, nullptr, nullptr);
}

__global__ __launch_bounds__(256, 2)
void gemm_out_fused(const bf16* __restrict__ o1h, const bf16* __restrict__ o1l,
                    const bf16* __restrict__ o2h, const bf16* __restrict__ o2l,
                    const bf16* __restrict__ wouth, const bf16* __restrict__ woutl,
                    const bf16* __restrict__ houth, const bf16* __restrict__ houtl,
                    float* __restrict__ C, const float* __restrict__ wout_b,
                    const float* __restrict__ hout_b)
{
    const int m0 = blockIdx.y * 128, n0 = blockIdx.x * 128;
    gemm_core5<2, 4, 1, 0, 1, 32, 3>(o1h + (size_t)m0 * INNER, o1l + (size_t)m0 * INNER, INNER, 64,
                                     wouth + n0, woutl + n0, DIM, 0,
                                     o2h + (size_t)m0 * INNER, o2l + (size_t)m0 * INNER,
                                     houth + n0, houtl + n0, INNER,
                                     C + (size_t)m0 * DIM + n0, nullptr, nullptr,
                                     DIM, 2 * INNER, wout_b + n0, hout_b + n0);
}

__global__ __launch_bounds__(128, 3)
void gemm_av2(const bf16* __restrict__ Ph, const bf16* __restrict__ Pl,
              const bf16* __restrict__ Vh, const bf16* __restrict__ Vl,
              bf16* __restrict__ Oh, bf16* __restrict__ Ol)
{
    const int i0 = blockIdx.x * 128;
    const int h = blockIdx.y, r = blockIdx.z;
    const size_t aoff = (size_t)h * (MSAW * MSAW) + (size_t)i0 * MSAW;
    const size_t boff = (size_t)INNER + (size_t)h * 64 + (size_t)r * MSAW * 2 * INNER;
    const size_t coff = ((size_t)r * MSAW + i0) * INNER + h * 64;
    gemm_core5<2, 2, 1, 1, 0, 16, 4>(Ph + aoff, Pl + aoff, MSAW, 64,
                                     Vh + boff, Vl + boff, 2 * INNER, 0,
                                     nullptr, nullptr, nullptr, nullptr, 0,
                                     nullptr, Oh + coff, Ol + coff, INNER, MSAW, nullptr, nullptr);
}

// smem bytes
#define SM_PROJ (3 * (2 * 128 * 40 + 2 * 32 * 136) * 2)
#define SM_AV   (4 * (2 * 128 * 24 + 2 * 16 * 72) * 2)
#define COL_SMEM2 (6 * 128 * 72 * 2)

// ================= column attention body =================
__device__ __forceinline__
void col_attn_body(int wi, int head,
                   const bf16* __restrict__ qh, const bf16* __restrict__ ql,
                   const bf16* __restrict__ kvh, const bf16* __restrict__ kvl,
                   bf16* __restrict__ oh, bf16* __restrict__ ol)
{
    extern __shared__ bf16 smc[];
    const int PL = 128 * 72;
    bf16 *sqh = smc,          *sql = smc + PL;
    bf16 *skh = smc + 2 * PL, *skl = smc + 3 * PL;
    bf16 *svh = smc + 4 * PL, *svl = smc + 5 * PL;

    const int tid = threadIdx.x, warp = tid >> 5, lane = tid & 31;

#pragma unroll
    for (int i = 0; i < 4; i++) {
        const int idx = i * 256 + tid;
        const int row = idx >> 3, g = (idx & 7) * 8;
        const size_t gq = ((size_t)(row * MSAW + wi)) * INNER + head * 64 + g;
        const size_t gk = ((size_t)(row * MSAW + wi)) * 2 * INNER + head * 64 + g;
        cpa16(smem_u32(sqh + row * 72 + g), qh + gq);
        cpa16(smem_u32(sql + row * 72 + g), ql + gq);
        cpa16(smem_u32(skh + row * 72 + g), kvh + gk);
        cpa16(smem_u32(skl + row * 72 + g), kvl + gk);
        cpa16(smem_u32(svh + row * 72 + g), kvh + gk + INNER);
        cpa16(smem_u32(svl + row * 72 + g), kvl + gk + INNER);
    }
    CP_COMMIT();
    CP_WAIT0();
    __syncthreads();

    const int m0 = warp * 16;
    float s[16][4];
#pragma unroll
    for (int nt = 0; nt < 16; nt++)
#pragma unroll
        for (int e = 0; e < 4; e++) s[nt][e] = 0.f;

#pragma unroll
    for (int kc = 0; kc < 4; kc++) {
        uint32_t ah[4], al[4];
        const int arow = m0 + (lane & 15);
        const int acol = kc * 16 + ((lane >> 4) & 1) * 8;
        ldsm4(ah[0], ah[1], ah[2], ah[3], smem_u32(sqh + arow * 72 + acol));
        ldsm4(al[0], al[1], al[2], al[3], smem_u32(sql + arow * 72 + acol));
#pragma unroll
        for (int ng = 0; ng < 4; ng++) {
            uint32_t bh[4][2], bl[4][2];
#pragma unroll
            for (int npp = 0; npp < 2; npp++) {
                const int nt0 = ng * 4 + npp * 2;
                const int brow = nt0 * 8 + (lane & 7) + ((lane >> 4) & 1) * 8;
                const int bcol = kc * 16 + ((lane >> 3) & 1) * 8;
                ldsm4(bh[npp*2][0], bh[npp*2][1], bh[npp*2+1][0], bh[npp*2+1][1],
                      smem_u32(skh + brow * 72 + bcol));
                ldsm4(bl[npp*2][0], bl[npp*2][1], bl[npp*2+1][0], bl[npp*2+1][1],
                      smem_u32(skl + brow * 72 + bcol));
            }
#pragma unroll
            for (int t = 0; t < 4; t++) mma16816(s[ng * 4 + t], ah, bh[t]);
#pragma unroll
            for (int t = 0; t < 4; t++) mma16816(s[ng * 4 + t], ah, bl[t]);
#pragma unroll
            for (int t = 0; t < 4; t++) mma16816(s[ng * 4 + t], al, bh[t]);
        }
    }

    const float sc = 0.125f;
    float mx0 = -1e30f, mx1 = -1e30f;
#pragma unroll
    for (int nt = 0; nt < 16; nt++) {
        mx0 = fmaxf(mx0, fmaxf(s[nt][0], s[nt][1]));
        mx1 = fmaxf(mx1, fmaxf(s[nt][2], s[nt][3]));
    }
    mx0 = fmaxf(mx0, __shfl_xor_sync(0xffffffffu, mx0, 1));
    mx0 = fmaxf(mx0, __shfl_xor_sync(0xffffffffu, mx0, 2));
    mx1 = fmaxf(mx1, __shfl_xor_sync(0xffffffffu, mx1, 1));
    mx1 = fmaxf(mx1, __shfl_xor_sync(0xffffffffu, mx1, 2));
    float sum0 = 0.f, sum1 = 0.f;
#pragma unroll
    for (int nt = 0; nt < 16; nt++) {
        s[nt][0] = __expf(sc * (s[nt][0] - mx0)); sum0 += s[nt][0];
        s[nt][1] = __expf(sc * (s[nt][1] - mx0)); sum0 += s[nt][1];
        s[nt][2] = __expf(sc * (s[nt][2] - mx1)); sum1 += s[nt][2];
        s[nt][3] = __expf(sc * (s[nt][3] - mx1)); sum1 += s[nt][3];
    }
    sum0 += __shfl_xor_sync(0xffffffffu, sum0, 1);
    sum0 += __shfl_xor_sync(0xffffffffu, sum0, 2);
    sum1 += __shfl_xor_sync(0xffffffffu, sum1, 1);
    sum1 += __shfl_xor_sync(0xffffffffu, sum1, 2);
    const float inv0 = 1.f / sum0, inv1 = 1.f / sum1;
#pragma unroll
    for (int nt = 0; nt < 16; nt++) {
        s[nt][0] *= inv0; s[nt][1] *= inv0;
        s[nt][2] *= inv1; s[nt][3] *= inv1;
    }

    float o[8][4];
#pragma unroll
    for (int dt = 0; dt < 8; dt++)
#pragma unroll
        for (int e = 0; e < 4; e++) o[dt][e] = 0.f;

#pragma unroll
    for (int jc = 0; jc < 8; jc++) {
        uint32_t pah[4], pal[4];
        split_pair(s[2 * jc][0],     s[2 * jc][1],     pah[0], pal[0]);
        split_pair(s[2 * jc][2],     s[2 * jc][3],     pah[1], pal[1]);
        split_pair(s[2 * jc + 1][0], s[2 * jc + 1][1], pah[2], pal[2]);
        split_pair(s[2 * jc + 1][2], s[2 * jc + 1][3], pah[3], pal[3]);
        const int jrow = jc * 16 + (lane & 7) + ((lane >> 3) & 1) * 8;
#pragma unroll
        for (int dg = 0; dg < 2; dg++) {
            uint32_t bh[4][2], bl[4][2];
#pragma unroll
            for (int dpp = 0; dpp < 2; dpp++) {
                const int dt0 = dg * 4 + dpp * 2;
                const int dcol = dt0 * 8 + ((lane >> 4) & 1) * 8;
                ldsm4t(bh[dpp*2][0], bh[dpp*2][1], bh[dpp*2+1][0], bh[dpp*2+1][1],
                       smem_u32(svh + jrow * 72 + dcol));
                ldsm4t(bl[dpp*2][0], bl[dpp*2][1], bl[dpp*2+1][0], bl[dpp*2+1][1],
                       smem_u32(svl + jrow * 72 + dcol));
            }
#pragma unroll
            for (int t = 0; t < 4; t++) mma16816(o[dg * 4 + t], pah, bh[t]);
#pragma unroll
            for (int t = 0; t < 4; t++) mma16816(o[dg * 4 + t], pah, bl[t]);
#pragma unroll
            for (int t = 0; t < 4; t++) mma16816(o[dg * 4 + t], pal, bh[t]);
        }
    }

    const int g = lane >> 2, tg = lane & 3;
    const int r0 = m0 + g, r1 = r0 + 8;
#pragma unroll
    for (int dt = 0; dt < 8; dt++) {
        const int d = head * 64 + dt * 8 + tg * 2;
        const size_t b0 = ((size_t)(r0 * MSAW + wi)) * INNER + d;
        const size_t b1 = ((size_t)(r1 * MSAW + wi)) * INNER + d;
        uint32_t h0, l0, h1, l1;
        split_pair(o[dt][0], o[dt][1], h0, l0);
        split_pair(o[dt][2], o[dt][3], h1, l1);
        *(uint32_t*)(oh + b0) = h0;
        *(uint32_t*)(ol + b0) = l0;
        *(uint32_t*)(oh + b1) = h1;
        *(uint32_t*)(ol + b1) = l1;
    }
}

// ============= fused attention: dots tiles (blocks 0..127) + col attn (128..2175) =============
__global__ __launch_bounds__(256, 2)
void attn_fused(const bf16* __restrict__ q1h, const bf16* __restrict__ q1l,
                const bf16* __restrict__ kv1h, const bf16* __restrict__ kv1l,
                const bf16* __restrict__ q2h, const bf16* __restrict__ q2l,
                const bf16* __restrict__ kv2h, const bf16* __restrict__ kv2l,
                bf16* __restrict__ o1h, bf16* __restrict__ o1l,
                float* __restrict__ Pp)
{
    const int b = blockIdx.x;
    if (b < 128) {
        const int j0 = (b & 1) * 128, i0 = ((b >> 1) & 1) * 128;
        const int z = b >> 2;
        const int h = z >> 2, s = z & 3;
        const size_t r0 = (size_t)s * 32;
        const size_t aoff = (size_t)h * 64 + (size_t)i0 * INNER + r0 * MSAW * INNER;
        const size_t boff = (size_t)h * 64 + (size_t)j0 * 2 * INNER + r0 * MSAW * 2 * INNER;
        gemm_core5<2, 4, 0, 0, 0, 16, 4>(q2h + aoff, q2l + aoff, INNER, (size_t)MSAW * INNER,
                                         kv2h + boff, kv2l + boff, 2 * INNER, (size_t)MSAW * 2 * INNER,
                                         nullptr, nullptr, nullptr, nullptr, 0,
                                         Pp + (size_t)z * (MSAW * MSAW) + (size_t)i0 * MSAW + j0,
                                         nullptr, nullptr, MSAW, 32 * 64, nullptr, nullptr);
    } else {
        const int cb = b - 128;
        col_attn_body(cb & 255, cb >> 8, q1h, q1l, kv1h, kv1l, o1h, o1l);
    }
}

// ============= reduce 4 dots partials + scale + softmax -> hi/lo planes =============
__global__ __launch_bounds__(256)
void softmax_reduce2(const float* __restrict__ Pp, bf16* __restrict__ Ph, bf16* __restrict__ Pl)
{
    const int h = blockIdx.x >> 8, i = blockIdx.x & 255;
    const int tid = threadIdx.x;
    __shared__ float red[34];
    float v = 0.f;
#pragma unroll
    for (int s = 0; s < 4; s++)
        v += Pp[((size_t)(h * 4 + s) * MSAW + i) * MSAW + tid];
    v *= 0.011048543456039806f;  // (1/8) * 128^-0.5

    float m = v;
#pragma unroll
    for (int o = 16; o; o >>= 1) m = fmaxf(m, __shfl_xor_sync(0xffffffffu, m, o));
    if ((tid & 31) == 0) red[tid >> 5] = m;
    __syncthreads();
    if (tid == 0) {
        float mm = red[0];
#pragma unroll
        for (int w = 1; w < 8; w++) mm = fmaxf(mm, red[w]);
        red[32] = mm;
    }
    __syncthreads();
    const float e = __expf(v - red[32]);
    float s = e;
#pragma unroll
    for (int o = 16; o; o >>= 1) s += __shfl_xor_sync(0xffffffffu, s, o);
    if ((tid & 31) == 0) red[8 + (tid >> 5)] = s;
    __syncthreads();
    if (tid == 0) {
        float ss = 0.f;
#pragma unroll
        for (int w = 0; w < 8; w++) ss += red[8 + w];
        red[33] = 1.f / ss;
    }
    __syncthreads();
    const float p = e * red[33];
    const bf16 hp = __float2bfloat16(p);
    const bf16 lp = __float2bfloat16(p - __bfloat162float(hp));
    const size_t off = ((size_t)h * MSAW + i) * MSAW + tid;
    Ph[off] = hp;
    Pl[off] = lp;
}

// =============================== launch ===============================
extern "C" void kernel_launch(void* const* d_in, const int* in_sizes, int n_in,
                              void* d_out, int out_size)
{
    const float* x      = (const float*)d_in[0];
    const float* wq_w   = (const float*)d_in[1];
    const float* wkv_w  = (const float*)d_in[2];
    const float* wout_w = (const float*)d_in[3];
    const float* wout_b = (const float*)d_in[4];
    const float* hq_w   = (const float*)d_in[5];
    const float* hkv_w  = (const float*)d_in[6];
    const float* hout_w = (const float*)d_in[7];
    const float* hout_b = (const float*)d_in[8];
    float* out = (float*)d_out;

    void* p;
    bf16 *xh, *xl, *wqh, *wql, *wkvh, *wkvl, *hqh, *hql, *hkvh, *hkvl;
    bf16 *wouth, *woutl, *houth, *houtl;
    bf16 *q1h, *q1l, *kv1h, *kv1l, *q2h, *q2l, *kv2h, *kv2l;
    bf16 *o1h, *o1l, *o2h, *o2l, *p2h, *p2l;
    float* Pp;
    cudaGetSymbolAddress(&p, g_xh);    xh = (bf16*)p;
    cudaGetSymbolAddress(&p, g_xl);    xl = (bf16*)p;
    cudaGetSymbolAddress(&p, g_wqh);   wqh = (bf16*)p;
    cudaGetSymbolAddress(&p, g_wql);   wql = (bf16*)p;
    cudaGetSymbolAddress(&p, g_wkvh);  wkvh = (bf16*)p;
    cudaGetSymbolAddress(&p, g_wkvl);  wkvl = (bf16*)p;
    cudaGetSymbolAddress(&p, g_hqh);   hqh = (bf16*)p;
    cudaGetSymbolAddress(&p, g_hql);   hql = (bf16*)p;
    cudaGetSymbolAddress(&p, g_hkvh);  hkvh = (bf16*)p;
    cudaGetSymbolAddress(&p, g_hkvl);  hkvl = (bf16*)p;
    cudaGetSymbolAddress(&p, g_wouth); wouth = (bf16*)p;
    cudaGetSymbolAddress(&p, g_woutl); woutl = (bf16*)p;
    cudaGetSymbolAddress(&p, g_houth); houth = (bf16*)p;
    cudaGetSymbolAddress(&p, g_houtl); houtl = (bf16*)p;
    cudaGetSymbolAddress(&p, g_q1h);   q1h = (bf16*)p;
    cudaGetSymbolAddress(&p, g_q1l);   q1l = (bf16*)p;
    cudaGetSymbolAddress(&p, g_kv1h);  kv1h = (bf16*)p;
    cudaGetSymbolAddress(&p, g_kv1l);  kv1l = (bf16*)p;
    cudaGetSymbolAddress(&p, g_q2h);   q2h = (bf16*)p;
    cudaGetSymbolAddress(&p, g_q2l);   q2l = (bf16*)p;
    cudaGetSymbolAddress(&p, g_kv2h);  kv2h = (bf16*)p;
    cudaGetSymbolAddress(&p, g_kv2l);  kv2l = (bf16*)p;
    cudaGetSymbolAddress(&p, g_o1h);   o1h = (bf16*)p;
    cudaGetSymbolAddress(&p, g_o1l);   o1l = (bf16*)p;
    cudaGetSymbolAddress(&p, g_o2h);   o2h = (bf16*)p;
    cudaGetSymbolAddress(&p, g_o2l);   o2l = (bf16*)p;
    cudaGetSymbolAddress(&p, g_p2h);   p2h = (bf16*)p;
    cudaGetSymbolAddress(&p, g_p2l);   p2l = (bf16*)p;
    cudaGetSymbolAddress(&p, g_Pp);    Pp = (float*)p;

    cudaFuncSetAttribute(gemm_proj_all,  cudaFuncAttributeMaxDynamicSharedMemorySize, SM_PROJ);
    cudaFuncSetAttribute(gemm_out_fused, cudaFuncAttributeMaxDynamicSharedMemorySize, SM_PROJ);
    cudaFuncSetAttribute(gemm_av2,       cudaFuncAttributeMaxDynamicSharedMemorySize, SM_AV);
    cudaFuncSetAttribute(attn_fused,     cudaFuncAttributeMaxDynamicSharedMemorySize, COL_SMEM2);

    split_all<<<8192 + 1024, 256>>>(x, wq_w, wkv_w, hq_w, hkv_w, wout_w, hout_w,
                                    xh, xl, wqh, wql, wkvh, wkvl, hqh, hql, hkvh, hkvl,
                                    wouth, woutl, houth, houtl);

    gemm_proj_all<<<dim3(12, NTOK / 128, 2), 256, SM_PROJ>>>(
        xh, xl, wqh, wql, wkvh, wkvl, hqh, hql, hkvh, hkvl,
        q1h, q1l, kv1h, kv1l, q2h, q2l, kv2h, kv2l);

    attn_fused<<<128 + MSAW * HEADS, 256, COL_SMEM2>>>(
        q1h, q1l, kv1h, kv1l, q2h, q2l, kv2h, kv2l, o1h, o1l, Pp);

    softmax_reduce2<<<HEADS * MSAW, 256>>>(Pp, p2h, p2l);
    gemm_av2<<<dim3(2, HEADS, MSAH), 128, SM_AV>>>(p2h, p2l, kv2h, kv2l, o2h, o2l);

    gemm_out_fused<<<dim3(2, NTOK / 128), 256, SM_PROJ>>>(
        o1h, o1l, o2h, o2l, wouth, woutl, houth, houtl, out, wout_b, hout_b);
}

// round 10
// speedup vs baseline: 3.7834x; 1.0275x over previous
#include <cuda_runtime.h>
#include <cuda_bf16.h>
#include <math.h>
#include <cstdint>

#define HEADS 8
#define DH    64
#define INNER 512
#define DIM   256
#define MSAH  128
#define MSAW  256
#define NTOK  (MSAH*MSAW)

typedef __nv_bfloat16 bf16;

// -------- scratch (static device globals; no runtime allocation) --------
__device__ bf16 g_xh [(size_t)NTOK*DIM],      g_xl [(size_t)NTOK*DIM];
__device__ bf16 g_wqh [(size_t)DIM*INNER],    g_wql [(size_t)DIM*INNER];
__device__ bf16 g_wkvh[(size_t)DIM*2*INNER],  g_wkvl[(size_t)DIM*2*INNER];
__device__ bf16 g_hqh [(size_t)DIM*INNER],    g_hql [(size_t)DIM*INNER];
__device__ bf16 g_hkvh[(size_t)DIM*2*INNER],  g_hkvl[(size_t)DIM*2*INNER];
__device__ bf16 g_wouth[(size_t)INNER*DIM],   g_woutl[(size_t)INNER*DIM];
__device__ bf16 g_houth[(size_t)INNER*DIM],   g_houtl[(size_t)INNER*DIM];
__device__ bf16 g_q1h [(size_t)NTOK*INNER],   g_q1l [(size_t)NTOK*INNER];
__device__ bf16 g_kv1h[(size_t)NTOK*2*INNER], g_kv1l[(size_t)NTOK*2*INNER];
__device__ bf16 g_q2h [(size_t)NTOK*INNER],   g_q2l [(size_t)NTOK*INNER];
__device__ bf16 g_kv2h[(size_t)NTOK*2*INNER], g_kv2l[(size_t)NTOK*2*INNER];
__device__ bf16 g_o1h [(size_t)NTOK*INNER],   g_o1l [(size_t)NTOK*INNER];
__device__ bf16 g_o2h [(size_t)NTOK*INNER],   g_o2l [(size_t)NTOK*INNER];
__device__ bf16 g_p2h [(size_t)HEADS*MSAW*MSAW], g_p2l [(size_t)HEADS*MSAW*MSAW];
__device__ float g_Pp [(size_t)32*MSAW*MSAW];

// ===================== helpers =====================
__device__ __forceinline__ uint32_t smem_u32(const void* p) {
    uint32_t a;
    asm("{ .reg .u64 t; cvta.to.shared.u64 t, %1; cvt.u32.u64 %0, t; }" : "=r"(a) : "l"(p));
    return a;
}
__device__ __forceinline__ void ldsm4(uint32_t& r0, uint32_t& r1, uint32_t& r2, uint32_t& r3, uint32_t a) {
    asm volatile("ldmatrix.sync.aligned.m8n8.x4.shared.b16 {%0,%1,%2,%3}, [%4];"
                 : "=r"(r0), "=r"(r1), "=r"(r2), "=r"(r3) : "r"(a));
}
__device__ __forceinline__ void ldsm4t(uint32_t& r0, uint32_t& r1, uint32_t& r2, uint32_t& r3, uint32_t a) {
    asm volatile("ldmatrix.sync.aligned.m8n8.x4.trans.shared.b16 {%0,%1,%2,%3}, [%4];"
                 : "=r"(r0), "=r"(r1), "=r"(r2), "=r"(r3) : "r"(a));
}
__device__ __forceinline__ void mma16816(float* c, const uint32_t* a, const uint32_t* b) {
    asm volatile("mma.sync.aligned.m16n8k16.row.col.f32.bf16.bf16.f32 "
                 "{%0,%1,%2,%3}, {%4,%5,%6,%7}, {%8,%9}, {%0,%1,%2,%3};"
                 : "+f"(c[0]), "+f"(c[1]), "+f"(c[2]), "+f"(c[3])
                 : "r"(a[0]), "r"(a[1]), "r"(a[2]), "r"(a[3]), "r"(b[0]), "r"(b[1]));
}
__device__ __forceinline__ void cpa16(uint32_t dst, const void* src) {
    asm volatile("cp.async.cg.shared.global [%0], [%1], 16;" :: "r"(dst), "l"(src));
}
#define CP_COMMIT() asm volatile("cp.async.commit_group;" ::: "memory")
#define CP_WAIT1()  asm volatile("cp.async.wait_group 1;" ::: "memory")
#define CP_WAIT2()  asm volatile("cp.async.wait_group 2;" ::: "memory")
#define CP_WAIT0()  asm volatile("cp.async.wait_group 0;" ::: "memory")
__device__ __forceinline__ void split_pair(float a, float b, uint32_t& hi, uint32_t& lo) {
    bf16 ha = __float2bfloat16(a), hb = __float2bfloat16(b);
    bf16 la = __float2bfloat16(a - __bfloat162float(ha));
    bf16 lb = __float2bfloat16(b - __bfloat162float(hb));
    __nv_bfloat162 h2 = __halves2bfloat162(ha, hb);
    __nv_bfloat162 l2 = __halves2bfloat162(la, lb);
    hi = *(uint32_t*)&h2;
    lo = *(uint32_t*)&l2;
}

// ================= split fp32 -> bf16 hi/lo planes (one launch) =================
__device__ __forceinline__ void split_one(const float* in, bf16* H, bf16* L, int i) {
    const float4 v = ((const float4*)in)[i];
    uint32_t h0, l0, h1, l1;
    split_pair(v.x, v.y, h0, l0);
    split_pair(v.z, v.w, h1, l1);
    *(uint2*)(H + (size_t)i * 4) = make_uint2(h0, h1);
    *(uint2*)(L + (size_t)i * 4) = make_uint2(l0, l1);
}
__global__ __launch_bounds__(256)
void split_all(const float* x, const float* wq, const float* wkv, const float* hq,
               const float* hkv, const float* wo, const float* ho,
               bf16* xh, bf16* xl,
               bf16* wqh, bf16* wql, bf16* wkvh, bf16* wkvl,
               bf16* hqh, bf16* hql, bf16* hkvh, bf16* hkvl,
               bf16* woh, bf16* wol, bf16* hoh, bf16* hol)
{
    const int b = blockIdx.x;
    if (b < 8192) {
        split_one(x, xh, xl, b * 256 + threadIdx.x);
        return;
    }
    const int i = (b - 8192) * 256 + threadIdx.x;
    if (i < 32768)        split_one(wq,  wqh,  wql,  i);
    else if (i < 98304)   split_one(wkv, wkvh, wkvl, i - 32768);
    else if (i < 131072)  split_one(hq,  hqh,  hql,  i - 98304);
    else if (i < 196608)  split_one(hkv, hkvh, hkvl, i - 131072);
    else if (i < 229376)  split_one(wo,  woh,  wol,  i - 196608);
    else                  split_one(ho,  hoh,  hol,  i - 229376);
}

// ======== big-tile GEMM core: 128x128 block, 4 warps, warp tile 64x64, CH=32, 3-stage ========
// BT=1 only (B is [k][n], n contiguous). OSPLIT / DUAL as before.
template<int OSPLIT, int DUAL>
__device__ __forceinline__ void gemm_core6(
    const bf16* __restrict__ Ah_, const bf16* __restrict__ Al_, size_t sAr,
    const bf16* __restrict__ Bh_, const bf16* __restrict__ Bl_, size_t sBr,
    const bf16* __restrict__ Ah2_, const bf16* __restrict__ Al2_,
    const bf16* __restrict__ Bh2_, const bf16* __restrict__ Bl2_, int K1,
    float* __restrict__ Cf, bf16* __restrict__ Chp, bf16* __restrict__ Clp,
    int ldc, int K, const float* __restrict__ bias, const float* __restrict__ bias2)
{
    constexpr int CH = 32, NSTG = 3;
    constexpr int AP = 40;           // 32 + 8 pad (halves)
    constexpr int BP = 136;          // 128 + 8 pad
    constexpr int AH = 128 * AP;
    constexpr int BH = CH * BP;
    constexpr int STAGE = 2 * AH + 2 * BH;

    extern __shared__ bf16 smn[];
    const int tid = threadIdx.x, warp = tid >> 5, lane = tid & 31;
    const int wm = warp >> 1, wn = warp & 1;

    float c[4][8][4];
#pragma unroll
    for (int mt = 0; mt < 4; mt++)
#pragma unroll
        for (int nt = 0; nt < 8; nt++)
#pragma unroll
            for (int e = 0; e < 4; e++) c[mt][nt][e] = 0.f;

    auto issue = [&](int cc) {
        const int s = cc % NSTG;
        bf16* Ah = smn + (size_t)s * STAGE;
        bf16* Al = Ah + AH;
        bf16* Bh = Ah + 2 * AH;
        bf16* Bl = Bh + BH;
        int k0 = cc * CH;
        const bf16 *Ap = Ah_, *Alp = Al_, *Bp = Bh_, *Blp = Bl_;
        if (DUAL && k0 >= K1) { Ap = Ah2_; Alp = Al2_; Bp = Bh2_; Blp = Bl2_; k0 -= K1; }
        // A: 128 rows x 32 cols, 4 x 16B per row -> 512 cpa / 128 thr = 4 per plane
#pragma unroll
        for (int i = 0; i < 4; i++) {
            const int idx = i * 128 + tid;
            const int row = idx >> 2, g = (idx & 3) * 8;
            const size_t go = (size_t)row * sAr + k0 + g;
            const int off = row * AP + g;
            cpa16(smem_u32(Ah + off), Ap + go);
            cpa16(smem_u32(Al + off), Alp + go);
        }
        // B: 32 k-rows x 128 n, 16 x 16B per row -> 512 / 128 = 4 per plane
#pragma unroll
        for (int i = 0; i < 4; i++) {
            const int idx = i * 128 + tid;
            const int kr = idx >> 4, q = (idx & 15) * 8;
            const size_t go = (size_t)(k0 + kr) * sBr + q;
            const int off = kr * BP + q;
            cpa16(smem_u32(Bh + off), Bp + go);
            cpa16(smem_u32(Bl + off), Blp + go);
        }
    };

    auto compute = [&](int s) {
        bf16* Ah = smn + (size_t)s * STAGE;
        bf16* Al = Ah + AH;
        bf16* Bh = Ah + 2 * AH;
        bf16* Bl = Bh + BH;
#pragma unroll
        for (int h = 0; h < 2; h++) {
            uint32_t ah[4][4], al[4][4];
#pragma unroll
            for (int mt = 0; mt < 4; mt++) {
                const int row = wm * 64 + mt * 16 + (lane & 15);
                const int ko = h * 16 + ((lane >> 4) & 1) * 8;
                ldsm4(ah[mt][0], ah[mt][1], ah[mt][2], ah[mt][3], smem_u32(Ah + row * AP + ko));
                ldsm4(al[mt][0], al[mt][1], al[mt][2], al[mt][3], smem_u32(Al + row * AP + ko));
            }
            // B in two groups of 4 n-tiles to cap registers
#pragma unroll
            for (int bg = 0; bg < 2; bg++) {
                uint32_t bh[4][2], bl[4][2];
#pragma unroll
                for (int np = 0; np < 2; np++) {
                    const int k = h * 16 + (lane & 7) + ((lane >> 3) & 1) * 8;
                    const int col = wn * 64 + bg * 32 + np * 16 + ((lane >> 4) & 1) * 8;
                    ldsm4t(bh[2*np][0], bh[2*np][1], bh[2*np+1][0], bh[2*np+1][1],
                           smem_u32(Bh + k * BP + col));
                    ldsm4t(bl[2*np][0], bl[2*np][1], bl[2*np+1][0], bl[2*np+1][1],
                           smem_u32(Bl + k * BP + col));
                }
                // product-major within group (per-accumulator order: hh, hl, lh — unchanged)
#pragma unroll
                for (int mt = 0; mt < 4; mt++)
#pragma unroll
                    for (int t = 0; t < 4; t++)
                        mma16816(c[mt][bg * 4 + t], ah[mt], bh[t]);
#pragma unroll
                for (int mt = 0; mt < 4; mt++)
#pragma unroll
                    for (int t = 0; t < 4; t++)
                        mma16816(c[mt][bg * 4 + t], ah[mt], bl[t]);
#pragma unroll
                for (int mt = 0; mt < 4; mt++)
#pragma unroll
                    for (int t = 0; t < 4; t++)
                        mma16816(c[mt][bg * 4 + t], al[mt], bh[t]);
            }
        }
    };

    const int NC = K / CH;
    issue(0); CP_COMMIT();
    issue(1); CP_COMMIT();
    for (int cc = 0; cc < NC; cc++) {
        CP_WAIT1();
        __syncthreads();
        if (cc + 2 < NC) issue(cc + 2);
        CP_COMMIT();
        compute(cc % NSTG);
    }

    const int g = lane >> 2, tg = lane & 3;
#pragma unroll
    for (int mt = 0; mt < 4; mt++) {
#pragma unroll
        for (int nt = 0; nt < 8; nt++) {
            const int row0 = wm * 64 + mt * 16 + g;
            const int col = wn * 64 + nt * 8 + tg * 2;
            float2 v0 = make_float2(c[mt][nt][0], c[mt][nt][1]);
            float2 v1 = make_float2(c[mt][nt][2], c[mt][nt][3]);
            if (OSPLIT) {
                uint32_t h0, l0, h1, l1;
                split_pair(v0.x, v0.y, h0, l0);
                split_pair(v1.x, v1.y, h1, l1);
                *(uint32_t*)(Chp + (size_t)row0 * ldc + col) = h0;
                *(uint32_t*)(Clp + (size_t)row0 * ldc + col) = l0;
                *(uint32_t*)(Chp + (size_t)(row0 + 8) * ldc + col) = h1;
                *(uint32_t*)(Clp + (size_t)(row0 + 8) * ldc + col) = l1;
            } else {
                float b0 = 0.f, b1 = 0.f;
                if (bias)  { b0 += bias[col];  b1 += bias[col + 1]; }
                if (bias2) { b0 += bias2[col]; b1 += bias2[col + 1]; }
                v0.x += b0; v0.y += b1; v1.x += b0; v1.y += b1;
                *(float2*)(Cf + (size_t)row0 * ldc + col) = v0;
                *(float2*)(Cf + (size_t)(row0 + 8) * ldc + col) = v1;
            }
        }
    }
}

// ================= pre-split bf16x3 mma GEMM (64x32 warp tile) for av/dots =================
template<int WM, int WN, int BT, int OSPLIT, int CH, int NSTG>
__device__ __forceinline__ void gemm_core5(
    const bf16* __restrict__ Ah_, const bf16* __restrict__ Al_, size_t sAr, size_t sAk,
    const bf16* __restrict__ Bh_, const bf16* __restrict__ Bl_, size_t sBr, size_t sBk,
    float* __restrict__ Cf, bf16* __restrict__ Chp, bf16* __restrict__ Clp,
    int ldc, int K)
{
    constexpr int TM = WM * 64, TN = WN * 32;
    constexpr int THREADS = WM * WN * 32;
    constexpr int AP = CH + 8;
    constexpr int BP = BT ? (TN + 8) : (CH + 8);
    constexpr int AH = TM * AP;
    constexpr int BH = BT ? CH * BP : TN * AP;
    constexpr int STAGE = 2 * AH + 2 * BH;
    constexpr int C8 = CH / 8;
    constexpr int NA = TM * C8 / THREADS;
    constexpr int NB = BT ? (CH * TN / 8) / THREADS : (TN * C8) / THREADS;

    extern __shared__ bf16 smn[];
    const int tid = threadIdx.x, warp = tid >> 5, lane = tid & 31;
    const int wm = warp / WN, wn = warp % WN;

    float c[4][4][4];
#pragma unroll
    for (int mt = 0; mt < 4; mt++)
#pragma unroll
        for (int nt = 0; nt < 4; nt++)
#pragma unroll
            for (int e = 0; e < 4; e++) c[mt][nt][e] = 0.f;

    auto issue = [&](int cc) {
        const int s = cc % NSTG;
        bf16* Ah = smn + (size_t)s * STAGE;
        bf16* Al = Ah + AH;
        bf16* Bh = Ah + 2 * AH;
        bf16* Bl = Bh + BH;
        int k0 = cc * CH;
        const size_t cb = (size_t)(k0 >> 6) * sAk + (k0 & 63);
#pragma unroll
        for (int i = 0; i < NA; i++) {
            const int idx = i * THREADS + tid;
            const int row = idx / C8, g = (idx % C8) * 8;
            const size_t go = (size_t)row * sAr + cb + g;
            const int off = row * AP + g;
            cpa16(smem_u32(Ah + off), Ah_ + go);
            cpa16(smem_u32(Al + off), Al_ + go);
        }
#pragma unroll
        for (int i = 0; i < NB; i++) {
            const int idx = i * THREADS + tid;
            size_t go; int off;
            if (BT) {
                const int kr = idx / (TN / 8), q = idx % (TN / 8);
                go = (size_t)(k0 + kr) * sBr + q * 8;
                off = kr * BP + q * 8;
            } else {
                const int nr = idx / C8, g = (idx % C8) * 8;
                go = (size_t)nr * sBr + (size_t)(k0 >> 6) * sBk + (k0 & 63) + g;
                off = nr * AP + g;
            }
            cpa16(smem_u32(Bh + off), Bh_ + go);
            cpa16(smem_u32(Bl + off), Bl_ + go);
        }
    };

    auto compute = [&](int s) {
        bf16* Ah = smn + (size_t)s * STAGE;
        bf16* Al = Ah + AH;
        bf16* Bh = Ah + 2 * AH;
        bf16* Bl = Bh + BH;
#pragma unroll
        for (int h = 0; h < CH / 16; h++) {
            uint32_t ah[4][4], al[4][4], bh[4][2], bl[4][2];
#pragma unroll
            for (int mt = 0; mt < 4; mt++) {
                const int row = wm * 64 + mt * 16 + (lane & 15);
                const int ko = h * 16 + ((lane >> 4) & 1) * 8;
                ldsm4(ah[mt][0], ah[mt][1], ah[mt][2], ah[mt][3], smem_u32(Ah + row * AP + ko));
                ldsm4(al[mt][0], al[mt][1], al[mt][2], al[mt][3], smem_u32(Al + row * AP + ko));
            }
#pragma unroll
            for (int np = 0; np < 2; np++) {
                if (BT) {
                    const int k = h * 16 + (lane & 7) + ((lane >> 3) & 1) * 8;
                    const int col = wn * 32 + np * 16 + ((lane >> 4) & 1) * 8;
                    ldsm4t(bh[2*np][0], bh[2*np][1], bh[2*np+1][0], bh[2*np+1][1],
                           smem_u32(Bh + k * BP + col));
                    ldsm4t(bl[2*np][0], bl[2*np][1], bl[2*np+1][0], bl[2*np+1][1],
                           smem_u32(Bl + k * BP + col));
                } else {
                    const int nrow = wn * 32 + np * 16 + (lane & 7) + ((lane >> 4) & 1) * 8;
                    const int ko = h * 16 + ((lane >> 3) & 1) * 8;
                    ldsm4(bh[2*np][0], bh[2*np][1], bh[2*np+1][0], bh[2*np+1][1],
                          smem_u32(Bh + nrow * AP + ko));
                    ldsm4(bl[2*np][0], bl[2*np][1], bl[2*np+1][0], bl[2*np+1][1],
                          smem_u32(Bl + nrow * AP + ko));
                }
            }
#pragma unroll
            for (int mt = 0; mt < 4; mt++)
#pragma unroll
                for (int nt = 0; nt < 4; nt++)
                    mma16816(c[mt][nt], ah[mt], bh[nt]);
#pragma unroll
            for (int mt = 0; mt < 4; mt++)
#pragma unroll
                for (int nt = 0; nt < 4; nt++)
                    mma16816(c[mt][nt], ah[mt], bl[nt]);
#pragma unroll
            for (int mt = 0; mt < 4; mt++)
#pragma unroll
                for (int nt = 0; nt < 4; nt++)
                    mma16816(c[mt][nt], al[mt], bh[nt]);
        }
    };

    const int NC = K / CH;
#pragma unroll
    for (int p = 0; p < NSTG - 1; p++) { issue(p); CP_COMMIT(); }
    for (int cc = 0; cc < NC; cc++) {
        if constexpr (NSTG == 3) CP_WAIT1(); else CP_WAIT2();
        __syncthreads();
        if (cc + NSTG - 1 < NC) issue(cc + NSTG - 1);
        CP_COMMIT();
        compute(cc % NSTG);
    }

    const int g = lane >> 2, tg = lane & 3;
#pragma unroll
    for (int mt = 0; mt < 4; mt++) {
#pragma unroll
        for (int nt = 0; nt < 4; nt++) {
            const int row0 = wm * 64 + mt * 16 + g;
            const int col = wn * 32 + nt * 8 + tg * 2;
            float2 v0 = make_float2(c[mt][nt][0], c[mt][nt][1]);
            float2 v1 = make_float2(c[mt][nt][2], c[mt][nt][3]);
            if (OSPLIT) {
                uint32_t h0, l0, h1, l1;
                split_pair(v0.x, v0.y, h0, l0);
                split_pair(v1.x, v1.y, h1, l1);
                *(uint32_t*)(Chp + (size_t)row0 * ldc + col) = h0;
                *(uint32_t*)(Clp + (size_t)row0 * ldc + col) = l0;
                *(uint32_t*)(Chp + (size_t)(row0 + 8) * ldc + col) = h1;
                *(uint32_t*)(Clp + (size_t)(row0 + 8) * ldc + col) = l1;
            } else {
                *(float2*)(Cf + (size_t)row0 * ldc + col) = v0;
                *(float2*)(Cf + (size_t)(row0 + 8) * ldc + col) = v1;
            }
        }
    }
}

// ---- wrappers ----
__global__ __launch_bounds__(128, 2)
void gemm_proj_all(const bf16* __restrict__ xh, const bf16* __restrict__ xl,
                   const bf16* __restrict__ wqh, const bf16* __restrict__ wql,
                   const bf16* __restrict__ wkvh, const bf16* __restrict__ wkvl,
                   const bf16* __restrict__ hqh, const bf16* __restrict__ hql,
                   const bf16* __restrict__ hkvh, const bf16* __restrict__ hkvl,
                   bf16* __restrict__ q1h, bf16* __restrict__ q1l,
                   bf16* __restrict__ kv1h, bf16* __restrict__ kv1l,
                   bf16* __restrict__ q2h, bf16* __restrict__ q2l,
                   bf16* __restrict__ kv2h, bf16* __restrict__ kv2l)
{
    const int m0 = blockIdx.y * 128;
    const int n0 = blockIdx.x * 128;
    const int fam = blockIdx.z;
    const bf16 *Bh, *Bl;
    bf16 *Ch, *Cl;
    int ldc;
    if (n0 < INNER) {
        Bh = (fam ? hqh : wqh) + n0;
        Bl = (fam ? hql : wql) + n0;
        Ch = (fam ? q2h : q1h) + (size_t)m0 * INNER + n0;
        Cl = (fam ? q2l : q1l) + (size_t)m0 * INNER + n0;
        ldc = INNER;
    } else {
        const int nn = n0 - INNER;
        Bh = (fam ? hkvh : wkvh) + nn;
        Bl = (fam ? hkvl : wkvl) + nn;
        Ch = (fam ? kv2h : kv1h) + (size_t)m0 * 2 * INNER + nn;
        Cl = (fam ? kv2l : kv1l) + (size_t)m0 * 2 * INNER + nn;
        ldc = 2 * INNER;
    }
    const int Nw = (n0 < INNER) ? INNER : 2 * INNER;
    gemm_core6<1, 0>(xh + (size_t)m0 * DIM, xl + (size_t)m0 * DIM, DIM,
                     Bh, Bl, Nw,
                     nullptr, nullptr, nullptr, nullptr, 0,
                     nullptr, Ch, Cl, ldc, DIM, nullptr, nullptr);
}

__global__ __launch_bounds__(128, 2)
void gemm_out_fused(const bf16* __restrict__ o1h, const bf16* __restrict__ o1l,
                    const bf16* __restrict__ o2h, const bf16* __restrict__ o2l,
                    const bf16* __restrict__ wouth, const bf16* __restrict__ woutl,
                    const bf16* __restrict__ houth, const bf16* __restrict__ houtl,
                    float* __restrict__ C, const float* __restrict__ wout_b,
                    const float* __restrict__ hout_b)
{
    const int m0 = blockIdx.y * 128, n0 = blockIdx.x * 128;
    gemm_core6<0, 1>(o1h + (size_t)m0 * INNER, o1l + (size_t)m0 * INNER, INNER,
                     wouth + n0, woutl + n0, DIM,
                     o2h + (size_t)m0 * INNER, o2l + (size_t)m0 * INNER,
                     houth + n0, houtl + n0, INNER,
                     C + (size_t)m0 * DIM + n0, nullptr, nullptr,
                     DIM, 2 * INNER, wout_b + n0, hout_b + n0);
}

__global__ __launch_bounds__(128, 3)
void gemm_av2(const bf16* __restrict__ Ph, const bf16* __restrict__ Pl,
              const bf16* __restrict__ Vh, const bf16* __restrict__ Vl,
              bf16* __restrict__ Oh, bf16* __restrict__ Ol)
{
    const int i0 = blockIdx.x * 128;
    const int h = blockIdx.y, r = blockIdx.z;
    const size_t aoff = (size_t)h * (MSAW * MSAW) + (size_t)i0 * MSAW;
    const size_t boff = (size_t)INNER + (size_t)h * 64 + (size_t)r * MSAW * 2 * INNER;
    const size_t coff = ((size_t)r * MSAW + i0) * INNER + h * 64;
    gemm_core5<2, 2, 1, 1, 16, 4>(Ph + aoff, Pl + aoff, MSAW, 64,
                                  Vh + boff, Vl + boff, 2 * INNER, 0,
                                  nullptr, Oh + coff, Ol + coff, INNER, MSAW);
}

// smem bytes
#define SM_PROJ (3 * (2 * 128 * 40 + 2 * 32 * 136) * 2)
#define SM_AV   (4 * (2 * 128 * 24 + 2 * 16 * 72) * 2)
#define COL_SMEM2 (6 * 128 * 72 * 2)

// ================= column attention body =================
__device__ __forceinline__
void col_attn_body(int wi, int head,
                   const bf16* __restrict__ qh, const bf16* __restrict__ ql,
                   const bf16* __restrict__ kvh, const bf16* __restrict__ kvl,
                   bf16* __restrict__ oh, bf16* __restrict__ ol)
{
    extern __shared__ bf16 smc[];
    const int PL = 128 * 72;
    bf16 *sqh = smc,          *sql = smc + PL;
    bf16 *skh = smc + 2 * PL, *skl = smc + 3 * PL;
    bf16 *svh = smc + 4 * PL, *svl = smc + 5 * PL;

    const int tid = threadIdx.x, warp = tid >> 5, lane = tid & 31;

#pragma unroll
    for (int i = 0; i < 4; i++) {
        const int idx = i * 256 + tid;
        const int row = idx >> 3, g = (idx & 7) * 8;
        const size_t gq = ((size_t)(row * MSAW + wi)) * INNER + head * 64 + g;
        const size_t gk = ((size_t)(row * MSAW + wi)) * 2 * INNER + head * 64 + g;
        cpa16(smem_u32(sqh + row * 72 + g), qh + gq);
        cpa16(smem_u32(sql + row * 72 + g), ql + gq);
        cpa16(smem_u32(skh + row * 72 + g), kvh + gk);
        cpa16(smem_u32(skl + row * 72 + g), kvl + gk);
        cpa16(smem_u32(svh + row * 72 + g), kvh + gk + INNER);
        cpa16(smem_u32(svl + row * 72 + g), kvl + gk + INNER);
    }
    CP_COMMIT();
    CP_WAIT0();
    __syncthreads();

    const int m0 = warp * 16;
    float s[16][4];
#pragma unroll
    for (int nt = 0; nt < 16; nt++)
#pragma unroll
        for (int e = 0; e < 4; e++) s[nt][e] = 0.f;

#pragma unroll
    for (int kc = 0; kc < 4; kc++) {
        uint32_t ah[4], al[4];
        const int arow = m0 + (lane & 15);
        const int acol = kc * 16 + ((lane >> 4) & 1) * 8;
        ldsm4(ah[0], ah[1], ah[2], ah[3], smem_u32(sqh + arow * 72 + acol));
        ldsm4(al[0], al[1], al[2], al[3], smem_u32(sql + arow * 72 + acol));
#pragma unroll
        for (int ng = 0; ng < 4; ng++) {
            uint32_t bh[4][2], bl[4][2];
#pragma unroll
            for (int npp = 0; npp < 2; npp++) {
                const int nt0 = ng * 4 + npp * 2;
                const int brow = nt0 * 8 + (lane & 7) + ((lane >> 4) & 1) * 8;
                const int bcol = kc * 16 + ((lane >> 3) & 1) * 8;
                ldsm4(bh[npp*2][0], bh[npp*2][1], bh[npp*2+1][0], bh[npp*2+1][1],
                      smem_u32(skh + brow * 72 + bcol));
                ldsm4(bl[npp*2][0], bl[npp*2][1], bl[npp*2+1][0], bl[npp*2+1][1],
                      smem_u32(skl + brow * 72 + bcol));
            }
#pragma unroll
            for (int t = 0; t < 4; t++) mma16816(s[ng * 4 + t], ah, bh[t]);
#pragma unroll
            for (int t = 0; t < 4; t++) mma16816(s[ng * 4 + t], ah, bl[t]);
#pragma unroll
            for (int t = 0; t < 4; t++) mma16816(s[ng * 4 + t], al, bh[t]);
        }
    }

    const float sc = 0.125f;
    float mx0 = -1e30f, mx1 = -1e30f;
#pragma unroll
    for (int nt = 0; nt < 16; nt++) {
        mx0 = fmaxf(mx0, fmaxf(s[nt][0], s[nt][1]));
        mx1 = fmaxf(mx1, fmaxf(s[nt][2], s[nt][3]));
    }
    mx0 = fmaxf(mx0, __shfl_xor_sync(0xffffffffu, mx0, 1));
    mx0 = fmaxf(mx0, __shfl_xor_sync(0xffffffffu, mx0, 2));
    mx1 = fmaxf(mx1, __shfl_xor_sync(0xffffffffu, mx1, 1));
    mx1 = fmaxf(mx1, __shfl_xor_sync(0xffffffffu, mx1, 2));
    float sum0 = 0.f, sum1 = 0.f;
#pragma unroll
    for (int nt = 0; nt < 16; nt++) {
        s[nt][0] = __expf(sc * (s[nt][0] - mx0)); sum0 += s[nt][0];
        s[nt][1] = __expf(sc * (s[nt][1] - mx0)); sum0 += s[nt][1];
        s[nt][2] = __expf(sc * (s[nt][2] - mx1)); sum1 += s[nt][2];
        s[nt][3] = __expf(sc * (s[nt][3] - mx1)); sum1 += s[nt][3];
    }
    sum0 += __shfl_xor_sync(0xffffffffu, sum0, 1);
    sum0 += __shfl_xor_sync(0xffffffffu, sum0, 2);
    sum1 += __shfl_xor_sync(0xffffffffu, sum1, 1);
    sum1 += __shfl_xor_sync(0xffffffffu, sum1, 2);
    const float inv0 = 1.f / sum0, inv1 = 1.f / sum1;
#pragma unroll
    for (int nt = 0; nt < 16; nt++) {
        s[nt][0] *= inv0; s[nt][1] *= inv0;
        s[nt][2] *= inv1; s[nt][3] *= inv1;
    }

    float o[8][4];
#pragma unroll
    for (int dt = 0; dt < 8; dt++)
#pragma unroll
        for (int e = 0; e < 4; e++) o[dt][e] = 0.f;

#pragma unroll
    for (int jc = 0; jc < 8; jc++) {
        uint32_t pah[4], pal[4];
        split_pair(s[2 * jc][0],     s[2 * jc][1],     pah[0], pal[0]);
        split_pair(s[2 * jc][2],     s[2 * jc][3],     pah[1], pal[1]);
        split_pair(s[2 * jc + 1][0], s[2 * jc + 1][1], pah[2], pal[2]);
        split_pair(s[2 * jc + 1][2], s[2 * jc + 1][3], pah[3], pal[3]);
        const int jrow = jc * 16 + (lane & 7) + ((lane >> 3) & 1) * 8;
#pragma unroll
        for (int dg = 0; dg < 2; dg++) {
            uint32_t bh[4][2], bl[4][2];
#pragma unroll
            for (int dpp = 0; dpp < 2; dpp++) {
                const int dt0 = dg * 4 + dpp * 2;
                const int dcol = dt0 * 8 + ((lane >> 4) & 1) * 8;
                ldsm4t(bh[dpp*2][0], bh[dpp*2][1], bh[dpp*2+1][0], bh[dpp*2+1][1],
                       smem_u32(svh + jrow * 72 + dcol));
                ldsm4t(bl[dpp*2][0], bl[dpp*2][1], bl[dpp*2+1][0], bl[dpp*2+1][1],
                       smem_u32(svl + jrow * 72 + dcol));
            }
#pragma unroll
            for (int t = 0; t < 4; t++) mma16816(o[dg * 4 + t], pah, bh[t]);
#pragma unroll
            for (int t = 0; t < 4; t++) mma16816(o[dg * 4 + t], pah, bl[t]);
#pragma unroll
            for (int t = 0; t < 4; t++) mma16816(o[dg * 4 + t], pal, bh[t]);
        }
    }

    const int g = lane >> 2, tg = lane & 3;
    const int r0 = m0 + g, r1 = r0 + 8;
#pragma unroll
    for (int dt = 0; dt < 8; dt++) {
        const int d = head * 64 + dt * 8 + tg * 2;
        const size_t b0 = ((size_t)(r0 * MSAW + wi)) * INNER + d;
        const size_t b1 = ((size_t)(r1 * MSAW + wi)) * INNER + d;
        uint32_t h0, l0, h1, l1;
        split_pair(o[dt][0], o[dt][1], h0, l0);
        split_pair(o[dt][2], o[dt][3], h1, l1);
        *(uint32_t*)(oh + b0) = h0;
        *(uint32_t*)(ol + b0) = l0;
        *(uint32_t*)(oh + b1) = h1;
        *(uint32_t*)(ol + b1) = l1;
    }
}

// ============= fused attention: dots tiles (blocks 0..127) + col attn (128..2175) =============
__global__ __launch_bounds__(256, 2)
void attn_fused(const bf16* __restrict__ q1h, const bf16* __restrict__ q1l,
                const bf16* __restrict__ kv1h, const bf16* __restrict__ kv1l,
                const bf16* __restrict__ q2h, const bf16* __restrict__ q2l,
                const bf16* __restrict__ kv2h, const bf16* __restrict__ kv2l,
                bf16* __restrict__ o1h, bf16* __restrict__ o1l,
                float* __restrict__ Pp)
{
    const int b = blockIdx.x;
    if (b < 128) {
        const int j0 = (b & 1) * 128, i0 = ((b >> 1) & 1) * 128;
        const int z = b >> 2;
        const int h = z >> 2, s = z & 3;
        const size_t r0 = (size_t)s * 32;
        const size_t aoff = (size_t)h * 64 + (size_t)i0 * INNER + r0 * MSAW * INNER;
        const size_t boff = (size_t)h * 64 + (size_t)j0 * 2 * INNER + r0 * MSAW * 2 * INNER;
        gemm_core5<2, 4, 0, 0, 16, 4>(q2h + aoff, q2l + aoff, INNER, (size_t)MSAW * INNER,
                                      kv2h + boff, kv2l + boff, 2 * INNER, (size_t)MSAW * 2 * INNER,
                                      Pp + (size_t)z * (MSAW * MSAW) + (size_t)i0 * MSAW + j0,
                                      nullptr, nullptr, MSAW, 32 * 64);
    } else {
        const int cb = b - 128;
        col_attn_body(cb & 255, cb >> 8, q1h, q1l, kv1h, kv1l, o1h, o1l);
    }
}

// ============= reduce 4 dots partials + scale + softmax -> hi/lo planes =============
__global__ __launch_bounds__(256)
void softmax_reduce2(const float* __restrict__ Pp, bf16* __restrict__ Ph, bf16* __restrict__ Pl)
{
    const int h = blockIdx.x >> 8, i = blockIdx.x & 255;
    const int tid = threadIdx.x;
    __shared__ float red[34];
    float v = 0.f;
#pragma unroll
    for (int s = 0; s < 4; s++)
        v += Pp[((size_t)(h * 4 + s) * MSAW + i) * MSAW + tid];
    v *= 0.011048543456039806f;  // (1/8) * 128^-0.5

    float m = v;
#pragma unroll
    for (int o = 16; o; o >>= 1) m = fmaxf(m, __shfl_xor_sync(0xffffffffu, m, o));
    if ((tid & 31) == 0) red[tid >> 5] = m;
    __syncthreads();
    if (tid == 0) {
        float mm = red[0];
#pragma unroll
        for (int w = 1; w < 8; w++) mm = fmaxf(mm, red[w]);
        red[32] = mm;
    }
    __syncthreads();
    const float e = __expf(v - red[32]);
    float s = e;
#pragma unroll
    for (int o = 16; o; o >>= 1) s += __shfl_xor_sync(0xffffffffu, s, o);
    if ((tid & 31) == 0) red[8 + (tid >> 5)] = s;
    __syncthreads();
    if (tid == 0) {
        float ss = 0.f;
#pragma unroll
        for (int w = 0; w < 8; w++) ss += red[8 + w];
        red[33] = 1.f / ss;
    }
    __syncthreads();
    const float p = e * red[33];
    const bf16 hp = __float2bfloat16(p);
    const bf16 lp = __float2bfloat16(p - __bfloat162float(hp));
    const size_t off = ((size_t)h * MSAW + i) * MSAW + tid;
    Ph[off] = hp;
    Pl[off] = lp;
}

// =============================== launch ===============================
extern "C" void kernel_launch(void* const* d_in, const int* in_sizes, int n_in,
                              void* d_out, int out_size)
{
    const float* x      = (const float*)d_in[0];
    const float* wq_w   = (const float*)d_in[1];
    const float* wkv_w  = (const float*)d_in[2];
    const float* wout_w = (const float*)d_in[3];
    const float* wout_b = (const float*)d_in[4];
    const float* hq_w   = (const float*)d_in[5];
    const float* hkv_w  = (const float*)d_in[6];
    const float* hout_w = (const float*)d_in[7];
    const float* hout_b = (const float*)d_in[8];
    float* out = (float*)d_out;

    void* p;
    bf16 *xh, *xl, *wqh, *wql, *wkvh, *wkvl, *hqh, *hql, *hkvh, *hkvl;
    bf16 *wouth, *woutl, *houth, *houtl;
    bf16 *q1h, *q1l, *kv1h, *kv1l, *q2h, *q2l, *kv2h, *kv2l;
    bf16 *o1h, *o1l, *o2h, *o2l, *p2h, *p2l;
    float* Pp;
    cudaGetSymbolAddress(&p, g_xh);    xh = (bf16*)p;
    cudaGetSymbolAddress(&p, g_xl);    xl = (bf16*)p;
    cudaGetSymbolAddress(&p, g_wqh);   wqh = (bf16*)p;
    cudaGetSymbolAddress(&p, g_wql);   wql = (bf16*)p;
    cudaGetSymbolAddress(&p, g_wkvh);  wkvh = (bf16*)p;
    cudaGetSymbolAddress(&p, g_wkvl);  wkvl = (bf16*)p;
    cudaGetSymbolAddress(&p, g_hqh);   hqh = (bf16*)p;
    cudaGetSymbolAddress(&p, g_hql);   hql = (bf16*)p;
    cudaGetSymbolAddress(&p, g_hkvh);  hkvh = (bf16*)p;
    cudaGetSymbolAddress(&p, g_hkvl);  hkvl = (bf16*)p;
    cudaGetSymbolAddress(&p, g_wouth); wouth = (bf16*)p;
    cudaGetSymbolAddress(&p, g_woutl); woutl = (bf16*)p;
    cudaGetSymbolAddress(&p, g_houth); houth = (bf16*)p;
    cudaGetSymbolAddress(&p, g_houtl); houtl = (bf16*)p;
    cudaGetSymbolAddress(&p, g_q1h);   q1h = (bf16*)p;
    cudaGetSymbolAddress(&p, g_q1l);   q1l = (bf16*)p;
    cudaGetSymbolAddress(&p, g_kv1h);  kv1h = (bf16*)p;
    cudaGetSymbolAddress(&p, g_kv1l);  kv1l = (bf16*)p;
    cudaGetSymbolAddress(&p, g_q2h);   q2h = (bf16*)p;
    cudaGetSymbolAddress(&p, g_q2l);   q2l = (bf16*)p;
    cudaGetSymbolAddress(&p, g_kv2h);  kv2h = (bf16*)p;
    cudaGetSymbolAddress(&p, g_kv2l);  kv2l = (bf16*)p;
    cudaGetSymbolAddress(&p, g_o1h);   o1h = (bf16*)p;
    cudaGetSymbolAddress(&p, g_o1l);   o1l = (bf16*)p;
    cudaGetSymbolAddress(&p, g_o2h);   o2h = (bf16*)p;
    cudaGetSymbolAddress(&p, g_o2l);   o2l = (bf16*)p;
    cudaGetSymbolAddress(&p, g_p2h);   p2h = (bf16*)p;
    cudaGetSymbolAddress(&p, g_p2l);   p2l = (bf16*)p;
    cudaGetSymbolAddress(&p, g_Pp);    Pp = (float*)p;

    cudaFuncSetAttribute(gemm_proj_all,  cudaFuncAttributeMaxDynamicSharedMemorySize, SM_PROJ);
    cudaFuncSetAttribute(gemm_out_fused, cudaFuncAttributeMaxDynamicSharedMemorySize, SM_PROJ);
    cudaFuncSetAttribute(gemm_av2,       cudaFuncAttributeMaxDynamicSharedMemorySize, SM_AV);
    cudaFuncSetAttribute(attn_fused,     cudaFuncAttributeMaxDynamicSharedMemorySize, COL_SMEM2);

    split_all<<<8192 + 1024, 256>>>(x, wq_w, wkv_w, hq_w, hkv_w, wout_w, hout_w,
                                    xh, xl, wqh, wql, wkvh, wkvl, hqh, hql, hkvh, hkvl,
                                    wouth, woutl, houth, houtl);

    gemm_proj_all<<<dim3(12, NTOK / 128, 2), 128, SM_PROJ>>>(
        xh, xl, wqh, wql, wkvh, wkvl, hqh, hql, hkvh, hkvl,
        q1h, q1l, kv1h, kv1l, q2h, q2l, kv2h, kv2l);

    attn_fused<<<128 + MSAW * HEADS, 256, COL_SMEM2>>>(
        q1h, q1l, kv1h, kv1l, q2h, q2l, kv2h, kv2l, o1h, o1l, Pp);

    softmax_reduce2<<<HEADS * MSAW, 256>>>(Pp, p2h, p2l);
    gemm_av2<<<dim3(2, HEADS, MSAH), 128, SM_AV>>>(p2h, p2l, kv2h, kv2l, o2h, o2l);

    gemm_out_fused<<<dim3(2, NTOK / 128), 128, SM_PROJ>>>(
        o1h, o1l, o2h, o2l, wouth, woutl, houth, houtl, out, wout_b, hout_b);
}

// round 11
// speedup vs baseline: 4.4791x; 1.1839x over previous
#include <cuda_runtime.h>
#include <cuda_fp16.h>
#include <math.h>
#include <cstdint>

#define HEADS 8
#define DH    64
#define INNER 512
#define DIM   256
#define MSAH  128
#define MSAW  256
#define NTOK  (MSAH*MSAW)

typedef __half hf;

// -------- scratch (static device globals; no runtime allocation) --------
__device__ hf g_xh [(size_t)NTOK*DIM],      g_xl [(size_t)NTOK*DIM];
__device__ hf g_wqh [(size_t)DIM*INNER];
__device__ hf g_wkvh[(size_t)DIM*2*INNER];
__device__ hf g_hqh [(size_t)DIM*INNER];
__device__ hf g_hkvh[(size_t)DIM*2*INNER];
__device__ hf g_wouth[(size_t)INNER*DIM];
__device__ hf g_houth[(size_t)INNER*DIM];
__device__ hf g_q1h [(size_t)NTOK*INNER],   g_q1l [(size_t)NTOK*INNER];
__device__ hf g_kv1h[(size_t)NTOK*2*INNER], g_kv1l[(size_t)NTOK*2*INNER];
__device__ hf g_q2h [(size_t)NTOK*INNER],   g_q2l [(size_t)NTOK*INNER];
__device__ hf g_kv2h[(size_t)NTOK*2*INNER], g_kv2l[(size_t)NTOK*2*INNER];
__device__ hf g_o1h [(size_t)NTOK*INNER],   g_o1l [(size_t)NTOK*INNER];
__device__ hf g_o2h [(size_t)NTOK*INNER],   g_o2l [(size_t)NTOK*INNER];
__device__ hf g_p2h [(size_t)HEADS*MSAW*MSAW], g_p2l [(size_t)HEADS*MSAW*MSAW];
__device__ float g_Pp [(size_t)32*MSAW*MSAW];

// ===================== helpers =====================
__device__ __forceinline__ uint32_t smem_u32(const void* p) {
    uint32_t a;
    asm("{ .reg .u64 t; cvta.to.shared.u64 t, %1; cvt.u32.u64 %0, t; }" : "=r"(a) : "l"(p));
    return a;
}
__device__ __forceinline__ void ldsm4(uint32_t& r0, uint32_t& r1, uint32_t& r2, uint32_t& r3, uint32_t a) {
    asm volatile("ldmatrix.sync.aligned.m8n8.x4.shared.b16 {%0,%1,%2,%3}, [%4];"
                 : "=r"(r0), "=r"(r1), "=r"(r2), "=r"(r3) : "r"(a));
}
__device__ __forceinline__ void ldsm4t(uint32_t& r0, uint32_t& r1, uint32_t& r2, uint32_t& r3, uint32_t a) {
    asm volatile("ldmatrix.sync.aligned.m8n8.x4.trans.shared.b16 {%0,%1,%2,%3}, [%4];"
                 : "=r"(r0), "=r"(r1), "=r"(r2), "=r"(r3) : "r"(a));
}
__device__ __forceinline__ void mma16816(float* c, const uint32_t* a, const uint32_t* b) {
    asm volatile("mma.sync.aligned.m16n8k16.row.col.f32.f16.f16.f32 "
                 "{%0,%1,%2,%3}, {%4,%5,%6,%7}, {%8,%9}, {%0,%1,%2,%3};"
                 : "+f"(c[0]), "+f"(c[1]), "+f"(c[2]), "+f"(c[3])
                 : "r"(a[0]), "r"(a[1]), "r"(a[2]), "r"(a[3]), "r"(b[0]), "r"(b[1]));
}
__device__ __forceinline__ void cpa16(uint32_t dst, const void* src) {
    asm volatile("cp.async.cg.shared.global [%0], [%1], 16;" :: "r"(dst), "l"(src));
}
#define CP_COMMIT() asm volatile("cp.async.commit_group;" ::: "memory")
#define CP_WAIT1()  asm volatile("cp.async.wait_group 1;" ::: "memory")
#define CP_WAIT2()  asm volatile("cp.async.wait_group 2;" ::: "memory")
#define CP_WAIT0()  asm volatile("cp.async.wait_group 0;" ::: "memory")
__device__ __forceinline__ void split_pair(float a, float b, uint32_t& hi, uint32_t& lo) {
    hf ha = __float2half_rn(a), hb = __float2half_rn(b);
    hf la = __float2half_rn(a - __half2float(ha));
    hf lb = __float2half_rn(b - __half2float(hb));
    __half2 h2 = __halves2half2(ha, hb);
    __half2 l2 = __halves2half2(la, lb);
    hi = *(uint32_t*)&h2;
    lo = *(uint32_t*)&l2;
}

// ================= split / convert fp32 -> fp16 planes (one launch) =================
__device__ __forceinline__ void split_one(const float* in, hf* H, hf* L, int i) {
    const float4 v = ((const float4*)in)[i];
    uint32_t h0, l0, h1, l1;
    split_pair(v.x, v.y, h0, l0);
    split_pair(v.z, v.w, h1, l1);
    *(uint2*)(H + (size_t)i * 4) = make_uint2(h0, h1);
    *(uint2*)(L + (size_t)i * 4) = make_uint2(l0, l1);
}
__device__ __forceinline__ void conv_one(const float* in, hf* H, int i) {
    const float4 v = ((const float4*)in)[i];
    __half2 a = __halves2half2(__float2half_rn(v.x), __float2half_rn(v.y));
    __half2 b = __halves2half2(__float2half_rn(v.z), __float2half_rn(v.w));
    *(uint2*)(H + (size_t)i * 4) = make_uint2(*(uint32_t*)&a, *(uint32_t*)&b);
}
__global__ __launch_bounds__(256)
void split_all(const float* x, const float* wq, const float* wkv, const float* hq,
               const float* hkv, const float* wo, const float* ho,
               hf* xh, hf* xl,
               hf* wqh, hf* wkvh, hf* hqh, hf* hkvh, hf* woh, hf* hoh)
{
    const int b = blockIdx.x;
    if (b < 8192) {
        split_one(x, xh, xl, b * 256 + threadIdx.x);
        return;
    }
    const int i = (b - 8192) * 256 + threadIdx.x;
    if (i < 32768)        conv_one(wq,  wqh,  i);
    else if (i < 98304)   conv_one(wkv, wkvh, i - 32768);
    else if (i < 131072)  conv_one(hq,  hqh,  i - 98304);
    else if (i < 196608)  conv_one(hkv, hkvh, i - 131072);
    else if (i < 229376)  conv_one(wo,  woh,  i - 196608);
    else                  conv_one(ho,  hoh,  i - 229376);
}

// ======== big-tile GEMM core: 128x128 block, 4 warps, warp tile 64x64, CH=32, 3-stage ========
// A split (hi/lo), B SINGLE fp16 plane -> 2 products per accumulator.
template<int OSPLIT, int DUAL>
__device__ __forceinline__ void gemm_core6(
    const hf* __restrict__ Ah_, const hf* __restrict__ Al_, size_t sAr,
    const hf* __restrict__ Bh_, size_t sBr,
    const hf* __restrict__ Ah2_, const hf* __restrict__ Al2_,
    const hf* __restrict__ Bh2_, int K1,
    float* __restrict__ Cf, hf* __restrict__ Chp, hf* __restrict__ Clp,
    int ldc, int K, const float* __restrict__ bias, const float* __restrict__ bias2)
{
    constexpr int CH = 32, NSTG = 3;
    constexpr int AP = 40;           // 32 + 8 pad (halves)
    constexpr int BP = 136;          // 128 + 8 pad
    constexpr int AH = 128 * AP;
    constexpr int BH = CH * BP;
    constexpr int STAGE = 2 * AH + BH;

    extern __shared__ hf smn[];
    const int tid = threadIdx.x, warp = tid >> 5, lane = tid & 31;
    const int wm = warp >> 1, wn = warp & 1;

    float c[4][8][4];
#pragma unroll
    for (int mt = 0; mt < 4; mt++)
#pragma unroll
        for (int nt = 0; nt < 8; nt++)
#pragma unroll
            for (int e = 0; e < 4; e++) c[mt][nt][e] = 0.f;

    auto issue = [&](int cc) {
        const int s = cc % NSTG;
        hf* Ah = smn + (size_t)s * STAGE;
        hf* Al = Ah + AH;
        hf* Bh = Ah + 2 * AH;
        int k0 = cc * CH;
        const hf *Ap = Ah_, *Alp = Al_, *Bp = Bh_;
        if (DUAL && k0 >= K1) { Ap = Ah2_; Alp = Al2_; Bp = Bh2_; k0 -= K1; }
#pragma unroll
        for (int i = 0; i < 4; i++) {
            const int idx = i * 128 + tid;
            const int row = idx >> 2, g = (idx & 3) * 8;
            const size_t go = (size_t)row * sAr + k0 + g;
            const int off = row * AP + g;
            cpa16(smem_u32(Ah + off), Ap + go);
            cpa16(smem_u32(Al + off), Alp + go);
        }
#pragma unroll
        for (int i = 0; i < 4; i++) {
            const int idx = i * 128 + tid;
            const int kr = idx >> 4, q = (idx & 15) * 8;
            const size_t go = (size_t)(k0 + kr) * sBr + q;
            const int off = kr * BP + q;
            cpa16(smem_u32(Bh + off), Bp + go);
        }
    };

    auto compute = [&](int s) {
        hf* Ah = smn + (size_t)s * STAGE;
        hf* Al = Ah + AH;
        hf* Bh = Ah + 2 * AH;
#pragma unroll
        for (int h = 0; h < 2; h++) {
            uint32_t ah[4][4], al[4][4];
#pragma unroll
            for (int mt = 0; mt < 4; mt++) {
                const int row = wm * 64 + mt * 16 + (lane & 15);
                const int ko = h * 16 + ((lane >> 4) & 1) * 8;
                ldsm4(ah[mt][0], ah[mt][1], ah[mt][2], ah[mt][3], smem_u32(Ah + row * AP + ko));
                ldsm4(al[mt][0], al[mt][1], al[mt][2], al[mt][3], smem_u32(Al + row * AP + ko));
            }
#pragma unroll
            for (int bg = 0; bg < 2; bg++) {
                uint32_t bh[4][2];
#pragma unroll
                for (int np = 0; np < 2; np++) {
                    const int k = h * 16 + (lane & 7) + ((lane >> 3) & 1) * 8;
                    const int col = wn * 64 + bg * 32 + np * 16 + ((lane >> 4) & 1) * 8;
                    ldsm4t(bh[2*np][0], bh[2*np][1], bh[2*np+1][0], bh[2*np+1][1],
                           smem_u32(Bh + k * BP + col));
                }
                // 2 products: A-hi then A-lo
#pragma unroll
                for (int mt = 0; mt < 4; mt++)
#pragma unroll
                    for (int t = 0; t < 4; t++)
                        mma16816(c[mt][bg * 4 + t], ah[mt], bh[t]);
#pragma unroll
                for (int mt = 0; mt < 4; mt++)
#pragma unroll
                    for (int t = 0; t < 4; t++)
                        mma16816(c[mt][bg * 4 + t], al[mt], bh[t]);
            }
        }
    };

    const int NC = K / CH;
    issue(0); CP_COMMIT();
    issue(1); CP_COMMIT();
    for (int cc = 0; cc < NC; cc++) {
        CP_WAIT1();
        __syncthreads();
        if (cc + 2 < NC) issue(cc + 2);
        CP_COMMIT();
        compute(cc % NSTG);
    }

    const int g = lane >> 2, tg = lane & 3;
#pragma unroll
    for (int mt = 0; mt < 4; mt++) {
#pragma unroll
        for (int nt = 0; nt < 8; nt++) {
            const int row0 = wm * 64 + mt * 16 + g;
            const int col = wn * 64 + nt * 8 + tg * 2;
            float2 v0 = make_float2(c[mt][nt][0], c[mt][nt][1]);
            float2 v1 = make_float2(c[mt][nt][2], c[mt][nt][3]);
            if (OSPLIT) {
                uint32_t h0, l0, h1, l1;
                split_pair(v0.x, v0.y, h0, l0);
                split_pair(v1.x, v1.y, h1, l1);
                *(uint32_t*)(Chp + (size_t)row0 * ldc + col) = h0;
                *(uint32_t*)(Clp + (size_t)row0 * ldc + col) = l0;
                *(uint32_t*)(Chp + (size_t)(row0 + 8) * ldc + col) = h1;
                *(uint32_t*)(Clp + (size_t)(row0 + 8) * ldc + col) = l1;
            } else {
                float b0 = 0.f, b1 = 0.f;
                if (bias)  { b0 += bias[col];  b1 += bias[col + 1]; }
                if (bias2) { b0 += bias2[col]; b1 += bias2[col + 1]; }
                v0.x += b0; v0.y += b1; v1.x += b0; v1.y += b1;
                *(float2*)(Cf + (size_t)row0 * ldc + col) = v0;
                *(float2*)(Cf + (size_t)(row0 + 8) * ldc + col) = v1;
            }
        }
    }
}

// ================= 3-product split GEMM (64x32 warp tile) for av/dots =================
template<int WM, int WN, int BT, int OSPLIT, int CH, int NSTG>
__device__ __forceinline__ void gemm_core5(
    const hf* __restrict__ Ah_, const hf* __restrict__ Al_, size_t sAr, size_t sAk,
    const hf* __restrict__ Bh_, const hf* __restrict__ Bl_, size_t sBr, size_t sBk,
    float* __restrict__ Cf, hf* __restrict__ Chp, hf* __restrict__ Clp,
    int ldc, int K)
{
    constexpr int TM = WM * 64, TN = WN * 32;
    constexpr int THREADS = WM * WN * 32;
    constexpr int AP = CH + 8;
    constexpr int BP = BT ? (TN + 8) : (CH + 8);
    constexpr int AH = TM * AP;
    constexpr int BH = BT ? CH * BP : TN * AP;
    constexpr int STAGE = 2 * AH + 2 * BH;
    constexpr int C8 = CH / 8;
    constexpr int NA = TM * C8 / THREADS;
    constexpr int NB = BT ? (CH * TN / 8) / THREADS : (TN * C8) / THREADS;

    extern __shared__ hf smn[];
    const int tid = threadIdx.x, warp = tid >> 5, lane = tid & 31;
    const int wm = warp / WN, wn = warp % WN;

    float c[4][4][4];
#pragma unroll
    for (int mt = 0; mt < 4; mt++)
#pragma unroll
        for (int nt = 0; nt < 4; nt++)
#pragma unroll
            for (int e = 0; e < 4; e++) c[mt][nt][e] = 0.f;

    auto issue = [&](int cc) {
        const int s = cc % NSTG;
        hf* Ah = smn + (size_t)s * STAGE;
        hf* Al = Ah + AH;
        hf* Bh = Ah + 2 * AH;
        hf* Bl = Bh + BH;
        int k0 = cc * CH;
        const size_t cb = (size_t)(k0 >> 6) * sAk + (k0 & 63);
#pragma unroll
        for (int i = 0; i < NA; i++) {
            const int idx = i * THREADS + tid;
            const int row = idx / C8, g = (idx % C8) * 8;
            const size_t go = (size_t)row * sAr + cb + g;
            const int off = row * AP + g;
            cpa16(smem_u32(Ah + off), Ah_ + go);
            cpa16(smem_u32(Al + off), Al_ + go);
        }
#pragma unroll
        for (int i = 0; i < NB; i++) {
            const int idx = i * THREADS + tid;
            size_t go; int off;
            if (BT) {
                const int kr = idx / (TN / 8), q = idx % (TN / 8);
                go = (size_t)(k0 + kr) * sBr + q * 8;
                off = kr * BP + q * 8;
            } else {
                const int nr = idx / C8, g = (idx % C8) * 8;
                go = (size_t)nr * sBr + (size_t)(k0 >> 6) * sBk + (k0 & 63) + g;
                off = nr * AP + g;
            }
            cpa16(smem_u32(Bh + off), Bh_ + go);
            cpa16(smem_u32(Bl + off), Bl_ + go);
        }
    };

    auto compute = [&](int s) {
        hf* Ah = smn + (size_t)s * STAGE;
        hf* Al = Ah + AH;
        hf* Bh = Ah + 2 * AH;
        hf* Bl = Bh + BH;
#pragma unroll
        for (int h = 0; h < CH / 16; h++) {
            uint32_t ah[4][4], al[4][4], bh[4][2], bl[4][2];
#pragma unroll
            for (int mt = 0; mt < 4; mt++) {
                const int row = wm * 64 + mt * 16 + (lane & 15);
                const int ko = h * 16 + ((lane >> 4) & 1) * 8;
                ldsm4(ah[mt][0], ah[mt][1], ah[mt][2], ah[mt][3], smem_u32(Ah + row * AP + ko));
                ldsm4(al[mt][0], al[mt][1], al[mt][2], al[mt][3], smem_u32(Al + row * AP + ko));
            }
#pragma unroll
            for (int np = 0; np < 2; np++) {
                if (BT) {
                    const int k = h * 16 + (lane & 7) + ((lane >> 3) & 1) * 8;
                    const int col = wn * 32 + np * 16 + ((lane >> 4) & 1) * 8;
                    ldsm4t(bh[2*np][0], bh[2*np][1], bh[2*np+1][0], bh[2*np+1][1],
                           smem_u32(Bh + k * BP + col));
                    ldsm4t(bl[2*np][0], bl[2*np][1], bl[2*np+1][0], bl[2*np+1][1],
                           smem_u32(Bl + k * BP + col));
                } else {
                    const int nrow = wn * 32 + np * 16 + (lane & 7) + ((lane >> 4) & 1) * 8;
                    const int ko = h * 16 + ((lane >> 3) & 1) * 8;
                    ldsm4(bh[2*np][0], bh[2*np][1], bh[2*np+1][0], bh[2*np+1][1],
                          smem_u32(Bh + nrow * AP + ko));
                    ldsm4(bl[2*np][0], bl[2*np][1], bl[2*np+1][0], bl[2*np+1][1],
                          smem_u32(Bl + nrow * AP + ko));
                }
            }
#pragma unroll
            for (int mt = 0; mt < 4; mt++)
#pragma unroll
                for (int nt = 0; nt < 4; nt++)
                    mma16816(c[mt][nt], ah[mt], bh[nt]);
#pragma unroll
            for (int mt = 0; mt < 4; mt++)
#pragma unroll
                for (int nt = 0; nt < 4; nt++)
                    mma16816(c[mt][nt], ah[mt], bl[nt]);
#pragma unroll
            for (int mt = 0; mt < 4; mt++)
#pragma unroll
                for (int nt = 0; nt < 4; nt++)
                    mma16816(c[mt][nt], al[mt], bh[nt]);
        }
    };

    const int NC = K / CH;
#pragma unroll
    for (int p = 0; p < NSTG - 1; p++) { issue(p); CP_COMMIT(); }
    for (int cc = 0; cc < NC; cc++) {
        if constexpr (NSTG == 3) CP_WAIT1(); else CP_WAIT2();
        __syncthreads();
        if (cc + NSTG - 1 < NC) issue(cc + NSTG - 1);
        CP_COMMIT();
        compute(cc % NSTG);
    }

    const int g = lane >> 2, tg = lane & 3;
#pragma unroll
    for (int mt = 0; mt < 4; mt++) {
#pragma unroll
        for (int nt = 0; nt < 4; nt++) {
            const int row0 = wm * 64 + mt * 16 + g;
            const int col = wn * 32 + nt * 8 + tg * 2;
            float2 v0 = make_float2(c[mt][nt][0], c[mt][nt][1]);
            float2 v1 = make_float2(c[mt][nt][2], c[mt][nt][3]);
            if (OSPLIT) {
                uint32_t h0, l0, h1, l1;
                split_pair(v0.x, v0.y, h0, l0);
                split_pair(v1.x, v1.y, h1, l1);
                *(uint32_t*)(Chp + (size_t)row0 * ldc + col) = h0;
                *(uint32_t*)(Clp + (size_t)row0 * ldc + col) = l0;
                *(uint32_t*)(Chp + (size_t)(row0 + 8) * ldc + col) = h1;
                *(uint32_t*)(Clp + (size_t)(row0 + 8) * ldc + col) = l1;
            } else {
                *(float2*)(Cf + (size_t)row0 * ldc + col) = v0;
                *(float2*)(Cf + (size_t)(row0 + 8) * ldc + col) = v1;
            }
        }
    }
}

// ---- wrappers ----
__global__ __launch_bounds__(128, 2)
void gemm_proj_all(const hf* __restrict__ xh, const hf* __restrict__ xl,
                   const hf* __restrict__ wqh, const hf* __restrict__ wkvh,
                   const hf* __restrict__ hqh, const hf* __restrict__ hkvh,
                   hf* __restrict__ q1h, hf* __restrict__ q1l,
                   hf* __restrict__ kv1h, hf* __restrict__ kv1l,
                   hf* __restrict__ q2h, hf* __restrict__ q2l,
                   hf* __restrict__ kv2h, hf* __restrict__ kv2l)
{
    const int m0 = blockIdx.y * 128;
    const int n0 = blockIdx.x * 128;
    const int fam = blockIdx.z;
    const hf* Bh;
    hf *Ch, *Cl;
    int ldc;
    if (n0 < INNER) {
        Bh = (fam ? hqh : wqh) + n0;
        Ch = (fam ? q2h : q1h) + (size_t)m0 * INNER + n0;
        Cl = (fam ? q2l : q1l) + (size_t)m0 * INNER + n0;
        ldc = INNER;
    } else {
        const int nn = n0 - INNER;
        Bh = (fam ? hkvh : wkvh) + nn;
        Ch = (fam ? kv2h : kv1h) + (size_t)m0 * 2 * INNER + nn;
        Cl = (fam ? kv2l : kv1l) + (size_t)m0 * 2 * INNER + nn;
        ldc = 2 * INNER;
    }
    const int Nw = (n0 < INNER) ? INNER : 2 * INNER;
    gemm_core6<1, 0>(xh + (size_t)m0 * DIM, xl + (size_t)m0 * DIM, DIM,
                     Bh, Nw,
                     nullptr, nullptr, nullptr, 0,
                     nullptr, Ch, Cl, ldc, DIM, nullptr, nullptr);
}

__global__ __launch_bounds__(128, 2)
void gemm_out_fused(const hf* __restrict__ o1h, const hf* __restrict__ o1l,
                    const hf* __restrict__ o2h, const hf* __restrict__ o2l,
                    const hf* __restrict__ wouth, const hf* __restrict__ houth,
                    float* __restrict__ C, const float* __restrict__ wout_b,
                    const float* __restrict__ hout_b)
{
    const int m0 = blockIdx.y * 128, n0 = blockIdx.x * 128;
    gemm_core6<0, 1>(o1h + (size_t)m0 * INNER, o1l + (size_t)m0 * INNER, INNER,
                     wouth + n0, DIM,
                     o2h + (size_t)m0 * INNER, o2l + (size_t)m0 * INNER,
                     houth + n0, INNER,
                     C + (size_t)m0 * DIM + n0, nullptr, nullptr,
                     DIM, 2 * INNER, wout_b + n0, hout_b + n0);
}

__global__ __launch_bounds__(128, 3)
void gemm_av2(const hf* __restrict__ Ph, const hf* __restrict__ Pl,
              const hf* __restrict__ Vh, const hf* __restrict__ Vl,
              hf* __restrict__ Oh, hf* __restrict__ Ol)
{
    const int i0 = blockIdx.x * 128;
    const int h = blockIdx.y, r = blockIdx.z;
    const size_t aoff = (size_t)h * (MSAW * MSAW) + (size_t)i0 * MSAW;
    const size_t boff = (size_t)INNER + (size_t)h * 64 + (size_t)r * MSAW * 2 * INNER;
    const size_t coff = ((size_t)r * MSAW + i0) * INNER + h * 64;
    gemm_core5<2, 2, 1, 1, 16, 4>(Ph + aoff, Pl + aoff, MSAW, 64,
                                  Vh + boff, Vl + boff, 2 * INNER, 0,
                                  nullptr, Oh + coff, Ol + coff, INNER, MSAW);
}

// smem bytes
#define SM_PROJ (3 * (2 * 128 * 40 + 32 * 136) * 2)
#define SM_AV   (4 * (2 * 128 * 24 + 2 * 16 * 72) * 2)
#define COL_SMEM2 (6 * 128 * 72 * 2)

// ================= column attention body (3-product fp16 split) =================
__device__ __forceinline__
void col_attn_body(int wi, int head,
                   const hf* __restrict__ qh, const hf* __restrict__ ql,
                   const hf* __restrict__ kvh, const hf* __restrict__ kvl,
                   hf* __restrict__ oh, hf* __restrict__ ol)
{
    extern __shared__ hf smc[];
    const int PL = 128 * 72;
    hf *sqh = smc,          *sql = smc + PL;
    hf *skh = smc + 2 * PL, *skl = smc + 3 * PL;
    hf *svh = smc + 4 * PL, *svl = smc + 5 * PL;

    const int tid = threadIdx.x, warp = tid >> 5, lane = tid & 31;

#pragma unroll
    for (int i = 0; i < 4; i++) {
        const int idx = i * 256 + tid;
        const int row = idx >> 3, g = (idx & 7) * 8;
        const size_t gq = ((size_t)(row * MSAW + wi)) * INNER + head * 64 + g;
        const size_t gk = ((size_t)(row * MSAW + wi)) * 2 * INNER + head * 64 + g;
        cpa16(smem_u32(sqh + row * 72 + g), qh + gq);
        cpa16(smem_u32(sql + row * 72 + g), ql + gq);
        cpa16(smem_u32(skh + row * 72 + g), kvh + gk);
        cpa16(smem_u32(skl + row * 72 + g), kvl + gk);
        cpa16(smem_u32(svh + row * 72 + g), kvh + gk + INNER);
        cpa16(smem_u32(svl + row * 72 + g), kvl + gk + INNER);
    }
    CP_COMMIT();
    CP_WAIT0();
    __syncthreads();

    const int m0 = warp * 16;
    float s[16][4];
#pragma unroll
    for (int nt = 0; nt < 16; nt++)
#pragma unroll
        for (int e = 0; e < 4; e++) s[nt][e] = 0.f;

#pragma unroll
    for (int kc = 0; kc < 4; kc++) {
        uint32_t ah[4], al[4];
        const int arow = m0 + (lane & 15);
        const int acol = kc * 16 + ((lane >> 4) & 1) * 8;
        ldsm4(ah[0], ah[1], ah[2], ah[3], smem_u32(sqh + arow * 72 + acol));
        ldsm4(al[0], al[1], al[2], al[3], smem_u32(sql + arow * 72 + acol));
#pragma unroll
        for (int ng = 0; ng < 4; ng++) {
            uint32_t bh[4][2], bl[4][2];
#pragma unroll
            for (int npp = 0; npp < 2; npp++) {
                const int nt0 = ng * 4 + npp * 2;
                const int brow = nt0 * 8 + (lane & 7) + ((lane >> 4) & 1) * 8;
                const int bcol = kc * 16 + ((lane >> 3) & 1) * 8;
                ldsm4(bh[npp*2][0], bh[npp*2][1], bh[npp*2+1][0], bh[npp*2+1][1],
                      smem_u32(skh + brow * 72 + bcol));
                ldsm4(bl[npp*2][0], bl[npp*2][1], bl[npp*2+1][0], bl[npp*2+1][1],
                      smem_u32(skl + brow * 72 + bcol));
            }
#pragma unroll
            for (int t = 0; t < 4; t++) mma16816(s[ng * 4 + t], ah, bh[t]);
#pragma unroll
            for (int t = 0; t < 4; t++) mma16816(s[ng * 4 + t], ah, bl[t]);
#pragma unroll
            for (int t = 0; t < 4; t++) mma16816(s[ng * 4 + t], al, bh[t]);
        }
    }

    const float sc = 0.125f;
    float mx0 = -1e30f, mx1 = -1e30f;
#pragma unroll
    for (int nt = 0; nt < 16; nt++) {
        mx0 = fmaxf(mx0, fmaxf(s[nt][0], s[nt][1]));
        mx1 = fmaxf(mx1, fmaxf(s[nt][2], s[nt][3]));
    }
    mx0 = fmaxf(mx0, __shfl_xor_sync(0xffffffffu, mx0, 1));
    mx0 = fmaxf(mx0, __shfl_xor_sync(0xffffffffu, mx0, 2));
    mx1 = fmaxf(mx1, __shfl_xor_sync(0xffffffffu, mx1, 1));
    mx1 = fmaxf(mx1, __shfl_xor_sync(0xffffffffu, mx1, 2));
    float sum0 = 0.f, sum1 = 0.f;
#pragma unroll
    for (int nt = 0; nt < 16; nt++) {
        s[nt][0] = __expf(sc * (s[nt][0] - mx0)); sum0 += s[nt][0];
        s[nt][1] = __expf(sc * (s[nt][1] - mx0)); sum0 += s[nt][1];
        s[nt][2] = __expf(sc * (s[nt][2] - mx1)); sum1 += s[nt][2];
        s[nt][3] = __expf(sc * (s[nt][3] - mx1)); sum1 += s[nt][3];
    }
    sum0 += __shfl_xor_sync(0xffffffffu, sum0, 1);
    sum0 += __shfl_xor_sync(0xffffffffu, sum0, 2);
    sum1 += __shfl_xor_sync(0xffffffffu, sum1, 1);
    sum1 += __shfl_xor_sync(0xffffffffu, sum1, 2);
    const float inv0 = 1.f / sum0, inv1 = 1.f / sum1;
#pragma unroll
    for (int nt = 0; nt < 16; nt++) {
        s[nt][0] *= inv0; s[nt][1] *= inv0;
        s[nt][2] *= inv1; s[nt][3] *= inv1;
    }

    float o[8][4];
#pragma unroll
    for (int dt = 0; dt < 8; dt++)
#pragma unroll
        for (int e = 0; e < 4; e++) o[dt][e] = 0.f;

#pragma unroll
    for (int jc = 0; jc < 8; jc++) {
        uint32_t pah[4], pal[4];
        split_pair(s[2 * jc][0],     s[2 * jc][1],     pah[0], pal[0]);
        split_pair(s[2 * jc][2],     s[2 * jc][3],     pah[1], pal[1]);
        split_pair(s[2 * jc + 1][0], s[2 * jc + 1][1], pah[2], pal[2]);
        split_pair(s[2 * jc + 1][2], s[2 * jc + 1][3], pah[3], pal[3]);
        const int jrow = jc * 16 + (lane & 7) + ((lane >> 3) & 1) * 8;
#pragma unroll
        for (int dg = 0; dg < 2; dg++) {
            uint32_t bh[4][2], bl[4][2];
#pragma unroll
            for (int dpp = 0; dpp < 2; dpp++) {
                const int dt0 = dg * 4 + dpp * 2;
                const int dcol = dt0 * 8 + ((lane >> 4) & 1) * 8;
                ldsm4t(bh[dpp*2][0], bh[dpp*2][1], bh[dpp*2+1][0], bh[dpp*2+1][1],
                       smem_u32(svh + jrow * 72 + dcol));
                ldsm4t(bl[dpp*2][0], bl[dpp*2][1], bl[dpp*2+1][0], bl[dpp*2+1][1],
                       smem_u32(svl + jrow * 72 + dcol));
            }
#pragma unroll
            for (int t = 0; t < 4; t++) mma16816(o[dg * 4 + t], pah, bh[t]);
#pragma unroll
            for (int t = 0; t < 4; t++) mma16816(o[dg * 4 + t], pah, bl[t]);
#pragma unroll
            for (int t = 0; t < 4; t++) mma16816(o[dg * 4 + t], pal, bh[t]);
        }
    }

    const int g = lane >> 2, tg = lane & 3;
    const int r0 = m0 + g, r1 = r0 + 8;
#pragma unroll
    for (int dt = 0; dt < 8; dt++) {
        const int d = head * 64 + dt * 8 + tg * 2;
        const size_t b0 = ((size_t)(r0 * MSAW + wi)) * INNER + d;
        const size_t b1 = ((size_t)(r1 * MSAW + wi)) * INNER + d;
        uint32_t h0, l0, h1, l1;
        split_pair(o[dt][0], o[dt][1], h0, l0);
        split_pair(o[dt][2], o[dt][3], h1, l1);
        *(uint32_t*)(oh + b0) = h0;
        *(uint32_t*)(ol + b0) = l0;
        *(uint32_t*)(oh + b1) = h1;
        *(uint32_t*)(ol + b1) = l1;
    }
}

// ============= fused attention: dots tiles (blocks 0..127) + col attn (128..2175) =============
__global__ __launch_bounds__(256, 2)
void attn_fused(const hf* __restrict__ q1h, const hf* __restrict__ q1l,
                const hf* __restrict__ kv1h, const hf* __restrict__ kv1l,
                const hf* __restrict__ q2h, const hf* __restrict__ q2l,
                const hf* __restrict__ kv2h, const hf* __restrict__ kv2l,
                hf* __restrict__ o1h, hf* __restrict__ o1l,
                float* __restrict__ Pp)
{
    const int b = blockIdx.x;
    if (b < 128) {
        const int j0 = (b & 1) * 128, i0 = ((b >> 1) & 1) * 128;
        const int z = b >> 2;
        const int h = z >> 2, s = z & 3;
        const size_t r0 = (size_t)s * 32;
        const size_t aoff = (size_t)h * 64 + (size_t)i0 * INNER + r0 * MSAW * INNER;
        const size_t boff = (size_t)h * 64 + (size_t)j0 * 2 * INNER + r0 * MSAW * 2 * INNER;
        gemm_core5<2, 4, 0, 0, 16, 4>(q2h + aoff, q2l + aoff, INNER, (size_t)MSAW * INNER,
                                      kv2h + boff, kv2l + boff, 2 * INNER, (size_t)MSAW * 2 * INNER,
                                      Pp + (size_t)z * (MSAW * MSAW) + (size_t)i0 * MSAW + j0,
                                      nullptr, nullptr, MSAW, 32 * 64);
    } else {
        const int cb = b - 128;
        col_attn_body(cb & 255, cb >> 8, q1h, q1l, kv1h, kv1l, o1h, o1l);
    }
}

// ============= reduce 4 dots partials + scale + softmax -> fp16 hi/lo planes =============
__global__ __launch_bounds__(256)
void softmax_reduce2(const float* __restrict__ Pp, hf* __restrict__ Ph, hf* __restrict__ Pl)
{
    const int h = blockIdx.x >> 8, i = blockIdx.x & 255;
    const int tid = threadIdx.x;
    __shared__ float red[34];
    float v = 0.f;
#pragma unroll
    for (int s = 0; s < 4; s++)
        v += Pp[((size_t)(h * 4 + s) * MSAW + i) * MSAW + tid];
    v *= 0.011048543456039806f;  // (1/8) * 128^-0.5

    float m = v;
#pragma unroll
    for (int o = 16; o; o >>= 1) m = fmaxf(m, __shfl_xor_sync(0xffffffffu, m, o));
    if ((tid & 31) == 0) red[tid >> 5] = m;
    __syncthreads();
    if (tid == 0) {
        float mm = red[0];
#pragma unroll
        for (int w = 1; w < 8; w++) mm = fmaxf(mm, red[w]);
        red[32] = mm;
    }
    __syncthreads();
    const float e = __expf(v - red[32]);
    float s = e;
#pragma unroll
    for (int o = 16; o; o >>= 1) s += __shfl_xor_sync(0xffffffffu, s, o);
    if ((tid & 31) == 0) red[8 + (tid >> 5)] = s;
    __syncthreads();
    if (tid == 0) {
        float ss = 0.f;
#pragma unroll
        for (int w = 0; w < 8; w++) ss += red[8 + w];
        red[33] = 1.f / ss;
    }
    __syncthreads();
    const float p = e * red[33];
    const hf hp = __float2half_rn(p);
    const hf lp = __float2half_rn(p - __half2float(hp));
    const size_t off = ((size_t)h * MSAW + i) * MSAW + tid;
    Ph[off] = hp;
    Pl[off] = lp;
}

// =============================== launch ===============================
extern "C" void kernel_launch(void* const* d_in, const int* in_sizes, int n_in,
                              void* d_out, int out_size)
{
    const float* x      = (const float*)d_in[0];
    const float* wq_w   = (const float*)d_in[1];
    const float* wkv_w  = (const float*)d_in[2];
    const float* wout_w = (const float*)d_in[3];
    const float* wout_b = (const float*)d_in[4];
    const float* hq_w   = (const float*)d_in[5];
    const float* hkv_w  = (const float*)d_in[6];
    const float* hout_w = (const float*)d_in[7];
    const float* hout_b = (const float*)d_in[8];
    float* out = (float*)d_out;

    void* p;
    hf *xh, *xl, *wqh, *wkvh, *hqh, *hkvh, *wouth, *houth;
    hf *q1h, *q1l, *kv1h, *kv1l, *q2h, *q2l, *kv2h, *kv2l;
    hf *o1h, *o1l, *o2h, *o2l, *p2h, *p2l;
    float* Pp;
    cudaGetSymbolAddress(&p, g_xh);    xh = (hf*)p;
    cudaGetSymbolAddress(&p, g_xl);    xl = (hf*)p;
    cudaGetSymbolAddress(&p, g_wqh);   wqh = (hf*)p;
    cudaGetSymbolAddress(&p, g_wkvh);  wkvh = (hf*)p;
    cudaGetSymbolAddress(&p, g_hqh);   hqh = (hf*)p;
    cudaGetSymbolAddress(&p, g_hkvh);  hkvh = (hf*)p;
    cudaGetSymbolAddress(&p, g_wouth); wouth = (hf*)p;
    cudaGetSymbolAddress(&p, g_houth); houth = (hf*)p;
    cudaGetSymbolAddress(&p, g_q1h);   q1h = (hf*)p;
    cudaGetSymbolAddress(&p, g_q1l);   q1l = (hf*)p;
    cudaGetSymbolAddress(&p, g_kv1h);  kv1h = (hf*)p;
    cudaGetSymbolAddress(&p, g_kv1l);  kv1l = (hf*)p;
    cudaGetSymbolAddress(&p, g_q2h);   q2h = (hf*)p;
    cudaGetSymbolAddress(&p, g_q2l);   q2l = (hf*)p;
    cudaGetSymbolAddress(&p, g_kv2h);  kv2h = (hf*)p;
    cudaGetSymbolAddress(&p, g_kv2l);  kv2l = (hf*)p;
    cudaGetSymbolAddress(&p, g_o1h);   o1h = (hf*)p;
    cudaGetSymbolAddress(&p, g_o1l);   o1l = (hf*)p;
    cudaGetSymbolAddress(&p, g_o2h);   o2h = (hf*)p;
    cudaGetSymbolAddress(&p, g_o2l);   o2l = (hf*)p;
    cudaGetSymbolAddress(&p, g_p2h);   p2h = (hf*)p;
    cudaGetSymbolAddress(&p, g_p2l);   p2l = (hf*)p;
    cudaGetSymbolAddress(&p, g_Pp);    Pp = (float*)p;

    cudaFuncSetAttribute(gemm_proj_all,  cudaFuncAttributeMaxDynamicSharedMemorySize, SM_PROJ);
    cudaFuncSetAttribute(gemm_out_fused, cudaFuncAttributeMaxDynamicSharedMemorySize, SM_PROJ);
    cudaFuncSetAttribute(gemm_av2,       cudaFuncAttributeMaxDynamicSharedMemorySize, SM_AV);
    cudaFuncSetAttribute(attn_fused,     cudaFuncAttributeMaxDynamicSharedMemorySize, COL_SMEM2);

    split_all<<<8192 + 1024, 256>>>(x, wq_w, wkv_w, hq_w, hkv_w, wout_w, hout_w,
                                    xh, xl, wqh, wkvh, hqh, hkvh, wouth, houth);

    gemm_proj_all<<<dim3(12, NTOK / 128, 2), 128, SM_PROJ>>>(
        xh, xl, wqh, wkvh, hqh, hkvh,
        q1h, q1l, kv1h, kv1l, q2h, q2l, kv2h, kv2l);

    attn_fused<<<128 + MSAW * HEADS, 256, COL_SMEM2>>>(
        q1h, q1l, kv1h, kv1l, q2h, q2l, kv2h, kv2l, o1h, o1l, Pp);

    softmax_reduce2<<<HEADS * MSAW, 256>>>(Pp, p2h, p2l);
    gemm_av2<<<dim3(2, HEADS, MSAH), 128, SM_AV>>>(p2h, p2l, kv2h, kv2l, o2h, o2l);

    gemm_out_fused<<<dim3(2, NTOK / 128), 128, SM_PROJ>>>(
        o1h, o1l, o2h, o2l, wouth, houth, out, wout_b, hout_b);
}

// round 12
// speedup vs baseline: 5.2229x; 1.1661x over previous
#include <cuda_runtime.h>
#include <cuda_fp16.h>
#include <math.h>
#include <cstdint>

#define HEADS 8
#define DH    64
#define INNER 512
#define DIM   256
#define MSAH  128
#define MSAW  256
#define NTOK  (MSAH*MSAW)

typedef __half hf;

// -------- scratch (static device globals; no runtime allocation) --------
__device__ hf g_xh [(size_t)NTOK*DIM],      g_xl [(size_t)NTOK*DIM];
__device__ hf g_wqh [(size_t)DIM*INNER];
__device__ hf g_wkvh[(size_t)DIM*2*INNER];
__device__ hf g_hqh [(size_t)DIM*INNER];
__device__ hf g_hkvh[(size_t)DIM*2*INNER];
__device__ hf g_wouth[(size_t)INNER*DIM];
__device__ hf g_houth[(size_t)INNER*DIM];
__device__ hf g_q1h [(size_t)NTOK*INNER],   g_q1l [(size_t)NTOK*INNER];
__device__ hf g_kv1h[(size_t)NTOK*2*INNER];
__device__ hf g_q2h [(size_t)NTOK*INNER],   g_q2l [(size_t)NTOK*INNER];
__device__ hf g_kv2h[(size_t)NTOK*2*INNER];
__device__ hf g_o1h [(size_t)NTOK*INNER],   g_o1l [(size_t)NTOK*INNER];
__device__ hf g_o2h [(size_t)NTOK*INNER],   g_o2l [(size_t)NTOK*INNER];
__device__ hf g_p2h [(size_t)HEADS*MSAW*MSAW], g_p2l [(size_t)HEADS*MSAW*MSAW];
__device__ float g_Pp [(size_t)32*MSAW*MSAW];

// ===================== helpers =====================
__device__ __forceinline__ uint32_t smem_u32(const void* p) {
    uint32_t a;
    asm("{ .reg .u64 t; cvta.to.shared.u64 t, %1; cvt.u32.u64 %0, t; }" : "=r"(a) : "l"(p));
    return a;
}
__device__ __forceinline__ void ldsm4(uint32_t& r0, uint32_t& r1, uint32_t& r2, uint32_t& r3, uint32_t a) {
    asm volatile("ldmatrix.sync.aligned.m8n8.x4.shared.b16 {%0,%1,%2,%3}, [%4];"
                 : "=r"(r0), "=r"(r1), "=r"(r2), "=r"(r3) : "r"(a));
}
__device__ __forceinline__ void ldsm4t(uint32_t& r0, uint32_t& r1, uint32_t& r2, uint32_t& r3, uint32_t a) {
    asm volatile("ldmatrix.sync.aligned.m8n8.x4.trans.shared.b16 {%0,%1,%2,%3}, [%4];"
                 : "=r"(r0), "=r"(r1), "=r"(r2), "=r"(r3) : "r"(a));
}
__device__ __forceinline__ void mma16816(float* c, const uint32_t* a, const uint32_t* b) {
    asm volatile("mma.sync.aligned.m16n8k16.row.col.f32.f16.f16.f32 "
                 "{%0,%1,%2,%3}, {%4,%5,%6,%7}, {%8,%9}, {%0,%1,%2,%3};"
                 : "+f"(c[0]), "+f"(c[1]), "+f"(c[2]), "+f"(c[3])
                 : "r"(a[0]), "r"(a[1]), "r"(a[2]), "r"(a[3]), "r"(b[0]), "r"(b[1]));
}
__device__ __forceinline__ void cpa16(uint32_t dst, const void* src) {
    asm volatile("cp.async.cg.shared.global [%0], [%1], 16;" :: "r"(dst), "l"(src));
}
#define CP_COMMIT() asm volatile("cp.async.commit_group;" ::: "memory")
#define CP_WAIT1()  asm volatile("cp.async.wait_group 1;" ::: "memory")
#define CP_WAIT2()  asm volatile("cp.async.wait_group 2;" ::: "memory")
#define CP_WAIT0()  asm volatile("cp.async.wait_group 0;" ::: "memory")
__device__ __forceinline__ void split_pair(float a, float b, uint32_t& hi, uint32_t& lo) {
    hf ha = __float2half_rn(a), hb = __float2half_rn(b);
    hf la = __float2half_rn(a - __half2float(ha));
    hf lb = __float2half_rn(b - __half2float(hb));
    __half2 h2 = __halves2half2(ha, hb);
    __half2 l2 = __halves2half2(la, lb);
    hi = *(uint32_t*)&h2;
    lo = *(uint32_t*)&l2;
}

// ================= split / convert fp32 -> fp16 planes (one launch) =================
__device__ __forceinline__ void split_one(const float* in, hf* H, hf* L, int i) {
    const float4 v = ((const float4*)in)[i];
    uint32_t h0, l0, h1, l1;
    split_pair(v.x, v.y, h0, l0);
    split_pair(v.z, v.w, h1, l1);
    *(uint2*)(H + (size_t)i * 4) = make_uint2(h0, h1);
    *(uint2*)(L + (size_t)i * 4) = make_uint2(l0, l1);
}
__device__ __forceinline__ void conv_one(const float* in, hf* H, int i) {
    const float4 v = ((const float4*)in)[i];
    __half2 a = __halves2half2(__float2half_rn(v.x), __float2half_rn(v.y));
    __half2 b = __halves2half2(__float2half_rn(v.z), __float2half_rn(v.w));
    *(uint2*)(H + (size_t)i * 4) = make_uint2(*(uint32_t*)&a, *(uint32_t*)&b);
}
__global__ __launch_bounds__(256)
void split_all(const float* x, const float* wq, const float* wkv, const float* hq,
               const float* hkv, const float* wo, const float* ho,
               hf* xh, hf* xl,
               hf* wqh, hf* wkvh, hf* hqh, hf* hkvh, hf* woh, hf* hoh)
{
    const int b = blockIdx.x;
    if (b < 8192) {
        split_one(x, xh, xl, b * 256 + threadIdx.x);
        return;
    }
    const int i = (b - 8192) * 256 + threadIdx.x;
    if (i < 32768)        conv_one(wq,  wqh,  i);
    else if (i < 98304)   conv_one(wkv, wkvh, i - 32768);
    else if (i < 131072)  conv_one(hq,  hqh,  i - 98304);
    else if (i < 196608)  conv_one(hkv, hkvh, i - 131072);
    else if (i < 229376)  conv_one(wo,  woh,  i - 196608);
    else                  conv_one(ho,  hoh,  i - 229376);
}

// ======== big-tile GEMM core: 128x128 block, 4 warps, warp tile 64x64, CH=32, 3-stage ========
// A split (hi/lo), B SINGLE fp16 plane -> 2 products per accumulator.
// OSPLIT=0: fp32 out. OSPLIT=1: split out; store_lo selects whether low plane is written.
template<int OSPLIT, int DUAL>
__device__ __forceinline__ void gemm_core6(
    const hf* __restrict__ Ah_, const hf* __restrict__ Al_, size_t sAr,
    const hf* __restrict__ Bh_, size_t sBr,
    const hf* __restrict__ Ah2_, const hf* __restrict__ Al2_,
    const hf* __restrict__ Bh2_, int K1,
    float* __restrict__ Cf, hf* __restrict__ Chp, hf* __restrict__ Clp,
    int ldc, int K, const float* __restrict__ bias, const float* __restrict__ bias2,
    int store_lo)
{
    constexpr int CH = 32, NSTG = 3;
    constexpr int AP = 40;
    constexpr int BP = 136;
    constexpr int AH = 128 * AP;
    constexpr int BH = CH * BP;
    constexpr int STAGE = 2 * AH + BH;

    extern __shared__ hf smn[];
    const int tid = threadIdx.x, warp = tid >> 5, lane = tid & 31;
    const int wm = warp >> 1, wn = warp & 1;

    float c[4][8][4];
#pragma unroll
    for (int mt = 0; mt < 4; mt++)
#pragma unroll
        for (int nt = 0; nt < 8; nt++)
#pragma unroll
            for (int e = 0; e < 4; e++) c[mt][nt][e] = 0.f;

    auto issue = [&](int cc) {
        const int s = cc % NSTG;
        hf* Ah = smn + (size_t)s * STAGE;
        hf* Al = Ah + AH;
        hf* Bh = Ah + 2 * AH;
        int k0 = cc * CH;
        const hf *Ap = Ah_, *Alp = Al_, *Bp = Bh_;
        if (DUAL && k0 >= K1) { Ap = Ah2_; Alp = Al2_; Bp = Bh2_; k0 -= K1; }
#pragma unroll
        for (int i = 0; i < 4; i++) {
            const int idx = i * 128 + tid;
            const int row = idx >> 2, g = (idx & 3) * 8;
            const size_t go = (size_t)row * sAr + k0 + g;
            const int off = row * AP + g;
            cpa16(smem_u32(Ah + off), Ap + go);
            cpa16(smem_u32(Al + off), Alp + go);
        }
#pragma unroll
        for (int i = 0; i < 4; i++) {
            const int idx = i * 128 + tid;
            const int kr = idx >> 4, q = (idx & 15) * 8;
            const size_t go = (size_t)(k0 + kr) * sBr + q;
            const int off = kr * BP + q;
            cpa16(smem_u32(Bh + off), Bp + go);
        }
    };

    auto compute = [&](int s) {
        hf* Ah = smn + (size_t)s * STAGE;
        hf* Al = Ah + AH;
        hf* Bh = Ah + 2 * AH;
#pragma unroll
        for (int h = 0; h < 2; h++) {
            uint32_t ah[4][4], al[4][4];
#pragma unroll
            for (int mt = 0; mt < 4; mt++) {
                const int row = wm * 64 + mt * 16 + (lane & 15);
                const int ko = h * 16 + ((lane >> 4) & 1) * 8;
                ldsm4(ah[mt][0], ah[mt][1], ah[mt][2], ah[mt][3], smem_u32(Ah + row * AP + ko));
                ldsm4(al[mt][0], al[mt][1], al[mt][2], al[mt][3], smem_u32(Al + row * AP + ko));
            }
#pragma unroll
            for (int bg = 0; bg < 2; bg++) {
                uint32_t bh[4][2];
#pragma unroll
                for (int np = 0; np < 2; np++) {
                    const int k = h * 16 + (lane & 7) + ((lane >> 3) & 1) * 8;
                    const int col = wn * 64 + bg * 32 + np * 16 + ((lane >> 4) & 1) * 8;
                    ldsm4t(bh[2*np][0], bh[2*np][1], bh[2*np+1][0], bh[2*np+1][1],
                           smem_u32(Bh + k * BP + col));
                }
#pragma unroll
                for (int mt = 0; mt < 4; mt++)
#pragma unroll
                    for (int t = 0; t < 4; t++)
                        mma16816(c[mt][bg * 4 + t], ah[mt], bh[t]);
#pragma unroll
                for (int mt = 0; mt < 4; mt++)
#pragma unroll
                    for (int t = 0; t < 4; t++)
                        mma16816(c[mt][bg * 4 + t], al[mt], bh[t]);
            }
        }
    };

    const int NC = K / CH;
    issue(0); CP_COMMIT();
    issue(1); CP_COMMIT();
    for (int cc = 0; cc < NC; cc++) {
        CP_WAIT1();
        __syncthreads();
        if (cc + 2 < NC) issue(cc + 2);
        CP_COMMIT();
        compute(cc % NSTG);
    }

    const int g = lane >> 2, tg = lane & 3;
#pragma unroll
    for (int mt = 0; mt < 4; mt++) {
#pragma unroll
        for (int nt = 0; nt < 8; nt++) {
            const int row0 = wm * 64 + mt * 16 + g;
            const int col = wn * 64 + nt * 8 + tg * 2;
            float2 v0 = make_float2(c[mt][nt][0], c[mt][nt][1]);
            float2 v1 = make_float2(c[mt][nt][2], c[mt][nt][3]);
            if (OSPLIT) {
                uint32_t h0, l0, h1, l1;
                split_pair(v0.x, v0.y, h0, l0);
                split_pair(v1.x, v1.y, h1, l1);
                *(uint32_t*)(Chp + (size_t)row0 * ldc + col) = h0;
                *(uint32_t*)(Chp + (size_t)(row0 + 8) * ldc + col) = h1;
                if (store_lo) {
                    *(uint32_t*)(Clp + (size_t)row0 * ldc + col) = l0;
                    *(uint32_t*)(Clp + (size_t)(row0 + 8) * ldc + col) = l1;
                }
            } else {
                float b0 = 0.f, b1 = 0.f;
                if (bias)  { b0 += bias[col];  b1 += bias[col + 1]; }
                if (bias2) { b0 += bias2[col]; b1 += bias2[col + 1]; }
                v0.x += b0; v0.y += b1; v1.x += b0; v1.y += b1;
                *(float2*)(Cf + (size_t)row0 * ldc + col) = v0;
                *(float2*)(Cf + (size_t)(row0 + 8) * ldc + col) = v1;
            }
        }
    }
}

// ======== 2-product split GEMM (64x32 warp tile), B single plane ========
template<int WM, int WN, int BT, int OSPLIT, int CH, int NSTG>
__device__ __forceinline__ void gemm_core5(
    const hf* __restrict__ Ah_, const hf* __restrict__ Al_, size_t sAr, size_t sAk,
    const hf* __restrict__ Bh_, size_t sBr, size_t sBk,
    float* __restrict__ Cf, hf* __restrict__ Chp, hf* __restrict__ Clp,
    int ldc, int K)
{
    constexpr int TM = WM * 64, TN = WN * 32;
    constexpr int THREADS = WM * WN * 32;
    constexpr int AP = CH + 8;
    constexpr int BP = BT ? (TN + 8) : (CH + 8);
    constexpr int AH = TM * AP;
    constexpr int BH = BT ? CH * BP : TN * AP;
    constexpr int STAGE = 2 * AH + BH;
    constexpr int C8 = CH / 8;
    constexpr int NA = TM * C8 / THREADS;
    constexpr int NB = BT ? (CH * TN / 8) / THREADS : (TN * C8) / THREADS;

    extern __shared__ hf smn[];
    const int tid = threadIdx.x, warp = tid >> 5, lane = tid & 31;
    const int wm = warp / WN, wn = warp % WN;

    float c[4][4][4];
#pragma unroll
    for (int mt = 0; mt < 4; mt++)
#pragma unroll
        for (int nt = 0; nt < 4; nt++)
#pragma unroll
            for (int e = 0; e < 4; e++) c[mt][nt][e] = 0.f;

    auto issue = [&](int cc) {
        const int s = cc % NSTG;
        hf* Ah = smn + (size_t)s * STAGE;
        hf* Al = Ah + AH;
        hf* Bh = Ah + 2 * AH;
        int k0 = cc * CH;
        const size_t cb = (size_t)(k0 >> 6) * sAk + (k0 & 63);
#pragma unroll
        for (int i = 0; i < NA; i++) {
            const int idx = i * THREADS + tid;
            const int row = idx / C8, g = (idx % C8) * 8;
            const size_t go = (size_t)row * sAr + cb + g;
            const int off = row * AP + g;
            cpa16(smem_u32(Ah + off), Ah_ + go);
            cpa16(smem_u32(Al + off), Al_ + go);
        }
#pragma unroll
        for (int i = 0; i < NB; i++) {
            const int idx = i * THREADS + tid;
            size_t go; int off;
            if (BT) {
                const int kr = idx / (TN / 8), q = idx % (TN / 8);
                go = (size_t)(k0 + kr) * sBr + q * 8;
                off = kr * BP + q * 8;
            } else {
                const int nr = idx / C8, g = (idx % C8) * 8;
                go = (size_t)nr * sBr + (size_t)(k0 >> 6) * sBk + (k0 & 63) + g;
                off = nr * AP + g;
            }
            cpa16(smem_u32(Bh + off), Bh_ + go);
        }
    };

    auto compute = [&](int s) {
        hf* Ah = smn + (size_t)s * STAGE;
        hf* Al = Ah + AH;
        hf* Bh = Ah + 2 * AH;
#pragma unroll
        for (int h = 0; h < CH / 16; h++) {
            uint32_t ah[4][4], al[4][4], bh[4][2];
#pragma unroll
            for (int mt = 0; mt < 4; mt++) {
                const int row = wm * 64 + mt * 16 + (lane & 15);
                const int ko = h * 16 + ((lane >> 4) & 1) * 8;
                ldsm4(ah[mt][0], ah[mt][1], ah[mt][2], ah[mt][3], smem_u32(Ah + row * AP + ko));
                ldsm4(al[mt][0], al[mt][1], al[mt][2], al[mt][3], smem_u32(Al + row * AP + ko));
            }
#pragma unroll
            for (int np = 0; np < 2; np++) {
                if (BT) {
                    const int k = h * 16 + (lane & 7) + ((lane >> 3) & 1) * 8;
                    const int col = wn * 32 + np * 16 + ((lane >> 4) & 1) * 8;
                    ldsm4t(bh[2*np][0], bh[2*np][1], bh[2*np+1][0], bh[2*np+1][1],
                           smem_u32(Bh + k * BP + col));
                } else {
                    const int nrow = wn * 32 + np * 16 + (lane & 7) + ((lane >> 4) & 1) * 8;
                    const int ko = h * 16 + ((lane >> 3) & 1) * 8;
                    ldsm4(bh[2*np][0], bh[2*np][1], bh[2*np+1][0], bh[2*np+1][1],
                          smem_u32(Bh + nrow * AP + ko));
                }
            }
#pragma unroll
            for (int mt = 0; mt < 4; mt++)
#pragma unroll
                for (int nt = 0; nt < 4; nt++)
                    mma16816(c[mt][nt], ah[mt], bh[nt]);
#pragma unroll
            for (int mt = 0; mt < 4; mt++)
#pragma unroll
                for (int nt = 0; nt < 4; nt++)
                    mma16816(c[mt][nt], al[mt], bh[nt]);
        }
    };

    const int NC = K / CH;
#pragma unroll
    for (int p = 0; p < NSTG - 1; p++) { issue(p); CP_COMMIT(); }
    for (int cc = 0; cc < NC; cc++) {
        if constexpr (NSTG == 3) CP_WAIT1(); else CP_WAIT2();
        __syncthreads();
        if (cc + NSTG - 1 < NC) issue(cc + NSTG - 1);
        CP_COMMIT();
        compute(cc % NSTG);
    }

    const int g = lane >> 2, tg = lane & 3;
#pragma unroll
    for (int mt = 0; mt < 4; mt++) {
#pragma unroll
        for (int nt = 0; nt < 4; nt++) {
            const int row0 = wm * 64 + mt * 16 + g;
            const int col = wn * 32 + nt * 8 + tg * 2;
            float2 v0 = make_float2(c[mt][nt][0], c[mt][nt][1]);
            float2 v1 = make_float2(c[mt][nt][2], c[mt][nt][3]);
            if (OSPLIT) {
                uint32_t h0, l0, h1, l1;
                split_pair(v0.x, v0.y, h0, l0);
                split_pair(v1.x, v1.y, h1, l1);
                *(uint32_t*)(Chp + (size_t)row0 * ldc + col) = h0;
                *(uint32_t*)(Clp + (size_t)row0 * ldc + col) = l0;
                *(uint32_t*)(Chp + (size_t)(row0 + 8) * ldc + col) = h1;
                *(uint32_t*)(Clp + (size_t)(row0 + 8) * ldc + col) = l1;
            } else {
                *(float2*)(Cf + (size_t)row0 * ldc + col) = v0;
                *(float2*)(Cf + (size_t)(row0 + 8) * ldc + col) = v1;
            }
        }
    }
}

// ---- wrappers ----
__global__ __launch_bounds__(128, 2)
void gemm_proj_all(const hf* __restrict__ xh, const hf* __restrict__ xl,
                   const hf* __restrict__ wqh, const hf* __restrict__ wkvh,
                   const hf* __restrict__ hqh, const hf* __restrict__ hkvh,
                   hf* __restrict__ q1h, hf* __restrict__ q1l,
                   hf* __restrict__ kv1h,
                   hf* __restrict__ q2h, hf* __restrict__ q2l,
                   hf* __restrict__ kv2h)
{
    const int m0 = blockIdx.y * 128;
    const int n0 = blockIdx.x * 128;
    const int fam = blockIdx.z;
    const hf* Bh;
    hf *Ch, *Cl;
    int ldc, store_lo;
    if (n0 < INNER) {
        Bh = (fam ? hqh : wqh) + n0;
        Ch = (fam ? q2h : q1h) + (size_t)m0 * INNER + n0;
        Cl = (fam ? q2l : q1l) + (size_t)m0 * INNER + n0;
        ldc = INNER;
        store_lo = 1;
    } else {
        const int nn = n0 - INNER;
        Bh = (fam ? hkvh : wkvh) + nn;
        Ch = (fam ? kv2h : kv1h) + (size_t)m0 * 2 * INNER + nn;
        Cl = nullptr;
        ldc = 2 * INNER;
        store_lo = 0;
    }
    const int Nw = (n0 < INNER) ? INNER : 2 * INNER;
    gemm_core6<1, 0>(xh + (size_t)m0 * DIM, xl + (size_t)m0 * DIM, DIM,
                     Bh, Nw,
                     nullptr, nullptr, nullptr, 0,
                     nullptr, Ch, Cl, ldc, DIM, nullptr, nullptr, store_lo);
}

__global__ __launch_bounds__(128, 2)
void gemm_out_fused(const hf* __restrict__ o1h, const hf* __restrict__ o1l,
                    const hf* __restrict__ o2h, const hf* __restrict__ o2l,
                    const hf* __restrict__ wouth, const hf* __restrict__ houth,
                    float* __restrict__ C, const float* __restrict__ wout_b,
                    const float* __restrict__ hout_b)
{
    const int m0 = blockIdx.y * 128, n0 = blockIdx.x * 128;
    gemm_core6<0, 1>(o1h + (size_t)m0 * INNER, o1l + (size_t)m0 * INNER, INNER,
                     wouth + n0, DIM,
                     o2h + (size_t)m0 * INNER, o2l + (size_t)m0 * INNER,
                     houth + n0, INNER,
                     C + (size_t)m0 * DIM + n0, nullptr, nullptr,
                     DIM, 2 * INNER, wout_b + n0, hout_b + n0, 0);
}

__global__ __launch_bounds__(128, 3)
void gemm_av2(const hf* __restrict__ Ph, const hf* __restrict__ Pl,
              const hf* __restrict__ Vh,
              hf* __restrict__ Oh, hf* __restrict__ Ol)
{
    const int i0 = blockIdx.x * 128;
    const int h = blockIdx.y, r = blockIdx.z;
    const size_t aoff = (size_t)h * (MSAW * MSAW) + (size_t)i0 * MSAW;
    const size_t boff = (size_t)INNER + (size_t)h * 64 + (size_t)r * MSAW * 2 * INNER;
    const size_t coff = ((size_t)r * MSAW + i0) * INNER + h * 64;
    gemm_core5<2, 2, 1, 1, 16, 4>(Ph + aoff, Pl + aoff, MSAW, 64,
                                  Vh + boff, 2 * INNER, 0,
                                  nullptr, Oh + coff, Ol + coff, INNER, MSAW);
}

// smem bytes
#define SM_PROJ (3 * (2 * 128 * 40 + 32 * 136) * 2)
#define SM_AV   (4 * (2 * 128 * 24 + 16 * 72) * 2)
#define SM_DOTS (4 * (2 * 128 * 24 + 128 * 24) * 2)
#define COL_SMEM2 (4 * 128 * 72 * 2)
#define ATTN_SMEM (SM_DOTS > COL_SMEM2 ? SM_DOTS : COL_SMEM2)

// ================= column attention body (2-product, K/V single plane) =================
__device__ __forceinline__
void col_attn_body(int wi, int head,
                   const hf* __restrict__ qh, const hf* __restrict__ ql,
                   const hf* __restrict__ kvh,
                   hf* __restrict__ oh, hf* __restrict__ ol)
{
    extern __shared__ hf smc[];
    const int PL = 128 * 72;
    hf *sqh = smc,          *sql = smc + PL;
    hf *skh = smc + 2 * PL, *svh = smc + 3 * PL;

    const int tid = threadIdx.x, warp = tid >> 5, lane = tid & 31;

#pragma unroll
    for (int i = 0; i < 4; i++) {
        const int idx = i * 256 + tid;
        const int row = idx >> 3, g = (idx & 7) * 8;
        const size_t gq = ((size_t)(row * MSAW + wi)) * INNER + head * 64 + g;
        const size_t gk = ((size_t)(row * MSAW + wi)) * 2 * INNER + head * 64 + g;
        cpa16(smem_u32(sqh + row * 72 + g), qh + gq);
        cpa16(smem_u32(sql + row * 72 + g), ql + gq);
        cpa16(smem_u32(skh + row * 72 + g), kvh + gk);
        cpa16(smem_u32(svh + row * 72 + g), kvh + gk + INNER);
    }
    CP_COMMIT();
    CP_WAIT0();
    __syncthreads();

    const int m0 = warp * 16;
    float s[16][4];
#pragma unroll
    for (int nt = 0; nt < 16; nt++)
#pragma unroll
        for (int e = 0; e < 4; e++) s[nt][e] = 0.f;

#pragma unroll
    for (int kc = 0; kc < 4; kc++) {
        uint32_t ah[4], al[4];
        const int arow = m0 + (lane & 15);
        const int acol = kc * 16 + ((lane >> 4) & 1) * 8;
        ldsm4(ah[0], ah[1], ah[2], ah[3], smem_u32(sqh + arow * 72 + acol));
        ldsm4(al[0], al[1], al[2], al[3], smem_u32(sql + arow * 72 + acol));
#pragma unroll
        for (int ng = 0; ng < 4; ng++) {
            uint32_t bh[4][2];
#pragma unroll
            for (int npp = 0; npp < 2; npp++) {
                const int nt0 = ng * 4 + npp * 2;
                const int brow = nt0 * 8 + (lane & 7) + ((lane >> 4) & 1) * 8;
                const int bcol = kc * 16 + ((lane >> 3) & 1) * 8;
                ldsm4(bh[npp*2][0], bh[npp*2][1], bh[npp*2+1][0], bh[npp*2+1][1],
                      smem_u32(skh + brow * 72 + bcol));
            }
#pragma unroll
            for (int t = 0; t < 4; t++) mma16816(s[ng * 4 + t], ah, bh[t]);
#pragma unroll
            for (int t = 0; t < 4; t++) mma16816(s[ng * 4 + t], al, bh[t]);
        }
    }

    const float sc = 0.125f;
    float mx0 = -1e30f, mx1 = -1e30f;
#pragma unroll
    for (int nt = 0; nt < 16; nt++) {
        mx0 = fmaxf(mx0, fmaxf(s[nt][0], s[nt][1]));
        mx1 = fmaxf(mx1, fmaxf(s[nt][2], s[nt][3]));
    }
    mx0 = fmaxf(mx0, __shfl_xor_sync(0xffffffffu, mx0, 1));
    mx0 = fmaxf(mx0, __shfl_xor_sync(0xffffffffu, mx0, 2));
    mx1 = fmaxf(mx1, __shfl_xor_sync(0xffffffffu, mx1, 1));
    mx1 = fmaxf(mx1, __shfl_xor_sync(0xffffffffu, mx1, 2));
    float sum0 = 0.f, sum1 = 0.f;
#pragma unroll
    for (int nt = 0; nt < 16; nt++) {
        s[nt][0] = __expf(sc * (s[nt][0] - mx0)); sum0 += s[nt][0];
        s[nt][1] = __expf(sc * (s[nt][1] - mx0)); sum0 += s[nt][1];
        s[nt][2] = __expf(sc * (s[nt][2] - mx1)); sum1 += s[nt][2];
        s[nt][3] = __expf(sc * (s[nt][3] - mx1)); sum1 += s[nt][3];
    }
    sum0 += __shfl_xor_sync(0xffffffffu, sum0, 1);
    sum0 += __shfl_xor_sync(0xffffffffu, sum0, 2);
    sum1 += __shfl_xor_sync(0xffffffffu, sum1, 1);
    sum1 += __shfl_xor_sync(0xffffffffu, sum1, 2);
    const float inv0 = 1.f / sum0, inv1 = 1.f / sum1;
#pragma unroll
    for (int nt = 0; nt < 16; nt++) {
        s[nt][0] *= inv0; s[nt][1] *= inv0;
        s[nt][2] *= inv1; s[nt][3] *= inv1;
    }

    float o[8][4];
#pragma unroll
    for (int dt = 0; dt < 8; dt++)
#pragma unroll
        for (int e = 0; e < 4; e++) o[dt][e] = 0.f;

#pragma unroll
    for (int jc = 0; jc < 8; jc++) {
        uint32_t pah[4], pal[4];
        split_pair(s[2 * jc][0],     s[2 * jc][1],     pah[0], pal[0]);
        split_pair(s[2 * jc][2],     s[2 * jc][3],     pah[1], pal[1]);
        split_pair(s[2 * jc + 1][0], s[2 * jc + 1][1], pah[2], pal[2]);
        split_pair(s[2 * jc + 1][2], s[2 * jc + 1][3], pah[3], pal[3]);
        const int jrow = jc * 16 + (lane & 7) + ((lane >> 3) & 1) * 8;
#pragma unroll
        for (int dg = 0; dg < 2; dg++) {
            uint32_t bh[4][2];
#pragma unroll
            for (int dpp = 0; dpp < 2; dpp++) {
                const int dt0 = dg * 4 + dpp * 2;
                const int dcol = dt0 * 8 + ((lane >> 4) & 1) * 8;
                ldsm4t(bh[dpp*2][0], bh[dpp*2][1], bh[dpp*2+1][0], bh[dpp*2+1][1],
                       smem_u32(svh + jrow * 72 + dcol));
            }
#pragma unroll
            for (int t = 0; t < 4; t++) mma16816(o[dg * 4 + t], pah, bh[t]);
#pragma unroll
            for (int t = 0; t < 4; t++) mma16816(o[dg * 4 + t], pal, bh[t]);
        }
    }

    const int g = lane >> 2, tg = lane & 3;
    const int r0 = m0 + g, r1 = r0 + 8;
#pragma unroll
    for (int dt = 0; dt < 8; dt++) {
        const int d = head * 64 + dt * 8 + tg * 2;
        const size_t b0 = ((size_t)(r0 * MSAW + wi)) * INNER + d;
        const size_t b1 = ((size_t)(r1 * MSAW + wi)) * INNER + d;
        uint32_t h0, l0, h1, l1;
        split_pair(o[dt][0], o[dt][1], h0, l0);
        split_pair(o[dt][2], o[dt][3], h1, l1);
        *(uint32_t*)(oh + b0) = h0;
        *(uint32_t*)(ol + b0) = l0;
        *(uint32_t*)(oh + b1) = h1;
        *(uint32_t*)(ol + b1) = l1;
    }
}

// ============= fused attention: dots tiles (blocks 0..127) + col attn (128..2175) =============
__global__ __launch_bounds__(256, 2)
void attn_fused(const hf* __restrict__ q1h, const hf* __restrict__ q1l,
                const hf* __restrict__ kv1h,
                const hf* __restrict__ q2h, const hf* __restrict__ q2l,
                const hf* __restrict__ kv2h,
                hf* __restrict__ o1h, hf* __restrict__ o1l,
                float* __restrict__ Pp)
{
    const int b = blockIdx.x;
    if (b < 128) {
        const int j0 = (b & 1) * 128, i0 = ((b >> 1) & 1) * 128;
        const int z = b >> 2;
        const int h = z >> 2, s = z & 3;
        const size_t r0 = (size_t)s * 32;
        const size_t aoff = (size_t)h * 64 + (size_t)i0 * INNER + r0 * MSAW * INNER;
        const size_t boff = (size_t)h * 64 + (size_t)j0 * 2 * INNER + r0 * MSAW * 2 * INNER;
        gemm_core5<2, 4, 0, 0, 16, 4>(q2h + aoff, q2l + aoff, INNER, (size_t)MSAW * INNER,
                                      kv2h + boff, 2 * INNER, (size_t)MSAW * 2 * INNER,
                                      Pp + (size_t)z * (MSAW * MSAW) + (size_t)i0 * MSAW + j0,
                                      nullptr, nullptr, MSAW, 32 * 64);
    } else {
        const int cb = b - 128;
        col_attn_body(cb & 255, cb >> 8, q1h, q1l, kv1h, o1h, o1l);
    }
}

// ============= reduce 4 dots partials + scale + softmax -> fp16 hi/lo planes =============
__global__ __launch_bounds__(256)
void softmax_reduce2(const float* __restrict__ Pp, hf* __restrict__ Ph, hf* __restrict__ Pl)
{
    const int h = blockIdx.x >> 8, i = blockIdx.x & 255;
    const int tid = threadIdx.x;
    __shared__ float red[34];
    float v = 0.f;
#pragma unroll
    for (int s = 0; s < 4; s++)
        v += Pp[((size_t)(h * 4 + s) * MSAW + i) * MSAW + tid];
    v *= 0.011048543456039806f;  // (1/8) * 128^-0.5

    float m = v;
#pragma unroll
    for (int o = 16; o; o >>= 1) m = fmaxf(m, __shfl_xor_sync(0xffffffffu, m, o));
    if ((tid & 31) == 0) red[tid >> 5] = m;
    __syncthreads();
    if (tid == 0) {
        float mm = red[0];
#pragma unroll
        for (int w = 1; w < 8; w++) mm = fmaxf(mm, red[w]);
        red[32] = mm;
    }
    __syncthreads();
    const float e = __expf(v - red[32]);
    float s = e;
#pragma unroll
    for (int o = 16; o; o >>= 1) s += __shfl_xor_sync(0xffffffffu, s, o);
    if ((tid & 31) == 0) red[8 + (tid >> 5)] = s;
    __syncthreads();
    if (tid == 0) {
        float ss = 0.f;
#pragma unroll
        for (int w = 0; w < 8; w++) ss += red[8 + w];
        red[33] = 1.f / ss;
    }
    __syncthreads();
    const float p = e * red[33];
    const hf hp = __float2half_rn(p);
    const hf lp = __float2half_rn(p - __half2float(hp));
    const size_t off = ((size_t)h * MSAW + i) * MSAW + tid;
    Ph[off] = hp;
    Pl[off] = lp;
}

// =============================== launch ===============================
extern "C" void kernel_launch(void* const* d_in, const int* in_sizes, int n_in,
                              void* d_out, int out_size)
{
    const float* x      = (const float*)d_in[0];
    const float* wq_w   = (const float*)d_in[1];
    const float* wkv_w  = (const float*)d_in[2];
    const float* wout_w = (const float*)d_in[3];
    const float* wout_b = (const float*)d_in[4];
    const float* hq_w   = (const float*)d_in[5];
    const float* hkv_w  = (const float*)d_in[6];
    const float* hout_w = (const float*)d_in[7];
    const float* hout_b = (const float*)d_in[8];
    float* out = (float*)d_out;

    void* p;
    hf *xh, *xl, *wqh, *wkvh, *hqh, *hkvh, *wouth, *houth;
    hf *q1h, *q1l, *kv1h, *q2h, *q2l, *kv2h;
    hf *o1h, *o1l, *o2h, *o2l, *p2h, *p2l;
    float* Pp;
    cudaGetSymbolAddress(&p, g_xh);    xh = (hf*)p;
    cudaGetSymbolAddress(&p, g_xl);    xl = (hf*)p;
    cudaGetSymbolAddress(&p, g_wqh);   wqh = (hf*)p;
    cudaGetSymbolAddress(&p, g_wkvh);  wkvh = (hf*)p;
    cudaGetSymbolAddress(&p, g_hqh);   hqh = (hf*)p;
    cudaGetSymbolAddress(&p, g_hkvh);  hkvh = (hf*)p;
    cudaGetSymbolAddress(&p, g_wouth); wouth = (hf*)p;
    cudaGetSymbolAddress(&p, g_houth); houth = (hf*)p;
    cudaGetSymbolAddress(&p, g_q1h);   q1h = (hf*)p;
    cudaGetSymbolAddress(&p, g_q1l);   q1l = (hf*)p;
    cudaGetSymbolAddress(&p, g_kv1h);  kv1h = (hf*)p;
    cudaGetSymbolAddress(&p, g_q2h);   q2h = (hf*)p;
    cudaGetSymbolAddress(&p, g_q2l);   q2l = (hf*)p;
    cudaGetSymbolAddress(&p, g_kv2h);  kv2h = (hf*)p;
    cudaGetSymbolAddress(&p, g_o1h);   o1h = (hf*)p;
    cudaGetSymbolAddress(&p, g_o1l);   o1l = (hf*)p;
    cudaGetSymbolAddress(&p, g_o2h);   o2h = (hf*)p;
    cudaGetSymbolAddress(&p, g_o2l);   o2l = (hf*)p;
    cudaGetSymbolAddress(&p, g_p2h);   p2h = (hf*)p;
    cudaGetSymbolAddress(&p, g_p2l);   p2l = (hf*)p;
    cudaGetSymbolAddress(&p, g_Pp);    Pp = (float*)p;

    cudaFuncSetAttribute(gemm_proj_all,  cudaFuncAttributeMaxDynamicSharedMemorySize, SM_PROJ);
    cudaFuncSetAttribute(gemm_out_fused, cudaFuncAttributeMaxDynamicSharedMemorySize, SM_PROJ);
    cudaFuncSetAttribute(gemm_av2,       cudaFuncAttributeMaxDynamicSharedMemorySize, SM_AV);
    cudaFuncSetAttribute(attn_fused,     cudaFuncAttributeMaxDynamicSharedMemorySize, ATTN_SMEM);

    split_all<<<8192 + 1024, 256>>>(x, wq_w, wkv_w, hq_w, hkv_w, wout_w, hout_w,
                                    xh, xl, wqh, wkvh, hqh, hkvh, wouth, houth);

    gemm_proj_all<<<dim3(12, NTOK / 128, 2), 128, SM_PROJ>>>(
        xh, xl, wqh, wkvh, hqh, hkvh,
        q1h, q1l, kv1h, q2h, q2l, kv2h);

    attn_fused<<<128 + MSAW * HEADS, 256, ATTN_SMEM>>>(
        q1h, q1l, kv1h, q2h, q2l, kv2h, o1h, o1l, Pp);

    softmax_reduce2<<<HEADS * MSAW, 256>>>(Pp, p2h, p2l);
    gemm_av2<<<dim3(2, HEADS, MSAH), 128, SM_AV>>>(p2h, p2l, kv2h, o2h, o2l);

    gemm_out_fused<<<dim3(2, NTOK / 128), 128, SM_PROJ>>>(
        o1h, o1l, o2h, o2l, wouth, houth, out, wout_b, hout_b);
}

// round 13
// speedup vs baseline: 6.9832x; 1.3370x over previous
#include <cuda_runtime.h>
#include <cuda_fp16.h>
#include <math.h>
#include <cstdint>

#define HEADS 8
#define DH    64
#define INNER 512
#define DIM   256
#define MSAH  128
#define MSAW  256
#define NTOK  (MSAH*MSAW)

typedef __half hf;

// -------- scratch (static device globals; no runtime allocation) --------
__device__ hf g_xh [(size_t)NTOK*DIM];
__device__ hf g_wqh [(size_t)DIM*INNER];
__device__ hf g_wkvh[(size_t)DIM*2*INNER];
__device__ hf g_hqh [(size_t)DIM*INNER];
__device__ hf g_hkvh[(size_t)DIM*2*INNER];
__device__ hf g_wouth[(size_t)INNER*DIM];
__device__ hf g_houth[(size_t)INNER*DIM];
__device__ hf g_q1h [(size_t)NTOK*INNER],   g_q1l [(size_t)NTOK*INNER];
__device__ hf g_kv1h[(size_t)NTOK*2*INNER];
__device__ hf g_q2h [(size_t)NTOK*INNER],   g_q2l [(size_t)NTOK*INNER];
__device__ hf g_kv2h[(size_t)NTOK*2*INNER];
__device__ hf g_o1h [(size_t)NTOK*INNER];
__device__ hf g_o2h [(size_t)NTOK*INNER];
__device__ hf g_p2h [(size_t)HEADS*MSAW*MSAW], g_p2l [(size_t)HEADS*MSAW*MSAW];
__device__ float g_Pp [(size_t)32*MSAW*MSAW];

// ===================== helpers =====================
__device__ __forceinline__ uint32_t smem_u32(const void* p) {
    uint32_t a;
    asm("{ .reg .u64 t; cvta.to.shared.u64 t, %1; cvt.u32.u64 %0, t; }" : "=r"(a) : "l"(p));
    return a;
}
__device__ __forceinline__ void ldsm4(uint32_t& r0, uint32_t& r1, uint32_t& r2, uint32_t& r3, uint32_t a) {
    asm volatile("ldmatrix.sync.aligned.m8n8.x4.shared.b16 {%0,%1,%2,%3}, [%4];"
                 : "=r"(r0), "=r"(r1), "=r"(r2), "=r"(r3) : "r"(a));
}
__device__ __forceinline__ void ldsm4t(uint32_t& r0, uint32_t& r1, uint32_t& r2, uint32_t& r3, uint32_t a) {
    asm volatile("ldmatrix.sync.aligned.m8n8.x4.trans.shared.b16 {%0,%1,%2,%3}, [%4];"
                 : "=r"(r0), "=r"(r1), "=r"(r2), "=r"(r3) : "r"(a));
}
__device__ __forceinline__ void mma16816(float* c, const uint32_t* a, const uint32_t* b) {
    asm volatile("mma.sync.aligned.m16n8k16.row.col.f32.f16.f16.f32 "
                 "{%0,%1,%2,%3}, {%4,%5,%6,%7}, {%8,%9}, {%0,%1,%2,%3};"
                 : "+f"(c[0]), "+f"(c[1]), "+f"(c[2]), "+f"(c[3])
                 : "r"(a[0]), "r"(a[1]), "r"(a[2]), "r"(a[3]), "r"(b[0]), "r"(b[1]));
}
__device__ __forceinline__ void cpa16(uint32_t dst, const void* src) {
    asm volatile("cp.async.cg.shared.global [%0], [%1], 16;" :: "r"(dst), "l"(src));
}
#define CP_COMMIT() asm volatile("cp.async.commit_group;" ::: "memory")
#define CP_WAIT1()  asm volatile("cp.async.wait_group 1;" ::: "memory")
#define CP_WAIT2()  asm volatile("cp.async.wait_group 2;" ::: "memory")
#define CP_WAIT0()  asm volatile("cp.async.wait_group 0;" ::: "memory")
__device__ __forceinline__ void split_pair(float a, float b, uint32_t& hi, uint32_t& lo) {
    hf ha = __float2half_rn(a), hb = __float2half_rn(b);
    hf la = __float2half_rn(a - __half2float(ha));
    hf lb = __float2half_rn(b - __half2float(hb));
    __half2 h2 = __halves2half2(ha, hb);
    __half2 l2 = __halves2half2(la, lb);
    hi = *(uint32_t*)&h2;
    lo = *(uint32_t*)&l2;
}
__device__ __forceinline__ uint32_t pack_h2(float a, float b) {
    __half2 h2 = __halves2half2(__float2half_rn(a), __float2half_rn(b));
    return *(uint32_t*)&h2;
}

// ================= convert fp32 -> fp16 plane(s) (one launch) =================
__device__ __forceinline__ void conv_one(const float* in, hf* H, int i) {
    const float4 v = ((const float4*)in)[i];
    *(uint2*)(H + (size_t)i * 4) = make_uint2(pack_h2(v.x, v.y), pack_h2(v.z, v.w));
}
__global__ __launch_bounds__(256)
void split_all(const float* x, const float* wq, const float* wkv, const float* hq,
               const float* hkv, const float* wo, const float* ho,
               hf* xh, hf* wqh, hf* wkvh, hf* hqh, hf* hkvh, hf* woh, hf* hoh)
{
    const int b = blockIdx.x;
    if (b < 8192) {
        conv_one(x, xh, b * 256 + threadIdx.x);
        return;
    }
    const int i = (b - 8192) * 256 + threadIdx.x;
    if (i < 32768)        conv_one(wq,  wqh,  i);
    else if (i < 98304)   conv_one(wkv, wkvh, i - 32768);
    else if (i < 131072)  conv_one(hq,  hqh,  i - 98304);
    else if (i < 196608)  conv_one(hkv, hkvh, i - 131072);
    else if (i < 229376)  conv_one(wo,  woh,  i - 196608);
    else                  conv_one(ho,  hoh,  i - 229376);
}

// ======== big-tile GEMM core: 128x128 block, 4 warps, warp tile 64x64, CH=32, 3-stage ========
// ASPLIT: A has hi/lo planes (2 products) or single (1 product). B always single plane.
template<int ASPLIT, int OSPLIT, int DUAL>
__device__ __forceinline__ void gemm_core6(
    const hf* __restrict__ Ah_, const hf* __restrict__ Al_, size_t sAr,
    const hf* __restrict__ Bh_, size_t sBr,
    const hf* __restrict__ Ah2_, const hf* __restrict__ Al2_,
    const hf* __restrict__ Bh2_, int K1,
    float* __restrict__ Cf, hf* __restrict__ Chp, hf* __restrict__ Clp,
    int ldc, int K, const float* __restrict__ bias, const float* __restrict__ bias2,
    int store_lo)
{
    constexpr int CH = 32, NSTG = 3;
    constexpr int AP = 40;
    constexpr int BP = 136;
    constexpr int AH = 128 * AP;
    constexpr int BH = CH * BP;
    constexpr int NAP = ASPLIT ? 2 : 1;
    constexpr int STAGE = NAP * AH + BH;

    extern __shared__ hf smn[];
    const int tid = threadIdx.x, warp = tid >> 5, lane = tid & 31;
    const int wm = warp >> 1, wn = warp & 1;

    float c[4][8][4];
#pragma unroll
    for (int mt = 0; mt < 4; mt++)
#pragma unroll
        for (int nt = 0; nt < 8; nt++)
#pragma unroll
            for (int e = 0; e < 4; e++) c[mt][nt][e] = 0.f;

    auto issue = [&](int cc) {
        const int s = cc % NSTG;
        hf* Ah = smn + (size_t)s * STAGE;
        hf* Al = Ah + AH;
        hf* Bh = Ah + NAP * AH;
        int k0 = cc * CH;
        const hf *Ap = Ah_, *Alp = Al_, *Bp = Bh_;
        if (DUAL && k0 >= K1) { Ap = Ah2_; Alp = Al2_; Bp = Bh2_; k0 -= K1; }
#pragma unroll
        for (int i = 0; i < 4; i++) {
            const int idx = i * 128 + tid;
            const int row = idx >> 2, g = (idx & 3) * 8;
            const size_t go = (size_t)row * sAr + k0 + g;
            const int off = row * AP + g;
            cpa16(smem_u32(Ah + off), Ap + go);
            if (ASPLIT) cpa16(smem_u32(Al + off), Alp + go);
        }
#pragma unroll
        for (int i = 0; i < 4; i++) {
            const int idx = i * 128 + tid;
            const int kr = idx >> 4, q = (idx & 15) * 8;
            const size_t go = (size_t)(k0 + kr) * sBr + q;
            const int off = kr * BP + q;
            cpa16(smem_u32(Bh + off), Bp + go);
        }
    };

    auto compute = [&](int s) {
        hf* Ah = smn + (size_t)s * STAGE;
        hf* Al = Ah + AH;
        hf* Bh = Ah + NAP * AH;
#pragma unroll
        for (int h = 0; h < 2; h++) {
            uint32_t ah[4][4], al[4][4];
#pragma unroll
            for (int mt = 0; mt < 4; mt++) {
                const int row = wm * 64 + mt * 16 + (lane & 15);
                const int ko = h * 16 + ((lane >> 4) & 1) * 8;
                ldsm4(ah[mt][0], ah[mt][1], ah[mt][2], ah[mt][3], smem_u32(Ah + row * AP + ko));
                if (ASPLIT)
                    ldsm4(al[mt][0], al[mt][1], al[mt][2], al[mt][3], smem_u32(Al + row * AP + ko));
            }
#pragma unroll
            for (int bg = 0; bg < 2; bg++) {
                uint32_t bh[4][2];
#pragma unroll
                for (int np = 0; np < 2; np++) {
                    const int k = h * 16 + (lane & 7) + ((lane >> 3) & 1) * 8;
                    const int col = wn * 64 + bg * 32 + np * 16 + ((lane >> 4) & 1) * 8;
                    ldsm4t(bh[2*np][0], bh[2*np][1], bh[2*np+1][0], bh[2*np+1][1],
                           smem_u32(Bh + k * BP + col));
                }
#pragma unroll
                for (int mt = 0; mt < 4; mt++)
#pragma unroll
                    for (int t = 0; t < 4; t++)
                        mma16816(c[mt][bg * 4 + t], ah[mt], bh[t]);
                if (ASPLIT) {
#pragma unroll
                    for (int mt = 0; mt < 4; mt++)
#pragma unroll
                        for (int t = 0; t < 4; t++)
                            mma16816(c[mt][bg * 4 + t], al[mt], bh[t]);
                }
            }
        }
    };

    const int NC = K / CH;
    issue(0); CP_COMMIT();
    issue(1); CP_COMMIT();
    for (int cc = 0; cc < NC; cc++) {
        CP_WAIT1();
        __syncthreads();
        if (cc + 2 < NC) issue(cc + 2);
        CP_COMMIT();
        compute(cc % NSTG);
    }

    const int g = lane >> 2, tg = lane & 3;
#pragma unroll
    for (int mt = 0; mt < 4; mt++) {
#pragma unroll
        for (int nt = 0; nt < 8; nt++) {
            const int row0 = wm * 64 + mt * 16 + g;
            const int col = wn * 64 + nt * 8 + tg * 2;
            float2 v0 = make_float2(c[mt][nt][0], c[mt][nt][1]);
            float2 v1 = make_float2(c[mt][nt][2], c[mt][nt][3]);
            if (OSPLIT) {
                uint32_t h0, l0, h1, l1;
                split_pair(v0.x, v0.y, h0, l0);
                split_pair(v1.x, v1.y, h1, l1);
                *(uint32_t*)(Chp + (size_t)row0 * ldc + col) = h0;
                *(uint32_t*)(Chp + (size_t)(row0 + 8) * ldc + col) = h1;
                if (store_lo) {
                    *(uint32_t*)(Clp + (size_t)row0 * ldc + col) = l0;
                    *(uint32_t*)(Clp + (size_t)(row0 + 8) * ldc + col) = l1;
                }
            } else {
                float b0 = 0.f, b1 = 0.f;
                if (bias)  { b0 += bias[col];  b1 += bias[col + 1]; }
                if (bias2) { b0 += bias2[col]; b1 += bias2[col + 1]; }
                v0.x += b0; v0.y += b1; v1.x += b0; v1.y += b1;
                *(float2*)(Cf + (size_t)row0 * ldc + col) = v0;
                *(float2*)(Cf + (size_t)(row0 + 8) * ldc + col) = v1;
            }
        }
    }
}

// ======== 2-product split GEMM (64x32 warp tile), B single plane ========
template<int WM, int WN, int BT, int OSPLIT, int CH, int NSTG>
__device__ __forceinline__ void gemm_core5(
    const hf* __restrict__ Ah_, const hf* __restrict__ Al_, size_t sAr, size_t sAk,
    const hf* __restrict__ Bh_, size_t sBr, size_t sBk,
    float* __restrict__ Cf, hf* __restrict__ Chp, hf* __restrict__ Clp,
    int ldc, int K, int store_lo)
{
    constexpr int TM = WM * 64, TN = WN * 32;
    constexpr int THREADS = WM * WN * 32;
    constexpr int AP = CH + 8;
    constexpr int BP = BT ? (TN + 8) : (CH + 8);
    constexpr int AH = TM * AP;
    constexpr int BH = BT ? CH * BP : TN * AP;
    constexpr int STAGE = 2 * AH + BH;
    constexpr int C8 = CH / 8;
    constexpr int NA = TM * C8 / THREADS;
    constexpr int NB = BT ? (CH * TN / 8) / THREADS : (TN * C8) / THREADS;

    extern __shared__ hf smn[];
    const int tid = threadIdx.x, warp = tid >> 5, lane = tid & 31;
    const int wm = warp / WN, wn = warp % WN;

    float c[4][4][4];
#pragma unroll
    for (int mt = 0; mt < 4; mt++)
#pragma unroll
        for (int nt = 0; nt < 4; nt++)
#pragma unroll
            for (int e = 0; e < 4; e++) c[mt][nt][e] = 0.f;

    auto issue = [&](int cc) {
        const int s = cc % NSTG;
        hf* Ah = smn + (size_t)s * STAGE;
        hf* Al = Ah + AH;
        hf* Bh = Ah + 2 * AH;
        int k0 = cc * CH;
        const size_t cb = (size_t)(k0 >> 6) * sAk + (k0 & 63);
#pragma unroll
        for (int i = 0; i < NA; i++) {
            const int idx = i * THREADS + tid;
            const int row = idx / C8, g = (idx % C8) * 8;
            const size_t go = (size_t)row * sAr + cb + g;
            const int off = row * AP + g;
            cpa16(smem_u32(Ah + off), Ah_ + go);
            cpa16(smem_u32(Al + off), Al_ + go);
        }
#pragma unroll
        for (int i = 0; i < NB; i++) {
            const int idx = i * THREADS + tid;
            size_t go; int off;
            if (BT) {
                const int kr = idx / (TN / 8), q = idx % (TN / 8);
                go = (size_t)(k0 + kr) * sBr + q * 8;
                off = kr * BP + q * 8;
            } else {
                const int nr = idx / C8, g = (idx % C8) * 8;
                go = (size_t)nr * sBr + (size_t)(k0 >> 6) * sBk + (k0 & 63) + g;
                off = nr * AP + g;
            }
            cpa16(smem_u32(Bh + off), Bh_ + go);
        }
    };

    auto compute = [&](int s) {
        hf* Ah = smn + (size_t)s * STAGE;
        hf* Al = Ah + AH;
        hf* Bh = Ah + 2 * AH;
#pragma unroll
        for (int h = 0; h < CH / 16; h++) {
            uint32_t ah[4][4], al[4][4], bh[4][2];
#pragma unroll
            for (int mt = 0; mt < 4; mt++) {
                const int row = wm * 64 + mt * 16 + (lane & 15);
                const int ko = h * 16 + ((lane >> 4) & 1) * 8;
                ldsm4(ah[mt][0], ah[mt][1], ah[mt][2], ah[mt][3], smem_u32(Ah + row * AP + ko));
                ldsm4(al[mt][0], al[mt][1], al[mt][2], al[mt][3], smem_u32(Al + row * AP + ko));
            }
#pragma unroll
            for (int np = 0; np < 2; np++) {
                if (BT) {
                    const int k = h * 16 + (lane & 7) + ((lane >> 3) & 1) * 8;
                    const int col = wn * 32 + np * 16 + ((lane >> 4) & 1) * 8;
                    ldsm4t(bh[2*np][0], bh[2*np][1], bh[2*np+1][0], bh[2*np+1][1],
                           smem_u32(Bh + k * BP + col));
                } else {
                    const int nrow = wn * 32 + np * 16 + (lane & 7) + ((lane >> 4) & 1) * 8;
                    const int ko = h * 16 + ((lane >> 3) & 1) * 8;
                    ldsm4(bh[2*np][0], bh[2*np][1], bh[2*np+1][0], bh[2*np+1][1],
                          smem_u32(Bh + nrow * AP + ko));
                }
            }
#pragma unroll
            for (int mt = 0; mt < 4; mt++)
#pragma unroll
                for (int nt = 0; nt < 4; nt++)
                    mma16816(c[mt][nt], ah[mt], bh[nt]);
#pragma unroll
            for (int mt = 0; mt < 4; mt++)
#pragma unroll
                for (int nt = 0; nt < 4; nt++)
                    mma16816(c[mt][nt], al[mt], bh[nt]);
        }
    };

    const int NC = K / CH;
#pragma unroll
    for (int p = 0; p < NSTG - 1; p++) { issue(p); CP_COMMIT(); }
    for (int cc = 0; cc < NC; cc++) {
        if constexpr (NSTG == 3) CP_WAIT1(); else CP_WAIT2();
        __syncthreads();
        if (cc + NSTG - 1 < NC) issue(cc + NSTG - 1);
        CP_COMMIT();
        compute(cc % NSTG);
    }

    const int g = lane >> 2, tg = lane & 3;
#pragma unroll
    for (int mt = 0; mt < 4; mt++) {
#pragma unroll
        for (int nt = 0; nt < 4; nt++) {
            const int row0 = wm * 64 + mt * 16 + g;
            const int col = wn * 32 + nt * 8 + tg * 2;
            float2 v0 = make_float2(c[mt][nt][0], c[mt][nt][1]);
            float2 v1 = make_float2(c[mt][nt][2], c[mt][nt][3]);
            if (OSPLIT) {
                uint32_t h0, l0, h1, l1;
                split_pair(v0.x, v0.y, h0, l0);
                split_pair(v1.x, v1.y, h1, l1);
                *(uint32_t*)(Chp + (size_t)row0 * ldc + col) = h0;
                *(uint32_t*)(Chp + (size_t)(row0 + 8) * ldc + col) = h1;
                if (store_lo) {
                    *(uint32_t*)(Clp + (size_t)row0 * ldc + col) = l0;
                    *(uint32_t*)(Clp + (size_t)(row0 + 8) * ldc + col) = l1;
                }
            } else {
                *(float2*)(Cf + (size_t)row0 * ldc + col) = v0;
                *(float2*)(Cf + (size_t)(row0 + 8) * ldc + col) = v1;
            }
        }
    }
}

// ---- wrappers ----
__global__ __launch_bounds__(128, 2)
void gemm_proj_all(const hf* __restrict__ xh,
                   const hf* __restrict__ wqh, const hf* __restrict__ wkvh,
                   const hf* __restrict__ hqh, const hf* __restrict__ hkvh,
                   hf* __restrict__ q1h, hf* __restrict__ q1l,
                   hf* __restrict__ kv1h,
                   hf* __restrict__ q2h, hf* __restrict__ q2l,
                   hf* __restrict__ kv2h)
{
    const int m0 = blockIdx.y * 128;
    const int n0 = blockIdx.x * 128;
    const int fam = blockIdx.z;
    const hf* Bh;
    hf *Ch, *Cl;
    int ldc, store_lo;
    if (n0 < INNER) {
        Bh = (fam ? hqh : wqh) + n0;
        Ch = (fam ? q2h : q1h) + (size_t)m0 * INNER + n0;
        Cl = (fam ? q2l : q1l) + (size_t)m0 * INNER + n0;
        ldc = INNER;
        store_lo = 1;
    } else {
        const int nn = n0 - INNER;
        Bh = (fam ? hkvh : wkvh) + nn;
        Ch = (fam ? kv2h : kv1h) + (size_t)m0 * 2 * INNER + nn;
        Cl = nullptr;
        ldc = 2 * INNER;
        store_lo = 0;
    }
    const int Nw = (n0 < INNER) ? INNER : 2 * INNER;
    gemm_core6<0, 1, 0>(xh + (size_t)m0 * DIM, nullptr, DIM,
                        Bh, Nw,
                        nullptr, nullptr, nullptr, 0,
                        nullptr, Ch, Cl, ldc, DIM, nullptr, nullptr, store_lo);
}

__global__ __launch_bounds__(128, 2)
void gemm_out_fused(const hf* __restrict__ o1h, const hf* __restrict__ o2h,
                    const hf* __restrict__ wouth, const hf* __restrict__ houth,
                    float* __restrict__ C, const float* __restrict__ wout_b,
                    const float* __restrict__ hout_b)
{
    const int m0 = blockIdx.y * 128, n0 = blockIdx.x * 128;
    gemm_core6<0, 0, 1>(o1h + (size_t)m0 * INNER, nullptr, INNER,
                        wouth + n0, DIM,
                        o2h + (size_t)m0 * INNER, nullptr,
                        houth + n0, INNER,
                        C + (size_t)m0 * DIM + n0, nullptr, nullptr,
                        DIM, 2 * INNER, wout_b + n0, hout_b + n0, 0);
}

__global__ __launch_bounds__(128, 3)
void gemm_av2(const hf* __restrict__ Ph, const hf* __restrict__ Pl,
              const hf* __restrict__ Vh, hf* __restrict__ Oh)
{
    const int i0 = blockIdx.x * 128;
    const int h = blockIdx.y, r = blockIdx.z;
    const size_t aoff = (size_t)h * (MSAW * MSAW) + (size_t)i0 * MSAW;
    const size_t boff = (size_t)INNER + (size_t)h * 64 + (size_t)r * MSAW * 2 * INNER;
    const size_t coff = ((size_t)r * MSAW + i0) * INNER + h * 64;
    gemm_core5<2, 2, 1, 1, 16, 4>(Ph + aoff, Pl + aoff, MSAW, 64,
                                  Vh + boff, 2 * INNER, 0,
                                  nullptr, Oh + coff, nullptr, INNER, MSAW, 0);
}

// smem bytes
#define SM_PROJ (3 * (128 * 40 + 32 * 136) * 2)
#define SM_AV   (4 * (2 * 128 * 24 + 16 * 72) * 2)
#define SM_DOTS (4 * (2 * 128 * 24 + 128 * 24) * 2)
#define COL_SMEM2 (4 * 128 * 72 * 2)
#define ATTN_SMEM (SM_DOTS > COL_SMEM2 ? SM_DOTS : COL_SMEM2)

// ================= column attention body (2-product, K/V single plane) =================
__device__ __forceinline__
void col_attn_body(int wi, int head,
                   const hf* __restrict__ qh, const hf* __restrict__ ql,
                   const hf* __restrict__ kvh,
                   hf* __restrict__ oh)
{
    extern __shared__ hf smc[];
    const int PL = 128 * 72;
    hf *sqh = smc,          *sql = smc + PL;
    hf *skh = smc + 2 * PL, *svh = smc + 3 * PL;

    const int tid = threadIdx.x, warp = tid >> 5, lane = tid & 31;

#pragma unroll
    for (int i = 0; i < 4; i++) {
        const int idx = i * 256 + tid;
        const int row = idx >> 3, g = (idx & 7) * 8;
        const size_t gq = ((size_t)(row * MSAW + wi)) * INNER + head * 64 + g;
        const size_t gk = ((size_t)(row * MSAW + wi)) * 2 * INNER + head * 64 + g;
        cpa16(smem_u32(sqh + row * 72 + g), qh + gq);
        cpa16(smem_u32(sql + row * 72 + g), ql + gq);
        cpa16(smem_u32(skh + row * 72 + g), kvh + gk);
        cpa16(smem_u32(svh + row * 72 + g), kvh + gk + INNER);
    }
    CP_COMMIT();
    CP_WAIT0();
    __syncthreads();

    const int m0 = warp * 16;
    float s[16][4];
#pragma unroll
    for (int nt = 0; nt < 16; nt++)
#pragma unroll
        for (int e = 0; e < 4; e++) s[nt][e] = 0.f;

#pragma unroll
    for (int kc = 0; kc < 4; kc++) {
        uint32_t ah[4], al[4];
        const int arow = m0 + (lane & 15);
        const int acol = kc * 16 + ((lane >> 4) & 1) * 8;
        ldsm4(ah[0], ah[1], ah[2], ah[3], smem_u32(sqh + arow * 72 + acol));
        ldsm4(al[0], al[1], al[2], al[3], smem_u32(sql + arow * 72 + acol));
#pragma unroll
        for (int ng = 0; ng < 4; ng++) {
            uint32_t bh[4][2];
#pragma unroll
            for (int npp = 0; npp < 2; npp++) {
                const int nt0 = ng * 4 + npp * 2;
                const int brow = nt0 * 8 + (lane & 7) + ((lane >> 4) & 1) * 8;
                const int bcol = kc * 16 + ((lane >> 3) & 1) * 8;
                ldsm4(bh[npp*2][0], bh[npp*2][1], bh[npp*2+1][0], bh[npp*2+1][1],
                      smem_u32(skh + brow * 72 + bcol));
            }
#pragma unroll
            for (int t = 0; t < 4; t++) mma16816(s[ng * 4 + t], ah, bh[t]);
#pragma unroll
            for (int t = 0; t < 4; t++) mma16816(s[ng * 4 + t], al, bh[t]);
        }
    }

    const float sc = 0.125f;
    float mx0 = -1e30f, mx1 = -1e30f;
#pragma unroll
    for (int nt = 0; nt < 16; nt++) {
        mx0 = fmaxf(mx0, fmaxf(s[nt][0], s[nt][1]));
        mx1 = fmaxf(mx1, fmaxf(s[nt][2], s[nt][3]));
    }
    mx0 = fmaxf(mx0, __shfl_xor_sync(0xffffffffu, mx0, 1));
    mx0 = fmaxf(mx0, __shfl_xor_sync(0xffffffffu, mx0, 2));
    mx1 = fmaxf(mx1, __shfl_xor_sync(0xffffffffu, mx1, 1));
    mx1 = fmaxf(mx1, __shfl_xor_sync(0xffffffffu, mx1, 2));
    float sum0 = 0.f, sum1 = 0.f;
#pragma unroll
    for (int nt = 0; nt < 16; nt++) {
        s[nt][0] = __expf(sc * (s[nt][0] - mx0)); sum0 += s[nt][0];
        s[nt][1] = __expf(sc * (s[nt][1] - mx0)); sum0 += s[nt][1];
        s[nt][2] = __expf(sc * (s[nt][2] - mx1)); sum1 += s[nt][2];
        s[nt][3] = __expf(sc * (s[nt][3] - mx1)); sum1 += s[nt][3];
    }
    sum0 += __shfl_xor_sync(0xffffffffu, sum0, 1);
    sum0 += __shfl_xor_sync(0xffffffffu, sum0, 2);
    sum1 += __shfl_xor_sync(0xffffffffu, sum1, 1);
    sum1 += __shfl_xor_sync(0xffffffffu, sum1, 2);
    const float inv0 = 1.f / sum0, inv1 = 1.f / sum1;
#pragma unroll
    for (int nt = 0; nt < 16; nt++) {
        s[nt][0] *= inv0; s[nt][1] *= inv0;
        s[nt][2] *= inv1; s[nt][3] *= inv1;
    }

    float o[8][4];
#pragma unroll
    for (int dt = 0; dt < 8; dt++)
#pragma unroll
        for (int e = 0; e < 4; e++) o[dt][e] = 0.f;

#pragma unroll
    for (int jc = 0; jc < 8; jc++) {
        uint32_t pah[4], pal[4];
        split_pair(s[2 * jc][0],     s[2 * jc][1],     pah[0], pal[0]);
        split_pair(s[2 * jc][2],     s[2 * jc][3],     pah[1], pal[1]);
        split_pair(s[2 * jc + 1][0], s[2 * jc + 1][1], pah[2], pal[2]);
        split_pair(s[2 * jc + 1][2], s[2 * jc + 1][3], pah[3], pal[3]);
        const int jrow = jc * 16 + (lane & 7) + ((lane >> 3) & 1) * 8;
#pragma unroll
        for (int dg = 0; dg < 2; dg++) {
            uint32_t bh[4][2];
#pragma unroll
            for (int dpp = 0; dpp < 2; dpp++) {
                const int dt0 = dg * 4 + dpp * 2;
                const int dcol = dt0 * 8 + ((lane >> 4) & 1) * 8;
                ldsm4t(bh[dpp*2][0], bh[dpp*2][1], bh[dpp*2+1][0], bh[dpp*2+1][1],
                       smem_u32(svh + jrow * 72 + dcol));
            }
#pragma unroll
            for (int t = 0; t < 4; t++) mma16816(o[dg * 4 + t], pah, bh[t]);
#pragma unroll
            for (int t = 0; t < 4; t++) mma16816(o[dg * 4 + t], pal, bh[t]);
        }
    }

    const int g = lane >> 2, tg = lane & 3;
    const int r0 = m0 + g, r1 = r0 + 8;
#pragma unroll
    for (int dt = 0; dt < 8; dt++) {
        const int d = head * 64 + dt * 8 + tg * 2;
        const size_t b0 = ((size_t)(r0 * MSAW + wi)) * INNER + d;
        const size_t b1 = ((size_t)(r1 * MSAW + wi)) * INNER + d;
        *(uint32_t*)(oh + b0) = pack_h2(o[dt][0], o[dt][1]);
        *(uint32_t*)(oh + b1) = pack_h2(o[dt][2], o[dt][3]);
    }
}

// ============= fused attention: dots tiles (blocks 0..127) + col attn (128..2175) =============
__global__ __launch_bounds__(256, 2)
void attn_fused(const hf* __restrict__ q1h, const hf* __restrict__ q1l,
                const hf* __restrict__ kv1h,
                const hf* __restrict__ q2h, const hf* __restrict__ q2l,
                const hf* __restrict__ kv2h,
                hf* __restrict__ o1h,
                float* __restrict__ Pp)
{
    const int b = blockIdx.x;
    if (b < 128) {
        const int j0 = (b & 1) * 128, i0 = ((b >> 1) & 1) * 128;
        const int z = b >> 2;
        const int h = z >> 2, s = z & 3;
        const size_t r0 = (size_t)s * 32;
        const size_t aoff = (size_t)h * 64 + (size_t)i0 * INNER + r0 * MSAW * INNER;
        const size_t boff = (size_t)h * 64 + (size_t)j0 * 2 * INNER + r0 * MSAW * 2 * INNER;
        gemm_core5<2, 4, 0, 0, 16, 4>(q2h + aoff, q2l + aoff, INNER, (size_t)MSAW * INNER,
                                      kv2h + boff, 2 * INNER, (size_t)MSAW * 2 * INNER,
                                      Pp + (size_t)z * (MSAW * MSAW) + (size_t)i0 * MSAW + j0,
                                      nullptr, nullptr, MSAW, 32 * 64, 0);
    } else {
        const int cb = b - 128;
        col_attn_body(cb & 255, cb >> 8, q1h, q1l, kv1h, o1h);
    }
}

// ============= reduce 4 dots partials + scale + softmax -> fp16 hi/lo planes =============
__global__ __launch_bounds__(256)
void softmax_reduce2(const float* __restrict__ Pp, hf* __restrict__ Ph, hf* __restrict__ Pl)
{
    const int h = blockIdx.x >> 8, i = blockIdx.x & 255;
    const int tid = threadIdx.x;
    __shared__ float red[34];
    float v = 0.f;
#pragma unroll
    for (int s = 0; s < 4; s++)
        v += Pp[((size_t)(h * 4 + s) * MSAW + i) * MSAW + tid];
    v *= 0.011048543456039806f;  // (1/8) * 128^-0.5

    float m = v;
#pragma unroll
    for (int o = 16; o; o >>= 1) m = fmaxf(m, __shfl_xor_sync(0xffffffffu, m, o));
    if ((tid & 31) == 0) red[tid >> 5] = m;
    __syncthreads();
    if (tid == 0) {
        float mm = red[0];
#pragma unroll
        for (int w = 1; w < 8; w++) mm = fmaxf(mm, red[w]);
        red[32] = mm;
    }
    __syncthreads();
    const float e = __expf(v - red[32]);
    float s = e;
#pragma unroll
    for (int o = 16; o; o >>= 1) s += __shfl_xor_sync(0xffffffffu, s, o);
    if ((tid & 31) == 0) red[8 + (tid >> 5)] = s;
    __syncthreads();
    if (tid == 0) {
        float ss = 0.f;
#pragma unroll
        for (int w = 0; w < 8; w++) ss += red[8 + w];
        red[33] = 1.f / ss;
    }
    __syncthreads();
    const float p = e * red[33];
    const hf hp = __float2half_rn(p);
    const hf lp = __float2half_rn(p - __half2float(hp));
    const size_t off = ((size_t)h * MSAW + i) * MSAW + tid;
    Ph[off] = hp;
    Pl[off] = lp;
}

// =============================== launch ===============================
extern "C" void kernel_launch(void* const* d_in, const int* in_sizes, int n_in,
                              void* d_out, int out_size)
{
    const float* x      = (const float*)d_in[0];
    const float* wq_w   = (const float*)d_in[1];
    const float* wkv_w  = (const float*)d_in[2];
    const float* wout_w = (const float*)d_in[3];
    const float* wout_b = (const float*)d_in[4];
    const float* hq_w   = (const float*)d_in[5];
    const float* hkv_w  = (const float*)d_in[6];
    const float* hout_w = (const float*)d_in[7];
    const float* hout_b = (const float*)d_in[8];
    float* out = (float*)d_out;

    void* p;
    hf *xh, *wqh, *wkvh, *hqh, *hkvh, *wouth, *houth;
    hf *q1h, *q1l, *kv1h, *q2h, *q2l, *kv2h;
    hf *o1h, *o2h, *p2h, *p2l;
    float* Pp;
    cudaGetSymbolAddress(&p, g_xh);    xh = (hf*)p;
    cudaGetSymbolAddress(&p, g_wqh);   wqh = (hf*)p;
    cudaGetSymbolAddress(&p, g_wkvh);  wkvh = (hf*)p;
    cudaGetSymbolAddress(&p, g_hqh);   hqh = (hf*)p;
    cudaGetSymbolAddress(&p, g_hkvh);  hkvh = (hf*)p;
    cudaGetSymbolAddress(&p, g_wouth); wouth = (hf*)p;
    cudaGetSymbolAddress(&p, g_houth); houth = (hf*)p;
    cudaGetSymbolAddress(&p, g_q1h);   q1h = (hf*)p;
    cudaGetSymbolAddress(&p, g_q1l);   q1l = (hf*)p;
    cudaGetSymbolAddress(&p, g_kv1h);  kv1h = (hf*)p;
    cudaGetSymbolAddress(&p, g_q2h);   q2h = (hf*)p;
    cudaGetSymbolAddress(&p, g_q2l);   q2l = (hf*)p;
    cudaGetSymbolAddress(&p, g_kv2h);  kv2h = (hf*)p;
    cudaGetSymbolAddress(&p, g_o1h);   o1h = (hf*)p;
    cudaGetSymbolAddress(&p, g_o2h);   o2h = (hf*)p;
    cudaGetSymbolAddress(&p, g_p2h);   p2h = (hf*)p;
    cudaGetSymbolAddress(&p, g_p2l);   p2l = (hf*)p;
    cudaGetSymbolAddress(&p, g_Pp);    Pp = (float*)p;

    cudaFuncSetAttribute(gemm_proj_all,  cudaFuncAttributeMaxDynamicSharedMemorySize, SM_PROJ);
    cudaFuncSetAttribute(gemm_out_fused, cudaFuncAttributeMaxDynamicSharedMemorySize, SM_PROJ);
    cudaFuncSetAttribute(gemm_av2,       cudaFuncAttributeMaxDynamicSharedMemorySize, SM_AV);
    cudaFuncSetAttribute(attn_fused,     cudaFuncAttributeMaxDynamicSharedMemorySize, ATTN_SMEM);

    split_all<<<8192 + 1024, 256>>>(x, wq_w, wkv_w, hq_w, hkv_w, wout_w, hout_w,
                                    xh, wqh, wkvh, hqh, hkvh, wouth, houth);

    gemm_proj_all<<<dim3(12, NTOK / 128, 2), 128, SM_PROJ>>>(
        xh, wqh, wkvh, hqh, hkvh,
        q1h, q1l, kv1h, q2h, q2l, kv2h);

    attn_fused<<<128 + MSAW * HEADS, 256, ATTN_SMEM>>>(
        q1h, q1l, kv1h, q2h, q2l, kv2h, o1h, Pp);

    softmax_reduce2<<<HEADS * MSAW, 256>>>(Pp, p2h, p2l);
    gemm_av2<<<dim3(2, HEADS, MSAH), 128, SM_AV>>>(p2h, p2l, kv2h, o2h);

    gemm_out_fused<<<dim3(2, NTOK / 128), 128, SM_PROJ>>>(
        o1h, o2h, wouth, houth, out, wout_b, hout_b);
}

// round 14
// speedup vs baseline: 8.2789x; 1.1855x over previous
#include <cuda_runtime.h>
#include <cuda_fp16.h>
#include <math.h>
#include <cstdint>

#define HEADS 8
#define DH    64
#define INNER 512
#define DIM   256
#define MSAH  128
#define MSAW  256
#define NTOK  (MSAH*MSAW)

typedef __half hf;

// -------- scratch (static device globals; no runtime allocation) --------
__device__ hf g_xh [(size_t)NTOK*DIM];
__device__ hf g_wqh [(size_t)DIM*INNER];
__device__ hf g_wkvh[(size_t)DIM*2*INNER];
__device__ hf g_hqh [(size_t)DIM*INNER];
__device__ hf g_hkvh[(size_t)DIM*2*INNER];
__device__ hf g_wouth[(size_t)INNER*DIM];
__device__ hf g_houth[(size_t)INNER*DIM];
__device__ hf g_q1h [(size_t)NTOK*INNER],   g_q1l [(size_t)NTOK*INNER];
__device__ hf g_kv1h[(size_t)NTOK*2*INNER];
__device__ hf g_q2h [(size_t)NTOK*INNER];
__device__ hf g_kv2h[(size_t)NTOK*2*INNER];
__device__ hf g_o1h [(size_t)NTOK*INNER];
__device__ hf g_o2h [(size_t)NTOK*INNER];
__device__ hf g_p2h [(size_t)HEADS*MSAW*MSAW];
__device__ float g_Pp [(size_t)32*MSAW*MSAW];

// ===================== helpers =====================
__device__ __forceinline__ uint32_t smem_u32(const void* p) {
    uint32_t a;
    asm("{ .reg .u64 t; cvta.to.shared.u64 t, %1; cvt.u32.u64 %0, t; }" : "=r"(a) : "l"(p));
    return a;
}
__device__ __forceinline__ void ldsm4(uint32_t& r0, uint32_t& r1, uint32_t& r2, uint32_t& r3, uint32_t a) {
    asm volatile("ldmatrix.sync.aligned.m8n8.x4.shared.b16 {%0,%1,%2,%3}, [%4];"
                 : "=r"(r0), "=r"(r1), "=r"(r2), "=r"(r3) : "r"(a));
}
__device__ __forceinline__ void ldsm4t(uint32_t& r0, uint32_t& r1, uint32_t& r2, uint32_t& r3, uint32_t a) {
    asm volatile("ldmatrix.sync.aligned.m8n8.x4.trans.shared.b16 {%0,%1,%2,%3}, [%4];"
                 : "=r"(r0), "=r"(r1), "=r"(r2), "=r"(r3) : "r"(a));
}
__device__ __forceinline__ void mma16816(float* c, const uint32_t* a, const uint32_t* b) {
    asm volatile("mma.sync.aligned.m16n8k16.row.col.f32.f16.f16.f32 "
                 "{%0,%1,%2,%3}, {%4,%5,%6,%7}, {%8,%9}, {%0,%1,%2,%3};"
                 : "+f"(c[0]), "+f"(c[1]), "+f"(c[2]), "+f"(c[3])
                 : "r"(a[0]), "r"(a[1]), "r"(a[2]), "r"(a[3]), "r"(b[0]), "r"(b[1]));
}
__device__ __forceinline__ void cpa16(uint32_t dst, const void* src) {
    asm volatile("cp.async.cg.shared.global [%0], [%1], 16;" :: "r"(dst), "l"(src));
}
#define CP_COMMIT() asm volatile("cp.async.commit_group;" ::: "memory")
#define CP_WAIT1()  asm volatile("cp.async.wait_group 1;" ::: "memory")
#define CP_WAIT2()  asm volatile("cp.async.wait_group 2;" ::: "memory")
#define CP_WAIT0()  asm volatile("cp.async.wait_group 0;" ::: "memory")
__device__ __forceinline__ void split_pair(float a, float b, uint32_t& hi, uint32_t& lo) {
    hf ha = __float2half_rn(a), hb = __float2half_rn(b);
    hf la = __float2half_rn(a - __half2float(ha));
    hf lb = __float2half_rn(b - __half2float(hb));
    __half2 h2 = __halves2half2(ha, hb);
    __half2 l2 = __halves2half2(la, lb);
    hi = *(uint32_t*)&h2;
    lo = *(uint32_t*)&l2;
}
__device__ __forceinline__ uint32_t pack_h2(float a, float b) {
    __half2 h2 = __halves2half2(__float2half_rn(a), __float2half_rn(b));
    return *(uint32_t*)&h2;
}

// ================= convert fp32 -> fp16 plane(s) (one launch) =================
__device__ __forceinline__ void conv_one(const float* in, hf* H, int i) {
    const float4 v = ((const float4*)in)[i];
    *(uint2*)(H + (size_t)i * 4) = make_uint2(pack_h2(v.x, v.y), pack_h2(v.z, v.w));
}
__global__ __launch_bounds__(256)
void split_all(const float* x, const float* wq, const float* wkv, const float* hq,
               const float* hkv, const float* wo, const float* ho,
               hf* xh, hf* wqh, hf* wkvh, hf* hqh, hf* hkvh, hf* woh, hf* hoh)
{
    const int b = blockIdx.x;
    if (b < 8192) {
        conv_one(x, xh, b * 256 + threadIdx.x);
        return;
    }
    const int i = (b - 8192) * 256 + threadIdx.x;
    if (i < 32768)        conv_one(wq,  wqh,  i);
    else if (i < 98304)   conv_one(wkv, wkvh, i - 32768);
    else if (i < 131072)  conv_one(hq,  hqh,  i - 98304);
    else if (i < 196608)  conv_one(hkv, hkvh, i - 131072);
    else if (i < 229376)  conv_one(wo,  woh,  i - 196608);
    else                  conv_one(ho,  hoh,  i - 229376);
}

// ======== big-tile GEMM core: 128x128 block, 4 warps, warp tile 64x64, CH=32, 3-stage ========
template<int ASPLIT, int OSPLIT, int DUAL>
__device__ __forceinline__ void gemm_core6(
    const hf* __restrict__ Ah_, const hf* __restrict__ Al_, size_t sAr,
    const hf* __restrict__ Bh_, size_t sBr,
    const hf* __restrict__ Ah2_, const hf* __restrict__ Al2_,
    const hf* __restrict__ Bh2_, int K1,
    float* __restrict__ Cf, hf* __restrict__ Chp, hf* __restrict__ Clp,
    int ldc, int K, const float* __restrict__ bias, const float* __restrict__ bias2,
    int store_lo)
{
    constexpr int CH = 32, NSTG = 3;
    constexpr int AP = 40;
    constexpr int BP = 136;
    constexpr int AH = 128 * AP;
    constexpr int BH = CH * BP;
    constexpr int NAP = ASPLIT ? 2 : 1;
    constexpr int STAGE = NAP * AH + BH;

    extern __shared__ hf smn[];
    const int tid = threadIdx.x, warp = tid >> 5, lane = tid & 31;
    const int wm = warp >> 1, wn = warp & 1;

    float c[4][8][4];
#pragma unroll
    for (int mt = 0; mt < 4; mt++)
#pragma unroll
        for (int nt = 0; nt < 8; nt++)
#pragma unroll
            for (int e = 0; e < 4; e++) c[mt][nt][e] = 0.f;

    auto issue = [&](int cc) {
        const int s = cc % NSTG;
        hf* Ah = smn + (size_t)s * STAGE;
        hf* Al = Ah + AH;
        hf* Bh = Ah + NAP * AH;
        int k0 = cc * CH;
        const hf *Ap = Ah_, *Alp = Al_, *Bp = Bh_;
        if (DUAL && k0 >= K1) { Ap = Ah2_; Alp = Al2_; Bp = Bh2_; k0 -= K1; }
#pragma unroll
        for (int i = 0; i < 4; i++) {
            const int idx = i * 128 + tid;
            const int row = idx >> 2, g = (idx & 3) * 8;
            const size_t go = (size_t)row * sAr + k0 + g;
            const int off = row * AP + g;
            cpa16(smem_u32(Ah + off), Ap + go);
            if (ASPLIT) cpa16(smem_u32(Al + off), Alp + go);
        }
#pragma unroll
        for (int i = 0; i < 4; i++) {
            const int idx = i * 128 + tid;
            const int kr = idx >> 4, q = (idx & 15) * 8;
            const size_t go = (size_t)(k0 + kr) * sBr + q;
            const int off = kr * BP + q;
            cpa16(smem_u32(Bh + off), Bp + go);
        }
    };

    auto compute = [&](int s) {
        hf* Ah = smn + (size_t)s * STAGE;
        hf* Al = Ah + AH;
        hf* Bh = Ah + NAP * AH;
#pragma unroll
        for (int h = 0; h < 2; h++) {
            uint32_t ah[4][4], al[4][4];
#pragma unroll
            for (int mt = 0; mt < 4; mt++) {
                const int row = wm * 64 + mt * 16 + (lane & 15);
                const int ko = h * 16 + ((lane >> 4) & 1) * 8;
                ldsm4(ah[mt][0], ah[mt][1], ah[mt][2], ah[mt][3], smem_u32(Ah + row * AP + ko));
                if (ASPLIT)
                    ldsm4(al[mt][0], al[mt][1], al[mt][2], al[mt][3], smem_u32(Al + row * AP + ko));
            }
#pragma unroll
            for (int bg = 0; bg < 2; bg++) {
                uint32_t bh[4][2];
#pragma unroll
                for (int np = 0; np < 2; np++) {
                    const int k = h * 16 + (lane & 7) + ((lane >> 3) & 1) * 8;
                    const int col = wn * 64 + bg * 32 + np * 16 + ((lane >> 4) & 1) * 8;
                    ldsm4t(bh[2*np][0], bh[2*np][1], bh[2*np+1][0], bh[2*np+1][1],
                           smem_u32(Bh + k * BP + col));
                }
#pragma unroll
                for (int mt = 0; mt < 4; mt++)
#pragma unroll
                    for (int t = 0; t < 4; t++)
                        mma16816(c[mt][bg * 4 + t], ah[mt], bh[t]);
                if (ASPLIT) {
#pragma unroll
                    for (int mt = 0; mt < 4; mt++)
#pragma unroll
                        for (int t = 0; t < 4; t++)
                            mma16816(c[mt][bg * 4 + t], al[mt], bh[t]);
                }
            }
        }
    };

    const int NC = K / CH;
    issue(0); CP_COMMIT();
    issue(1); CP_COMMIT();
    for (int cc = 0; cc < NC; cc++) {
        CP_WAIT1();
        __syncthreads();
        if (cc + 2 < NC) issue(cc + 2);
        CP_COMMIT();
        compute(cc % NSTG);
    }

    const int g = lane >> 2, tg = lane & 3;
#pragma unroll
    for (int mt = 0; mt < 4; mt++) {
#pragma unroll
        for (int nt = 0; nt < 8; nt++) {
            const int row0 = wm * 64 + mt * 16 + g;
            const int col = wn * 64 + nt * 8 + tg * 2;
            float2 v0 = make_float2(c[mt][nt][0], c[mt][nt][1]);
            float2 v1 = make_float2(c[mt][nt][2], c[mt][nt][3]);
            if (OSPLIT) {
                uint32_t h0, l0, h1, l1;
                split_pair(v0.x, v0.y, h0, l0);
                split_pair(v1.x, v1.y, h1, l1);
                *(uint32_t*)(Chp + (size_t)row0 * ldc + col) = h0;
                *(uint32_t*)(Chp + (size_t)(row0 + 8) * ldc + col) = h1;
                if (store_lo) {
                    *(uint32_t*)(Clp + (size_t)row0 * ldc + col) = l0;
                    *(uint32_t*)(Clp + (size_t)(row0 + 8) * ldc + col) = l1;
                }
            } else {
                float b0 = 0.f, b1 = 0.f;
                if (bias)  { b0 += bias[col];  b1 += bias[col + 1]; }
                if (bias2) { b0 += bias2[col]; b1 += bias2[col + 1]; }
                v0.x += b0; v0.y += b1; v1.x += b0; v1.y += b1;
                *(float2*)(Cf + (size_t)row0 * ldc + col) = v0;
                *(float2*)(Cf + (size_t)(row0 + 8) * ldc + col) = v1;
            }
        }
    }
}

// ======== split GEMM (64x32 warp tile), B single plane; ASPLIT selects 1/2 products ========
template<int WM, int WN, int BT, int ASPLIT, int OSPLIT, int CH, int NSTG>
__device__ __forceinline__ void gemm_core5(
    const hf* __restrict__ Ah_, const hf* __restrict__ Al_, size_t sAr, size_t sAk,
    const hf* __restrict__ Bh_, size_t sBr, size_t sBk,
    float* __restrict__ Cf, hf* __restrict__ Chp,
    int ldc, int K)
{
    constexpr int TM = WM * 64, TN = WN * 32;
    constexpr int THREADS = WM * WN * 32;
    constexpr int AP = CH + 8;
    constexpr int BP = BT ? (TN + 8) : (CH + 8);
    constexpr int AH = TM * AP;
    constexpr int BH = BT ? CH * BP : TN * AP;
    constexpr int NAP = ASPLIT ? 2 : 1;
    constexpr int STAGE = NAP * AH + BH;
    constexpr int C8 = CH / 8;
    constexpr int NA = TM * C8 / THREADS;
    constexpr int NB = BT ? (CH * TN / 8) / THREADS : (TN * C8) / THREADS;

    extern __shared__ hf smn[];
    const int tid = threadIdx.x, warp = tid >> 5, lane = tid & 31;
    const int wm = warp / WN, wn = warp % WN;

    float c[4][4][4];
#pragma unroll
    for (int mt = 0; mt < 4; mt++)
#pragma unroll
        for (int nt = 0; nt < 4; nt++)
#pragma unroll
            for (int e = 0; e < 4; e++) c[mt][nt][e] = 0.f;

    auto issue = [&](int cc) {
        const int s = cc % NSTG;
        hf* Ah = smn + (size_t)s * STAGE;
        hf* Al = Ah + AH;
        hf* Bh = Ah + NAP * AH;
        int k0 = cc * CH;
        const size_t cb = (size_t)(k0 >> 6) * sAk + (k0 & 63);
#pragma unroll
        for (int i = 0; i < NA; i++) {
            const int idx = i * THREADS + tid;
            const int row = idx / C8, g = (idx % C8) * 8;
            const size_t go = (size_t)row * sAr + cb + g;
            const int off = row * AP + g;
            cpa16(smem_u32(Ah + off), Ah_ + go);
            if (ASPLIT) cpa16(smem_u32(Al + off), Al_ + go);
        }
#pragma unroll
        for (int i = 0; i < NB; i++) {
            const int idx = i * THREADS + tid;
            size_t go; int off;
            if (BT) {
                const int kr = idx / (TN / 8), q = idx % (TN / 8);
                go = (size_t)(k0 + kr) * sBr + q * 8;
                off = kr * BP + q * 8;
            } else {
                const int nr = idx / C8, g = (idx % C8) * 8;
                go = (size_t)nr * sBr + (size_t)(k0 >> 6) * sBk + (k0 & 63) + g;
                off = nr * AP + g;
            }
            cpa16(smem_u32(Bh + off), Bh_ + go);
        }
    };

    auto compute = [&](int s) {
        hf* Ah = smn + (size_t)s * STAGE;
        hf* Al = Ah + AH;
        hf* Bh = Ah + NAP * AH;
#pragma unroll
        for (int h = 0; h < CH / 16; h++) {
            uint32_t ah[4][4], al[4][4], bh[4][2];
#pragma unroll
            for (int mt = 0; mt < 4; mt++) {
                const int row = wm * 64 + mt * 16 + (lane & 15);
                const int ko = h * 16 + ((lane >> 4) & 1) * 8;
                ldsm4(ah[mt][0], ah[mt][1], ah[mt][2], ah[mt][3], smem_u32(Ah + row * AP + ko));
                if (ASPLIT)
                    ldsm4(al[mt][0], al[mt][1], al[mt][2], al[mt][3], smem_u32(Al + row * AP + ko));
            }
#pragma unroll
            for (int np = 0; np < 2; np++) {
                if (BT) {
                    const int k = h * 16 + (lane & 7) + ((lane >> 3) & 1) * 8;
                    const int col = wn * 32 + np * 16 + ((lane >> 4) & 1) * 8;
                    ldsm4t(bh[2*np][0], bh[2*np][1], bh[2*np+1][0], bh[2*np+1][1],
                           smem_u32(Bh + k * BP + col));
                } else {
                    const int nrow = wn * 32 + np * 16 + (lane & 7) + ((lane >> 4) & 1) * 8;
                    const int ko = h * 16 + ((lane >> 3) & 1) * 8;
                    ldsm4(bh[2*np][0], bh[2*np][1], bh[2*np+1][0], bh[2*np+1][1],
                          smem_u32(Bh + nrow * AP + ko));
                }
            }
#pragma unroll
            for (int mt = 0; mt < 4; mt++)
#pragma unroll
                for (int nt = 0; nt < 4; nt++)
                    mma16816(c[mt][nt], ah[mt], bh[nt]);
            if (ASPLIT) {
#pragma unroll
                for (int mt = 0; mt < 4; mt++)
#pragma unroll
                    for (int nt = 0; nt < 4; nt++)
                        mma16816(c[mt][nt], al[mt], bh[nt]);
            }
        }
    };

    const int NC = K / CH;
#pragma unroll
    for (int p = 0; p < NSTG - 1; p++) { issue(p); CP_COMMIT(); }
    for (int cc = 0; cc < NC; cc++) {
        if constexpr (NSTG == 3) CP_WAIT1(); else CP_WAIT2();
        __syncthreads();
        if (cc + NSTG - 1 < NC) issue(cc + NSTG - 1);
        CP_COMMIT();
        compute(cc % NSTG);
    }

    const int g = lane >> 2, tg = lane & 3;
#pragma unroll
    for (int mt = 0; mt < 4; mt++) {
#pragma unroll
        for (int nt = 0; nt < 4; nt++) {
            const int row0 = wm * 64 + mt * 16 + g;
            const int col = wn * 32 + nt * 8 + tg * 2;
            float2 v0 = make_float2(c[mt][nt][0], c[mt][nt][1]);
            float2 v1 = make_float2(c[mt][nt][2], c[mt][nt][3]);
            if (OSPLIT) {
                *(uint32_t*)(Chp + (size_t)row0 * ldc + col) = pack_h2(v0.x, v0.y);
                *(uint32_t*)(Chp + (size_t)(row0 + 8) * ldc + col) = pack_h2(v1.x, v1.y);
            } else {
                *(float2*)(Cf + (size_t)row0 * ldc + col) = v0;
                *(float2*)(Cf + (size_t)(row0 + 8) * ldc + col) = v1;
            }
        }
    }
}

// ---- wrappers ----
__global__ __launch_bounds__(128, 2)
void gemm_proj_all(const hf* __restrict__ xh,
                   const hf* __restrict__ wqh, const hf* __restrict__ wkvh,
                   const hf* __restrict__ hqh, const hf* __restrict__ hkvh,
                   hf* __restrict__ q1h, hf* __restrict__ q1l,
                   hf* __restrict__ kv1h,
                   hf* __restrict__ q2h,
                   hf* __restrict__ kv2h)
{
    const int m0 = blockIdx.y * 128;
    const int n0 = blockIdx.x * 128;
    const int fam = blockIdx.z;
    const hf* Bh;
    hf *Ch, *Cl;
    int ldc, store_lo;
    if (n0 < INNER) {
        Bh = (fam ? hqh : wqh) + n0;
        Ch = (fam ? q2h : q1h) + (size_t)m0 * INNER + n0;
        Cl = fam ? nullptr : (q1l + (size_t)m0 * INNER + n0);
        ldc = INNER;
        store_lo = fam ? 0 : 1;    // only col-attn Q keeps the low plane
    } else {
        const int nn = n0 - INNER;
        Bh = (fam ? hkvh : wkvh) + nn;
        Ch = (fam ? kv2h : kv1h) + (size_t)m0 * 2 * INNER + nn;
        Cl = nullptr;
        ldc = 2 * INNER;
        store_lo = 0;
    }
    const int Nw = (n0 < INNER) ? INNER : 2 * INNER;
    gemm_core6<0, 1, 0>(xh + (size_t)m0 * DIM, nullptr, DIM,
                        Bh, Nw,
                        nullptr, nullptr, nullptr, 0,
                        nullptr, Ch, Cl, ldc, DIM, nullptr, nullptr, store_lo);
}

__global__ __launch_bounds__(128, 2)
void gemm_out_fused(const hf* __restrict__ o1h, const hf* __restrict__ o2h,
                    const hf* __restrict__ wouth, const hf* __restrict__ houth,
                    float* __restrict__ C, const float* __restrict__ wout_b,
                    const float* __restrict__ hout_b)
{
    const int m0 = blockIdx.y * 128, n0 = blockIdx.x * 128;
    gemm_core6<0, 0, 1>(o1h + (size_t)m0 * INNER, nullptr, INNER,
                        wouth + n0, DIM,
                        o2h + (size_t)m0 * INNER, nullptr,
                        houth + n0, INNER,
                        C + (size_t)m0 * DIM + n0, nullptr, nullptr,
                        DIM, 2 * INNER, wout_b + n0, hout_b + n0, 0);
}

__global__ __launch_bounds__(128, 3)
void gemm_av2(const hf* __restrict__ Ph, const hf* __restrict__ Vh, hf* __restrict__ Oh)
{
    const int i0 = blockIdx.x * 128;
    const int h = blockIdx.y, r = blockIdx.z;
    const size_t aoff = (size_t)h * (MSAW * MSAW) + (size_t)i0 * MSAW;
    const size_t boff = (size_t)INNER + (size_t)h * 64 + (size_t)r * MSAW * 2 * INNER;
    const size_t coff = ((size_t)r * MSAW + i0) * INNER + h * 64;
    gemm_core5<2, 2, 1, 0, 1, 16, 4>(Ph + aoff, nullptr, MSAW, 64,
                                     Vh + boff, 2 * INNER, 0,
                                     nullptr, Oh + coff, INNER, MSAW);
}

// smem bytes
#define SM_PROJ (3 * (128 * 40 + 32 * 136) * 2)
#define SM_AV   (4 * (128 * 24 + 16 * 72) * 2)
#define SM_DOTS (4 * (128 * 24 + 128 * 24) * 2)
#define COL_SMEM2 (4 * 128 * 72 * 2)
#define ATTN_SMEM (SM_DOTS > COL_SMEM2 ? SM_DOTS : COL_SMEM2)

// ================= column attention body (2-product QK, K/V single plane) =================
__device__ __forceinline__
void col_attn_body(int wi, int head,
                   const hf* __restrict__ qh, const hf* __restrict__ ql,
                   const hf* __restrict__ kvh,
                   hf* __restrict__ oh)
{
    extern __shared__ hf smc[];
    const int PL = 128 * 72;
    hf *sqh = smc,          *sql = smc + PL;
    hf *skh = smc + 2 * PL, *svh = smc + 3 * PL;

    const int tid = threadIdx.x, warp = tid >> 5, lane = tid & 31;

#pragma unroll
    for (int i = 0; i < 4; i++) {
        const int idx = i * 256 + tid;
        const int row = idx >> 3, g = (idx & 7) * 8;
        const size_t gq = ((size_t)(row * MSAW + wi)) * INNER + head * 64 + g;
        const size_t gk = ((size_t)(row * MSAW + wi)) * 2 * INNER + head * 64 + g;
        cpa16(smem_u32(sqh + row * 72 + g), qh + gq);
        cpa16(smem_u32(sql + row * 72 + g), ql + gq);
        cpa16(smem_u32(skh + row * 72 + g), kvh + gk);
        cpa16(smem_u32(svh + row * 72 + g), kvh + gk + INNER);
    }
    CP_COMMIT();
    CP_WAIT0();
    __syncthreads();

    const int m0 = warp * 16;
    float s[16][4];
#pragma unroll
    for (int nt = 0; nt < 16; nt++)
#pragma unroll
        for (int e = 0; e < 4; e++) s[nt][e] = 0.f;

#pragma unroll
    for (int kc = 0; kc < 4; kc++) {
        uint32_t ah[4], al[4];
        const int arow = m0 + (lane & 15);
        const int acol = kc * 16 + ((lane >> 4) & 1) * 8;
        ldsm4(ah[0], ah[1], ah[2], ah[3], smem_u32(sqh + arow * 72 + acol));
        ldsm4(al[0], al[1], al[2], al[3], smem_u32(sql + arow * 72 + acol));
#pragma unroll
        for (int ng = 0; ng < 4; ng++) {
            uint32_t bh[4][2];
#pragma unroll
            for (int npp = 0; npp < 2; npp++) {
                const int nt0 = ng * 4 + npp * 2;
                const int brow = nt0 * 8 + (lane & 7) + ((lane >> 4) & 1) * 8;
                const int bcol = kc * 16 + ((lane >> 3) & 1) * 8;
                ldsm4(bh[npp*2][0], bh[npp*2][1], bh[npp*2+1][0], bh[npp*2+1][1],
                      smem_u32(skh + brow * 72 + bcol));
            }
#pragma unroll
            for (int t = 0; t < 4; t++) mma16816(s[ng * 4 + t], ah, bh[t]);
#pragma unroll
            for (int t = 0; t < 4; t++) mma16816(s[ng * 4 + t], al, bh[t]);
        }
    }

    const float sc = 0.125f;
    float mx0 = -1e30f, mx1 = -1e30f;
#pragma unroll
    for (int nt = 0; nt < 16; nt++) {
        mx0 = fmaxf(mx0, fmaxf(s[nt][0], s[nt][1]));
        mx1 = fmaxf(mx1, fmaxf(s[nt][2], s[nt][3]));
    }
    mx0 = fmaxf(mx0, __shfl_xor_sync(0xffffffffu, mx0, 1));
    mx0 = fmaxf(mx0, __shfl_xor_sync(0xffffffffu, mx0, 2));
    mx1 = fmaxf(mx1, __shfl_xor_sync(0xffffffffu, mx1, 1));
    mx1 = fmaxf(mx1, __shfl_xor_sync(0xffffffffu, mx1, 2));
    float sum0 = 0.f, sum1 = 0.f;
#pragma unroll
    for (int nt = 0; nt < 16; nt++) {
        s[nt][0] = __expf(sc * (s[nt][0] - mx0)); sum0 += s[nt][0];
        s[nt][1] = __expf(sc * (s[nt][1] - mx0)); sum0 += s[nt][1];
        s[nt][2] = __expf(sc * (s[nt][2] - mx1)); sum1 += s[nt][2];
        s[nt][3] = __expf(sc * (s[nt][3] - mx1)); sum1 += s[nt][3];
    }
    sum0 += __shfl_xor_sync(0xffffffffu, sum0, 1);
    sum0 += __shfl_xor_sync(0xffffffffu, sum0, 2);
    sum1 += __shfl_xor_sync(0xffffffffu, sum1, 1);
    sum1 += __shfl_xor_sync(0xffffffffu, sum1, 2);
    const float inv0 = 1.f / sum0, inv1 = 1.f / sum1;
#pragma unroll
    for (int nt = 0; nt < 16; nt++) {
        s[nt][0] *= inv0; s[nt][1] *= inv0;
        s[nt][2] *= inv1; s[nt][3] *= inv1;
    }

    float o[8][4];
#pragma unroll
    for (int dt = 0; dt < 8; dt++)
#pragma unroll
        for (int e = 0; e < 4; e++) o[dt][e] = 0.f;

#pragma unroll
    for (int jc = 0; jc < 8; jc++) {
        uint32_t pah[4], pal[4];
        split_pair(s[2 * jc][0],     s[2 * jc][1],     pah[0], pal[0]);
        split_pair(s[2 * jc][2],     s[2 * jc][3],     pah[1], pal[1]);
        split_pair(s[2 * jc + 1][0], s[2 * jc + 1][1], pah[2], pal[2]);
        split_pair(s[2 * jc + 1][2], s[2 * jc + 1][3], pah[3], pal[3]);
        const int jrow = jc * 16 + (lane & 7) + ((lane >> 3) & 1) * 8;
#pragma unroll
        for (int dg = 0; dg < 2; dg++) {
            uint32_t bh[4][2];
#pragma unroll
            for (int dpp = 0; dpp < 2; dpp++) {
                const int dt0 = dg * 4 + dpp * 2;
                const int dcol = dt0 * 8 + ((lane >> 4) & 1) * 8;
                ldsm4t(bh[dpp*2][0], bh[dpp*2][1], bh[dpp*2+1][0], bh[dpp*2+1][1],
                       smem_u32(svh + jrow * 72 + dcol));
            }
#pragma unroll
            for (int t = 0; t < 4; t++) mma16816(o[dg * 4 + t], pah, bh[t]);
#pragma unroll
            for (int t = 0; t < 4; t++) mma16816(o[dg * 4 + t], pal, bh[t]);
        }
    }

    const int g = lane >> 2, tg = lane & 3;
    const int r0 = m0 + g, r1 = r0 + 8;
#pragma unroll
    for (int dt = 0; dt < 8; dt++) {
        const int d = head * 64 + dt * 8 + tg * 2;
        const size_t b0 = ((size_t)(r0 * MSAW + wi)) * INNER + d;
        const size_t b1 = ((size_t)(r1 * MSAW + wi)) * INNER + d;
        *(uint32_t*)(oh + b0) = pack_h2(o[dt][0], o[dt][1]);
        *(uint32_t*)(oh + b1) = pack_h2(o[dt][2], o[dt][3]);
    }
}

// ============= fused attention: dots tiles (blocks 0..127) + col attn (128..2175) =============
__global__ __launch_bounds__(256, 2)
void attn_fused(const hf* __restrict__ q1h, const hf* __restrict__ q1l,
                const hf* __restrict__ kv1h,
                const hf* __restrict__ q2h,
                const hf* __restrict__ kv2h,
                hf* __restrict__ o1h,
                float* __restrict__ Pp)
{
    const int b = blockIdx.x;
    if (b < 128) {
        const int j0 = (b & 1) * 128, i0 = ((b >> 1) & 1) * 128;
        const int z = b >> 2;
        const int h = z >> 2, s = z & 3;
        const size_t r0 = (size_t)s * 32;
        const size_t aoff = (size_t)h * 64 + (size_t)i0 * INNER + r0 * MSAW * INNER;
        const size_t boff = (size_t)h * 64 + (size_t)j0 * 2 * INNER + r0 * MSAW * 2 * INNER;
        gemm_core5<2, 4, 0, 0, 0, 16, 4>(q2h + aoff, nullptr, INNER, (size_t)MSAW * INNER,
                                         kv2h + boff, 2 * INNER, (size_t)MSAW * 2 * INNER,
                                         Pp + (size_t)z * (MSAW * MSAW) + (size_t)i0 * MSAW + j0,
                                         nullptr, MSAW, 32 * 64);
    } else {
        const int cb = b - 128;
        col_attn_body(cb & 255, cb >> 8, q1h, q1l, kv1h, o1h);
    }
}

// ============= reduce 4 dots partials + scale + softmax -> fp16 plane =============
__global__ __launch_bounds__(256)
void softmax_reduce2(const float* __restrict__ Pp, hf* __restrict__ Ph)
{
    const int h = blockIdx.x >> 8, i = blockIdx.x & 255;
    const int tid = threadIdx.x;
    __shared__ float red[34];
    float v = 0.f;
#pragma unroll
    for (int s = 0; s < 4; s++)
        v += Pp[((size_t)(h * 4 + s) * MSAW + i) * MSAW + tid];
    v *= 0.011048543456039806f;  // (1/8) * 128^-0.5

    float m = v;
#pragma unroll
    for (int o = 16; o; o >>= 1) m = fmaxf(m, __shfl_xor_sync(0xffffffffu, m, o));
    if ((tid & 31) == 0) red[tid >> 5] = m;
    __syncthreads();
    if (tid == 0) {
        float mm = red[0];
#pragma unroll
        for (int w = 1; w < 8; w++) mm = fmaxf(mm, red[w]);
        red[32] = mm;
    }
    __syncthreads();
    const float e = __expf(v - red[32]);
    float s = e;
#pragma unroll
    for (int o = 16; o; o >>= 1) s += __shfl_xor_sync(0xffffffffu, s, o);
    if ((tid & 31) == 0) red[8 + (tid >> 5)] = s;
    __syncthreads();
    if (tid == 0) {
        float ss = 0.f;
#pragma unroll
        for (int w = 0; w < 8; w++) ss += red[8 + w];
        red[33] = 1.f / ss;
    }
    __syncthreads();
    Ph[((size_t)h * MSAW + i) * MSAW + tid] = __float2half_rn(e * red[33]);
}

// =============================== launch ===============================
extern "C" void kernel_launch(void* const* d_in, const int* in_sizes, int n_in,
                              void* d_out, int out_size)
{
    const float* x      = (const float*)d_in[0];
    const float* wq_w   = (const float*)d_in[1];
    const float* wkv_w  = (const float*)d_in[2];
    const float* wout_w = (const float*)d_in[3];
    const float* wout_b = (const float*)d_in[4];
    const float* hq_w   = (const float*)d_in[5];
    const float* hkv_w  = (const float*)d_in[6];
    const float* hout_w = (const float*)d_in[7];
    const float* hout_b = (const float*)d_in[8];
    float* out = (float*)d_out;

    void* p;
    hf *xh, *wqh, *wkvh, *hqh, *hkvh, *wouth, *houth;
    hf *q1h, *q1l, *kv1h, *q2h, *kv2h;
    hf *o1h, *o2h, *p2h;
    float* Pp;
    cudaGetSymbolAddress(&p, g_xh);    xh = (hf*)p;
    cudaGetSymbolAddress(&p, g_wqh);   wqh = (hf*)p;
    cudaGetSymbolAddress(&p, g_wkvh);  wkvh = (hf*)p;
    cudaGetSymbolAddress(&p, g_hqh);   hqh = (hf*)p;
    cudaGetSymbolAddress(&p, g_hkvh);  hkvh = (hf*)p;
    cudaGetSymbolAddress(&p, g_wouth); wouth = (hf*)p;
    cudaGetSymbolAddress(&p, g_houth); houth = (hf*)p;
    cudaGetSymbolAddress(&p, g_q1h);   q1h = (hf*)p;
    cudaGetSymbolAddress(&p, g_q1l);   q1l = (hf*)p;
    cudaGetSymbolAddress(&p, g_kv1h);  kv1h = (hf*)p;
    cudaGetSymbolAddress(&p, g_q2h);   q2h = (hf*)p;
    cudaGetSymbolAddress(&p, g_kv2h);  kv2h = (hf*)p;
    cudaGetSymbolAddress(&p, g_o1h);   o1h = (hf*)p;
    cudaGetSymbolAddress(&p, g_o2h);   o2h = (hf*)p;
    cudaGetSymbolAddress(&p, g_p2h);   p2h = (hf*)p;
    cudaGetSymbolAddress(&p, g_Pp);    Pp = (float*)p;

    cudaFuncSetAttribute(gemm_proj_all,  cudaFuncAttributeMaxDynamicSharedMemorySize, SM_PROJ);
    cudaFuncSetAttribute(gemm_out_fused, cudaFuncAttributeMaxDynamicSharedMemorySize, SM_PROJ);
    cudaFuncSetAttribute(gemm_av2,       cudaFuncAttributeMaxDynamicSharedMemorySize, SM_AV);
    cudaFuncSetAttribute(attn_fused,     cudaFuncAttributeMaxDynamicSharedMemorySize, ATTN_SMEM);

    split_all<<<8192 + 1024, 256>>>(x, wq_w, wkv_w, hq_w, hkv_w, wout_w, hout_w,
                                    xh, wqh, wkvh, hqh, hkvh, wouth, houth);

    gemm_proj_all<<<dim3(12, NTOK / 128, 2), 128, SM_PROJ>>>(
        xh, wqh, wkvh, hqh, hkvh,
        q1h, q1l, kv1h, q2h, kv2h);

    attn_fused<<<128 + MSAW * HEADS, 256, ATTN_SMEM>>>(
        q1h, q1l, kv1h, q2h, kv2h, o1h, Pp);

    softmax_reduce2<<<HEADS * MSAW, 256>>>(Pp, p2h);
    gemm_av2<<<dim3(2, HEADS, MSAH), 128, SM_AV>>>(p2h, kv2h, o2h);

    gemm_out_fused<<<dim3(2, NTOK / 128), 128, SM_PROJ>>>(
        o1h, o2h, wouth, houth, out, wout_b, hout_b);
}

// round 15
// speedup vs baseline: 8.8131x; 1.0645x over previous
#include <cuda_runtime.h>
#include <cuda_fp16.h>
#include <math.h>
#include <cstdint>

#define HEADS 8
#define DH    64
#define INNER 512
#define DIM   256
#define MSAH  128
#define MSAW  256
#define NTOK  (MSAH*MSAW)

typedef __half hf;

// -------- scratch (static device globals; no runtime allocation) --------
__device__ hf g_xh [(size_t)NTOK*DIM];
__device__ hf g_wqh [(size_t)DIM*INNER];
__device__ hf g_wkvh[(size_t)DIM*2*INNER];
__device__ hf g_hqh [(size_t)DIM*INNER];
__device__ hf g_hkvh[(size_t)DIM*2*INNER];
__device__ hf g_wouth[(size_t)INNER*DIM];
__device__ hf g_houth[(size_t)INNER*DIM];
__device__ hf g_q1h [(size_t)NTOK*INNER];
__device__ hf g_kv1h[(size_t)NTOK*2*INNER];
__device__ hf g_q2h [(size_t)NTOK*INNER];
__device__ hf g_kv2h[(size_t)NTOK*2*INNER];
__device__ hf g_o1h [(size_t)NTOK*INNER];
__device__ hf g_o2h [(size_t)NTOK*INNER];
__device__ hf g_p2h [(size_t)HEADS*MSAW*MSAW];
__device__ float g_Pp [(size_t)32*MSAW*MSAW];

// ===================== helpers =====================
__device__ __forceinline__ uint32_t smem_u32(const void* p) {
    uint32_t a;
    asm("{ .reg .u64 t; cvta.to.shared.u64 t, %1; cvt.u32.u64 %0, t; }" : "=r"(a) : "l"(p));
    return a;
}
__device__ __forceinline__ void ldsm4(uint32_t& r0, uint32_t& r1, uint32_t& r2, uint32_t& r3, uint32_t a) {
    asm volatile("ldmatrix.sync.aligned.m8n8.x4.shared.b16 {%0,%1,%2,%3}, [%4];"
                 : "=r"(r0), "=r"(r1), "=r"(r2), "=r"(r3) : "r"(a));
}
__device__ __forceinline__ void ldsm4t(uint32_t& r0, uint32_t& r1, uint32_t& r2, uint32_t& r3, uint32_t a) {
    asm volatile("ldmatrix.sync.aligned.m8n8.x4.trans.shared.b16 {%0,%1,%2,%3}, [%4];"
                 : "=r"(r0), "=r"(r1), "=r"(r2), "=r"(r3) : "r"(a));
}
__device__ __forceinline__ void mma16816(float* c, const uint32_t* a, const uint32_t* b) {
    asm volatile("mma.sync.aligned.m16n8k16.row.col.f32.f16.f16.f32 "
                 "{%0,%1,%2,%3}, {%4,%5,%6,%7}, {%8,%9}, {%0,%1,%2,%3};"
                 : "+f"(c[0]), "+f"(c[1]), "+f"(c[2]), "+f"(c[3])
                 : "r"(a[0]), "r"(a[1]), "r"(a[2]), "r"(a[3]), "r"(b[0]), "r"(b[1]));
}
__device__ __forceinline__ void cpa16(uint32_t dst, const void* src) {
    asm volatile("cp.async.cg.shared.global [%0], [%1], 16;" :: "r"(dst), "l"(src));
}
#define CP_COMMIT() asm volatile("cp.async.commit_group;" ::: "memory")
#define CP_WAIT1()  asm volatile("cp.async.wait_group 1;" ::: "memory")
#define CP_WAIT2()  asm volatile("cp.async.wait_group 2;" ::: "memory")
#define CP_WAIT0()  asm volatile("cp.async.wait_group 0;" ::: "memory")
__device__ __forceinline__ uint32_t pack_h2(float a, float b) {
    __half2 h2 = __halves2half2(__float2half_rn(a), __float2half_rn(b));
    return *(uint32_t*)&h2;
}

// ================= convert fp32 -> fp16 plane(s) (one launch) =================
__device__ __forceinline__ void conv_one(const float* in, hf* H, int i) {
    const float4 v = ((const float4*)in)[i];
    *(uint2*)(H + (size_t)i * 4) = make_uint2(pack_h2(v.x, v.y), pack_h2(v.z, v.w));
}
__global__ __launch_bounds__(256)
void split_all(const float* x, const float* wq, const float* wkv, const float* hq,
               const float* hkv, const float* wo, const float* ho,
               hf* xh, hf* wqh, hf* wkvh, hf* hqh, hf* hkvh, hf* woh, hf* hoh)
{
    const int b = blockIdx.x;
    if (b < 8192) {
        conv_one(x, xh, b * 256 + threadIdx.x);
        return;
    }
    const int i = (b - 8192) * 256 + threadIdx.x;
    if (i < 32768)        conv_one(wq,  wqh,  i);
    else if (i < 98304)   conv_one(wkv, wkvh, i - 32768);
    else if (i < 131072)  conv_one(hq,  hqh,  i - 98304);
    else if (i < 196608)  conv_one(hkv, hkvh, i - 131072);
    else if (i < 229376)  conv_one(wo,  woh,  i - 196608);
    else                  conv_one(ho,  hoh,  i - 229376);
}

// ======== big-tile GEMM core: 128x128 block, 4 warps, warp tile 64x64, CH=32, 3-stage ========
template<int OSPLIT, int DUAL>
__device__ __forceinline__ void gemm_core6(
    const hf* __restrict__ Ah_, size_t sAr,
    const hf* __restrict__ Bh_, size_t sBr,
    const hf* __restrict__ Ah2_, const hf* __restrict__ Bh2_, int K1,
    float* __restrict__ Cf, hf* __restrict__ Chp,
    int ldc, int K, const float* __restrict__ bias, const float* __restrict__ bias2)
{
    constexpr int CH = 32, NSTG = 3;
    constexpr int AP = 40;
    constexpr int BP = 136;
    constexpr int AH = 128 * AP;
    constexpr int BH = CH * BP;
    constexpr int STAGE = AH + BH;

    extern __shared__ hf smn[];
    const int tid = threadIdx.x, warp = tid >> 5, lane = tid & 31;
    const int wm = warp >> 1, wn = warp & 1;

    float c[4][8][4];
#pragma unroll
    for (int mt = 0; mt < 4; mt++)
#pragma unroll
        for (int nt = 0; nt < 8; nt++)
#pragma unroll
            for (int e = 0; e < 4; e++) c[mt][nt][e] = 0.f;

    auto issue = [&](int cc) {
        const int s = cc % NSTG;
        hf* Ah = smn + (size_t)s * STAGE;
        hf* Bh = Ah + AH;
        int k0 = cc * CH;
        const hf *Ap = Ah_, *Bp = Bh_;
        if (DUAL && k0 >= K1) { Ap = Ah2_; Bp = Bh2_; k0 -= K1; }
#pragma unroll
        for (int i = 0; i < 4; i++) {
            const int idx = i * 128 + tid;
            const int row = idx >> 2, g = (idx & 3) * 8;
            cpa16(smem_u32(Ah + row * AP + g), Ap + (size_t)row * sAr + k0 + g);
        }
#pragma unroll
        for (int i = 0; i < 4; i++) {
            const int idx = i * 128 + tid;
            const int kr = idx >> 4, q = (idx & 15) * 8;
            cpa16(smem_u32(Bh + kr * BP + q), Bp + (size_t)(k0 + kr) * sBr + q);
        }
    };

    auto compute = [&](int s) {
        hf* Ah = smn + (size_t)s * STAGE;
        hf* Bh = Ah + AH;
#pragma unroll
        for (int h = 0; h < 2; h++) {
            uint32_t ah[4][4];
#pragma unroll
            for (int mt = 0; mt < 4; mt++) {
                const int row = wm * 64 + mt * 16 + (lane & 15);
                const int ko = h * 16 + ((lane >> 4) & 1) * 8;
                ldsm4(ah[mt][0], ah[mt][1], ah[mt][2], ah[mt][3], smem_u32(Ah + row * AP + ko));
            }
#pragma unroll
            for (int bg = 0; bg < 2; bg++) {
                uint32_t bh[4][2];
#pragma unroll
                for (int np = 0; np < 2; np++) {
                    const int k = h * 16 + (lane & 7) + ((lane >> 3) & 1) * 8;
                    const int col = wn * 64 + bg * 32 + np * 16 + ((lane >> 4) & 1) * 8;
                    ldsm4t(bh[2*np][0], bh[2*np][1], bh[2*np+1][0], bh[2*np+1][1],
                           smem_u32(Bh + k * BP + col));
                }
#pragma unroll
                for (int mt = 0; mt < 4; mt++)
#pragma unroll
                    for (int t = 0; t < 4; t++)
                        mma16816(c[mt][bg * 4 + t], ah[mt], bh[t]);
            }
        }
    };

    const int NC = K / CH;
    issue(0); CP_COMMIT();
    issue(1); CP_COMMIT();
    for (int cc = 0; cc < NC; cc++) {
        CP_WAIT1();
        __syncthreads();
        if (cc + 2 < NC) issue(cc + 2);
        CP_COMMIT();
        compute(cc % NSTG);
    }

    const int g = lane >> 2, tg = lane & 3;
#pragma unroll
    for (int mt = 0; mt < 4; mt++) {
#pragma unroll
        for (int nt = 0; nt < 8; nt++) {
            const int row0 = wm * 64 + mt * 16 + g;
            const int col = wn * 64 + nt * 8 + tg * 2;
            float2 v0 = make_float2(c[mt][nt][0], c[mt][nt][1]);
            float2 v1 = make_float2(c[mt][nt][2], c[mt][nt][3]);
            if (OSPLIT) {
                *(uint32_t*)(Chp + (size_t)row0 * ldc + col) = pack_h2(v0.x, v0.y);
                *(uint32_t*)(Chp + (size_t)(row0 + 8) * ldc + col) = pack_h2(v1.x, v1.y);
            } else {
                float b0 = 0.f, b1 = 0.f;
                if (bias)  { b0 += bias[col];  b1 += bias[col + 1]; }
                if (bias2) { b0 += bias2[col]; b1 += bias2[col + 1]; }
                v0.x += b0; v0.y += b1; v1.x += b0; v1.y += b1;
                *(float2*)(Cf + (size_t)row0 * ldc + col) = v0;
                *(float2*)(Cf + (size_t)(row0 + 8) * ldc + col) = v1;
            }
        }
    }
}

// ======== 1-product GEMM (64x32 warp tile), both operands single plane ========
template<int WM, int WN, int BT, int OSPLIT, int CH, int NSTG>
__device__ __forceinline__ void gemm_core5(
    const hf* __restrict__ Ah_, size_t sAr, size_t sAk,
    const hf* __restrict__ Bh_, size_t sBr, size_t sBk,
    float* __restrict__ Cf, hf* __restrict__ Chp,
    int ldc, int K)
{
    constexpr int TM = WM * 64, TN = WN * 32;
    constexpr int THREADS = WM * WN * 32;
    constexpr int AP = CH + 8;
    constexpr int BP = BT ? (TN + 8) : (CH + 8);
    constexpr int AH = TM * AP;
    constexpr int BH = BT ? CH * BP : TN * AP;
    constexpr int STAGE = AH + BH;
    constexpr int C8 = CH / 8;
    constexpr int NA = TM * C8 / THREADS;
    constexpr int NB = BT ? (CH * TN / 8) / THREADS : (TN * C8) / THREADS;

    extern __shared__ hf smn[];
    const int tid = threadIdx.x, warp = tid >> 5, lane = tid & 31;
    const int wm = warp / WN, wn = warp % WN;

    float c[4][4][4];
#pragma unroll
    for (int mt = 0; mt < 4; mt++)
#pragma unroll
        for (int nt = 0; nt < 4; nt++)
#pragma unroll
            for (int e = 0; e < 4; e++) c[mt][nt][e] = 0.f;

    auto issue = [&](int cc) {
        const int s = cc % NSTG;
        hf* Ah = smn + (size_t)s * STAGE;
        hf* Bh = Ah + AH;
        int k0 = cc * CH;
        const size_t cb = (size_t)(k0 >> 6) * sAk + (k0 & 63);
#pragma unroll
        for (int i = 0; i < NA; i++) {
            const int idx = i * THREADS + tid;
            const int row = idx / C8, g = (idx % C8) * 8;
            cpa16(smem_u32(Ah + row * AP + g), Ah_ + (size_t)row * sAr + cb + g);
        }
#pragma unroll
        for (int i = 0; i < NB; i++) {
            const int idx = i * THREADS + tid;
            size_t go; int off;
            if (BT) {
                const int kr = idx / (TN / 8), q = idx % (TN / 8);
                go = (size_t)(k0 + kr) * sBr + q * 8;
                off = kr * BP + q * 8;
            } else {
                const int nr = idx / C8, g = (idx % C8) * 8;
                go = (size_t)nr * sBr + (size_t)(k0 >> 6) * sBk + (k0 & 63) + g;
                off = nr * AP + g;
            }
            cpa16(smem_u32(Bh + off), Bh_ + go);
        }
    };

    auto compute = [&](int s) {
        hf* Ah = smn + (size_t)s * STAGE;
        hf* Bh = Ah + AH;
#pragma unroll
        for (int h = 0; h < CH / 16; h++) {
            uint32_t ah[4][4], bh[4][2];
#pragma unroll
            for (int mt = 0; mt < 4; mt++) {
                const int row = wm * 64 + mt * 16 + (lane & 15);
                const int ko = h * 16 + ((lane >> 4) & 1) * 8;
                ldsm4(ah[mt][0], ah[mt][1], ah[mt][2], ah[mt][3], smem_u32(Ah + row * AP + ko));
            }
#pragma unroll
            for (int np = 0; np < 2; np++) {
                if (BT) {
                    const int k = h * 16 + (lane & 7) + ((lane >> 3) & 1) * 8;
                    const int col = wn * 32 + np * 16 + ((lane >> 4) & 1) * 8;
                    ldsm4t(bh[2*np][0], bh[2*np][1], bh[2*np+1][0], bh[2*np+1][1],
                           smem_u32(Bh + k * BP + col));
                } else {
                    const int nrow = wn * 32 + np * 16 + (lane & 7) + ((lane >> 4) & 1) * 8;
                    const int ko = h * 16 + ((lane >> 3) & 1) * 8;
                    ldsm4(bh[2*np][0], bh[2*np][1], bh[2*np+1][0], bh[2*np+1][1],
                          smem_u32(Bh + nrow * AP + ko));
                }
            }
#pragma unroll
            for (int mt = 0; mt < 4; mt++)
#pragma unroll
                for (int nt = 0; nt < 4; nt++)
                    mma16816(c[mt][nt], ah[mt], bh[nt]);
        }
    };

    const int NC = K / CH;
#pragma unroll
    for (int p = 0; p < NSTG - 1; p++) { issue(p); CP_COMMIT(); }
    for (int cc = 0; cc < NC; cc++) {
        if constexpr (NSTG == 3) CP_WAIT1(); else CP_WAIT2();
        __syncthreads();
        if (cc + NSTG - 1 < NC) issue(cc + NSTG - 1);
        CP_COMMIT();
        compute(cc % NSTG);
    }

    const int g = lane >> 2, tg = lane & 3;
#pragma unroll
    for (int mt = 0; mt < 4; mt++) {
#pragma unroll
        for (int nt = 0; nt < 4; nt++) {
            const int row0 = wm * 64 + mt * 16 + g;
            const int col = wn * 32 + nt * 8 + tg * 2;
            float2 v0 = make_float2(c[mt][nt][0], c[mt][nt][1]);
            float2 v1 = make_float2(c[mt][nt][2], c[mt][nt][3]);
            if (OSPLIT) {
                *(uint32_t*)(Chp + (size_t)row0 * ldc + col) = pack_h2(v0.x, v0.y);
                *(uint32_t*)(Chp + (size_t)(row0 + 8) * ldc + col) = pack_h2(v1.x, v1.y);
            } else {
                *(float2*)(Cf + (size_t)row0 * ldc + col) = v0;
                *(float2*)(Cf + (size_t)(row0 + 8) * ldc + col) = v1;
            }
        }
    }
}

// ---- wrappers ----
__global__ __launch_bounds__(128, 2)
void gemm_proj_all(const hf* __restrict__ xh,
                   const hf* __restrict__ wqh, const hf* __restrict__ wkvh,
                   const hf* __restrict__ hqh, const hf* __restrict__ hkvh,
                   hf* __restrict__ q1h, hf* __restrict__ kv1h,
                   hf* __restrict__ q2h, hf* __restrict__ kv2h)
{
    const int m0 = blockIdx.y * 128;
    const int n0 = blockIdx.x * 128;
    const int fam = blockIdx.z;
    const hf* Bh;
    hf* Ch;
    int ldc;
    if (n0 < INNER) {
        Bh = (fam ? hqh : wqh) + n0;
        Ch = (fam ? q2h : q1h) + (size_t)m0 * INNER + n0;
        ldc = INNER;
    } else {
        const int nn = n0 - INNER;
        Bh = (fam ? hkvh : wkvh) + nn;
        Ch = (fam ? kv2h : kv1h) + (size_t)m0 * 2 * INNER + nn;
        ldc = 2 * INNER;
    }
    const int Nw = (n0 < INNER) ? INNER : 2 * INNER;
    gemm_core6<1, 0>(xh + (size_t)m0 * DIM, DIM,
                     Bh, Nw,
                     nullptr, nullptr, 0,
                     nullptr, Ch, ldc, DIM, nullptr, nullptr);
}

__global__ __launch_bounds__(128, 2)
void gemm_out_fused(const hf* __restrict__ o1h, const hf* __restrict__ o2h,
                    const hf* __restrict__ wouth, const hf* __restrict__ houth,
                    float* __restrict__ C, const float* __restrict__ wout_b,
                    const float* __restrict__ hout_b)
{
    const int m0 = blockIdx.y * 128, n0 = blockIdx.x * 128;
    gemm_core6<0, 1>(o1h + (size_t)m0 * INNER, INNER,
                     wouth + n0, DIM,
                     o2h + (size_t)m0 * INNER, houth + n0, INNER,
                     C + (size_t)m0 * DIM + n0, nullptr,
                     DIM, 2 * INNER, wout_b + n0, hout_b + n0);
}

__global__ __launch_bounds__(128, 3)
void gemm_av2(const hf* __restrict__ Ph, const hf* __restrict__ Vh, hf* __restrict__ Oh)
{
    const int i0 = blockIdx.x * 128;
    const int h = blockIdx.y, r = blockIdx.z;
    const size_t aoff = (size_t)h * (MSAW * MSAW) + (size_t)i0 * MSAW;
    const size_t boff = (size_t)INNER + (size_t)h * 64 + (size_t)r * MSAW * 2 * INNER;
    const size_t coff = ((size_t)r * MSAW + i0) * INNER + h * 64;
    gemm_core5<2, 2, 1, 1, 16, 4>(Ph + aoff, MSAW, 64,
                                  Vh + boff, 2 * INNER, 0,
                                  nullptr, Oh + coff, INNER, MSAW);
}

// smem bytes
#define SM_PROJ (3 * (128 * 40 + 32 * 136) * 2)
#define SM_AV   (4 * (128 * 24 + 16 * 72) * 2)
#define SM_DOTS (4 * (128 * 24 + 128 * 24) * 2)
#define COL_SMEM2 (3 * 128 * 72 * 2)
#define ATTN_SMEM (SM_DOTS > COL_SMEM2 ? SM_DOTS : COL_SMEM2)

// ================= column attention body (1-product fp16 throughout) =================
__device__ __forceinline__
void col_attn_body(int wi, int head,
                   const hf* __restrict__ qh, const hf* __restrict__ kvh,
                   hf* __restrict__ oh)
{
    extern __shared__ hf smc[];
    const int PL = 128 * 72;
    hf *sqh = smc, *skh = smc + PL, *svh = smc + 2 * PL;

    const int tid = threadIdx.x, warp = tid >> 5, lane = tid & 31;

#pragma unroll
    for (int i = 0; i < 4; i++) {
        const int idx = i * 256 + tid;
        const int row = idx >> 3, g = (idx & 7) * 8;
        const size_t gq = ((size_t)(row * MSAW + wi)) * INNER + head * 64 + g;
        const size_t gk = ((size_t)(row * MSAW + wi)) * 2 * INNER + head * 64 + g;
        cpa16(smem_u32(sqh + row * 72 + g), qh + gq);
        cpa16(smem_u32(skh + row * 72 + g), kvh + gk);
        cpa16(smem_u32(svh + row * 72 + g), kvh + gk + INNER);
    }
    CP_COMMIT();
    CP_WAIT0();
    __syncthreads();

    const int m0 = warp * 16;
    float s[16][4];
#pragma unroll
    for (int nt = 0; nt < 16; nt++)
#pragma unroll
        for (int e = 0; e < 4; e++) s[nt][e] = 0.f;

#pragma unroll
    for (int kc = 0; kc < 4; kc++) {
        uint32_t ah[4];
        const int arow = m0 + (lane & 15);
        const int acol = kc * 16 + ((lane >> 4) & 1) * 8;
        ldsm4(ah[0], ah[1], ah[2], ah[3], smem_u32(sqh + arow * 72 + acol));
#pragma unroll
        for (int ng = 0; ng < 4; ng++) {
            uint32_t bh[4][2];
#pragma unroll
            for (int npp = 0; npp < 2; npp++) {
                const int nt0 = ng * 4 + npp * 2;
                const int brow = nt0 * 8 + (lane & 7) + ((lane >> 4) & 1) * 8;
                const int bcol = kc * 16 + ((lane >> 3) & 1) * 8;
                ldsm4(bh[npp*2][0], bh[npp*2][1], bh[npp*2+1][0], bh[npp*2+1][1],
                      smem_u32(skh + brow * 72 + bcol));
            }
#pragma unroll
            for (int t = 0; t < 4; t++) mma16816(s[ng * 4 + t], ah, bh[t]);
        }
    }

    const float sc = 0.125f;
    float mx0 = -1e30f, mx1 = -1e30f;
#pragma unroll
    for (int nt = 0; nt < 16; nt++) {
        mx0 = fmaxf(mx0, fmaxf(s[nt][0], s[nt][1]));
        mx1 = fmaxf(mx1, fmaxf(s[nt][2], s[nt][3]));
    }
    mx0 = fmaxf(mx0, __shfl_xor_sync(0xffffffffu, mx0, 1));
    mx0 = fmaxf(mx0, __shfl_xor_sync(0xffffffffu, mx0, 2));
    mx1 = fmaxf(mx1, __shfl_xor_sync(0xffffffffu, mx1, 1));
    mx1 = fmaxf(mx1, __shfl_xor_sync(0xffffffffu, mx1, 2));
    float sum0 = 0.f, sum1 = 0.f;
#pragma unroll
    for (int nt = 0; nt < 16; nt++) {
        s[nt][0] = __expf(sc * (s[nt][0] - mx0)); sum0 += s[nt][0];
        s[nt][1] = __expf(sc * (s[nt][1] - mx0)); sum0 += s[nt][1];
        s[nt][2] = __expf(sc * (s[nt][2] - mx1)); sum1 += s[nt][2];
        s[nt][3] = __expf(sc * (s[nt][3] - mx1)); sum1 += s[nt][3];
    }
    sum0 += __shfl_xor_sync(0xffffffffu, sum0, 1);
    sum0 += __shfl_xor_sync(0xffffffffu, sum0, 2);
    sum1 += __shfl_xor_sync(0xffffffffu, sum1, 1);
    sum1 += __shfl_xor_sync(0xffffffffu, sum1, 2);
    const float inv0 = 1.f / sum0, inv1 = 1.f / sum1;
#pragma unroll
    for (int nt = 0; nt < 16; nt++) {
        s[nt][0] *= inv0; s[nt][1] *= inv0;
        s[nt][2] *= inv1; s[nt][3] *= inv1;
    }

    float o[8][4];
#pragma unroll
    for (int dt = 0; dt < 8; dt++)
#pragma unroll
        for (int e = 0; e < 4; e++) o[dt][e] = 0.f;

#pragma unroll
    for (int jc = 0; jc < 8; jc++) {
        uint32_t pah[4];
        pah[0] = pack_h2(s[2 * jc][0],     s[2 * jc][1]);
        pah[1] = pack_h2(s[2 * jc][2],     s[2 * jc][3]);
        pah[2] = pack_h2(s[2 * jc + 1][0], s[2 * jc + 1][1]);
        pah[3] = pack_h2(s[2 * jc + 1][2], s[2 * jc + 1][3]);
        const int jrow = jc * 16 + (lane & 7) + ((lane >> 3) & 1) * 8;
#pragma unroll
        for (int dg = 0; dg < 2; dg++) {
            uint32_t bh[4][2];
#pragma unroll
            for (int dpp = 0; dpp < 2; dpp++) {
                const int dt0 = dg * 4 + dpp * 2;
                const int dcol = dt0 * 8 + ((lane >> 4) & 1) * 8;
                ldsm4t(bh[dpp*2][0], bh[dpp*2][1], bh[dpp*2+1][0], bh[dpp*2+1][1],
                       smem_u32(svh + jrow * 72 + dcol));
            }
#pragma unroll
            for (int t = 0; t < 4; t++) mma16816(o[dg * 4 + t], pah, bh[t]);
        }
    }

    const int g = lane >> 2, tg = lane & 3;
    const int r0 = m0 + g, r1 = r0 + 8;
#pragma unroll
    for (int dt = 0; dt < 8; dt++) {
        const int d = head * 64 + dt * 8 + tg * 2;
        const size_t b0 = ((size_t)(r0 * MSAW + wi)) * INNER + d;
        const size_t b1 = ((size_t)(r1 * MSAW + wi)) * INNER + d;
        *(uint32_t*)(oh + b0) = pack_h2(o[dt][0], o[dt][1]);
        *(uint32_t*)(oh + b1) = pack_h2(o[dt][2], o[dt][3]);
    }
}

// ============= fused attention: dots tiles (blocks 0..127) + col attn (128..2175) =============
__global__ __launch_bounds__(256, 2)
void attn_fused(const hf* __restrict__ q1h, const hf* __restrict__ kv1h,
                const hf* __restrict__ q2h, const hf* __restrict__ kv2h,
                hf* __restrict__ o1h,
                float* __restrict__ Pp)
{
    const int b = blockIdx.x;
    if (b < 128) {
        const int j0 = (b & 1) * 128, i0 = ((b >> 1) & 1) * 128;
        const int z = b >> 2;
        const int h = z >> 2, s = z & 3;
        const size_t r0 = (size_t)s * 32;
        const size_t aoff = (size_t)h * 64 + (size_t)i0 * INNER + r0 * MSAW * INNER;
        const size_t boff = (size_t)h * 64 + (size_t)j0 * 2 * INNER + r0 * MSAW * 2 * INNER;
        gemm_core5<2, 4, 0, 0, 16, 4>(q2h + aoff, INNER, (size_t)MSAW * INNER,
                                      kv2h + boff, 2 * INNER, (size_t)MSAW * 2 * INNER,
                                      Pp + (size_t)z * (MSAW * MSAW) + (size_t)i0 * MSAW + j0,
                                      nullptr, MSAW, 32 * 64);
    } else {
        const int cb = b - 128;
        col_attn_body(cb & 255, cb >> 8, q1h, kv1h, o1h);
    }
}

// ============= reduce 4 dots partials + scale + softmax -> fp16 plane =============
__global__ __launch_bounds__(256)
void softmax_reduce2(const float* __restrict__ Pp, hf* __restrict__ Ph)
{
    const int h = blockIdx.x >> 8, i = blockIdx.x & 255;
    const int tid = threadIdx.x;
    __shared__ float red[34];
    float v = 0.f;
#pragma unroll
    for (int s = 0; s < 4; s++)
        v += Pp[((size_t)(h * 4 + s) * MSAW + i) * MSAW + tid];
    v *= 0.011048543456039806f;  // (1/8) * 128^-0.5

    float m = v;
#pragma unroll
    for (int o = 16; o; o >>= 1) m = fmaxf(m, __shfl_xor_sync(0xffffffffu, m, o));
    if ((tid & 31) == 0) red[tid >> 5] = m;
    __syncthreads();
    if (tid == 0) {
        float mm = red[0];
#pragma unroll
        for (int w = 1; w < 8; w++) mm = fmaxf(mm, red[w]);
        red[32] = mm;
    }
    __syncthreads();
    const float e = __expf(v - red[32]);
    float s = e;
#pragma unroll
    for (int o = 16; o; o >>= 1) s += __shfl_xor_sync(0xffffffffu, s, o);
    if ((tid & 31) == 0) red[8 + (tid >> 5)] = s;
    __syncthreads();
    if (tid == 0) {
        float ss = 0.f;
#pragma unroll
        for (int w = 0; w < 8; w++) ss += red[8 + w];
        red[33] = 1.f / ss;
    }
    __syncthreads();
    Ph[((size_t)h * MSAW + i) * MSAW + tid] = __float2half_rn(e * red[33]);
}

// =============================== launch ===============================
extern "C" void kernel_launch(void* const* d_in, const int* in_sizes, int n_in,
                              void* d_out, int out_size)
{
    const float* x      = (const float*)d_in[0];
    const float* wq_w   = (const float*)d_in[1];
    const float* wkv_w  = (const float*)d_in[2];
    const float* wout_w = (const float*)d_in[3];
    const float* wout_b = (const float*)d_in[4];
    const float* hq_w   = (const float*)d_in[5];
    const float* hkv_w  = (const float*)d_in[6];
    const float* hout_w = (const float*)d_in[7];
    const float* hout_b = (const float*)d_in[8];
    float* out = (float*)d_out;

    void* p;
    hf *xh, *wqh, *wkvh, *hqh, *hkvh, *wouth, *houth;
    hf *q1h, *kv1h, *q2h, *kv2h;
    hf *o1h, *o2h, *p2h;
    float* Pp;
    cudaGetSymbolAddress(&p, g_xh);    xh = (hf*)p;
    cudaGetSymbolAddress(&p, g_wqh);   wqh = (hf*)p;
    cudaGetSymbolAddress(&p, g_wkvh);  wkvh = (hf*)p;
    cudaGetSymbolAddress(&p, g_hqh);   hqh = (hf*)p;
    cudaGetSymbolAddress(&p, g_hkvh);  hkvh = (hf*)p;
    cudaGetSymbolAddress(&p, g_wouth); wouth = (hf*)p;
    cudaGetSymbolAddress(&p, g_houth); houth = (hf*)p;
    cudaGetSymbolAddress(&p, g_q1h);   q1h = (hf*)p;
    cudaGetSymbolAddress(&p, g_kv1h);  kv1h = (hf*)p;
    cudaGetSymbolAddress(&p, g_q2h);   q2h = (hf*)p;
    cudaGetSymbolAddress(&p, g_kv2h);  kv2h = (hf*)p;
    cudaGetSymbolAddress(&p, g_o1h);   o1h = (hf*)p;
    cudaGetSymbolAddress(&p, g_o2h);   o2h = (hf*)p;
    cudaGetSymbolAddress(&p, g_p2h);   p2h = (hf*)p;
    cudaGetSymbolAddress(&p, g_Pp);    Pp = (float*)p;

    cudaFuncSetAttribute(gemm_proj_all,  cudaFuncAttributeMaxDynamicSharedMemorySize, SM_PROJ);
    cudaFuncSetAttribute(gemm_out_fused, cudaFuncAttributeMaxDynamicSharedMemorySize, SM_PROJ);
    cudaFuncSetAttribute(gemm_av2,       cudaFuncAttributeMaxDynamicSharedMemorySize, SM_AV);
    cudaFuncSetAttribute(attn_fused,     cudaFuncAttributeMaxDynamicSharedMemorySize, ATTN_SMEM);

    split_all<<<8192 + 1024, 256>>>(x, wq_w, wkv_w, hq_w, hkv_w, wout_w, hout_w,
                                    xh, wqh, wkvh, hqh, hkvh, wouth, houth);

    gemm_proj_all<<<dim3(12, NTOK / 128, 2), 128, SM_PROJ>>>(
        xh, wqh, wkvh, hqh, hkvh, q1h, kv1h, q2h, kv2h);

    attn_fused<<<128 + MSAW * HEADS, 256, ATTN_SMEM>>>(
        q1h, kv1h, q2h, kv2h, o1h, Pp);

    softmax_reduce2<<<HEADS * MSAW, 256>>>(Pp, p2h);
    gemm_av2<<<dim3(2, HEADS, MSAH), 128, SM_AV>>>(p2h, kv2h, o2h);

    gemm_out_fused<<<dim3(2, NTOK / 128), 128, SM_PROJ>>>(
        o1h, o2h, wouth, houth, out, wout_b, hout_b);
}

// round 16
// speedup vs baseline: 9.1764x; 1.0412x over previous
#include <cuda_runtime.h>
#include <cuda_fp16.h>
#include <math.h>
#include <cstdint>

#define HEADS 8
#define DH    64
#define INNER 512
#define DIM   256
#define MSAH  128
#define MSAW  256
#define NTOK  (MSAH*MSAW)

typedef __half hf;

// -------- scratch (static device globals; no runtime allocation) --------
__device__ hf g_xh [(size_t)NTOK*DIM];
__device__ hf g_wqh [(size_t)DIM*INNER];
__device__ hf g_wkvh[(size_t)DIM*2*INNER];
__device__ hf g_hqh [(size_t)DIM*INNER];
__device__ hf g_hkvh[(size_t)DIM*2*INNER];
__device__ hf g_wouth[(size_t)INNER*DIM];
__device__ hf g_houth[(size_t)INNER*DIM];
__device__ hf g_q1h [(size_t)NTOK*INNER];
__device__ hf g_kv1h[(size_t)NTOK*2*INNER];
__device__ hf g_q2h [(size_t)NTOK*INNER];
__device__ hf g_kv2h[(size_t)NTOK*2*INNER];
__device__ hf g_o1h [(size_t)NTOK*INNER];
__device__ hf g_o2h [(size_t)NTOK*INNER];
__device__ hf g_p2h [(size_t)HEADS*MSAW*MSAW];
__device__ float g_Pp [(size_t)32*MSAW*MSAW];

// ===================== helpers =====================
__device__ __forceinline__ uint32_t smem_u32(const void* p) {
    uint32_t a;
    asm("{ .reg .u64 t; cvta.to.shared.u64 t, %1; cvt.u32.u64 %0, t; }" : "=r"(a) : "l"(p));
    return a;
}
__device__ __forceinline__ void ldsm4(uint32_t& r0, uint32_t& r1, uint32_t& r2, uint32_t& r3, uint32_t a) {
    asm volatile("ldmatrix.sync.aligned.m8n8.x4.shared.b16 {%0,%1,%2,%3}, [%4];"
                 : "=r"(r0), "=r"(r1), "=r"(r2), "=r"(r3) : "r"(a));
}
__device__ __forceinline__ void ldsm4t(uint32_t& r0, uint32_t& r1, uint32_t& r2, uint32_t& r3, uint32_t a) {
    asm volatile("ldmatrix.sync.aligned.m8n8.x4.trans.shared.b16 {%0,%1,%2,%3}, [%4];"
                 : "=r"(r0), "=r"(r1), "=r"(r2), "=r"(r3) : "r"(a));
}
__device__ __forceinline__ void mma16816(float* c, const uint32_t* a, const uint32_t* b) {
    asm volatile("mma.sync.aligned.m16n8k16.row.col.f32.f16.f16.f32 "
                 "{%0,%1,%2,%3}, {%4,%5,%6,%7}, {%8,%9}, {%0,%1,%2,%3};"
                 : "+f"(c[0]), "+f"(c[1]), "+f"(c[2]), "+f"(c[3])
                 : "r"(a[0]), "r"(a[1]), "r"(a[2]), "r"(a[3]), "r"(b[0]), "r"(b[1]));
}
__device__ __forceinline__ void cpa16(uint32_t dst, const void* src) {
    asm volatile("cp.async.cg.shared.global [%0], [%1], 16;" :: "r"(dst), "l"(src));
}
#define CP_COMMIT() asm volatile("cp.async.commit_group;" ::: "memory")
#define CP_WAIT1()  asm volatile("cp.async.wait_group 1;" ::: "memory")
#define CP_WAIT2()  asm volatile("cp.async.wait_group 2;" ::: "memory")
#define CP_WAIT0()  asm volatile("cp.async.wait_group 0;" ::: "memory")
__device__ __forceinline__ uint32_t pack_h2(float a, float b) {
    __half2 h2 = __halves2half2(__float2half_rn(a), __float2half_rn(b));
    return *(uint32_t*)&h2;
}

// ================= convert fp32 -> fp16 plane(s) (one launch) =================
__device__ __forceinline__ void conv_one(const float* in, hf* H, int i) {
    const float4 v = ((const float4*)in)[i];
    *(uint2*)(H + (size_t)i * 4) = make_uint2(pack_h2(v.x, v.y), pack_h2(v.z, v.w));
}
__global__ __launch_bounds__(256)
void split_all(const float* x, const float* wq, const float* wkv, const float* hq,
               const float* hkv, const float* wo, const float* ho,
               hf* xh, hf* wqh, hf* wkvh, hf* hqh, hf* hkvh, hf* woh, hf* hoh)
{
    const int b = blockIdx.x;
    if (b < 8192) {
        conv_one(x, xh, b * 256 + threadIdx.x);
        return;
    }
    const int i = (b - 8192) * 256 + threadIdx.x;
    if (i < 32768)        conv_one(wq,  wqh,  i);
    else if (i < 98304)   conv_one(wkv, wkvh, i - 32768);
    else if (i < 131072)  conv_one(hq,  hqh,  i - 98304);
    else if (i < 196608)  conv_one(hkv, hkvh, i - 131072);
    else if (i < 229376)  conv_one(wo,  woh,  i - 196608);
    else                  conv_one(ho,  hoh,  i - 229376);
}

// ======== big-tile GEMM core: 128x128 block, 4 warps, warp tile 64x64, CH=32, 3-stage ========
template<int OSPLIT, int DUAL>
__device__ __forceinline__ void gemm_core6(
    const hf* __restrict__ Ah_, size_t sAr,
    const hf* __restrict__ Bh_, size_t sBr,
    const hf* __restrict__ Ah2_, const hf* __restrict__ Bh2_, int K1,
    float* __restrict__ Cf, hf* __restrict__ Chp,
    int ldc, int K, const float* __restrict__ bias, const float* __restrict__ bias2)
{
    constexpr int CH = 32, NSTG = 3;
    constexpr int AP = 40;
    constexpr int BP = 136;
    constexpr int AH = 128 * AP;
    constexpr int BH = CH * BP;
    constexpr int STAGE = AH + BH;

    extern __shared__ hf smn[];
    const int tid = threadIdx.x, warp = tid >> 5, lane = tid & 31;
    const int wm = warp >> 1, wn = warp & 1;

    float c[4][8][4];
#pragma unroll
    for (int mt = 0; mt < 4; mt++)
#pragma unroll
        for (int nt = 0; nt < 8; nt++)
#pragma unroll
            for (int e = 0; e < 4; e++) c[mt][nt][e] = 0.f;

    auto issue = [&](int cc) {
        const int s = cc % NSTG;
        hf* Ah = smn + (size_t)s * STAGE;
        hf* Bh = Ah + AH;
        int k0 = cc * CH;
        const hf *Ap = Ah_, *Bp = Bh_;
        if (DUAL && k0 >= K1) { Ap = Ah2_; Bp = Bh2_; k0 -= K1; }
#pragma unroll
        for (int i = 0; i < 4; i++) {
            const int idx = i * 128 + tid;
            const int row = idx >> 2, g = (idx & 3) * 8;
            cpa16(smem_u32(Ah + row * AP + g), Ap + (size_t)row * sAr + k0 + g);
        }
#pragma unroll
        for (int i = 0; i < 4; i++) {
            const int idx = i * 128 + tid;
            const int kr = idx >> 4, q = (idx & 15) * 8;
            cpa16(smem_u32(Bh + kr * BP + q), Bp + (size_t)(k0 + kr) * sBr + q);
        }
    };

    auto compute = [&](int s) {
        hf* Ah = smn + (size_t)s * STAGE;
        hf* Bh = Ah + AH;
#pragma unroll
        for (int h = 0; h < 2; h++) {
            uint32_t ah[4][4];
#pragma unroll
            for (int mt = 0; mt < 4; mt++) {
                const int row = wm * 64 + mt * 16 + (lane & 15);
                const int ko = h * 16 + ((lane >> 4) & 1) * 8;
                ldsm4(ah[mt][0], ah[mt][1], ah[mt][2], ah[mt][3], smem_u32(Ah + row * AP + ko));
            }
#pragma unroll
            for (int bg = 0; bg < 2; bg++) {
                uint32_t bh[4][2];
#pragma unroll
                for (int np = 0; np < 2; np++) {
                    const int k = h * 16 + (lane & 7) + ((lane >> 3) & 1) * 8;
                    const int col = wn * 64 + bg * 32 + np * 16 + ((lane >> 4) & 1) * 8;
                    ldsm4t(bh[2*np][0], bh[2*np][1], bh[2*np+1][0], bh[2*np+1][1],
                           smem_u32(Bh + k * BP + col));
                }
#pragma unroll
                for (int mt = 0; mt < 4; mt++)
#pragma unroll
                    for (int t = 0; t < 4; t++)
                        mma16816(c[mt][bg * 4 + t], ah[mt], bh[t]);
            }
        }
    };

    const int NC = K / CH;
    issue(0); CP_COMMIT();
    issue(1); CP_COMMIT();
    for (int cc = 0; cc < NC; cc++) {
        CP_WAIT1();
        __syncthreads();
        if (cc + 2 < NC) issue(cc + 2);
        CP_COMMIT();
        compute(cc % NSTG);
    }

    const int g = lane >> 2, tg = lane & 3;
#pragma unroll
    for (int mt = 0; mt < 4; mt++) {
#pragma unroll
        for (int nt = 0; nt < 8; nt++) {
            const int row0 = wm * 64 + mt * 16 + g;
            const int col = wn * 64 + nt * 8 + tg * 2;
            float2 v0 = make_float2(c[mt][nt][0], c[mt][nt][1]);
            float2 v1 = make_float2(c[mt][nt][2], c[mt][nt][3]);
            if (OSPLIT) {
                *(uint32_t*)(Chp + (size_t)row0 * ldc + col) = pack_h2(v0.x, v0.y);
                *(uint32_t*)(Chp + (size_t)(row0 + 8) * ldc + col) = pack_h2(v1.x, v1.y);
            } else {
                float b0 = 0.f, b1 = 0.f;
                if (bias)  { b0 += bias[col];  b1 += bias[col + 1]; }
                if (bias2) { b0 += bias2[col]; b1 += bias2[col + 1]; }
                v0.x += b0; v0.y += b1; v1.x += b0; v1.y += b1;
                *(float2*)(Cf + (size_t)row0 * ldc + col) = v0;
                *(float2*)(Cf + (size_t)(row0 + 8) * ldc + col) = v1;
            }
        }
    }
}

// ======== 1-product GEMM (64x32 warp tile), both operands single plane ========
template<int WM, int WN, int BT, int OSPLIT, int CH, int NSTG>
__device__ __forceinline__ void gemm_core5(
    const hf* __restrict__ Ah_, size_t sAr, size_t sAk,
    const hf* __restrict__ Bh_, size_t sBr, size_t sBk,
    float* __restrict__ Cf, hf* __restrict__ Chp,
    int ldc, int K)
{
    constexpr int TM = WM * 64, TN = WN * 32;
    constexpr int THREADS = WM * WN * 32;
    constexpr int AP = CH + 8;
    constexpr int BP = BT ? (TN + 8) : (CH + 8);
    constexpr int AH = TM * AP;
    constexpr int BH = BT ? CH * BP : TN * AP;
    constexpr int STAGE = AH + BH;
    constexpr int C8 = CH / 8;
    constexpr int NA = TM * C8 / THREADS;
    constexpr int NB = BT ? (CH * TN / 8) / THREADS : (TN * C8) / THREADS;

    extern __shared__ hf smn[];
    const int tid = threadIdx.x, warp = tid >> 5, lane = tid & 31;
    const int wm = warp / WN, wn = warp % WN;

    float c[4][4][4];
#pragma unroll
    for (int mt = 0; mt < 4; mt++)
#pragma unroll
        for (int nt = 0; nt < 4; nt++)
#pragma unroll
            for (int e = 0; e < 4; e++) c[mt][nt][e] = 0.f;

    auto issue = [&](int cc) {
        const int s = cc % NSTG;
        hf* Ah = smn + (size_t)s * STAGE;
        hf* Bh = Ah + AH;
        int k0 = cc * CH;
        const size_t cb = (size_t)(k0 >> 6) * sAk + (k0 & 63);
#pragma unroll
        for (int i = 0; i < NA; i++) {
            const int idx = i * THREADS + tid;
            const int row = idx / C8, g = (idx % C8) * 8;
            cpa16(smem_u32(Ah + row * AP + g), Ah_ + (size_t)row * sAr + cb + g);
        }
#pragma unroll
        for (int i = 0; i < NB; i++) {
            const int idx = i * THREADS + tid;
            size_t go; int off;
            if (BT) {
                const int kr = idx / (TN / 8), q = idx % (TN / 8);
                go = (size_t)(k0 + kr) * sBr + q * 8;
                off = kr * BP + q * 8;
            } else {
                const int nr = idx / C8, g = (idx % C8) * 8;
                go = (size_t)nr * sBr + (size_t)(k0 >> 6) * sBk + (k0 & 63) + g;
                off = nr * AP + g;
            }
            cpa16(smem_u32(Bh + off), Bh_ + go);
        }
    };

    auto compute = [&](int s) {
        hf* Ah = smn + (size_t)s * STAGE;
        hf* Bh = Ah + AH;
#pragma unroll
        for (int h = 0; h < CH / 16; h++) {
            uint32_t ah[4][4], bh[4][2];
#pragma unroll
            for (int mt = 0; mt < 4; mt++) {
                const int row = wm * 64 + mt * 16 + (lane & 15);
                const int ko = h * 16 + ((lane >> 4) & 1) * 8;
                ldsm4(ah[mt][0], ah[mt][1], ah[mt][2], ah[mt][3], smem_u32(Ah + row * AP + ko));
            }
#pragma unroll
            for (int np = 0; np < 2; np++) {
                if (BT) {
                    const int k = h * 16 + (lane & 7) + ((lane >> 3) & 1) * 8;
                    const int col = wn * 32 + np * 16 + ((lane >> 4) & 1) * 8;
                    ldsm4t(bh[2*np][0], bh[2*np][1], bh[2*np+1][0], bh[2*np+1][1],
                           smem_u32(Bh + k * BP + col));
                } else {
                    const int nrow = wn * 32 + np * 16 + (lane & 7) + ((lane >> 4) & 1) * 8;
                    const int ko = h * 16 + ((lane >> 3) & 1) * 8;
                    ldsm4(bh[2*np][0], bh[2*np][1], bh[2*np+1][0], bh[2*np+1][1],
                          smem_u32(Bh + nrow * AP + ko));
                }
            }
#pragma unroll
            for (int mt = 0; mt < 4; mt++)
#pragma unroll
                for (int nt = 0; nt < 4; nt++)
                    mma16816(c[mt][nt], ah[mt], bh[nt]);
        }
    };

    const int NC = K / CH;
#pragma unroll
    for (int p = 0; p < NSTG - 1; p++) { issue(p); CP_COMMIT(); }
    for (int cc = 0; cc < NC; cc++) {
        if constexpr (NSTG == 3) CP_WAIT1(); else CP_WAIT2();
        __syncthreads();
        if (cc + NSTG - 1 < NC) issue(cc + NSTG - 1);
        CP_COMMIT();
        compute(cc % NSTG);
    }

    const int g = lane >> 2, tg = lane & 3;
#pragma unroll
    for (int mt = 0; mt < 4; mt++) {
#pragma unroll
        for (int nt = 0; nt < 4; nt++) {
            const int row0 = wm * 64 + mt * 16 + g;
            const int col = wn * 32 + nt * 8 + tg * 2;
            float2 v0 = make_float2(c[mt][nt][0], c[mt][nt][1]);
            float2 v1 = make_float2(c[mt][nt][2], c[mt][nt][3]);
            if (OSPLIT) {
                *(uint32_t*)(Chp + (size_t)row0 * ldc + col) = pack_h2(v0.x, v0.y);
                *(uint32_t*)(Chp + (size_t)(row0 + 8) * ldc + col) = pack_h2(v1.x, v1.y);
            } else {
                *(float2*)(Cf + (size_t)row0 * ldc + col) = v0;
                *(float2*)(Cf + (size_t)(row0 + 8) * ldc + col) = v1;
            }
        }
    }
}

// ---- wrappers ----
__global__ __launch_bounds__(128, 3)
void gemm_proj_all(const hf* __restrict__ xh,
                   const hf* __restrict__ wqh, const hf* __restrict__ wkvh,
                   const hf* __restrict__ hqh, const hf* __restrict__ hkvh,
                   hf* __restrict__ q1h, hf* __restrict__ kv1h,
                   hf* __restrict__ q2h, hf* __restrict__ kv2h)
{
    const int m0 = blockIdx.y * 128;
    const int n0 = blockIdx.x * 128;
    const int fam = blockIdx.z;
    const hf* Bh;
    hf* Ch;
    int ldc;
    if (n0 < INNER) {
        Bh = (fam ? hqh : wqh) + n0;
        Ch = (fam ? q2h : q1h) + (size_t)m0 * INNER + n0;
        ldc = INNER;
    } else {
        const int nn = n0 - INNER;
        Bh = (fam ? hkvh : wkvh) + nn;
        Ch = (fam ? kv2h : kv1h) + (size_t)m0 * 2 * INNER + nn;
        ldc = 2 * INNER;
    }
    const int Nw = (n0 < INNER) ? INNER : 2 * INNER;
    gemm_core6<1, 0>(xh + (size_t)m0 * DIM, DIM,
                     Bh, Nw,
                     nullptr, nullptr, 0,
                     nullptr, Ch, ldc, DIM, nullptr, nullptr);
}

__global__ __launch_bounds__(128, 3)
void gemm_out_fused(const hf* __restrict__ o1h, const hf* __restrict__ o2h,
                    const hf* __restrict__ wouth, const hf* __restrict__ houth,
                    float* __restrict__ C, const float* __restrict__ wout_b,
                    const float* __restrict__ hout_b)
{
    const int m0 = blockIdx.y * 128, n0 = blockIdx.x * 128;
    gemm_core6<0, 1>(o1h + (size_t)m0 * INNER, INNER,
                     wouth + n0, DIM,
                     o2h + (size_t)m0 * INNER, houth + n0, INNER,
                     C + (size_t)m0 * DIM + n0, nullptr,
                     DIM, 2 * INNER, wout_b + n0, hout_b + n0);
}

__global__ __launch_bounds__(128, 4)
void gemm_av2(const hf* __restrict__ Ph, const hf* __restrict__ Vh, hf* __restrict__ Oh)
{
    const int i0 = blockIdx.x * 128;
    const int h = blockIdx.y, r = blockIdx.z;
    const size_t aoff = (size_t)h * (MSAW * MSAW) + (size_t)i0 * MSAW;
    const size_t boff = (size_t)INNER + (size_t)h * 64 + (size_t)r * MSAW * 2 * INNER;
    const size_t coff = ((size_t)r * MSAW + i0) * INNER + h * 64;
    gemm_core5<2, 2, 1, 1, 16, 4>(Ph + aoff, MSAW, 64,
                                  Vh + boff, 2 * INNER, 0,
                                  nullptr, Oh + coff, INNER, MSAW);
}

// smem bytes
#define SM_PROJ (3 * (128 * 40 + 32 * 136) * 2)
#define SM_AV   (4 * (128 * 24 + 16 * 72) * 2)
#define SM_DOTS (4 * (128 * 24 + 128 * 24) * 2)
#define COL_SMEM2 (3 * 128 * 72 * 2)
#define ATTN_SMEM (SM_DOTS > COL_SMEM2 ? SM_DOTS : COL_SMEM2)

// ================= column attention body (1-product fp16 throughout) =================
__device__ __forceinline__
void col_attn_body(int wi, int head,
                   const hf* __restrict__ qh, const hf* __restrict__ kvh,
                   hf* __restrict__ oh)
{
    extern __shared__ hf smc[];
    const int PL = 128 * 72;
    hf *sqh = smc, *skh = smc + PL, *svh = smc + 2 * PL;

    const int tid = threadIdx.x, warp = tid >> 5, lane = tid & 31;

#pragma unroll
    for (int i = 0; i < 4; i++) {
        const int idx = i * 256 + tid;
        const int row = idx >> 3, g = (idx & 7) * 8;
        const size_t gq = ((size_t)(row * MSAW + wi)) * INNER + head * 64 + g;
        const size_t gk = ((size_t)(row * MSAW + wi)) * 2 * INNER + head * 64 + g;
        cpa16(smem_u32(sqh + row * 72 + g), qh + gq);
        cpa16(smem_u32(skh + row * 72 + g), kvh + gk);
        cpa16(smem_u32(svh + row * 72 + g), kvh + gk + INNER);
    }
    CP_COMMIT();
    CP_WAIT0();
    __syncthreads();

    const int m0 = warp * 16;
    float s[16][4];
#pragma unroll
    for (int nt = 0; nt < 16; nt++)
#pragma unroll
        for (int e = 0; e < 4; e++) s[nt][e] = 0.f;

#pragma unroll
    for (int kc = 0; kc < 4; kc++) {
        uint32_t ah[4];
        const int arow = m0 + (lane & 15);
        const int acol = kc * 16 + ((lane >> 4) & 1) * 8;
        ldsm4(ah[0], ah[1], ah[2], ah[3], smem_u32(sqh + arow * 72 + acol));
#pragma unroll
        for (int ng = 0; ng < 4; ng++) {
            uint32_t bh[4][2];
#pragma unroll
            for (int npp = 0; npp < 2; npp++) {
                const int nt0 = ng * 4 + npp * 2;
                const int brow = nt0 * 8 + (lane & 7) + ((lane >> 4) & 1) * 8;
                const int bcol = kc * 16 + ((lane >> 3) & 1) * 8;
                ldsm4(bh[npp*2][0], bh[npp*2][1], bh[npp*2+1][0], bh[npp*2+1][1],
                      smem_u32(skh + brow * 72 + bcol));
            }
#pragma unroll
            for (int t = 0; t < 4; t++) mma16816(s[ng * 4 + t], ah, bh[t]);
        }
    }

    const float sc = 0.125f;
    float mx0 = -1e30f, mx1 = -1e30f;
#pragma unroll
    for (int nt = 0; nt < 16; nt++) {
        mx0 = fmaxf(mx0, fmaxf(s[nt][0], s[nt][1]));
        mx1 = fmaxf(mx1, fmaxf(s[nt][2], s[nt][3]));
    }
    mx0 = fmaxf(mx0, __shfl_xor_sync(0xffffffffu, mx0, 1));
    mx0 = fmaxf(mx0, __shfl_xor_sync(0xffffffffu, mx0, 2));
    mx1 = fmaxf(mx1, __shfl_xor_sync(0xffffffffu, mx1, 1));
    mx1 = fmaxf(mx1, __shfl_xor_sync(0xffffffffu, mx1, 2));
    float sum0 = 0.f, sum1 = 0.f;
#pragma unroll
    for (int nt = 0; nt < 16; nt++) {
        s[nt][0] = __expf(sc * (s[nt][0] - mx0)); sum0 += s[nt][0];
        s[nt][1] = __expf(sc * (s[nt][1] - mx0)); sum0 += s[nt][1];
        s[nt][2] = __expf(sc * (s[nt][2] - mx1)); sum1 += s[nt][2];
        s[nt][3] = __expf(sc * (s[nt][3] - mx1)); sum1 += s[nt][3];
    }
    sum0 += __shfl_xor_sync(0xffffffffu, sum0, 1);
    sum0 += __shfl_xor_sync(0xffffffffu, sum0, 2);
    sum1 += __shfl_xor_sync(0xffffffffu, sum1, 1);
    sum1 += __shfl_xor_sync(0xffffffffu, sum1, 2);
    const float inv0 = 1.f / sum0, inv1 = 1.f / sum1;
#pragma unroll
    for (int nt = 0; nt < 16; nt++) {
        s[nt][0] *= inv0; s[nt][1] *= inv0;
        s[nt][2] *= inv1; s[nt][3] *= inv1;
    }

    float o[8][4];
#pragma unroll
    for (int dt = 0; dt < 8; dt++)
#pragma unroll
        for (int e = 0; e < 4; e++) o[dt][e] = 0.f;

#pragma unroll
    for (int jc = 0; jc < 8; jc++) {
        uint32_t pah[4];
        pah[0] = pack_h2(s[2 * jc][0],     s[2 * jc][1]);
        pah[1] = pack_h2(s[2 * jc][2],     s[2 * jc][3]);
        pah[2] = pack_h2(s[2 * jc + 1][0], s[2 * jc + 1][1]);
        pah[3] = pack_h2(s[2 * jc + 1][2], s[2 * jc + 1][3]);
        const int jrow = jc * 16 + (lane & 7) + ((lane >> 3) & 1) * 8;
#pragma unroll
        for (int dg = 0; dg < 2; dg++) {
            uint32_t bh[4][2];
#pragma unroll
            for (int dpp = 0; dpp < 2; dpp++) {
                const int dt0 = dg * 4 + dpp * 2;
                const int dcol = dt0 * 8 + ((lane >> 4) & 1) * 8;
                ldsm4t(bh[dpp*2][0], bh[dpp*2][1], bh[dpp*2+1][0], bh[dpp*2+1][1],
                       smem_u32(svh + jrow * 72 + dcol));
            }
#pragma unroll
            for (int t = 0; t < 4; t++) mma16816(o[dg * 4 + t], pah, bh[t]);
        }
    }

    const int g = lane >> 2, tg = lane & 3;
    const int r0 = m0 + g, r1 = r0 + 8;
#pragma unroll
    for (int dt = 0; dt < 8; dt++) {
        const int d = head * 64 + dt * 8 + tg * 2;
        const size_t b0 = ((size_t)(r0 * MSAW + wi)) * INNER + d;
        const size_t b1 = ((size_t)(r1 * MSAW + wi)) * INNER + d;
        *(uint32_t*)(oh + b0) = pack_h2(o[dt][0], o[dt][1]);
        *(uint32_t*)(oh + b1) = pack_h2(o[dt][2], o[dt][3]);
    }
}

// ============= fused attention: dots tiles (blocks 0..127) + col attn (128..2175) =============
__global__ __launch_bounds__(256, 2)
void attn_fused(const hf* __restrict__ q1h, const hf* __restrict__ kv1h,
                const hf* __restrict__ q2h, const hf* __restrict__ kv2h,
                hf* __restrict__ o1h,
                float* __restrict__ Pp)
{
    const int b = blockIdx.x;
    if (b < 128) {
        const int j0 = (b & 1) * 128, i0 = ((b >> 1) & 1) * 128;
        const int z = b >> 2;
        const int h = z >> 2, s = z & 3;
        const size_t r0 = (size_t)s * 32;
        const size_t aoff = (size_t)h * 64 + (size_t)i0 * INNER + r0 * MSAW * INNER;
        const size_t boff = (size_t)h * 64 + (size_t)j0 * 2 * INNER + r0 * MSAW * 2 * INNER;
        gemm_core5<2, 4, 0, 0, 16, 4>(q2h + aoff, INNER, (size_t)MSAW * INNER,
                                      kv2h + boff, 2 * INNER, (size_t)MSAW * 2 * INNER,
                                      Pp + (size_t)z * (MSAW * MSAW) + (size_t)i0 * MSAW + j0,
                                      nullptr, MSAW, 32 * 64);
    } else {
        const int cb = b - 128;
        col_attn_body(cb & 255, cb >> 8, q1h, kv1h, o1h);
    }
}

// ============= reduce 4 dots partials + scale + softmax -> fp16 plane =============
__global__ __launch_bounds__(256)
void softmax_reduce2(const float* __restrict__ Pp, hf* __restrict__ Ph)
{
    const int h = blockIdx.x >> 8, i = blockIdx.x & 255;
    const int tid = threadIdx.x;
    __shared__ float red[34];
    float v = 0.f;
#pragma unroll
    for (int s = 0; s < 4; s++)
        v += Pp[((size_t)(h * 4 + s) * MSAW + i) * MSAW + tid];
    v *= 0.011048543456039806f;  // (1/8) * 128^-0.5

    float m = v;
#pragma unroll
    for (int o = 16; o; o >>= 1) m = fmaxf(m, __shfl_xor_sync(0xffffffffu, m, o));
    if ((tid & 31) == 0) red[tid >> 5] = m;
    __syncthreads();
    if (tid == 0) {
        float mm = red[0];
#pragma unroll
        for (int w = 1; w < 8; w++) mm = fmaxf(mm, red[w]);
        red[32] = mm;
    }
    __syncthreads();
    const float e = __expf(v - red[32]);
    float s = e;
#pragma unroll
    for (int o = 16; o; o >>= 1) s += __shfl_xor_sync(0xffffffffu, s, o);
    if ((tid & 31) == 0) red[8 + (tid >> 5)] = s;
    __syncthreads();
    if (tid == 0) {
        float ss = 0.f;
#pragma unroll
        for (int w = 0; w < 8; w++) ss += red[8 + w];
        red[33] = 1.f / ss;
    }
    __syncthreads();
    Ph[((size_t)h * MSAW + i) * MSAW + tid] = __float2half_rn(e * red[33]);
}

// =============================== launch ===============================
extern "C" void kernel_launch(void* const* d_in, const int* in_sizes, int n_in,
                              void* d_out, int out_size)
{
    const float* x      = (const float*)d_in[0];
    const float* wq_w   = (const float*)d_in[1];
    const float* wkv_w  = (const float*)d_in[2];
    const float* wout_w = (const float*)d_in[3];
    const float* wout_b = (const float*)d_in[4];
    const float* hq_w   = (const float*)d_in[5];
    const float* hkv_w  = (const float*)d_in[6];
    const float* hout_w = (const float*)d_in[7];
    const float* hout_b = (const float*)d_in[8];
    float* out = (float*)d_out;

    void* p;
    hf *xh, *wqh, *wkvh, *hqh, *hkvh, *wouth, *houth;
    hf *q1h, *kv1h, *q2h, *kv2h;
    hf *o1h, *o2h, *p2h;
    float* Pp;
    cudaGetSymbolAddress(&p, g_xh);    xh = (hf*)p;
    cudaGetSymbolAddress(&p, g_wqh);   wqh = (hf*)p;
    cudaGetSymbolAddress(&p, g_wkvh);  wkvh = (hf*)p;
    cudaGetSymbolAddress(&p, g_hqh);   hqh = (hf*)p;
    cudaGetSymbolAddress(&p, g_hkvh);  hkvh = (hf*)p;
    cudaGetSymbolAddress(&p, g_wouth); wouth = (hf*)p;
    cudaGetSymbolAddress(&p, g_houth); houth = (hf*)p;
    cudaGetSymbolAddress(&p, g_q1h);   q1h = (hf*)p;
    cudaGetSymbolAddress(&p, g_kv1h);  kv1h = (hf*)p;
    cudaGetSymbolAddress(&p, g_q2h);   q2h = (hf*)p;
    cudaGetSymbolAddress(&p, g_kv2h);  kv2h = (hf*)p;
    cudaGetSymbolAddress(&p, g_o1h);   o1h = (hf*)p;
    cudaGetSymbolAddress(&p, g_o2h);   o2h = (hf*)p;
    cudaGetSymbolAddress(&p, g_p2h);   p2h = (hf*)p;
    cudaGetSymbolAddress(&p, g_Pp);    Pp = (float*)p;

    cudaFuncSetAttribute(gemm_proj_all,  cudaFuncAttributeMaxDynamicSharedMemorySize, SM_PROJ);
    cudaFuncSetAttribute(gemm_out_fused, cudaFuncAttributeMaxDynamicSharedMemorySize, SM_PROJ);
    cudaFuncSetAttribute(gemm_av2,       cudaFuncAttributeMaxDynamicSharedMemorySize, SM_AV);
    cudaFuncSetAttribute(attn_fused,     cudaFuncAttributeMaxDynamicSharedMemorySize, ATTN_SMEM);

    split_all<<<8192 + 1024, 256>>>(x, wq_w, wkv_w, hq_w, hkv_w, wout_w, hout_w,
                                    xh, wqh, wkvh, hqh, hkvh, wouth, houth);

    gemm_proj_all<<<dim3(12, NTOK / 128, 2), 128, SM_PROJ>>>(
        xh, wqh, wkvh, hqh, hkvh, q1h, kv1h, q2h, kv2h);

    attn_fused<<<128 + MSAW * HEADS, 256, ATTN_SMEM>>>(
        q1h, kv1h, q2h, kv2h, o1h, Pp);

    softmax_reduce2<<<HEADS * MSAW, 256>>>(Pp, p2h);
    gemm_av2<<<dim3(2, HEADS, MSAH), 128, SM_AV>>>(p2h, kv2h, o2h);

    gemm_out_fused<<<dim3(2, NTOK / 128), 128, SM_PROJ>>>(
        o1h, o2h, wouth, houth, out, wout_b, hout_b);
}

// round 17
// speedup vs baseline: 9.2935x; 1.0128x over previous
#include <cuda_runtime.h>
#include <cuda_fp16.h>
#include <math.h>
#include <cstdint>

#define HEADS 8
#define DH    64
#define INNER 512
#define DIM   256
#define MSAH  128
#define MSAW  256
#define NTOK  (MSAH*MSAW)

typedef __half hf;

// -------- scratch (static device globals; no runtime allocation) --------
__device__ hf g_xh [(size_t)NTOK*DIM];
__device__ hf g_wqh [(size_t)DIM*INNER];
__device__ hf g_wkvh[(size_t)DIM*2*INNER];
__device__ hf g_hqh [(size_t)DIM*INNER];
__device__ hf g_hkvh[(size_t)DIM*2*INNER];
__device__ hf g_wouth[(size_t)INNER*DIM];
__device__ hf g_houth[(size_t)INNER*DIM];
__device__ hf g_q1h [(size_t)NTOK*INNER];
__device__ hf g_kv1h[(size_t)NTOK*2*INNER];
__device__ hf g_q2h [(size_t)NTOK*INNER];
__device__ hf g_kv2h[(size_t)NTOK*2*INNER];
__device__ hf g_o1h [(size_t)NTOK*INNER];
__device__ hf g_o2h [(size_t)NTOK*INNER];
__device__ hf g_p2h [(size_t)HEADS*MSAW*MSAW];
__device__ float g_Pp [(size_t)32*MSAW*MSAW];

// ===================== helpers =====================
__device__ __forceinline__ uint32_t smem_u32(const void* p) {
    uint32_t a;
    asm("{ .reg .u64 t; cvta.to.shared.u64 t, %1; cvt.u32.u64 %0, t; }" : "=r"(a) : "l"(p));
    return a;
}
__device__ __forceinline__ void ldsm4(uint32_t& r0, uint32_t& r1, uint32_t& r2, uint32_t& r3, uint32_t a) {
    asm volatile("ldmatrix.sync.aligned.m8n8.x4.shared.b16 {%0,%1,%2,%3}, [%4];"
                 : "=r"(r0), "=r"(r1), "=r"(r2), "=r"(r3) : "r"(a));
}
__device__ __forceinline__ void ldsm4t(uint32_t& r0, uint32_t& r1, uint32_t& r2, uint32_t& r3, uint32_t a) {
    asm volatile("ldmatrix.sync.aligned.m8n8.x4.trans.shared.b16 {%0,%1,%2,%3}, [%4];"
                 : "=r"(r0), "=r"(r1), "=r"(r2), "=r"(r3) : "r"(a));
}
__device__ __forceinline__ void mma16816(float* c, const uint32_t* a, const uint32_t* b) {
    asm volatile("mma.sync.aligned.m16n8k16.row.col.f32.f16.f16.f32 "
                 "{%0,%1,%2,%3}, {%4,%5,%6,%7}, {%8,%9}, {%0,%1,%2,%3};"
                 : "+f"(c[0]), "+f"(c[1]), "+f"(c[2]), "+f"(c[3])
                 : "r"(a[0]), "r"(a[1]), "r"(a[2]), "r"(a[3]), "r"(b[0]), "r"(b[1]));
}
__device__ __forceinline__ void cpa16(uint32_t dst, const void* src) {
    asm volatile("cp.async.cg.shared.global [%0], [%1], 16;" :: "r"(dst), "l"(src));
}
#define CP_COMMIT() asm volatile("cp.async.commit_group;" ::: "memory")
#define CP_WAIT1()  asm volatile("cp.async.wait_group 1;" ::: "memory")
#define CP_WAIT2()  asm volatile("cp.async.wait_group 2;" ::: "memory")
#define CP_WAIT0()  asm volatile("cp.async.wait_group 0;" ::: "memory")
__device__ __forceinline__ uint32_t pack_h2(float a, float b) {
    __half2 h2 = __halves2half2(__float2half_rn(a), __float2half_rn(b));
    return *(uint32_t*)&h2;
}

// ================= convert fp32 -> fp16 plane(s) (one launch) =================
__device__ __forceinline__ void conv_one(const float* in, hf* H, int i) {
    const float4 v = ((const float4*)in)[i];
    *(uint2*)(H + (size_t)i * 4) = make_uint2(pack_h2(v.x, v.y), pack_h2(v.z, v.w));
}
__global__ __launch_bounds__(256)
void split_all(const float* x, const float* wq, const float* wkv, const float* hq,
               const float* hkv, const float* wo, const float* ho,
               hf* xh, hf* wqh, hf* wkvh, hf* hqh, hf* hkvh, hf* woh, hf* hoh)
{
    const int b = blockIdx.x;
    if (b < 8192) {
        conv_one(x, xh, b * 256 + threadIdx.x);
        return;
    }
    const int i = (b - 8192) * 256 + threadIdx.x;
    if (i < 32768)        conv_one(wq,  wqh,  i);
    else if (i < 98304)   conv_one(wkv, wkvh, i - 32768);
    else if (i < 131072)  conv_one(hq,  hqh,  i - 98304);
    else if (i < 196608)  conv_one(hkv, hkvh, i - 131072);
    else if (i < 229376)  conv_one(wo,  woh,  i - 196608);
    else                  conv_one(ho,  hoh,  i - 229376);
}

// ======== big-tile GEMM core: 128x128 block, 4 warps, warp tile 64x64, CH=32, 3-stage ========
template<int OSPLIT, int DUAL>
__device__ __forceinline__ void gemm_core6(
    const hf* __restrict__ Ah_, size_t sAr,
    const hf* __restrict__ Bh_, size_t sBr,
    const hf* __restrict__ Ah2_, const hf* __restrict__ Bh2_, int K1,
    float* __restrict__ Cf, hf* __restrict__ Chp,
    int ldc, int K, const float* __restrict__ bias, const float* __restrict__ bias2)
{
    constexpr int CH = 32, NSTG = 3;
    constexpr int AP = 40;
    constexpr int BP = 136;
    constexpr int AH = 128 * AP;
    constexpr int BH = CH * BP;
    constexpr int STAGE = AH + BH;

    extern __shared__ hf smn[];
    const int tid = threadIdx.x, warp = tid >> 5, lane = tid & 31;
    const int wm = warp >> 1, wn = warp & 1;

    float c[4][8][4];
#pragma unroll
    for (int mt = 0; mt < 4; mt++)
#pragma unroll
        for (int nt = 0; nt < 8; nt++)
#pragma unroll
            for (int e = 0; e < 4; e++) c[mt][nt][e] = 0.f;

    auto issue = [&](int cc) {
        const int s = cc % NSTG;
        hf* Ah = smn + (size_t)s * STAGE;
        hf* Bh = Ah + AH;
        int k0 = cc * CH;
        const hf *Ap = Ah_, *Bp = Bh_;
        if (DUAL && k0 >= K1) { Ap = Ah2_; Bp = Bh2_; k0 -= K1; }
#pragma unroll
        for (int i = 0; i < 4; i++) {
            const int idx = i * 128 + tid;
            const int row = idx >> 2, g = (idx & 3) * 8;
            cpa16(smem_u32(Ah + row * AP + g), Ap + (size_t)row * sAr + k0 + g);
        }
#pragma unroll
        for (int i = 0; i < 4; i++) {
            const int idx = i * 128 + tid;
            const int kr = idx >> 4, q = (idx & 15) * 8;
            cpa16(smem_u32(Bh + kr * BP + q), Bp + (size_t)(k0 + kr) * sBr + q);
        }
    };

    auto compute = [&](int s) {
        hf* Ah = smn + (size_t)s * STAGE;
        hf* Bh = Ah + AH;
#pragma unroll
        for (int h = 0; h < 2; h++) {
            uint32_t ah[4][4];
#pragma unroll
            for (int mt = 0; mt < 4; mt++) {
                const int row = wm * 64 + mt * 16 + (lane & 15);
                const int ko = h * 16 + ((lane >> 4) & 1) * 8;
                ldsm4(ah[mt][0], ah[mt][1], ah[mt][2], ah[mt][3], smem_u32(Ah + row * AP + ko));
            }
#pragma unroll
            for (int bg = 0; bg < 2; bg++) {
                uint32_t bh[4][2];
#pragma unroll
                for (int np = 0; np < 2; np++) {
                    const int k = h * 16 + (lane & 7) + ((lane >> 3) & 1) * 8;
                    const int col = wn * 64 + bg * 32 + np * 16 + ((lane >> 4) & 1) * 8;
                    ldsm4t(bh[2*np][0], bh[2*np][1], bh[2*np+1][0], bh[2*np+1][1],
                           smem_u32(Bh + k * BP + col));
                }
#pragma unroll
                for (int mt = 0; mt < 4; mt++)
#pragma unroll
                    for (int t = 0; t < 4; t++)
                        mma16816(c[mt][bg * 4 + t], ah[mt], bh[t]);
            }
        }
    };

    const int NC = K / CH;
    issue(0); CP_COMMIT();
    issue(1); CP_COMMIT();
    for (int cc = 0; cc < NC; cc++) {
        CP_WAIT1();
        __syncthreads();
        if (cc + 2 < NC) issue(cc + 2);
        CP_COMMIT();
        compute(cc % NSTG);
    }

    const int g = lane >> 2, tg = lane & 3;
#pragma unroll
    for (int mt = 0; mt < 4; mt++) {
#pragma unroll
        for (int nt = 0; nt < 8; nt++) {
            const int row0 = wm * 64 + mt * 16 + g;
            const int col = wn * 64 + nt * 8 + tg * 2;
            float2 v0 = make_float2(c[mt][nt][0], c[mt][nt][1]);
            float2 v1 = make_float2(c[mt][nt][2], c[mt][nt][3]);
            if (OSPLIT) {
                *(uint32_t*)(Chp + (size_t)row0 * ldc + col) = pack_h2(v0.x, v0.y);
                *(uint32_t*)(Chp + (size_t)(row0 + 8) * ldc + col) = pack_h2(v1.x, v1.y);
            } else {
                float b0 = 0.f, b1 = 0.f;
                if (bias)  { b0 += bias[col];  b1 += bias[col + 1]; }
                if (bias2) { b0 += bias2[col]; b1 += bias2[col + 1]; }
                v0.x += b0; v0.y += b1; v1.x += b0; v1.y += b1;
                *(float2*)(Cf + (size_t)row0 * ldc + col) = v0;
                *(float2*)(Cf + (size_t)(row0 + 8) * ldc + col) = v1;
            }
        }
    }
}

// ======== 1-product GEMM (64x32 warp tile), both operands single plane ========
template<int WM, int WN, int BT, int OSPLIT, int CH, int NSTG>
__device__ __forceinline__ void gemm_core5(
    const hf* __restrict__ Ah_, size_t sAr, size_t sAk,
    const hf* __restrict__ Bh_, size_t sBr, size_t sBk,
    float* __restrict__ Cf, hf* __restrict__ Chp,
    int ldc, int K)
{
    constexpr int TM = WM * 64, TN = WN * 32;
    constexpr int THREADS = WM * WN * 32;
    constexpr int AP = CH + 8;
    constexpr int BP = BT ? (TN + 8) : (CH + 8);
    constexpr int AH = TM * AP;
    constexpr int BH = BT ? CH * BP : TN * AP;
    constexpr int STAGE = AH + BH;
    constexpr int C8 = CH / 8;
    constexpr int NA = TM * C8 / THREADS;
    constexpr int NB = BT ? (CH * TN / 8) / THREADS : (TN * C8) / THREADS;

    extern __shared__ hf smn[];
    const int tid = threadIdx.x, warp = tid >> 5, lane = tid & 31;
    const int wm = warp / WN, wn = warp % WN;

    float c[4][4][4];
#pragma unroll
    for (int mt = 0; mt < 4; mt++)
#pragma unroll
        for (int nt = 0; nt < 4; nt++)
#pragma unroll
            for (int e = 0; e < 4; e++) c[mt][nt][e] = 0.f;

    auto issue = [&](int cc) {
        const int s = cc % NSTG;
        hf* Ah = smn + (size_t)s * STAGE;
        hf* Bh = Ah + AH;
        int k0 = cc * CH;
        const size_t cb = (size_t)(k0 >> 6) * sAk + (k0 & 63);
#pragma unroll
        for (int i = 0; i < NA; i++) {
            const int idx = i * THREADS + tid;
            const int row = idx / C8, g = (idx % C8) * 8;
            cpa16(smem_u32(Ah + row * AP + g), Ah_ + (size_t)row * sAr + cb + g);
        }
#pragma unroll
        for (int i = 0; i < NB; i++) {
            const int idx = i * THREADS + tid;
            size_t go; int off;
            if (BT) {
                const int kr = idx / (TN / 8), q = idx % (TN / 8);
                go = (size_t)(k0 + kr) * sBr + q * 8;
                off = kr * BP + q * 8;
            } else {
                const int nr = idx / C8, g = (idx % C8) * 8;
                go = (size_t)nr * sBr + (size_t)(k0 >> 6) * sBk + (k0 & 63) + g;
                off = nr * AP + g;
            }
            cpa16(smem_u32(Bh + off), Bh_ + go);
        }
    };

    auto compute = [&](int s) {
        hf* Ah = smn + (size_t)s * STAGE;
        hf* Bh = Ah + AH;
#pragma unroll
        for (int h = 0; h < CH / 16; h++) {
            uint32_t ah[4][4], bh[4][2];
#pragma unroll
            for (int mt = 0; mt < 4; mt++) {
                const int row = wm * 64 + mt * 16 + (lane & 15);
                const int ko = h * 16 + ((lane >> 4) & 1) * 8;
                ldsm4(ah[mt][0], ah[mt][1], ah[mt][2], ah[mt][3], smem_u32(Ah + row * AP + ko));
            }
#pragma unroll
            for (int np = 0; np < 2; np++) {
                if (BT) {
                    const int k = h * 16 + (lane & 7) + ((lane >> 3) & 1) * 8;
                    const int col = wn * 32 + np * 16 + ((lane >> 4) & 1) * 8;
                    ldsm4t(bh[2*np][0], bh[2*np][1], bh[2*np+1][0], bh[2*np+1][1],
                           smem_u32(Bh + k * BP + col));
                } else {
                    const int nrow = wn * 32 + np * 16 + (lane & 7) + ((lane >> 4) & 1) * 8;
                    const int ko = h * 16 + ((lane >> 3) & 1) * 8;
                    ldsm4(bh[2*np][0], bh[2*np][1], bh[2*np+1][0], bh[2*np+1][1],
                          smem_u32(Bh + nrow * AP + ko));
                }
            }
#pragma unroll
            for (int mt = 0; mt < 4; mt++)
#pragma unroll
                for (int nt = 0; nt < 4; nt++)
                    mma16816(c[mt][nt], ah[mt], bh[nt]);
        }
    };

    const int NC = K / CH;
#pragma unroll
    for (int p = 0; p < NSTG - 1; p++) { issue(p); CP_COMMIT(); }
    for (int cc = 0; cc < NC; cc++) {
        if constexpr (NSTG == 3) CP_WAIT1(); else CP_WAIT2();
        __syncthreads();
        if (cc + NSTG - 1 < NC) issue(cc + NSTG - 1);
        CP_COMMIT();
        compute(cc % NSTG);
    }

    const int g = lane >> 2, tg = lane & 3;
#pragma unroll
    for (int mt = 0; mt < 4; mt++) {
#pragma unroll
        for (int nt = 0; nt < 4; nt++) {
            const int row0 = wm * 64 + mt * 16 + g;
            const int col = wn * 32 + nt * 8 + tg * 2;
            float2 v0 = make_float2(c[mt][nt][0], c[mt][nt][1]);
            float2 v1 = make_float2(c[mt][nt][2], c[mt][nt][3]);
            if (OSPLIT) {
                *(uint32_t*)(Chp + (size_t)row0 * ldc + col) = pack_h2(v0.x, v0.y);
                *(uint32_t*)(Chp + (size_t)(row0 + 8) * ldc + col) = pack_h2(v1.x, v1.y);
            } else {
                *(float2*)(Cf + (size_t)row0 * ldc + col) = v0;
                *(float2*)(Cf + (size_t)(row0 + 8) * ldc + col) = v1;
            }
        }
    }
}

// ---- wrappers ----
__global__ __launch_bounds__(128, 3)
void gemm_proj_all(const hf* __restrict__ xh,
                   const hf* __restrict__ wqh, const hf* __restrict__ wkvh,
                   const hf* __restrict__ hqh, const hf* __restrict__ hkvh,
                   hf* __restrict__ q1h, hf* __restrict__ kv1h,
                   hf* __restrict__ q2h, hf* __restrict__ kv2h)
{
    const int m0 = blockIdx.y * 128;
    const int n0 = blockIdx.x * 128;
    const int fam = blockIdx.z;
    const hf* Bh;
    hf* Ch;
    int ldc;
    if (n0 < INNER) {
        Bh = (fam ? hqh : wqh) + n0;
        Ch = (fam ? q2h : q1h) + (size_t)m0 * INNER + n0;
        ldc = INNER;
    } else {
        const int nn = n0 - INNER;
        Bh = (fam ? hkvh : wkvh) + nn;
        Ch = (fam ? kv2h : kv1h) + (size_t)m0 * 2 * INNER + nn;
        ldc = 2 * INNER;
    }
    const int Nw = (n0 < INNER) ? INNER : 2 * INNER;
    gemm_core6<1, 0>(xh + (size_t)m0 * DIM, DIM,
                     Bh, Nw,
                     nullptr, nullptr, 0,
                     nullptr, Ch, ldc, DIM, nullptr, nullptr);
}

__global__ __launch_bounds__(128, 3)
void gemm_out_fused(const hf* __restrict__ o1h, const hf* __restrict__ o2h,
                    const hf* __restrict__ wouth, const hf* __restrict__ houth,
                    float* __restrict__ C, const float* __restrict__ wout_b,
                    const float* __restrict__ hout_b)
{
    const int m0 = blockIdx.y * 128, n0 = blockIdx.x * 128;
    gemm_core6<0, 1>(o1h + (size_t)m0 * INNER, INNER,
                     wouth + n0, DIM,
                     o2h + (size_t)m0 * INNER, houth + n0, INNER,
                     C + (size_t)m0 * DIM + n0, nullptr,
                     DIM, 2 * INNER, wout_b + n0, hout_b + n0);
}

__global__ __launch_bounds__(128, 4)
void gemm_av2(const hf* __restrict__ Ph, const hf* __restrict__ Vh, hf* __restrict__ Oh)
{
    const int i0 = blockIdx.x * 128;
    const int h = blockIdx.y, r = blockIdx.z;
    const size_t aoff = (size_t)h * (MSAW * MSAW) + (size_t)i0 * MSAW;
    const size_t boff = (size_t)INNER + (size_t)h * 64 + (size_t)r * MSAW * 2 * INNER;
    const size_t coff = ((size_t)r * MSAW + i0) * INNER + h * 64;
    gemm_core5<2, 2, 1, 1, 32, 3>(Ph + aoff, MSAW, 64,
                                  Vh + boff, 2 * INNER, 0,
                                  nullptr, Oh + coff, INNER, MSAW);
}

// smem bytes
#define SM_PROJ (3 * (128 * 40 + 32 * 136) * 2)
#define SM_AV   (3 * (128 * 40 + 32 * 72) * 2)
#define SM_DOTS (3 * (128 * 40 + 128 * 40) * 2)
#define COL_SMEM2 (3 * 128 * 72 * 2)
#define ATTN_SMEM (SM_DOTS > COL_SMEM2 ? SM_DOTS : COL_SMEM2)

// ================= column attention body (1-product fp16 throughout) =================
__device__ __forceinline__
void col_attn_body(int wi, int head,
                   const hf* __restrict__ qh, const hf* __restrict__ kvh,
                   hf* __restrict__ oh)
{
    extern __shared__ hf smc[];
    const int PL = 128 * 72;
    hf *sqh = smc, *skh = smc + PL, *svh = smc + 2 * PL;

    const int tid = threadIdx.x, warp = tid >> 5, lane = tid & 31;

#pragma unroll
    for (int i = 0; i < 4; i++) {
        const int idx = i * 256 + tid;
        const int row = idx >> 3, g = (idx & 7) * 8;
        const size_t gq = ((size_t)(row * MSAW + wi)) * INNER + head * 64 + g;
        const size_t gk = ((size_t)(row * MSAW + wi)) * 2 * INNER + head * 64 + g;
        cpa16(smem_u32(sqh + row * 72 + g), qh + gq);
        cpa16(smem_u32(skh + row * 72 + g), kvh + gk);
        cpa16(smem_u32(svh + row * 72 + g), kvh + gk + INNER);
    }
    CP_COMMIT();
    CP_WAIT0();
    __syncthreads();

    const int m0 = warp * 16;
    float s[16][4];
#pragma unroll
    for (int nt = 0; nt < 16; nt++)
#pragma unroll
        for (int e = 0; e < 4; e++) s[nt][e] = 0.f;

#pragma unroll
    for (int kc = 0; kc < 4; kc++) {
        uint32_t ah[4];
        const int arow = m0 + (lane & 15);
        const int acol = kc * 16 + ((lane >> 4) & 1) * 8;
        ldsm4(ah[0], ah[1], ah[2], ah[3], smem_u32(sqh + arow * 72 + acol));
#pragma unroll
        for (int ng = 0; ng < 4; ng++) {
            uint32_t bh[4][2];
#pragma unroll
            for (int npp = 0; npp < 2; npp++) {
                const int nt0 = ng * 4 + npp * 2;
                const int brow = nt0 * 8 + (lane & 7) + ((lane >> 4) & 1) * 8;
                const int bcol = kc * 16 + ((lane >> 3) & 1) * 8;
                ldsm4(bh[npp*2][0], bh[npp*2][1], bh[npp*2+1][0], bh[npp*2+1][1],
                      smem_u32(skh + brow * 72 + bcol));
            }
#pragma unroll
            for (int t = 0; t < 4; t++) mma16816(s[ng * 4 + t], ah, bh[t]);
        }
    }

    const float sc = 0.125f;
    float mx0 = -1e30f, mx1 = -1e30f;
#pragma unroll
    for (int nt = 0; nt < 16; nt++) {
        mx0 = fmaxf(mx0, fmaxf(s[nt][0], s[nt][1]));
        mx1 = fmaxf(mx1, fmaxf(s[nt][2], s[nt][3]));
    }
    mx0 = fmaxf(mx0, __shfl_xor_sync(0xffffffffu, mx0, 1));
    mx0 = fmaxf(mx0, __shfl_xor_sync(0xffffffffu, mx0, 2));
    mx1 = fmaxf(mx1, __shfl_xor_sync(0xffffffffu, mx1, 1));
    mx1 = fmaxf(mx1, __shfl_xor_sync(0xffffffffu, mx1, 2));
    float sum0 = 0.f, sum1 = 0.f;
#pragma unroll
    for (int nt = 0; nt < 16; nt++) {
        s[nt][0] = __expf(sc * (s[nt][0] - mx0)); sum0 += s[nt][0];
        s[nt][1] = __expf(sc * (s[nt][1] - mx0)); sum0 += s[nt][1];
        s[nt][2] = __expf(sc * (s[nt][2] - mx1)); sum1 += s[nt][2];
        s[nt][3] = __expf(sc * (s[nt][3] - mx1)); sum1 += s[nt][3];
    }
    sum0 += __shfl_xor_sync(0xffffffffu, sum0, 1);
    sum0 += __shfl_xor_sync(0xffffffffu, sum0, 2);
    sum1 += __shfl_xor_sync(0xffffffffu, sum1, 1);
    sum1 += __shfl_xor_sync(0xffffffffu, sum1, 2);
    const float inv0 = 1.f / sum0, inv1 = 1.f / sum1;
#pragma unroll
    for (int nt = 0; nt < 16; nt++) {
        s[nt][0] *= inv0; s[nt][1] *= inv0;
        s[nt][2] *= inv1; s[nt][3] *= inv1;
    }

    float o[8][4];
#pragma unroll
    for (int dt = 0; dt < 8; dt++)
#pragma unroll
        for (int e = 0; e < 4; e++) o[dt][e] = 0.f;

#pragma unroll
    for (int jc = 0; jc < 8; jc++) {
        uint32_t pah[4];
        pah[0] = pack_h2(s[2 * jc][0],     s[2 * jc][1]);
        pah[1] = pack_h2(s[2 * jc][2],     s[2 * jc][3]);
        pah[2] = pack_h2(s[2 * jc + 1][0], s[2 * jc + 1][1]);
        pah[3] = pack_h2(s[2 * jc + 1][2], s[2 * jc + 1][3]);
        const int jrow = jc * 16 + (lane & 7) + ((lane >> 3) & 1) * 8;
#pragma unroll
        for (int dg = 0; dg < 2; dg++) {
            uint32_t bh[4][2];
#pragma unroll
            for (int dpp = 0; dpp < 2; dpp++) {
                const int dt0 = dg * 4 + dpp * 2;
                const int dcol = dt0 * 8 + ((lane >> 4) & 1) * 8;
                ldsm4t(bh[dpp*2][0], bh[dpp*2][1], bh[dpp*2+1][0], bh[dpp*2+1][1],
                       smem_u32(svh + jrow * 72 + dcol));
            }
#pragma unroll
            for (int t = 0; t < 4; t++) mma16816(o[dg * 4 + t], pah, bh[t]);
        }
    }

    const int g = lane >> 2, tg = lane & 3;
    const int r0 = m0 + g, r1 = r0 + 8;
#pragma unroll
    for (int dt = 0; dt < 8; dt++) {
        const int d = head * 64 + dt * 8 + tg * 2;
        const size_t b0 = ((size_t)(r0 * MSAW + wi)) * INNER + d;
        const size_t b1 = ((size_t)(r1 * MSAW + wi)) * INNER + d;
        *(uint32_t*)(oh + b0) = pack_h2(o[dt][0], o[dt][1]);
        *(uint32_t*)(oh + b1) = pack_h2(o[dt][2], o[dt][3]);
    }
}

// ============= fused attention: dots tiles (blocks 0..127) + col attn (128..2175) =============
__global__ __launch_bounds__(256, 2)
void attn_fused(const hf* __restrict__ q1h, const hf* __restrict__ kv1h,
                const hf* __restrict__ q2h, const hf* __restrict__ kv2h,
                hf* __restrict__ o1h,
                float* __restrict__ Pp)
{
    const int b = blockIdx.x;
    if (b < 128) {
        const int j0 = (b & 1) * 128, i0 = ((b >> 1) & 1) * 128;
        const int z = b >> 2;
        const int h = z >> 2, s = z & 3;
        const size_t r0 = (size_t)s * 32;
        const size_t aoff = (size_t)h * 64 + (size_t)i0 * INNER + r0 * MSAW * INNER;
        const size_t boff = (size_t)h * 64 + (size_t)j0 * 2 * INNER + r0 * MSAW * 2 * INNER;
        gemm_core5<2, 4, 0, 0, 32, 3>(q2h + aoff, INNER, (size_t)MSAW * INNER,
                                      kv2h + boff, 2 * INNER, (size_t)MSAW * 2 * INNER,
                                      Pp + (size_t)z * (MSAW * MSAW) + (size_t)i0 * MSAW + j0,
                                      nullptr, MSAW, 32 * 64);
    } else {
        const int cb = b - 128;
        col_attn_body(cb & 255, cb >> 8, q1h, kv1h, o1h);
    }
}

// ============= reduce 4 dots partials + scale + softmax -> fp16 plane =============
__global__ __launch_bounds__(256)
void softmax_reduce2(const float* __restrict__ Pp, hf* __restrict__ Ph)
{
    const int h = blockIdx.x >> 8, i = blockIdx.x & 255;
    const int tid = threadIdx.x;
    __shared__ float red[34];
    float v = 0.f;
#pragma unroll
    for (int s = 0; s < 4; s++)
        v += Pp[((size_t)(h * 4 + s) * MSAW + i) * MSAW + tid];
    v *= 0.011048543456039806f;  // (1/8) * 128^-0.5

    float m = v;
#pragma unroll
    for (int o = 16; o; o >>= 1) m = fmaxf(m, __shfl_xor_sync(0xffffffffu, m, o));
    if ((tid & 31) == 0) red[tid >> 5] = m;
    __syncthreads();
    if (tid == 0) {
        float mm = red[0];
#pragma unroll
        for (int w = 1; w < 8; w++) mm = fmaxf(mm, red[w]);
        red[32] = mm;
    }
    __syncthreads();
    const float e = __expf(v - red[32]);
    float s = e;
#pragma unroll
    for (int o = 16; o; o >>= 1) s += __shfl_xor_sync(0xffffffffu, s, o);
    if ((tid & 31) == 0) red[8 + (tid >> 5)] = s;
    __syncthreads();
    if (tid == 0) {
        float ss = 0.f;
#pragma unroll
        for (int w = 0; w < 8; w++) ss += red[8 + w];
        red[33] = 1.f / ss;
    }
    __syncthreads();
    Ph[((size_t)h * MSAW + i) * MSAW + tid] = __float2half_rn(e * red[33]);
}

// =============================== launch ===============================
extern "C" void kernel_launch(void* const* d_in, const int* in_sizes, int n_in,
                              void* d_out, int out_size)
{
    const float* x      = (const float*)d_in[0];
    const float* wq_w   = (const float*)d_in[1];
    const float* wkv_w  = (const float*)d_in[2];
    const float* wout_w = (const float*)d_in[3];
    const float* wout_b = (const float*)d_in[4];
    const float* hq_w   = (const float*)d_in[5];
    const float* hkv_w  = (const float*)d_in[6];
    const float* hout_w = (const float*)d_in[7];
    const float* hout_b = (const float*)d_in[8];
    float* out = (float*)d_out;

    void* p;
    hf *xh, *wqh, *wkvh, *hqh, *hkvh, *wouth, *houth;
    hf *q1h, *kv1h, *q2h, *kv2h;
    hf *o1h, *o2h, *p2h;
    float* Pp;
    cudaGetSymbolAddress(&p, g_xh);    xh = (hf*)p;
    cudaGetSymbolAddress(&p, g_wqh);   wqh = (hf*)p;
    cudaGetSymbolAddress(&p, g_wkvh);  wkvh = (hf*)p;
    cudaGetSymbolAddress(&p, g_hqh);   hqh = (hf*)p;
    cudaGetSymbolAddress(&p, g_hkvh);  hkvh = (hf*)p;
    cudaGetSymbolAddress(&p, g_wouth); wouth = (hf*)p;
    cudaGetSymbolAddress(&p, g_houth); houth = (hf*)p;
    cudaGetSymbolAddress(&p, g_q1h);   q1h = (hf*)p;
    cudaGetSymbolAddress(&p, g_kv1h);  kv1h = (hf*)p;
    cudaGetSymbolAddress(&p, g_q2h);   q2h = (hf*)p;
    cudaGetSymbolAddress(&p, g_kv2h);  kv2h = (hf*)p;
    cudaGetSymbolAddress(&p, g_o1h);   o1h = (hf*)p;
    cudaGetSymbolAddress(&p, g_o2h);   o2h = (hf*)p;
    cudaGetSymbolAddress(&p, g_p2h);   p2h = (hf*)p;
    cudaGetSymbolAddress(&p, g_Pp);    Pp = (float*)p;

    cudaFuncSetAttribute(gemm_proj_all,  cudaFuncAttributeMaxDynamicSharedMemorySize, SM_PROJ);
    cudaFuncSetAttribute(gemm_out_fused, cudaFuncAttributeMaxDynamicSharedMemorySize, SM_PROJ);
    cudaFuncSetAttribute(gemm_av2,       cudaFuncAttributeMaxDynamicSharedMemorySize, SM_AV);
    cudaFuncSetAttribute(attn_fused,     cudaFuncAttributeMaxDynamicSharedMemorySize, ATTN_SMEM);

    split_all<<<8192 + 1024, 256>>>(x, wq_w, wkv_w, hq_w, hkv_w, wout_w, hout_w,
                                    xh, wqh, wkvh, hqh, hkvh, wouth, houth);

    gemm_proj_all<<<dim3(12, NTOK / 128, 2), 128, SM_PROJ>>>(
        xh, wqh, wkvh, hqh, hkvh, q1h, kv1h, q2h, kv2h);

    attn_fused<<<128 + MSAW * HEADS, 256, ATTN_SMEM>>>(
        q1h, kv1h, q2h, kv2h, o1h, Pp);

    softmax_reduce2<<<HEADS * MSAW, 256>>>(Pp, p2h);
    gemm_av2<<<dim3(2, HEADS, MSAH), 128, SM_AV>>>(p2h, kv2h, o2h);

    gemm_out_fused<<<dim3(2, NTOK / 128), 128, SM_PROJ>>>(
        o1h, o2h, wouth, houth, out, wout_b, hout_b);
}